// round 2
// baseline (speedup 1.0000x reference)
#include <cuda_runtime.h>
#include <cuda_bf16.h>
#include <math.h>

// Problem constants
#define B_  2
#define S_  2048
#define D_  1024
#define H_  16
#define DH_ 64
#define SCALE_ 0.125f   // DH^-0.5

// Scratch (static device globals; no runtime allocation)
__device__ float g_q[(size_t)B_ * S_ * D_];
__device__ float g_k[(size_t)B_ * S_ * D_];
__device__ float g_v[(size_t)B_ * S_ * D_];
__device__ float g_ctx[(size_t)B_ * S_ * D_];
__device__ float g_attn_raw[(size_t)B_ * H_ * S_ * S_];     // P = exp(s - m_kt)
__device__ float g_mkt[(size_t)B_ * H_ * (S_ / 128) * S_];  // running max per (bh, kt, row)
__device__ float g_stats[(size_t)B_ * H_ * S_ * 2];         // (m_final, l_final)

// ---------------------------------------------------------------------------
// Fast exp via FFMA pipe (avoids MUFU bottleneck). x <= ~0; rel err ~1e-7.
// ---------------------------------------------------------------------------
__device__ __forceinline__ float fexp(float x) {
    float t = x * 1.4426950408889634f;      // log2(e)
    t = fmaxf(t, -125.0f);                  // flush huge negatives to ~0
    float ti = rintf(t);
    float f  = t - ti;                      // f in [-0.5, 0.5]
    float p  = 1.5252734e-05f;
    p = fmaf(p, f, 1.5403530e-04f);
    p = fmaf(p, f, 1.3333558e-03f);
    p = fmaf(p, f, 9.6181291e-03f);
    p = fmaf(p, f, 5.5504109e-02f);
    p = fmaf(p, f, 2.4022651e-01f);
    p = fmaf(p, f, 6.9314718e-01f);
    p = fmaf(p, f, 1.0f);
    float sc = __int_as_float(((int)ti + 127) << 23);
    return p * sc;
}

// ---------------------------------------------------------------------------
// fp32 GEMM: C[M,N] = A[M,K] @ B[N,K]^T + bias[N]. 128x128 tile, BK=8,
// 256 threads, 8x8 microtile, register prefetch of next K-slab.
// ---------------------------------------------------------------------------
__global__ __launch_bounds__(256) void gemm_abt_bias(
    const float* __restrict__ A, const float* __restrict__ Bm,
    const float* __restrict__ bias, float* __restrict__ C,
    int M, int N, int K)
{
    __shared__ float As[8][128];
    __shared__ float Bs[8][128];
    const int t  = threadIdx.x;
    const int tx = t & 15, ty = t >> 4;
    const int bm = blockIdx.y * 128, bn = blockIdx.x * 128;
    const int lr = t >> 1, lc = (t & 1) << 2;

    const float* Ag = A  + (size_t)(bm + lr) * K + lc;
    const float* Bg = Bm + (size_t)(bn + lr) * K + lc;

    float acc[8][8];
#pragma unroll
    for (int i = 0; i < 8; i++)
#pragma unroll
        for (int j = 0; j < 8; j++) acc[i][j] = 0.f;

    float4 av = *(const float4*)(Ag);
    float4 bv = *(const float4*)(Bg);

    for (int k0 = 0; k0 < K; k0 += 8) {
        __syncthreads();
        As[lc + 0][lr] = av.x; As[lc + 1][lr] = av.y;
        As[lc + 2][lr] = av.z; As[lc + 3][lr] = av.w;
        Bs[lc + 0][lr] = bv.x; Bs[lc + 1][lr] = bv.y;
        Bs[lc + 2][lr] = bv.z; Bs[lc + 3][lr] = bv.w;
        __syncthreads();
        if (k0 + 8 < K) {                // prefetch next slab (overlaps compute)
            av = *(const float4*)(Ag + k0 + 8);
            bv = *(const float4*)(Bg + k0 + 8);
        }
#pragma unroll
        for (int kk = 0; kk < 8; kk++) {
            float a[8], b[8];
            *(float4*)(a)     = *(const float4*)&As[kk][ty * 4];
            *(float4*)(a + 4) = *(const float4*)&As[kk][64 + ty * 4];
            *(float4*)(b)     = *(const float4*)&Bs[kk][tx * 4];
            *(float4*)(b + 4) = *(const float4*)&Bs[kk][64 + tx * 4];
#pragma unroll
            for (int i = 0; i < 8; i++)
#pragma unroll
                for (int j = 0; j < 8; j++) acc[i][j] += a[i] * b[j];
        }
    }

#pragma unroll
    for (int ib = 0; ib < 2; ib++)
#pragma unroll
        for (int ii = 0; ii < 4; ii++) {
            const int m = bm + ib * 64 + ty * 4 + ii;
#pragma unroll
            for (int jb = 0; jb < 2; jb++) {
                const int n = bn + jb * 64 + tx * 4;
                float4 o;
                o.x = acc[ib * 4 + ii][jb * 4 + 0] + bias[n + 0];
                o.y = acc[ib * 4 + ii][jb * 4 + 1] + bias[n + 1];
                o.z = acc[ib * 4 + ii][jb * 4 + 2] + bias[n + 2];
                o.w = acc[ib * 4 + ii][jb * 4 + 3] + bias[n + 3];
                *(float4*)&C[(size_t)m * N + n] = o;
            }
        }
}

// ---------------------------------------------------------------------------
// Fused flash attention pass: per (bh, 128-row q tile).
//   - QK^T 128x128 tile (GEMM-grade microtile)
//   - mask + scale, online softmax (poly exp), running rescale of O
//   - stores P = exp(s - m_kt) to global + m_kt per (row, kt)
//   - accumulates O = P @ V; final O/l -> ctx; (m,l) -> stats
// Smem layout (dynamic, ~166KB): Qs[64][132] Ks[64][132] Vs[128][68] Ps[128][132]
// ---------------------------------------------------------------------------
#define QP 132
#define VP 68
#define FLASH_SMEM ((64*132 + 64*132 + 128*68 + 128*132) * 4)

__global__ __launch_bounds__(256, 1) void flash_kernel(
    const float* __restrict__ q, const float* __restrict__ kmat,
    const float* __restrict__ v, const int* __restrict__ mask,
    float* __restrict__ Praw, float* __restrict__ mkt,
    float* __restrict__ stats, float* __restrict__ ctx)
{
    extern __shared__ float sm[];
    float* Qs = sm;                    // [64][132]  (dh-major)
    float* Ks = Qs + 64 * QP;          // [64][132]
    float* Vs = Ks + 64 * QP;          // [128][68]
    float* Ps = Vs + 128 * VP;         // [128][132] (k-major)

    const int t  = threadIdx.x;
    const int tx = t & 15, ty = t >> 4;
    const int bh = blockIdx.y;
    const int b  = bh >> 4, h = bh & 15;
    const int q0 = blockIdx.x * 128;

    // Load Q tile transposed: Qs[c][row]
    for (int i = t; i < 128 * 16; i += 256) {
        const int row = i >> 4, c = (i & 15) << 2;
        float4 vv = *(const float4*)&q[(((size_t)(b * S_ + q0 + row)) * H_ + h) * DH_ + c];
        Qs[(c + 0) * QP + row] = vv.x; Qs[(c + 1) * QP + row] = vv.y;
        Qs[(c + 2) * QP + row] = vv.z; Qs[(c + 3) * QP + row] = vv.w;
    }

    float O[8][4];
    float mr[8], lr[8];
#pragma unroll
    for (int i = 0; i < 8; i++) {
        mr[i] = -1e30f; lr[i] = 0.f;
#pragma unroll
        for (int c = 0; c < 4; c++) O[i][c] = 0.f;
    }

    for (int kt = 0; kt < S_ / 128; kt++) {
        const int k0 = kt * 128;
        __syncthreads();   // prior iteration's readers of Ks/Vs/Ps done
        for (int i = t; i < 128 * 16; i += 256) {
            const int row = i >> 4, c = (i & 15) << 2;
            const size_t gi = (((size_t)(b * S_ + k0 + row)) * H_ + h) * DH_ + c;
            float4 kv = *(const float4*)&kmat[gi];
            Ks[(c + 0) * QP + row] = kv.x; Ks[(c + 1) * QP + row] = kv.y;
            Ks[(c + 2) * QP + row] = kv.z; Ks[(c + 3) * QP + row] = kv.w;
            float4 vv = *(const float4*)&v[gi];
            *(float4*)&Vs[row * VP + c] = vv;
        }
        __syncthreads();

        // --- QK^T microtile: 8x8 per thread ---
        float acc[8][8];
#pragma unroll
        for (int i = 0; i < 8; i++)
#pragma unroll
            for (int j = 0; j < 8; j++) acc[i][j] = 0.f;
#pragma unroll 8
        for (int kk = 0; kk < 64; kk++) {
            float a[8], bb[8];
            *(float4*)(a)      = *(const float4*)&Qs[kk * QP + ty * 4];
            *(float4*)(a + 4)  = *(const float4*)&Qs[kk * QP + 64 + ty * 4];
            *(float4*)(bb)     = *(const float4*)&Ks[kk * QP + tx * 4];
            *(float4*)(bb + 4) = *(const float4*)&Ks[kk * QP + 64 + tx * 4];
#pragma unroll
            for (int i = 0; i < 8; i++)
#pragma unroll
                for (int j = 0; j < 8; j++) acc[i][j] += a[i] * bb[j];
        }

        // --- scale + mask ---
#pragma unroll
        for (int i = 0; i < 8; i++) {
            const int lrow = (i < 4) ? (ty * 4 + i) : (64 + ty * 4 + (i - 4));
            const int* mrow = &mask[((size_t)b * S_ + q0 + lrow) * S_ + k0];
            int4 m0 = *(const int4*)(mrow + tx * 4);
            int4 m1 = *(const int4*)(mrow + 64 + tx * 4);
            acc[i][0] = (m0.x == 0) ? -1e9f : acc[i][0] * SCALE_;
            acc[i][1] = (m0.y == 0) ? -1e9f : acc[i][1] * SCALE_;
            acc[i][2] = (m0.z == 0) ? -1e9f : acc[i][2] * SCALE_;
            acc[i][3] = (m0.w == 0) ? -1e9f : acc[i][3] * SCALE_;
            acc[i][4] = (m1.x == 0) ? -1e9f : acc[i][4] * SCALE_;
            acc[i][5] = (m1.y == 0) ? -1e9f : acc[i][5] * SCALE_;
            acc[i][6] = (m1.z == 0) ? -1e9f : acc[i][6] * SCALE_;
            acc[i][7] = (m1.w == 0) ? -1e9f : acc[i][7] * SCALE_;
        }

        // --- online softmax update (row reduce across 16 tx lanes) ---
#pragma unroll
        for (int i = 0; i < 8; i++) {
            float rm = acc[i][0];
#pragma unroll
            for (int j = 1; j < 8; j++) rm = fmaxf(rm, acc[i][j]);
            rm = fmaxf(rm, __shfl_xor_sync(0xffffffffu, rm, 1));
            rm = fmaxf(rm, __shfl_xor_sync(0xffffffffu, rm, 2));
            rm = fmaxf(rm, __shfl_xor_sync(0xffffffffu, rm, 4));
            rm = fmaxf(rm, __shfl_xor_sync(0xffffffffu, rm, 8));
            const float mn  = fmaxf(mr[i], rm);
            const float fct = fexp(mr[i] - mn);
            float rs = 0.f;
#pragma unroll
            for (int j = 0; j < 8; j++) {
                acc[i][j] = fexp(acc[i][j] - mn);
                rs += acc[i][j];
            }
            rs += __shfl_xor_sync(0xffffffffu, rs, 1);
            rs += __shfl_xor_sync(0xffffffffu, rs, 2);
            rs += __shfl_xor_sync(0xffffffffu, rs, 4);
            rs += __shfl_xor_sync(0xffffffffu, rs, 8);
            lr[i] = lr[i] * fct + rs;
            mr[i] = mn;
#pragma unroll
            for (int c = 0; c < 4; c++) O[i][c] *= fct;
        }

        // --- stream P to global, stash m_kt, write P^T to smem ---
#pragma unroll
        for (int i = 0; i < 8; i++) {
            const int lrow = (i < 4) ? (ty * 4 + i) : (64 + ty * 4 + (i - 4));
            const size_t gb = ((size_t)bh * S_ + q0 + lrow) * S_ + k0;
            float4 w0, w1;
            w0.x = acc[i][0]; w0.y = acc[i][1]; w0.z = acc[i][2]; w0.w = acc[i][3];
            w1.x = acc[i][4]; w1.y = acc[i][5]; w1.z = acc[i][6]; w1.w = acc[i][7];
            *(float4*)&Praw[gb + tx * 4]      = w0;
            *(float4*)&Praw[gb + 64 + tx * 4] = w1;
            if (tx == 0)
                mkt[((size_t)bh * (S_ / 128) + kt) * S_ + q0 + lrow] = mr[i];
#pragma unroll
            for (int j = 0; j < 4; j++) {
                Ps[(tx * 4 + j) * QP + lrow]      = acc[i][j];
                Ps[(64 + tx * 4 + j) * QP + lrow] = acc[i][4 + j];
            }
        }
        __syncthreads();

        // --- O += P @ V : 8 rows x 4 dcols per thread ---
#pragma unroll 8
        for (int kk = 0; kk < 128; kk++) {
            float a[8];
            *(float4*)(a)     = *(const float4*)&Ps[kk * QP + ty * 4];
            *(float4*)(a + 4) = *(const float4*)&Ps[kk * QP + 64 + ty * 4];
            const float4 bv = *(const float4*)&Vs[kk * VP + tx * 4];
#pragma unroll
            for (int i = 0; i < 8; i++) {
                O[i][0] += a[i] * bv.x;
                O[i][1] += a[i] * bv.y;
                O[i][2] += a[i] * bv.z;
                O[i][3] += a[i] * bv.w;
            }
        }
    }

    // --- epilogue: normalize O, write ctx + stats ---
#pragma unroll
    for (int i = 0; i < 8; i++) {
        const int lrow = (i < 4) ? (ty * 4 + i) : (64 + ty * 4 + (i - 4));
        const float inv = 1.0f / lr[i];
        float4 o;
        o.x = O[i][0] * inv; o.y = O[i][1] * inv;
        o.z = O[i][2] * inv; o.w = O[i][3] * inv;
        *(float4*)&ctx[(((size_t)(b * S_ + q0 + lrow)) * H_ + h) * DH_ + tx * 4] = o;
        if (tx == 0) {
            const size_t si = ((size_t)bh * S_ + q0 + lrow) * 2;
            stats[si]     = mr[i];
            stats[si + 1] = lr[i];
        }
    }
}

// ---------------------------------------------------------------------------
// Pass 2: attn = P * exp(m_kt - m_final) / l_final  (pure memory, no MUFU)
// One block per (bh, q-row); 256 threads x 8 floats = 2048 cols.
// ---------------------------------------------------------------------------
__global__ __launch_bounds__(256) void normalize_kernel(
    const float* __restrict__ P, const float* __restrict__ mkt,
    const float* __restrict__ stats, float* __restrict__ attn)
{
    __shared__ float corr[16];
    const int t   = threadIdx.x;
    const int row = blockIdx.x;
    const int bh  = blockIdx.y;

    const size_t si = ((size_t)bh * S_ + row) * 2;
    const float m_f = stats[si];
    const float inv_l = 1.0f / stats[si + 1];
    if (t < 16)
        corr[t] = fexp(mkt[((size_t)bh * 16 + t) * S_ + row] - m_f) * inv_l;
    __syncthreads();

    const size_t base = ((size_t)bh * S_ + row) * S_;
    const float c = corr[t >> 4];               // 8 floats stay inside one kt
    float4 v0 = *(const float4*)&P[base + t * 8];
    float4 v1 = *(const float4*)&P[base + t * 8 + 4];
    v0.x *= c; v0.y *= c; v0.z *= c; v0.w *= c;
    v1.x *= c; v1.y *= c; v1.z *= c; v1.w *= c;
    *(float4*)&attn[base + t * 8]     = v0;
    *(float4*)&attn[base + t * 8 + 4] = v1;
}

// ---------------------------------------------------------------------------
extern "C" void kernel_launch(void* const* d_in, const int* in_sizes, int n_in,
                              void* d_out, int out_size)
{
    const float* x    = (const float*)d_in[0];
    const int*   mask = (const int*)  d_in[1];
    const float* wq_w = (const float*)d_in[2];
    const float* wq_b = (const float*)d_in[3];
    const float* wk_w = (const float*)d_in[4];
    const float* wk_b = (const float*)d_in[5];
    const float* wv_w = (const float*)d_in[6];
    const float* wv_b = (const float*)d_in[7];
    const float* wo_w = (const float*)d_in[8];
    const float* wo_b = (const float*)d_in[9];

    float *q, *k, *v, *ctx, *attn_raw, *mkt, *stats;
    cudaGetSymbolAddress((void**)&q,        g_q);
    cudaGetSymbolAddress((void**)&k,        g_k);
    cudaGetSymbolAddress((void**)&v,        g_v);
    cudaGetSymbolAddress((void**)&ctx,      g_ctx);
    cudaGetSymbolAddress((void**)&attn_raw, g_attn_raw);
    cudaGetSymbolAddress((void**)&mkt,      g_mkt);
    cudaGetSymbolAddress((void**)&stats,    g_stats);

    const long long CTXSZ = (long long)B_ * S_ * D_;           // 4194304
    const long long ATTSZ = (long long)B_ * H_ * S_ * S_;      // 134217728

    float* out_base = (float*)d_out;
    float* out_ptr;
    float* attn_ptr;
    if ((long long)out_size >= CTXSZ + ATTSZ) {
        out_ptr  = out_base;
        attn_ptr = out_base + CTXSZ;
    } else if ((long long)out_size == ATTSZ) {
        out_ptr  = q;            // projection result unused, dump in scratch
        attn_ptr = out_base;
    } else {
        out_ptr  = out_base;
        attn_ptr = attn_raw;     // in-place (same-thread read-modify-write)
    }

    cudaFuncSetAttribute(flash_kernel,
                         cudaFuncAttributeMaxDynamicSharedMemorySize, FLASH_SMEM);

    const int M = B_ * S_;   // 4096
    const int N = D_;        // 1024
    const int K = D_;        // 1024
    dim3 gGrid(N / 128, M / 128);

    gemm_abt_bias<<<gGrid, 256>>>(x, wq_w, wq_b, q, M, N, K);
    gemm_abt_bias<<<gGrid, 256>>>(x, wk_w, wk_b, k, M, N, K);
    gemm_abt_bias<<<gGrid, 256>>>(x, wv_w, wv_b, v, M, N, K);

    dim3 fGrid(S_ / 128, B_ * H_);
    flash_kernel<<<fGrid, 256, FLASH_SMEM>>>(q, k, v, mask, attn_raw, mkt, stats, ctx);

    gemm_abt_bias<<<gGrid, 256>>>(ctx, wo_w, wo_b, out_ptr, M, N, K);

    dim3 nGrid(S_, B_ * H_);
    normalize_kernel<<<nGrid, 256>>>(attn_raw, mkt, stats, attn_ptr);
}

// round 3
// speedup vs baseline: 1.1086x; 1.1086x over previous
#include <cuda_runtime.h>
#include <cuda_bf16.h>
#include <math.h>

// Problem constants
#define B_  2
#define S_  2048
#define D_  1024
#define H_  16
#define DH_ 64
#define SCALE_ 0.125f   // DH^-0.5

typedef unsigned long long u64;

// Scratch (static device globals; no runtime allocation)
__device__ float g_q[(size_t)B_ * S_ * D_];
__device__ float g_k[(size_t)B_ * S_ * D_];
__device__ float g_v[(size_t)B_ * S_ * D_];
__device__ float g_ctx[(size_t)B_ * S_ * D_];
__device__ float g_attn_raw[(size_t)B_ * H_ * S_ * S_];     // P = exp(s - m_kt)
__device__ float g_mkt[(size_t)B_ * H_ * (S_ / 128) * S_];  // running max per (bh, kt, row)
__device__ float g_stats[(size_t)B_ * H_ * S_ * 2];         // (m_final, l_final)

// ---------------------------------------------------------------------------
// Packed f32x2 helpers (sm_103a FFMA2 path — 2x fp32 FLOP per issue)
// ---------------------------------------------------------------------------
__device__ __forceinline__ u64 f2pack(float x, float y) {
    u64 r; asm("mov.b64 %0, {%1, %2};" : "=l"(r) : "f"(x), "f"(y)); return r;
}
__device__ __forceinline__ void ffma2(u64& d, u64 a, u64 b) {
    asm("fma.rn.f32x2 %0, %1, %2, %0;" : "+l"(d) : "l"(a), "l"(b));
}
__device__ __forceinline__ void fmul2(u64& d, u64 a, u64 b) {
    asm("mul.rn.f32x2 %0, %1, %2;" : "=l"(d) : "l"(a), "l"(b));
}
__device__ __forceinline__ float2 f2unpack(u64 v) {
    float2 r; asm("mov.b64 {%0, %1}, %2;" : "=f"(r.x), "=f"(r.y) : "l"(v)); return r;
}

// ---------------------------------------------------------------------------
// Fast exp via FFMA pipe (avoids MUFU bottleneck). rel err ~1e-7.
// ---------------------------------------------------------------------------
__device__ __forceinline__ float fexp(float x) {
    float t = x * 1.4426950408889634f;
    t = fmaxf(t, -125.0f);
    float ti = rintf(t);
    float f  = t - ti;
    float p  = 1.5252734e-05f;
    p = fmaf(p, f, 1.5403530e-04f);
    p = fmaf(p, f, 1.3333558e-03f);
    p = fmaf(p, f, 9.6181291e-03f);
    p = fmaf(p, f, 5.5504109e-02f);
    p = fmaf(p, f, 2.4022651e-01f);
    p = fmaf(p, f, 6.9314718e-01f);
    p = fmaf(p, f, 1.0f);
    float sc = __int_as_float(((int)ti + 127) << 23);
    return p * sc;
}

// ---------------------------------------------------------------------------
// fp32 GEMM (FFMA2): C[M,N] = A[M,K] @ B[N,K]^T + bias[N]. 128x128 tile, BK=8,
// 256 threads, 8x8 microtile as 8x4 f32x2 pairs, register prefetch.
// ---------------------------------------------------------------------------
__global__ __launch_bounds__(256) void gemm_abt_bias(
    const float* __restrict__ A, const float* __restrict__ Bm,
    const float* __restrict__ bias, float* __restrict__ C,
    int M, int N, int K)
{
    __shared__ float As[8][128];
    __shared__ float Bs[8][128];
    const int t  = threadIdx.x;
    const int tx = t & 15, ty = t >> 4;
    const int bm = blockIdx.y * 128, bn = blockIdx.x * 128;
    const int lr = t >> 1, lc = (t & 1) << 2;

    const float* Ag = A  + (size_t)(bm + lr) * K + lc;
    const float* Bg = Bm + (size_t)(bn + lr) * K + lc;

    u64 acc2[8][4];
    const u64 z = f2pack(0.f, 0.f);
#pragma unroll
    for (int i = 0; i < 8; i++)
#pragma unroll
        for (int j = 0; j < 4; j++) acc2[i][j] = z;

    float4 av = *(const float4*)(Ag);
    float4 bv = *(const float4*)(Bg);

    for (int k0 = 0; k0 < K; k0 += 8) {
        __syncthreads();
        As[lc + 0][lr] = av.x; As[lc + 1][lr] = av.y;
        As[lc + 2][lr] = av.z; As[lc + 3][lr] = av.w;
        Bs[lc + 0][lr] = bv.x; Bs[lc + 1][lr] = bv.y;
        Bs[lc + 2][lr] = bv.z; Bs[lc + 3][lr] = bv.w;
        __syncthreads();
        if (k0 + 8 < K) {
            av = *(const float4*)(Ag + k0 + 8);
            bv = *(const float4*)(Bg + k0 + 8);
        }
#pragma unroll
        for (int kk = 0; kk < 8; kk++) {
            float a[8];
            *(float4*)(a)     = *(const float4*)&As[kk][ty * 4];
            *(float4*)(a + 4) = *(const float4*)&As[kk][64 + ty * 4];
            u64 b2[4];
            b2[0] = *(const u64*)&Bs[kk][tx * 4];
            b2[1] = *(const u64*)&Bs[kk][tx * 4 + 2];
            b2[2] = *(const u64*)&Bs[kk][64 + tx * 4];
            b2[3] = *(const u64*)&Bs[kk][64 + tx * 4 + 2];
#pragma unroll
            for (int i = 0; i < 8; i++) {
                const u64 ad = f2pack(a[i], a[i]);
#pragma unroll
                for (int j = 0; j < 4; j++) ffma2(acc2[i][j], ad, b2[j]);
            }
        }
    }

#pragma unroll
    for (int ib = 0; ib < 2; ib++)
#pragma unroll
        for (int ii = 0; ii < 4; ii++) {
            const int m = bm + ib * 64 + ty * 4 + ii;
#pragma unroll
            for (int jb = 0; jb < 2; jb++) {
                const int n = bn + jb * 64 + tx * 4;
                const float2 p0 = f2unpack(acc2[ib * 4 + ii][jb * 2 + 0]);
                const float2 p1 = f2unpack(acc2[ib * 4 + ii][jb * 2 + 1]);
                float4 o;
                o.x = p0.x + bias[n + 0];
                o.y = p0.y + bias[n + 1];
                o.z = p1.x + bias[n + 2];
                o.w = p1.y + bias[n + 3];
                *(float4*)&C[(size_t)m * N + n] = o;
            }
        }
}

// ---------------------------------------------------------------------------
// Fused flash attention pass (FFMA2): per (bh, 128-row q tile).
// ---------------------------------------------------------------------------
#define QP 132
#define VP 68
#define FLASH_SMEM ((64*132 + 64*132 + 128*68 + 128*132) * 4)

__global__ __launch_bounds__(256, 1) void flash_kernel(
    const float* __restrict__ q, const float* __restrict__ kmat,
    const float* __restrict__ v, const int* __restrict__ mask,
    float* __restrict__ Praw, float* __restrict__ mkt,
    float* __restrict__ stats, float* __restrict__ ctx)
{
    extern __shared__ float sm[];
    float* Qs = sm;                    // [64][132]  (dh-major, transposed)
    float* Ks = Qs + 64 * QP;          // [64][132]
    float* Vs = Ks + 64 * QP;          // [128][68]
    float* Ps = Vs + 128 * VP;         // [128][132] (k-major)

    const int t  = threadIdx.x;
    const int tx = t & 15, ty = t >> 4;
    const int bh = blockIdx.y;
    const int b  = bh >> 4, h = bh & 15;
    const int q0 = blockIdx.x * 128;

    for (int i = t; i < 128 * 16; i += 256) {
        const int row = i >> 4, c = (i & 15) << 2;
        float4 vv = *(const float4*)&q[(((size_t)(b * S_ + q0 + row)) * H_ + h) * DH_ + c];
        Qs[(c + 0) * QP + row] = vv.x; Qs[(c + 1) * QP + row] = vv.y;
        Qs[(c + 2) * QP + row] = vv.z; Qs[(c + 3) * QP + row] = vv.w;
    }

    u64 O2[8][2];
    float mr[8], lr[8];
    const u64 z = f2pack(0.f, 0.f);
#pragma unroll
    for (int i = 0; i < 8; i++) {
        mr[i] = -1e30f; lr[i] = 0.f;
        O2[i][0] = z; O2[i][1] = z;
    }

    for (int kt = 0; kt < S_ / 128; kt++) {
        const int k0 = kt * 128;
        __syncthreads();
        for (int i = t; i < 128 * 16; i += 256) {
            const int row = i >> 4, c = (i & 15) << 2;
            const size_t gi = (((size_t)(b * S_ + k0 + row)) * H_ + h) * DH_ + c;
            float4 kv = *(const float4*)&kmat[gi];
            Ks[(c + 0) * QP + row] = kv.x; Ks[(c + 1) * QP + row] = kv.y;
            Ks[(c + 2) * QP + row] = kv.z; Ks[(c + 3) * QP + row] = kv.w;
            float4 vv = *(const float4*)&v[gi];
            *(float4*)&Vs[row * VP + c] = vv;
        }
        __syncthreads();

        // --- QK^T microtile: 8 rows x 4 f32x2 pairs per thread ---
        u64 s2[8][4];
#pragma unroll
        for (int i = 0; i < 8; i++)
#pragma unroll
            for (int j = 0; j < 4; j++) s2[i][j] = z;
#pragma unroll 8
        for (int kk = 0; kk < 64; kk++) {
            float a[8];
            *(float4*)(a)     = *(const float4*)&Qs[kk * QP + ty * 4];
            *(float4*)(a + 4) = *(const float4*)&Qs[kk * QP + 64 + ty * 4];
            u64 b2[4];
            b2[0] = *(const u64*)&Ks[kk * QP + tx * 4];
            b2[1] = *(const u64*)&Ks[kk * QP + tx * 4 + 2];
            b2[2] = *(const u64*)&Ks[kk * QP + 64 + tx * 4];
            b2[3] = *(const u64*)&Ks[kk * QP + 64 + tx * 4 + 2];
#pragma unroll
            for (int i = 0; i < 8; i++) {
                const u64 ad = f2pack(a[i], a[i]);
#pragma unroll
                for (int j = 0; j < 4; j++) ffma2(s2[i][j], ad, b2[j]);
            }
        }

        // unpack -> acc[8][8]
        float acc[8][8];
#pragma unroll
        for (int i = 0; i < 8; i++)
#pragma unroll
            for (int j = 0; j < 4; j++) {
                const float2 p = f2unpack(s2[i][j]);
                acc[i][j * 2] = p.x; acc[i][j * 2 + 1] = p.y;
            }

        // --- scale + mask ---
#pragma unroll
        for (int i = 0; i < 8; i++) {
            const int lrow = (i < 4) ? (ty * 4 + i) : (64 + ty * 4 + (i - 4));
            const int* mrow = &mask[((size_t)b * S_ + q0 + lrow) * S_ + k0];
            int4 m0 = *(const int4*)(mrow + tx * 4);
            int4 m1 = *(const int4*)(mrow + 64 + tx * 4);
            acc[i][0] = (m0.x == 0) ? -1e9f : acc[i][0] * SCALE_;
            acc[i][1] = (m0.y == 0) ? -1e9f : acc[i][1] * SCALE_;
            acc[i][2] = (m0.z == 0) ? -1e9f : acc[i][2] * SCALE_;
            acc[i][3] = (m0.w == 0) ? -1e9f : acc[i][3] * SCALE_;
            acc[i][4] = (m1.x == 0) ? -1e9f : acc[i][4] * SCALE_;
            acc[i][5] = (m1.y == 0) ? -1e9f : acc[i][5] * SCALE_;
            acc[i][6] = (m1.z == 0) ? -1e9f : acc[i][6] * SCALE_;
            acc[i][7] = (m1.w == 0) ? -1e9f : acc[i][7] * SCALE_;
        }

        // --- online softmax ---
#pragma unroll
        for (int i = 0; i < 8; i++) {
            float rm = acc[i][0];
#pragma unroll
            for (int j = 1; j < 8; j++) rm = fmaxf(rm, acc[i][j]);
            rm = fmaxf(rm, __shfl_xor_sync(0xffffffffu, rm, 1));
            rm = fmaxf(rm, __shfl_xor_sync(0xffffffffu, rm, 2));
            rm = fmaxf(rm, __shfl_xor_sync(0xffffffffu, rm, 4));
            rm = fmaxf(rm, __shfl_xor_sync(0xffffffffu, rm, 8));
            const float mn  = fmaxf(mr[i], rm);
            const float fct = fexp(mr[i] - mn);
            float rs = 0.f;
#pragma unroll
            for (int j = 0; j < 8; j++) {
                acc[i][j] = fexp(acc[i][j] - mn);
                rs += acc[i][j];
            }
            rs += __shfl_xor_sync(0xffffffffu, rs, 1);
            rs += __shfl_xor_sync(0xffffffffu, rs, 2);
            rs += __shfl_xor_sync(0xffffffffu, rs, 4);
            rs += __shfl_xor_sync(0xffffffffu, rs, 8);
            lr[i] = lr[i] * fct + rs;
            mr[i] = mn;
            const u64 fd = f2pack(fct, fct);
            fmul2(O2[i][0], O2[i][0], fd);
            fmul2(O2[i][1], O2[i][1], fd);
        }

        // --- stream P to global, stash m_kt, write P^T to smem ---
#pragma unroll
        for (int i = 0; i < 8; i++) {
            const int lrow = (i < 4) ? (ty * 4 + i) : (64 + ty * 4 + (i - 4));
            const size_t gb = ((size_t)bh * S_ + q0 + lrow) * S_ + k0;
            float4 w0, w1;
            w0.x = acc[i][0]; w0.y = acc[i][1]; w0.z = acc[i][2]; w0.w = acc[i][3];
            w1.x = acc[i][4]; w1.y = acc[i][5]; w1.z = acc[i][6]; w1.w = acc[i][7];
            *(float4*)&Praw[gb + tx * 4]      = w0;
            *(float4*)&Praw[gb + 64 + tx * 4] = w1;
            if (tx == 0)
                mkt[((size_t)bh * (S_ / 128) + kt) * S_ + q0 + lrow] = mr[i];
#pragma unroll
            for (int j = 0; j < 4; j++) {
                Ps[(tx * 4 + j) * QP + lrow]      = acc[i][j];
                Ps[(64 + tx * 4 + j) * QP + lrow] = acc[i][4 + j];
            }
        }
        __syncthreads();

        // --- O += P @ V (FFMA2) ---
#pragma unroll 8
        for (int kk = 0; kk < 128; kk++) {
            float a[8];
            *(float4*)(a)     = *(const float4*)&Ps[kk * QP + ty * 4];
            *(float4*)(a + 4) = *(const float4*)&Ps[kk * QP + 64 + ty * 4];
            u64 b2[2];
            b2[0] = *(const u64*)&Vs[kk * VP + tx * 4];
            b2[1] = *(const u64*)&Vs[kk * VP + tx * 4 + 2];
#pragma unroll
            for (int i = 0; i < 8; i++) {
                const u64 ad = f2pack(a[i], a[i]);
                ffma2(O2[i][0], ad, b2[0]);
                ffma2(O2[i][1], ad, b2[1]);
            }
        }
    }

    // --- epilogue ---
#pragma unroll
    for (int i = 0; i < 8; i++) {
        const int lrow = (i < 4) ? (ty * 4 + i) : (64 + ty * 4 + (i - 4));
        const float inv = 1.0f / lr[i];
        const float2 p0 = f2unpack(O2[i][0]);
        const float2 p1 = f2unpack(O2[i][1]);
        float4 o;
        o.x = p0.x * inv; o.y = p0.y * inv;
        o.z = p1.x * inv; o.w = p1.y * inv;
        *(float4*)&ctx[(((size_t)(b * S_ + q0 + lrow)) * H_ + h) * DH_ + tx * 4] = o;
        if (tx == 0) {
            const size_t si = ((size_t)bh * S_ + q0 + lrow) * 2;
            stats[si]     = mr[i];
            stats[si + 1] = lr[i];
        }
    }
}

// ---------------------------------------------------------------------------
// Pass 2: attn = P * exp(m_kt - m_final) / l_final  (pure memory)
// ---------------------------------------------------------------------------
__global__ __launch_bounds__(256) void normalize_kernel(
    const float* __restrict__ P, const float* __restrict__ mkt,
    const float* __restrict__ stats, float* __restrict__ attn)
{
    __shared__ float corr[16];
    const int t   = threadIdx.x;
    const int row = blockIdx.x;
    const int bh  = blockIdx.y;

    const size_t si = ((size_t)bh * S_ + row) * 2;
    const float m_f = stats[si];
    const float inv_l = 1.0f / stats[si + 1];
    if (t < 16)
        corr[t] = fexp(mkt[((size_t)bh * 16 + t) * S_ + row] - m_f) * inv_l;
    __syncthreads();

    const size_t base = ((size_t)bh * S_ + row) * S_;
    const float c = corr[t >> 4];
    float4 v0 = *(const float4*)&P[base + t * 8];
    float4 v1 = *(const float4*)&P[base + t * 8 + 4];
    v0.x *= c; v0.y *= c; v0.z *= c; v0.w *= c;
    v1.x *= c; v1.y *= c; v1.z *= c; v1.w *= c;
    *(float4*)&attn[base + t * 8]     = v0;
    *(float4*)&attn[base + t * 8 + 4] = v1;
}

// ---------------------------------------------------------------------------
extern "C" void kernel_launch(void* const* d_in, const int* in_sizes, int n_in,
                              void* d_out, int out_size)
{
    const float* x    = (const float*)d_in[0];
    const int*   mask = (const int*)  d_in[1];
    const float* wq_w = (const float*)d_in[2];
    const float* wq_b = (const float*)d_in[3];
    const float* wk_w = (const float*)d_in[4];
    const float* wk_b = (const float*)d_in[5];
    const float* wv_w = (const float*)d_in[6];
    const float* wv_b = (const float*)d_in[7];
    const float* wo_w = (const float*)d_in[8];
    const float* wo_b = (const float*)d_in[9];

    float *q, *k, *v, *ctx, *attn_raw, *mkt, *stats;
    cudaGetSymbolAddress((void**)&q,        g_q);
    cudaGetSymbolAddress((void**)&k,        g_k);
    cudaGetSymbolAddress((void**)&v,        g_v);
    cudaGetSymbolAddress((void**)&ctx,      g_ctx);
    cudaGetSymbolAddress((void**)&attn_raw, g_attn_raw);
    cudaGetSymbolAddress((void**)&mkt,      g_mkt);
    cudaGetSymbolAddress((void**)&stats,    g_stats);

    const long long CTXSZ = (long long)B_ * S_ * D_;
    const long long ATTSZ = (long long)B_ * H_ * S_ * S_;

    float* out_base = (float*)d_out;
    float* out_ptr;
    float* attn_ptr;
    if ((long long)out_size >= CTXSZ + ATTSZ) {
        out_ptr  = out_base;
        attn_ptr = out_base + CTXSZ;
    } else if ((long long)out_size == ATTSZ) {
        out_ptr  = q;
        attn_ptr = out_base;
    } else {
        out_ptr  = out_base;
        attn_ptr = attn_raw;
    }

    cudaFuncSetAttribute(flash_kernel,
                         cudaFuncAttributeMaxDynamicSharedMemorySize, FLASH_SMEM);

    const int M = B_ * S_;
    const int N = D_;
    const int K = D_;
    dim3 gGrid(N / 128, M / 128);

    gemm_abt_bias<<<gGrid, 256>>>(x, wq_w, wq_b, q, M, N, K);
    gemm_abt_bias<<<gGrid, 256>>>(x, wk_w, wk_b, k, M, N, K);
    gemm_abt_bias<<<gGrid, 256>>>(x, wv_w, wv_b, v, M, N, K);

    dim3 fGrid(S_ / 128, B_ * H_);
    flash_kernel<<<fGrid, 256, FLASH_SMEM>>>(q, k, v, mask, attn_raw, mkt, stats, ctx);

    gemm_abt_bias<<<gGrid, 256>>>(ctx, wo_w, wo_b, out_ptr, M, N, K);

    dim3 nGrid(S_, B_ * H_);
    normalize_kernel<<<nGrid, 256>>>(attn_raw, mkt, stats, attn_ptr);
}

// round 5
// speedup vs baseline: 1.3849x; 1.2492x over previous
#include <cuda_runtime.h>
#include <cuda_bf16.h>
#include <math.h>
#include <stdint.h>

// Problem constants
#define B_  2
#define S_  2048
#define D_  1024
#define H_  16
#define DH_ 64
#define SCALE_ 0.125f   // DH^-0.5

typedef unsigned long long u64;

// ---------------------------------------------------------------------------
// Scratch (static device globals; no runtime allocation)
// ---------------------------------------------------------------------------
__device__ float g_q[(size_t)B_ * S_ * D_];
__device__ float g_k[(size_t)B_ * S_ * D_];
__device__ float g_v[(size_t)B_ * S_ * D_];
__device__ float g_ctx[(size_t)B_ * S_ * D_];
__device__ float g_attn_raw[(size_t)B_ * H_ * S_ * S_];
__device__ float g_mkt[(size_t)B_ * H_ * (S_ / 128) * S_];
__device__ float g_stats[(size_t)B_ * H_ * S_ * 2];

// bf16 hi/lo split operands for tensor-core GEMMs
__device__ __nv_bfloat16 g_xhi[(size_t)B_ * S_ * D_];
__device__ __nv_bfloat16 g_xlo[(size_t)B_ * S_ * D_];
__device__ __nv_bfloat16 g_chi[(size_t)B_ * S_ * D_];
__device__ __nv_bfloat16 g_clo[(size_t)B_ * S_ * D_];
__device__ __nv_bfloat16 g_wqhi[D_ * D_], g_wqlo[D_ * D_];
__device__ __nv_bfloat16 g_wkhi[D_ * D_], g_wklo[D_ * D_];
__device__ __nv_bfloat16 g_wvhi[D_ * D_], g_wvlo[D_ * D_];
__device__ __nv_bfloat16 g_wohi[D_ * D_], g_wolo[D_ * D_];

// ---------------------------------------------------------------------------
// mma.sync / ldmatrix helpers (arch-neutral tensor path, sm_80+)
// ---------------------------------------------------------------------------
__device__ __forceinline__ uint32_t smem_u32(const void* p) {
    uint32_t a;
    asm("{ .reg .u64 t; cvta.to.shared.u64 t, %1; cvt.u32.u64 %0, t; }"
        : "=r"(a) : "l"(p));
    return a;
}
__device__ __forceinline__ void ldmA4(uint32_t* a, uint32_t addr) {
    asm volatile("ldmatrix.sync.aligned.m8n8.x4.shared.b16 {%0,%1,%2,%3}, [%4];"
                 : "=r"(a[0]), "=r"(a[1]), "=r"(a[2]), "=r"(a[3]) : "r"(addr));
}
__device__ __forceinline__ void ldmB2(uint32_t* b, uint32_t addr) {
    asm volatile("ldmatrix.sync.aligned.m8n8.x2.shared.b16 {%0,%1}, [%2];"
                 : "=r"(b[0]), "=r"(b[1]) : "r"(addr));
}
__device__ __forceinline__ void mma16816(float* c, const uint32_t* a,
                                         const uint32_t* b) {
    asm volatile(
        "mma.sync.aligned.m16n8k16.row.col.f32.bf16.bf16.f32 "
        "{%0,%1,%2,%3}, {%4,%5,%6,%7}, {%8,%9}, {%0,%1,%2,%3};"
        : "+f"(c[0]), "+f"(c[1]), "+f"(c[2]), "+f"(c[3])
        : "r"(a[0]), "r"(a[1]), "r"(a[2]), "r"(a[3]), "r"(b[0]), "r"(b[1]));
}
__device__ __forceinline__ void cpasync16(uint32_t saddr, const void* gaddr) {
    asm volatile("cp.async.cg.shared.global [%0], [%1], 16;"
                 :: "r"(saddr), "l"(gaddr));
}
#define CP_COMMIT() asm volatile("cp.async.commit_group;" ::: "memory")
#define CP_WAIT0()  asm volatile("cp.async.wait_group 0;" ::: "memory")

// ---------------------------------------------------------------------------
// FFMA2 helpers + fast exp (flash kernel)
// ---------------------------------------------------------------------------
__device__ __forceinline__ u64 f2pack(float x, float y) {
    u64 r; asm("mov.b64 %0, {%1, %2};" : "=l"(r) : "f"(x), "f"(y)); return r;
}
__device__ __forceinline__ void ffma2(u64& d, u64 a, u64 b) {
    asm("fma.rn.f32x2 %0, %1, %2, %0;" : "+l"(d) : "l"(a), "l"(b));
}
__device__ __forceinline__ void fmul2(u64& d, u64 a, u64 b) {
    asm("mul.rn.f32x2 %0, %1, %2;" : "=l"(d) : "l"(a), "l"(b));
}
__device__ __forceinline__ float2 f2unpack(u64 v) {
    float2 r; asm("mov.b64 {%0, %1}, %2;" : "=f"(r.x), "=f"(r.y) : "l"(v)); return r;
}
__device__ __forceinline__ float fexp(float x) {
    float t = x * 1.4426950408889634f;
    t = fmaxf(t, -125.0f);
    float ti = rintf(t);
    float f  = t - ti;
    float p  = 1.5252734e-05f;
    p = fmaf(p, f, 1.5403530e-04f);
    p = fmaf(p, f, 1.3333558e-03f);
    p = fmaf(p, f, 9.6181291e-03f);
    p = fmaf(p, f, 5.5504109e-02f);
    p = fmaf(p, f, 2.4022651e-01f);
    p = fmaf(p, f, 6.9314718e-01f);
    p = fmaf(p, f, 1.0f);
    float sc = __int_as_float(((int)ti + 127) << 23);
    return p * sc;
}

// ---------------------------------------------------------------------------
// Split-conversion: float -> bf16 hi + bf16 lo (residual)
// ---------------------------------------------------------------------------
__global__ __launch_bounds__(256) void conv_split(
    const float4* __restrict__ src, uint2* __restrict__ hi,
    uint2* __restrict__ lo, int n4)
{
    const int i = blockIdx.x * 256 + threadIdx.x;
    if (i >= n4) return;
    const float4 v = src[i];
    const __nv_bfloat16 h0 = __float2bfloat16(v.x);
    const __nv_bfloat16 h1 = __float2bfloat16(v.y);
    const __nv_bfloat16 h2 = __float2bfloat16(v.z);
    const __nv_bfloat16 h3 = __float2bfloat16(v.w);
    const __nv_bfloat16 l0 = __float2bfloat16(v.x - __bfloat162float(h0));
    const __nv_bfloat16 l1 = __float2bfloat16(v.y - __bfloat162float(h1));
    const __nv_bfloat16 l2 = __float2bfloat16(v.z - __bfloat162float(h2));
    const __nv_bfloat16 l3 = __float2bfloat16(v.w - __bfloat162float(h3));
    uint2 ho, lu;
    ho.x = (uint32_t)__bfloat16_as_ushort(h0) | ((uint32_t)__bfloat16_as_ushort(h1) << 16);
    ho.y = (uint32_t)__bfloat16_as_ushort(h2) | ((uint32_t)__bfloat16_as_ushort(h3) << 16);
    lu.x = (uint32_t)__bfloat16_as_ushort(l0) | ((uint32_t)__bfloat16_as_ushort(l1) << 16);
    lu.y = (uint32_t)__bfloat16_as_ushort(l2) | ((uint32_t)__bfloat16_as_ushort(l3) << 16);
    hi[i] = ho;
    lo[i] = lu;
}

// ---------------------------------------------------------------------------
// Tensor-core split GEMM: C[M,N] = (Ahi+Alo)[M,K] @ (Bhi+Blo)[N,K]^T + bias
// 3 terms (hh + hl + lh). CTA 128x128, 8 warps 2(m)x4(n), warp 64x32, BK=64.
// mma.sync m16n8k16 bf16, ldmatrix from padded smem (72 bf16/row -> no
// bank conflicts), cp.async tile loads.
// ---------------------------------------------------------------------------
#define AP 72

__global__ __launch_bounds__(256) void gemm_mma_split(
    const __nv_bfloat16* __restrict__ Ahi, const __nv_bfloat16* __restrict__ Alo,
    const __nv_bfloat16* __restrict__ Bhi, const __nv_bfloat16* __restrict__ Blo,
    const float* __restrict__ bias, float* __restrict__ C,
    int M, int N, int K)
{
    __shared__ __nv_bfloat16 As[128 * AP];
    __shared__ __nv_bfloat16 Bs[128 * AP];
    const int tid  = threadIdx.x;
    const int lane = tid & 31, wid = tid >> 5;
    const int warp_m = wid >> 2, warp_n = wid & 3;
    const int bm = blockIdx.y * 128, bn = blockIdx.x * 128;

    const uint32_t sA = smem_u32(As), sB = smem_u32(Bs);
    // ldmatrix per-lane source rows/cols
    const int a_r = warp_m * 64 + (lane & 15);
    const int a_c = (lane >> 4) * 8;
    const int b_r = warp_n * 32 + (lane & 7);
    const int b_c = ((lane >> 3) & 1) * 8;

    float acc[4][4][4];
#pragma unroll
    for (int mt = 0; mt < 4; mt++)
#pragma unroll
        for (int nt = 0; nt < 4; nt++)
#pragma unroll
            for (int r = 0; r < 4; r++) acc[mt][nt][r] = 0.f;

    const __nv_bfloat16* Aops[3] = { Ahi, Ahi, Alo };
    const __nv_bfloat16* Bops[3] = { Bhi, Blo, Bhi };

    // load-loop constants: each thread copies 4x16B per tile
    const int lrow = tid >> 3;          // 0..31 base row
    const int lc8  = (tid & 7) * 8;     // bf16 col (16B chunk)

    for (int term = 0; term < 3; term++) {
        const __nv_bfloat16* A = Aops[term];
        const __nv_bfloat16* B = Bops[term];
        for (int k0 = 0; k0 < K; k0 += 64) {
            __syncthreads();
#pragma unroll
            for (int rr = 0; rr < 4; rr++) {
                const int row = lrow + rr * 32;
                cpasync16(sA + (uint32_t)(row * AP + lc8) * 2,
                          &A[(size_t)(bm + row) * K + k0 + lc8]);
                cpasync16(sB + (uint32_t)(row * AP + lc8) * 2,
                          &B[(size_t)(bn + row) * K + k0 + lc8]);
            }
            CP_COMMIT();
            CP_WAIT0();
            __syncthreads();

#pragma unroll
            for (int ks = 0; ks < 4; ks++) {
                uint32_t afr[4][4], bfr[4][2];
#pragma unroll
                for (int mt = 0; mt < 4; mt++)
                    ldmA4(afr[mt], sA + (uint32_t)((a_r + mt * 16) * AP +
                                                   ks * 16 + a_c) * 2);
#pragma unroll
                for (int nt = 0; nt < 4; nt++)
                    ldmB2(bfr[nt], sB + (uint32_t)((b_r + nt * 8) * AP +
                                                   ks * 16 + b_c) * 2);
#pragma unroll
                for (int mt = 0; mt < 4; mt++)
#pragma unroll
                    for (int nt = 0; nt < 4; nt++)
                        mma16816(acc[mt][nt], afr[mt], bfr[nt]);
            }
        }
    }

    // epilogue: c0,c1 -> (m = lane/4, n = (lane%4)*2), c2,c3 -> m+8
    const int em = bm + warp_m * 64 + (lane >> 2);
    const int en = bn + warp_n * 32 + (lane & 3) * 2;
#pragma unroll
    for (int mt = 0; mt < 4; mt++) {
#pragma unroll
        for (int nt = 0; nt < 4; nt++) {
            const int n = en + nt * 8;
            const float bx = bias[n], by = bias[n + 1];
            const int m0 = em + mt * 16;
            float2 o0, o1;
            o0.x = acc[mt][nt][0] + bx; o0.y = acc[mt][nt][1] + by;
            o1.x = acc[mt][nt][2] + bx; o1.y = acc[mt][nt][3] + by;
            *(float2*)&C[(size_t)m0 * N + n]       = o0;
            *(float2*)&C[(size_t)(m0 + 8) * N + n] = o1;
        }
    }
}

// ---------------------------------------------------------------------------
// Fused flash attention pass (FFMA2): per (bh, 128-row q tile). (unchanged)
// ---------------------------------------------------------------------------
#define QP 132
#define VP 68
#define FLASH_SMEM ((64*132 + 64*132 + 128*68 + 128*132) * 4)

__global__ __launch_bounds__(256, 1) void flash_kernel(
    const float* __restrict__ q, const float* __restrict__ kmat,
    const float* __restrict__ v, const int* __restrict__ mask,
    float* __restrict__ Praw, float* __restrict__ mkt,
    float* __restrict__ stats, float* __restrict__ ctx)
{
    extern __shared__ float sm[];
    float* Qs = sm;
    float* Ks = Qs + 64 * QP;
    float* Vs = Ks + 64 * QP;
    float* Ps = Vs + 128 * VP;

    const int t  = threadIdx.x;
    const int tx = t & 15, ty = t >> 4;
    const int bh = blockIdx.y;
    const int b  = bh >> 4, h = bh & 15;
    const int q0 = blockIdx.x * 128;

    for (int i = t; i < 128 * 16; i += 256) {
        const int row = i >> 4, c = (i & 15) << 2;
        float4 vv = *(const float4*)&q[(((size_t)(b * S_ + q0 + row)) * H_ + h) * DH_ + c];
        Qs[(c + 0) * QP + row] = vv.x; Qs[(c + 1) * QP + row] = vv.y;
        Qs[(c + 2) * QP + row] = vv.z; Qs[(c + 3) * QP + row] = vv.w;
    }

    u64 O2[8][2];
    float mr[8], lr[8];
    const u64 z = f2pack(0.f, 0.f);
#pragma unroll
    for (int i = 0; i < 8; i++) {
        mr[i] = -1e30f; lr[i] = 0.f;
        O2[i][0] = z; O2[i][1] = z;
    }

    for (int kt = 0; kt < S_ / 128; kt++) {
        const int k0 = kt * 128;
        __syncthreads();
        for (int i = t; i < 128 * 16; i += 256) {
            const int row = i >> 4, c = (i & 15) << 2;
            const size_t gi = (((size_t)(b * S_ + k0 + row)) * H_ + h) * DH_ + c;
            float4 kv = *(const float4*)&kmat[gi];
            Ks[(c + 0) * QP + row] = kv.x; Ks[(c + 1) * QP + row] = kv.y;
            Ks[(c + 2) * QP + row] = kv.z; Ks[(c + 3) * QP + row] = kv.w;
            float4 vv = *(const float4*)&v[gi];
            *(float4*)&Vs[row * VP + c] = vv;
        }
        __syncthreads();

        u64 s2[8][4];
#pragma unroll
        for (int i = 0; i < 8; i++)
#pragma unroll
            for (int j = 0; j < 4; j++) s2[i][j] = z;
#pragma unroll 8
        for (int kk = 0; kk < 64; kk++) {
            float a[8];
            *(float4*)(a)     = *(const float4*)&Qs[kk * QP + ty * 4];
            *(float4*)(a + 4) = *(const float4*)&Qs[kk * QP + 64 + ty * 4];
            u64 b2[4];
            b2[0] = *(const u64*)&Ks[kk * QP + tx * 4];
            b2[1] = *(const u64*)&Ks[kk * QP + tx * 4 + 2];
            b2[2] = *(const u64*)&Ks[kk * QP + 64 + tx * 4];
            b2[3] = *(const u64*)&Ks[kk * QP + 64 + tx * 4 + 2];
#pragma unroll
            for (int i = 0; i < 8; i++) {
                const u64 ad = f2pack(a[i], a[i]);
#pragma unroll
                for (int j = 0; j < 4; j++) ffma2(s2[i][j], ad, b2[j]);
            }
        }

        float acc[8][8];
#pragma unroll
        for (int i = 0; i < 8; i++)
#pragma unroll
            for (int j = 0; j < 4; j++) {
                const float2 p = f2unpack(s2[i][j]);
                acc[i][j * 2] = p.x; acc[i][j * 2 + 1] = p.y;
            }

#pragma unroll
        for (int i = 0; i < 8; i++) {
            const int lrow = (i < 4) ? (ty * 4 + i) : (64 + ty * 4 + (i - 4));
            const int* mrow = &mask[((size_t)b * S_ + q0 + lrow) * S_ + k0];
            int4 m0 = *(const int4*)(mrow + tx * 4);
            int4 m1 = *(const int4*)(mrow + 64 + tx * 4);
            acc[i][0] = (m0.x == 0) ? -1e9f : acc[i][0] * SCALE_;
            acc[i][1] = (m0.y == 0) ? -1e9f : acc[i][1] * SCALE_;
            acc[i][2] = (m0.z == 0) ? -1e9f : acc[i][2] * SCALE_;
            acc[i][3] = (m0.w == 0) ? -1e9f : acc[i][3] * SCALE_;
            acc[i][4] = (m1.x == 0) ? -1e9f : acc[i][4] * SCALE_;
            acc[i][5] = (m1.y == 0) ? -1e9f : acc[i][5] * SCALE_;
            acc[i][6] = (m1.z == 0) ? -1e9f : acc[i][6] * SCALE_;
            acc[i][7] = (m1.w == 0) ? -1e9f : acc[i][7] * SCALE_;
        }

#pragma unroll
        for (int i = 0; i < 8; i++) {
            float rm = acc[i][0];
#pragma unroll
            for (int j = 1; j < 8; j++) rm = fmaxf(rm, acc[i][j]);
            rm = fmaxf(rm, __shfl_xor_sync(0xffffffffu, rm, 1));
            rm = fmaxf(rm, __shfl_xor_sync(0xffffffffu, rm, 2));
            rm = fmaxf(rm, __shfl_xor_sync(0xffffffffu, rm, 4));
            rm = fmaxf(rm, __shfl_xor_sync(0xffffffffu, rm, 8));
            const float mn  = fmaxf(mr[i], rm);
            const float fct = fexp(mr[i] - mn);
            float rs = 0.f;
#pragma unroll
            for (int j = 0; j < 8; j++) {
                acc[i][j] = fexp(acc[i][j] - mn);
                rs += acc[i][j];
            }
            rs += __shfl_xor_sync(0xffffffffu, rs, 1);
            rs += __shfl_xor_sync(0xffffffffu, rs, 2);
            rs += __shfl_xor_sync(0xffffffffu, rs, 4);
            rs += __shfl_xor_sync(0xffffffffu, rs, 8);
            lr[i] = lr[i] * fct + rs;
            mr[i] = mn;
            const u64 fd = f2pack(fct, fct);
            fmul2(O2[i][0], O2[i][0], fd);
            fmul2(O2[i][1], O2[i][1], fd);
        }

#pragma unroll
        for (int i = 0; i < 8; i++) {
            const int lrow = (i < 4) ? (ty * 4 + i) : (64 + ty * 4 + (i - 4));
            const size_t gb = ((size_t)bh * S_ + q0 + lrow) * S_ + k0;
            float4 w0, w1;
            w0.x = acc[i][0]; w0.y = acc[i][1]; w0.z = acc[i][2]; w0.w = acc[i][3];
            w1.x = acc[i][4]; w1.y = acc[i][5]; w1.z = acc[i][6]; w1.w = acc[i][7];
            *(float4*)&Praw[gb + tx * 4]      = w0;
            *(float4*)&Praw[gb + 64 + tx * 4] = w1;
            if (tx == 0)
                mkt[((size_t)bh * (S_ / 128) + kt) * S_ + q0 + lrow] = mr[i];
#pragma unroll
            for (int j = 0; j < 4; j++) {
                Ps[(tx * 4 + j) * QP + lrow]      = acc[i][j];
                Ps[(64 + tx * 4 + j) * QP + lrow] = acc[i][4 + j];
            }
        }
        __syncthreads();

#pragma unroll 8
        for (int kk = 0; kk < 128; kk++) {
            float a[8];
            *(float4*)(a)     = *(const float4*)&Ps[kk * QP + ty * 4];
            *(float4*)(a + 4) = *(const float4*)&Ps[kk * QP + 64 + ty * 4];
            u64 b2[2];
            b2[0] = *(const u64*)&Vs[kk * VP + tx * 4];
            b2[1] = *(const u64*)&Vs[kk * VP + tx * 4 + 2];
#pragma unroll
            for (int i = 0; i < 8; i++) {
                const u64 ad = f2pack(a[i], a[i]);
                ffma2(O2[i][0], ad, b2[0]);
                ffma2(O2[i][1], ad, b2[1]);
            }
        }
    }

#pragma unroll
    for (int i = 0; i < 8; i++) {
        const int lrow = (i < 4) ? (ty * 4 + i) : (64 + ty * 4 + (i - 4));
        const float inv = 1.0f / lr[i];
        const float2 p0 = f2unpack(O2[i][0]);
        const float2 p1 = f2unpack(O2[i][1]);
        float4 o;
        o.x = p0.x * inv; o.y = p0.y * inv;
        o.z = p1.x * inv; o.w = p1.y * inv;
        *(float4*)&ctx[(((size_t)(b * S_ + q0 + lrow)) * H_ + h) * DH_ + tx * 4] = o;
        if (tx == 0) {
            const size_t si = ((size_t)bh * S_ + q0 + lrow) * 2;
            stats[si]     = mr[i];
            stats[si + 1] = lr[i];
        }
    }
}

// ---------------------------------------------------------------------------
// Pass 2: attn = P * exp(m_kt - m_final) / l_final  (pure memory)
// ---------------------------------------------------------------------------
__global__ __launch_bounds__(256) void normalize_kernel(
    const float* __restrict__ P, const float* __restrict__ mkt,
    const float* __restrict__ stats, float* __restrict__ attn)
{
    __shared__ float corr[16];
    const int t   = threadIdx.x;
    const int row = blockIdx.x;
    const int bh  = blockIdx.y;

    const size_t si = ((size_t)bh * S_ + row) * 2;
    const float m_f = stats[si];
    const float inv_l = 1.0f / stats[si + 1];
    if (t < 16)
        corr[t] = fexp(mkt[((size_t)bh * 16 + t) * S_ + row] - m_f) * inv_l;
    __syncthreads();

    const size_t base = ((size_t)bh * S_ + row) * S_;
    const float c = corr[t >> 4];
    float4 v0 = *(const float4*)&P[base + t * 8];
    float4 v1 = *(const float4*)&P[base + t * 8 + 4];
    v0.x *= c; v0.y *= c; v0.z *= c; v0.w *= c;
    v1.x *= c; v1.y *= c; v1.z *= c; v1.w *= c;
    *(float4*)&attn[base + t * 8]     = v0;
    *(float4*)&attn[base + t * 8 + 4] = v1;
}

// ---------------------------------------------------------------------------
extern "C" void kernel_launch(void* const* d_in, const int* in_sizes, int n_in,
                              void* d_out, int out_size)
{
    const float* x    = (const float*)d_in[0];
    const int*   mask = (const int*)  d_in[1];
    const float* wq_w = (const float*)d_in[2];
    const float* wq_b = (const float*)d_in[3];
    const float* wk_w = (const float*)d_in[4];
    const float* wk_b = (const float*)d_in[5];
    const float* wv_w = (const float*)d_in[6];
    const float* wv_b = (const float*)d_in[7];
    const float* wo_w = (const float*)d_in[8];
    const float* wo_b = (const float*)d_in[9];

    float *q, *k, *v, *ctx, *attn_raw, *mkt, *stats;
    cudaGetSymbolAddress((void**)&q,        g_q);
    cudaGetSymbolAddress((void**)&k,        g_k);
    cudaGetSymbolAddress((void**)&v,        g_v);
    cudaGetSymbolAddress((void**)&ctx,      g_ctx);
    cudaGetSymbolAddress((void**)&attn_raw, g_attn_raw);
    cudaGetSymbolAddress((void**)&mkt,      g_mkt);
    cudaGetSymbolAddress((void**)&stats,    g_stats);

    __nv_bfloat16 *xhi, *xlo, *chi, *clo;
    __nv_bfloat16 *wqhi, *wqlo, *wkhi, *wklo, *wvhi, *wvlo, *wohi, *wolo;
    cudaGetSymbolAddress((void**)&xhi, g_xhi);  cudaGetSymbolAddress((void**)&xlo, g_xlo);
    cudaGetSymbolAddress((void**)&chi, g_chi);  cudaGetSymbolAddress((void**)&clo, g_clo);
    cudaGetSymbolAddress((void**)&wqhi, g_wqhi); cudaGetSymbolAddress((void**)&wqlo, g_wqlo);
    cudaGetSymbolAddress((void**)&wkhi, g_wkhi); cudaGetSymbolAddress((void**)&wklo, g_wklo);
    cudaGetSymbolAddress((void**)&wvhi, g_wvhi); cudaGetSymbolAddress((void**)&wvlo, g_wvlo);
    cudaGetSymbolAddress((void**)&wohi, g_wohi); cudaGetSymbolAddress((void**)&wolo, g_wolo);

    const long long CTXSZ = (long long)B_ * S_ * D_;
    const long long ATTSZ = (long long)B_ * H_ * S_ * S_;

    float* out_base = (float*)d_out;
    float* out_ptr;
    float* attn_ptr;
    if ((long long)out_size >= CTXSZ + ATTSZ) {
        out_ptr  = out_base;
        attn_ptr = out_base + CTXSZ;
    } else if ((long long)out_size == ATTSZ) {
        out_ptr  = q;
        attn_ptr = out_base;
    } else {
        out_ptr  = out_base;
        attn_ptr = attn_raw;
    }

    cudaFuncSetAttribute(flash_kernel,
                         cudaFuncAttributeMaxDynamicSharedMemorySize, FLASH_SMEM);

    const int M = B_ * S_;   // 4096
    const int N = D_;        // 1024
    const int K = D_;        // 1024

    // Split conversions
    const int xn4 = (int)(CTXSZ / 4);
    const int wn4 = D_ * D_ / 4;
    conv_split<<<(xn4 + 255) / 256, 256>>>((const float4*)x, (uint2*)xhi, (uint2*)xlo, xn4);
    conv_split<<<(wn4 + 255) / 256, 256>>>((const float4*)wq_w, (uint2*)wqhi, (uint2*)wqlo, wn4);
    conv_split<<<(wn4 + 255) / 256, 256>>>((const float4*)wk_w, (uint2*)wkhi, (uint2*)wklo, wn4);
    conv_split<<<(wn4 + 255) / 256, 256>>>((const float4*)wv_w, (uint2*)wvhi, (uint2*)wvlo, wn4);
    conv_split<<<(wn4 + 255) / 256, 256>>>((const float4*)wo_w, (uint2*)wohi, (uint2*)wolo, wn4);

    // Projections on tensor cores (mma.sync path)
    dim3 gGrid(N / 128, M / 128);
    gemm_mma_split<<<gGrid, 256>>>(xhi, xlo, wqhi, wqlo, wq_b, q, M, N, K);
    gemm_mma_split<<<gGrid, 256>>>(xhi, xlo, wkhi, wklo, wk_b, k, M, N, K);
    gemm_mma_split<<<gGrid, 256>>>(xhi, xlo, wvhi, wvlo, wv_b, v, M, N, K);

    // Flash attention
    dim3 fGrid(S_ / 128, B_ * H_);
    flash_kernel<<<fGrid, 256, FLASH_SMEM>>>(q, k, v, mask, attn_raw, mkt, stats, ctx);

    // Output projection on tensor cores
    conv_split<<<(xn4 + 255) / 256, 256>>>((const float4*)ctx, (uint2*)chi, (uint2*)clo, xn4);
    gemm_mma_split<<<gGrid, 256>>>(chi, clo, wohi, wolo, wo_b, out_ptr, M, N, K);

    // attn normalize
    dim3 nGrid(S_, B_ * H_);
    normalize_kernel<<<nGrid, 256>>>(attn_raw, mkt, stats, attn_ptr);
}

// round 6
// speedup vs baseline: 1.9468x; 1.4058x over previous
#include <cuda_runtime.h>
#include <cuda_bf16.h>
#include <math.h>
#include <stdint.h>

// Problem constants
#define B_  2
#define S_  2048
#define D_  1024
#define H_  16
#define DH_ 64
#define SCALE_ 0.125f   // DH^-0.5

typedef unsigned long long u64;

// ---------------------------------------------------------------------------
// Scratch (static device globals; no runtime allocation)
// ---------------------------------------------------------------------------
__device__ float g_q[(size_t)B_ * S_ * D_];
__device__ float g_k[(size_t)B_ * S_ * D_];
__device__ float g_v[(size_t)B_ * S_ * D_];
__device__ float g_ctx[(size_t)B_ * S_ * D_];
__device__ float g_attn_raw[(size_t)B_ * H_ * S_ * S_];
__device__ float g_mkt[(size_t)B_ * H_ * (S_ / 128) * S_];
__device__ float g_stats[(size_t)B_ * H_ * S_ * 2];

// bf16 hi/lo split operands
__device__ __nv_bfloat16 g_xhi[(size_t)B_ * S_ * D_];
__device__ __nv_bfloat16 g_xlo[(size_t)B_ * S_ * D_];
__device__ __nv_bfloat16 g_qhi[(size_t)B_ * S_ * D_], g_qlo[(size_t)B_ * S_ * D_];
__device__ __nv_bfloat16 g_khi[(size_t)B_ * S_ * D_], g_klo[(size_t)B_ * S_ * D_];
__device__ __nv_bfloat16 g_vhi[(size_t)B_ * S_ * D_], g_vlo[(size_t)B_ * S_ * D_];
__device__ __nv_bfloat16 g_chi[(size_t)B_ * S_ * D_], g_clo[(size_t)B_ * S_ * D_];
__device__ __nv_bfloat16 g_wqhi[D_ * D_], g_wqlo[D_ * D_];
__device__ __nv_bfloat16 g_wkhi[D_ * D_], g_wklo[D_ * D_];
__device__ __nv_bfloat16 g_wvhi[D_ * D_], g_wvlo[D_ * D_];
__device__ __nv_bfloat16 g_wohi[D_ * D_], g_wolo[D_ * D_];

// ---------------------------------------------------------------------------
// mma.sync / ldmatrix helpers
// ---------------------------------------------------------------------------
__device__ __forceinline__ uint32_t smem_u32(const void* p) {
    uint32_t a;
    asm("{ .reg .u64 t; cvta.to.shared.u64 t, %1; cvt.u32.u64 %0, t; }"
        : "=r"(a) : "l"(p));
    return a;
}
__device__ __forceinline__ void ldmA4(uint32_t* a, uint32_t addr) {
    asm volatile("ldmatrix.sync.aligned.m8n8.x4.shared.b16 {%0,%1,%2,%3}, [%4];"
                 : "=r"(a[0]), "=r"(a[1]), "=r"(a[2]), "=r"(a[3]) : "r"(addr));
}
__device__ __forceinline__ void ldmB2(uint32_t* b, uint32_t addr) {
    asm volatile("ldmatrix.sync.aligned.m8n8.x2.shared.b16 {%0,%1}, [%2];"
                 : "=r"(b[0]), "=r"(b[1]) : "r"(addr));
}
__device__ __forceinline__ void ldmB2t(uint32_t* b, uint32_t addr) {
    asm volatile("ldmatrix.sync.aligned.m8n8.x2.trans.shared.b16 {%0,%1}, [%2];"
                 : "=r"(b[0]), "=r"(b[1]) : "r"(addr));
}
__device__ __forceinline__ void mma16816(float* c, const uint32_t* a,
                                         const uint32_t* b) {
    asm volatile(
        "mma.sync.aligned.m16n8k16.row.col.f32.bf16.bf16.f32 "
        "{%0,%1,%2,%3}, {%4,%5,%6,%7}, {%8,%9}, {%0,%1,%2,%3};"
        : "+f"(c[0]), "+f"(c[1]), "+f"(c[2]), "+f"(c[3])
        : "r"(a[0]), "r"(a[1]), "r"(a[2]), "r"(a[3]), "r"(b[0]), "r"(b[1]));
}
__device__ __forceinline__ void cpasync16(uint32_t saddr, const void* gaddr) {
    asm volatile("cp.async.cg.shared.global [%0], [%1], 16;"
                 :: "r"(saddr), "l"(gaddr));
}
#define CP_COMMIT() asm volatile("cp.async.commit_group;" ::: "memory")
#define CP_WAIT0()  asm volatile("cp.async.wait_group 0;" ::: "memory")

__device__ __forceinline__ uint32_t pack_bf2(float x, float y) {
    return (uint32_t)__bfloat16_as_ushort(__float2bfloat16(x)) |
           ((uint32_t)__bfloat16_as_ushort(__float2bfloat16(y)) << 16);
}
__device__ __forceinline__ float fexp(float x) {
    return __expf(x);   // MUFU path: overlaps tensor pipe
}

// ---------------------------------------------------------------------------
// Split-conversion: float -> bf16 hi + bf16 lo (residual)
// ---------------------------------------------------------------------------
__global__ __launch_bounds__(256) void conv_split(
    const float4* __restrict__ src, uint2* __restrict__ hi,
    uint2* __restrict__ lo, int n4)
{
    const int i = blockIdx.x * 256 + threadIdx.x;
    if (i >= n4) return;
    const float4 v = src[i];
    const __nv_bfloat16 h0 = __float2bfloat16(v.x);
    const __nv_bfloat16 h1 = __float2bfloat16(v.y);
    const __nv_bfloat16 h2 = __float2bfloat16(v.z);
    const __nv_bfloat16 h3 = __float2bfloat16(v.w);
    uint2 ho, lu;
    ho.x = (uint32_t)__bfloat16_as_ushort(h0) | ((uint32_t)__bfloat16_as_ushort(h1) << 16);
    ho.y = (uint32_t)__bfloat16_as_ushort(h2) | ((uint32_t)__bfloat16_as_ushort(h3) << 16);
    lu.x = pack_bf2(v.x - __bfloat162float(h0), v.y - __bfloat162float(h1));
    lu.y = pack_bf2(v.z - __bfloat162float(h2), v.w - __bfloat162float(h3));
    hi[i] = ho;
    lo[i] = lu;
}

// ---------------------------------------------------------------------------
// Tensor-core split GEMM: C = (Ahi+Alo) @ (Bhi+Blo)^T + bias.
// Optionally also writes bf16 hi/lo of the result (for downstream mma use).
// ---------------------------------------------------------------------------
#define AP 72

__global__ __launch_bounds__(256) void gemm_mma_split(
    const __nv_bfloat16* __restrict__ Ahi, const __nv_bfloat16* __restrict__ Alo,
    const __nv_bfloat16* __restrict__ Bhi, const __nv_bfloat16* __restrict__ Blo,
    const float* __restrict__ bias, float* __restrict__ C,
    __nv_bfloat16* __restrict__ Chi, __nv_bfloat16* __restrict__ Clo,
    int M, int N, int K)
{
    __shared__ __nv_bfloat16 As[128 * AP];
    __shared__ __nv_bfloat16 Bs[128 * AP];
    const int tid  = threadIdx.x;
    const int lane = tid & 31, wid = tid >> 5;
    const int warp_m = wid >> 2, warp_n = wid & 3;
    const int bm = blockIdx.y * 128, bn = blockIdx.x * 128;

    const uint32_t sA = smem_u32(As), sB = smem_u32(Bs);
    const int a_r = warp_m * 64 + (lane & 15);
    const int a_c = (lane >> 4) * 8;
    const int b_r = warp_n * 32 + (lane & 7);
    const int b_c = ((lane >> 3) & 1) * 8;

    float acc[4][4][4];
#pragma unroll
    for (int mt = 0; mt < 4; mt++)
#pragma unroll
        for (int nt = 0; nt < 4; nt++)
#pragma unroll
            for (int r = 0; r < 4; r++) acc[mt][nt][r] = 0.f;

    const __nv_bfloat16* Aops[3] = { Ahi, Ahi, Alo };
    const __nv_bfloat16* Bops[3] = { Bhi, Blo, Bhi };

    const int lrow = tid >> 3;
    const int lc8  = (tid & 7) * 8;

    for (int term = 0; term < 3; term++) {
        const __nv_bfloat16* A = Aops[term];
        const __nv_bfloat16* B = Bops[term];
        for (int k0 = 0; k0 < K; k0 += 64) {
            __syncthreads();
#pragma unroll
            for (int rr = 0; rr < 4; rr++) {
                const int row = lrow + rr * 32;
                cpasync16(sA + (uint32_t)(row * AP + lc8) * 2,
                          &A[(size_t)(bm + row) * K + k0 + lc8]);
                cpasync16(sB + (uint32_t)(row * AP + lc8) * 2,
                          &B[(size_t)(bn + row) * K + k0 + lc8]);
            }
            CP_COMMIT();
            CP_WAIT0();
            __syncthreads();

#pragma unroll
            for (int ks = 0; ks < 4; ks++) {
                uint32_t afr[4][4], bfr[4][2];
#pragma unroll
                for (int mt = 0; mt < 4; mt++)
                    ldmA4(afr[mt], sA + (uint32_t)((a_r + mt * 16) * AP +
                                                   ks * 16 + a_c) * 2);
#pragma unroll
                for (int nt = 0; nt < 4; nt++)
                    ldmB2(bfr[nt], sB + (uint32_t)((b_r + nt * 8) * AP +
                                                   ks * 16 + b_c) * 2);
#pragma unroll
                for (int mt = 0; mt < 4; mt++)
#pragma unroll
                    for (int nt = 0; nt < 4; nt++)
                        mma16816(acc[mt][nt], afr[mt], bfr[nt]);
            }
        }
    }

    const int em = bm + warp_m * 64 + (lane >> 2);
    const int en = bn + warp_n * 32 + (lane & 3) * 2;
#pragma unroll
    for (int mt = 0; mt < 4; mt++) {
#pragma unroll
        for (int nt = 0; nt < 4; nt++) {
            const int n = en + nt * 8;
            const float bx = bias[n], by = bias[n + 1];
            const int m0 = em + mt * 16;
            float2 o0, o1;
            o0.x = acc[mt][nt][0] + bx; o0.y = acc[mt][nt][1] + by;
            o1.x = acc[mt][nt][2] + bx; o1.y = acc[mt][nt][3] + by;
            *(float2*)&C[(size_t)m0 * N + n]       = o0;
            *(float2*)&C[(size_t)(m0 + 8) * N + n] = o1;
            if (Chi) {
                const __nv_bfloat16 h0x = __float2bfloat16(o0.x);
                const __nv_bfloat16 h0y = __float2bfloat16(o0.y);
                const __nv_bfloat16 h1x = __float2bfloat16(o1.x);
                const __nv_bfloat16 h1y = __float2bfloat16(o1.y);
                *(uint32_t*)&Chi[(size_t)m0 * N + n] =
                    (uint32_t)__bfloat16_as_ushort(h0x) |
                    ((uint32_t)__bfloat16_as_ushort(h0y) << 16);
                *(uint32_t*)&Chi[(size_t)(m0 + 8) * N + n] =
                    (uint32_t)__bfloat16_as_ushort(h1x) |
                    ((uint32_t)__bfloat16_as_ushort(h1y) << 16);
                *(uint32_t*)&Clo[(size_t)m0 * N + n] =
                    pack_bf2(o0.x - __bfloat162float(h0x),
                             o0.y - __bfloat162float(h0y));
                *(uint32_t*)&Clo[(size_t)(m0 + 8) * N + n] =
                    pack_bf2(o1.x - __bfloat162float(h1x),
                             o1.y - __bfloat162float(h1y));
            }
        }
    }
}

// ---------------------------------------------------------------------------
// Tensor-core flash attention: per (bh, 128-row q tile), 8 warps, warp = 16
// full score rows. QK^T and P@V via mma.sync bf16 hi/lo (3 terms each).
// P fragments feed P@V directly (no smem round-trip).
// ---------------------------------------------------------------------------
#define FP 72
#define FLASH_SMEM (6 * 128 * FP * 2)

__global__ __launch_bounds__(256, 1) void flash_mma_kernel(
    const __nv_bfloat16* __restrict__ qhi, const __nv_bfloat16* __restrict__ qlo,
    const __nv_bfloat16* __restrict__ khi, const __nv_bfloat16* __restrict__ klo,
    const __nv_bfloat16* __restrict__ vhi, const __nv_bfloat16* __restrict__ vlo,
    const int* __restrict__ mask, float* __restrict__ Praw,
    float* __restrict__ mkt, float* __restrict__ stats, float* __restrict__ ctx)
{
    extern __shared__ __nv_bfloat16 smb[];
    __nv_bfloat16* sQh = smb;
    __nv_bfloat16* sQl = sQh + 128 * FP;
    __nv_bfloat16* sKh = sQl + 128 * FP;
    __nv_bfloat16* sKl = sKh + 128 * FP;
    __nv_bfloat16* sVh = sKl + 128 * FP;
    __nv_bfloat16* sVl = sVh + 128 * FP;

    const int t = threadIdx.x, lane = t & 31, warp = t >> 5;
    const int bh = blockIdx.y;
    const int b = bh >> 4, h = bh & 15;
    const int q0 = blockIdx.x * 128;

    const uint32_t uQh = smem_u32(sQh), uQl = smem_u32(sQl);
    const uint32_t uKh = smem_u32(sKh), uKl = smem_u32(sKl);
    const uint32_t uVh = smem_u32(sVh), uVl = smem_u32(sVl);

    // Load Q tile (once)
    for (int i = t; i < 1024; i += 256) {
        const int row = i >> 3, c8 = (i & 7) * 8;
        const size_t g = (size_t)(b * S_ + q0 + row) * D_ + h * 64 + c8;
        *(uint4*)&sQh[row * FP + c8] = *(const uint4*)&qhi[g];
        *(uint4*)&sQl[row * FP + c8] = *(const uint4*)&qlo[g];
    }
    __syncthreads();

    // Hoist Q fragments (tile constant across kt)
    uint32_t qh[4][4], ql[4][4];
    const int a_r = warp * 16 + (lane & 15);
    const int a_c = (lane >> 4) * 8;
#pragma unroll
    for (int ks = 0; ks < 4; ks++) {
        ldmA4(qh[ks], uQh + (uint32_t)(a_r * FP + ks * 16 + a_c) * 2);
        ldmA4(ql[ks], uQl + (uint32_t)(a_r * FP + ks * 16 + a_c) * 2);
    }

    float O[8][4];
#pragma unroll
    for (int j = 0; j < 8; j++)
#pragma unroll
        for (int r = 0; r < 4; r++) O[j][r] = 0.f;
    float mr0 = -1e30f, mr1 = -1e30f, lr0 = 0.f, lr1 = 0.f;

    const int r0   = lane >> 2;
    const int row0 = q0 + warp * 16 + r0;     // global q row (c regs 0,1)
    const int row1 = row0 + 8;                // (c regs 2,3)
    const int col0 = (lane & 3) * 2;
    const int b_r  = lane & 7;
    const int b_hc = ((lane >> 3) & 1) * 8;
    const int t_r  = lane & 15;               // trans-ldmatrix row lane

    for (int kt = 0; kt < S_ / 128; kt++) {
        const int k0 = kt * 128;
        __syncthreads();
        for (int i = t; i < 1024; i += 256) {
            const int row = i >> 3, c8 = (i & 7) * 8;
            const size_t g = (size_t)(b * S_ + k0 + row) * D_ + h * 64 + c8;
            *(uint4*)&sKh[row * FP + c8] = *(const uint4*)&khi[g];
            *(uint4*)&sKl[row * FP + c8] = *(const uint4*)&klo[g];
            *(uint4*)&sVh[row * FP + c8] = *(const uint4*)&vhi[g];
            *(uint4*)&sVl[row * FP + c8] = *(const uint4*)&vlo[g];
        }
        __syncthreads();

        // --- QK^T: c[16][4] over 128 k-cols ---
        float c[16][4];
#pragma unroll
        for (int nt = 0; nt < 16; nt++)
#pragma unroll
            for (int r = 0; r < 4; r++) c[nt][r] = 0.f;
#pragma unroll
        for (int ks = 0; ks < 4; ks++) {
#pragma unroll
            for (int nt = 0; nt < 16; nt++) {
                uint32_t kh2[2], kl2[2];
                const uint32_t off = (uint32_t)((nt * 8 + b_r) * FP +
                                                ks * 16 + b_hc) * 2;
                ldmB2(kh2, uKh + off);
                ldmB2(kl2, uKl + off);
                mma16816(c[nt], qh[ks], kh2);
                mma16816(c[nt], qh[ks], kl2);
                mma16816(c[nt], ql[ks], kh2);
            }
        }

        // --- scale + mask ---
#pragma unroll
        for (int nt = 0; nt < 16; nt++) {
            const int cc = k0 + nt * 8 + col0;
            const int2 m0 = *(const int2*)&mask[((size_t)b * S_ + row0) * S_ + cc];
            const int2 m1 = *(const int2*)&mask[((size_t)b * S_ + row1) * S_ + cc];
            c[nt][0] = (m0.x == 0) ? -1e9f : c[nt][0] * SCALE_;
            c[nt][1] = (m0.y == 0) ? -1e9f : c[nt][1] * SCALE_;
            c[nt][2] = (m1.x == 0) ? -1e9f : c[nt][2] * SCALE_;
            c[nt][3] = (m1.y == 0) ? -1e9f : c[nt][3] * SCALE_;
        }

        // --- online softmax (rows fully within warp; quad shfl reduce) ---
        float rm0 = -1e30f, rm1 = -1e30f;
#pragma unroll
        for (int nt = 0; nt < 16; nt++) {
            rm0 = fmaxf(rm0, fmaxf(c[nt][0], c[nt][1]));
            rm1 = fmaxf(rm1, fmaxf(c[nt][2], c[nt][3]));
        }
        rm0 = fmaxf(rm0, __shfl_xor_sync(0xffffffffu, rm0, 1));
        rm0 = fmaxf(rm0, __shfl_xor_sync(0xffffffffu, rm0, 2));
        rm1 = fmaxf(rm1, __shfl_xor_sync(0xffffffffu, rm1, 1));
        rm1 = fmaxf(rm1, __shfl_xor_sync(0xffffffffu, rm1, 2));
        const float mn0 = fmaxf(mr0, rm0), mn1 = fmaxf(mr1, rm1);
        const float f0 = fexp(mr0 - mn0), f1 = fexp(mr1 - mn1);
        float rs0 = 0.f, rs1 = 0.f;
#pragma unroll
        for (int nt = 0; nt < 16; nt++) {
            c[nt][0] = fexp(c[nt][0] - mn0);
            c[nt][1] = fexp(c[nt][1] - mn0);
            c[nt][2] = fexp(c[nt][2] - mn1);
            c[nt][3] = fexp(c[nt][3] - mn1);
            rs0 += c[nt][0] + c[nt][1];
            rs1 += c[nt][2] + c[nt][3];
        }
        rs0 += __shfl_xor_sync(0xffffffffu, rs0, 1);
        rs0 += __shfl_xor_sync(0xffffffffu, rs0, 2);
        rs1 += __shfl_xor_sync(0xffffffffu, rs1, 1);
        rs1 += __shfl_xor_sync(0xffffffffu, rs1, 2);
        lr0 = lr0 * f0 + rs0; mr0 = mn0;
        lr1 = lr1 * f1 + rs1; mr1 = mn1;
#pragma unroll
        for (int j = 0; j < 8; j++) {
            O[j][0] *= f0; O[j][1] *= f0;
            O[j][2] *= f1; O[j][3] *= f1;
        }

        // --- stream P + m_kt ---
        {
            const size_t gb0 = ((size_t)bh * S_ + row0) * S_ + k0 + col0;
            const size_t gb1 = ((size_t)bh * S_ + row1) * S_ + k0 + col0;
#pragma unroll
            for (int nt = 0; nt < 16; nt++) {
                float2 w0, w1;
                w0.x = c[nt][0]; w0.y = c[nt][1];
                w1.x = c[nt][2]; w1.y = c[nt][3];
                *(float2*)&Praw[gb0 + nt * 8] = w0;
                *(float2*)&Praw[gb1 + nt * 8] = w1;
            }
            if ((lane & 3) == 0) {
                mkt[((size_t)bh * 16 + kt) * S_ + row0] = mn0;
                mkt[((size_t)bh * 16 + kt) * S_ + row1] = mn1;
            }
        }

        // --- P @ V : fragments straight from c, hi/lo split ---
#pragma unroll
        for (int ks2 = 0; ks2 < 8; ks2++) {
            const float* c0 = c[2 * ks2];
            const float* c1 = c[2 * ks2 + 1];
            uint32_t ah[4], al[4];
            ah[0] = pack_bf2(c0[0], c0[1]);
            ah[1] = pack_bf2(c0[2], c0[3]);
            ah[2] = pack_bf2(c1[0], c1[1]);
            ah[3] = pack_bf2(c1[2], c1[3]);
            al[0] = pack_bf2(c0[0] - __bfloat162float(__ushort_as_bfloat16((unsigned short)(ah[0] & 0xffff))),
                             c0[1] - __bfloat162float(__ushort_as_bfloat16((unsigned short)(ah[0] >> 16))));
            al[1] = pack_bf2(c0[2] - __bfloat162float(__ushort_as_bfloat16((unsigned short)(ah[1] & 0xffff))),
                             c0[3] - __bfloat162float(__ushort_as_bfloat16((unsigned short)(ah[1] >> 16))));
            al[2] = pack_bf2(c1[0] - __bfloat162float(__ushort_as_bfloat16((unsigned short)(ah[2] & 0xffff))),
                             c1[1] - __bfloat162float(__ushort_as_bfloat16((unsigned short)(ah[2] >> 16))));
            al[3] = pack_bf2(c1[2] - __bfloat162float(__ushort_as_bfloat16((unsigned short)(ah[3] & 0xffff))),
                             c1[3] - __bfloat162float(__ushort_as_bfloat16((unsigned short)(ah[3] >> 16))));
#pragma unroll
            for (int nt2 = 0; nt2 < 8; nt2++) {
                uint32_t vh2[2], vl2[2];
                const uint32_t off = (uint32_t)((ks2 * 16 + t_r) * FP +
                                                nt2 * 8) * 2;
                ldmB2t(vh2, uVh + off);
                ldmB2t(vl2, uVl + off);
                mma16816(O[nt2], ah, vh2);
                mma16816(O[nt2], ah, vl2);
                mma16816(O[nt2], al, vh2);
            }
        }
    }

    // --- epilogue ---
    const float inv0 = 1.0f / lr0, inv1 = 1.0f / lr1;
#pragma unroll
    for (int nt2 = 0; nt2 < 8; nt2++) {
        const int n = nt2 * 8 + col0;
        float2 o0, o1;
        o0.x = O[nt2][0] * inv0; o0.y = O[nt2][1] * inv0;
        o1.x = O[nt2][2] * inv1; o1.y = O[nt2][3] * inv1;
        *(float2*)&ctx[(size_t)(b * S_ + row0) * D_ + h * 64 + n] = o0;
        *(float2*)&ctx[(size_t)(b * S_ + row1) * D_ + h * 64 + n] = o1;
    }
    if ((lane & 3) == 0) {
        size_t si = ((size_t)bh * S_ + row0) * 2;
        stats[si] = mr0; stats[si + 1] = lr0;
        si = ((size_t)bh * S_ + row1) * 2;
        stats[si] = mr1; stats[si + 1] = lr1;
    }
}

// ---------------------------------------------------------------------------
// Pass 2: attn = P * exp(m_kt - m_final) / l_final  (pure memory)
// ---------------------------------------------------------------------------
__global__ __launch_bounds__(256) void normalize_kernel(
    const float* __restrict__ P, const float* __restrict__ mkt,
    const float* __restrict__ stats, float* __restrict__ attn)
{
    __shared__ float corr[16];
    const int t   = threadIdx.x;
    const int row = blockIdx.x;
    const int bh  = blockIdx.y;

    const size_t si = ((size_t)bh * S_ + row) * 2;
    const float m_f = stats[si];
    const float inv_l = 1.0f / stats[si + 1];
    if (t < 16)
        corr[t] = __expf(mkt[((size_t)bh * 16 + t) * S_ + row] - m_f) * inv_l;
    __syncthreads();

    const size_t base = ((size_t)bh * S_ + row) * S_;
    const float c = corr[t >> 4];
    float4 v0 = *(const float4*)&P[base + t * 8];
    float4 v1 = *(const float4*)&P[base + t * 8 + 4];
    v0.x *= c; v0.y *= c; v0.z *= c; v0.w *= c;
    v1.x *= c; v1.y *= c; v1.z *= c; v1.w *= c;
    *(float4*)&attn[base + t * 8]     = v0;
    *(float4*)&attn[base + t * 8 + 4] = v1;
}

// ---------------------------------------------------------------------------
extern "C" void kernel_launch(void* const* d_in, const int* in_sizes, int n_in,
                              void* d_out, int out_size)
{
    const float* x    = (const float*)d_in[0];
    const int*   mask = (const int*)  d_in[1];
    const float* wq_w = (const float*)d_in[2];
    const float* wq_b = (const float*)d_in[3];
    const float* wk_w = (const float*)d_in[4];
    const float* wk_b = (const float*)d_in[5];
    const float* wv_w = (const float*)d_in[6];
    const float* wv_b = (const float*)d_in[7];
    const float* wo_w = (const float*)d_in[8];
    const float* wo_b = (const float*)d_in[9];

    float *q, *k, *v, *ctx, *attn_raw, *mkt, *stats;
    cudaGetSymbolAddress((void**)&q,        g_q);
    cudaGetSymbolAddress((void**)&k,        g_k);
    cudaGetSymbolAddress((void**)&v,        g_v);
    cudaGetSymbolAddress((void**)&ctx,      g_ctx);
    cudaGetSymbolAddress((void**)&attn_raw, g_attn_raw);
    cudaGetSymbolAddress((void**)&mkt,      g_mkt);
    cudaGetSymbolAddress((void**)&stats,    g_stats);

    __nv_bfloat16 *xhi, *xlo, *chi, *clo;
    __nv_bfloat16 *qhi_p, *qlo_p, *khi_p, *klo_p, *vhi_p, *vlo_p;
    __nv_bfloat16 *wqhi, *wqlo, *wkhi, *wklo, *wvhi, *wvlo, *wohi, *wolo;
    cudaGetSymbolAddress((void**)&xhi, g_xhi);   cudaGetSymbolAddress((void**)&xlo, g_xlo);
    cudaGetSymbolAddress((void**)&chi, g_chi);   cudaGetSymbolAddress((void**)&clo, g_clo);
    cudaGetSymbolAddress((void**)&qhi_p, g_qhi); cudaGetSymbolAddress((void**)&qlo_p, g_qlo);
    cudaGetSymbolAddress((void**)&khi_p, g_khi); cudaGetSymbolAddress((void**)&klo_p, g_klo);
    cudaGetSymbolAddress((void**)&vhi_p, g_vhi); cudaGetSymbolAddress((void**)&vlo_p, g_vlo);
    cudaGetSymbolAddress((void**)&wqhi, g_wqhi); cudaGetSymbolAddress((void**)&wqlo, g_wqlo);
    cudaGetSymbolAddress((void**)&wkhi, g_wkhi); cudaGetSymbolAddress((void**)&wklo, g_wklo);
    cudaGetSymbolAddress((void**)&wvhi, g_wvhi); cudaGetSymbolAddress((void**)&wvlo, g_wvlo);
    cudaGetSymbolAddress((void**)&wohi, g_wohi); cudaGetSymbolAddress((void**)&wolo, g_wolo);

    const long long CTXSZ = (long long)B_ * S_ * D_;
    const long long ATTSZ = (long long)B_ * H_ * S_ * S_;

    float* out_base = (float*)d_out;
    float* out_ptr;
    float* attn_ptr;
    if ((long long)out_size >= CTXSZ + ATTSZ) {
        out_ptr  = out_base;
        attn_ptr = out_base + CTXSZ;
    } else if ((long long)out_size == ATTSZ) {
        out_ptr  = q;
        attn_ptr = out_base;
    } else {
        out_ptr  = out_base;
        attn_ptr = attn_raw;
    }

    cudaFuncSetAttribute(flash_mma_kernel,
                         cudaFuncAttributeMaxDynamicSharedMemorySize, FLASH_SMEM);

    const int M = B_ * S_;   // 4096
    const int N = D_;        // 1024
    const int K = D_;        // 1024

    // Split conversions (inputs only)
    const int xn4 = (int)(CTXSZ / 4);
    const int wn4 = D_ * D_ / 4;
    conv_split<<<(xn4 + 255) / 256, 256>>>((const float4*)x, (uint2*)xhi, (uint2*)xlo, xn4);
    conv_split<<<(wn4 + 255) / 256, 256>>>((const float4*)wq_w, (uint2*)wqhi, (uint2*)wqlo, wn4);
    conv_split<<<(wn4 + 255) / 256, 256>>>((const float4*)wk_w, (uint2*)wkhi, (uint2*)wklo, wn4);
    conv_split<<<(wn4 + 255) / 256, 256>>>((const float4*)wv_w, (uint2*)wvhi, (uint2*)wvlo, wn4);
    conv_split<<<(wn4 + 255) / 256, 256>>>((const float4*)wo_w, (uint2*)wohi, (uint2*)wolo, wn4);

    // Projections (epilogues emit bf16 hi/lo for flash)
    dim3 gGrid(N / 128, M / 128);
    gemm_mma_split<<<gGrid, 256>>>(xhi, xlo, wqhi, wqlo, wq_b, q, qhi_p, qlo_p, M, N, K);
    gemm_mma_split<<<gGrid, 256>>>(xhi, xlo, wkhi, wklo, wk_b, k, khi_p, klo_p, M, N, K);
    gemm_mma_split<<<gGrid, 256>>>(xhi, xlo, wvhi, wvlo, wv_b, v, vhi_p, vlo_p, M, N, K);

    // Tensor-core flash attention
    dim3 fGrid(S_ / 128, B_ * H_);
    flash_mma_kernel<<<fGrid, 256, FLASH_SMEM>>>(
        qhi_p, qlo_p, khi_p, klo_p, vhi_p, vlo_p,
        mask, attn_raw, mkt, stats, ctx);

    // Output projection
    conv_split<<<(xn4 + 255) / 256, 256>>>((const float4*)ctx, (uint2*)chi, (uint2*)clo, xn4);
    gemm_mma_split<<<gGrid, 256>>>(chi, clo, wohi, wolo, wo_b, out_ptr,
                                   (__nv_bfloat16*)nullptr, (__nv_bfloat16*)nullptr, M, N, K);

    // attn normalize
    dim3 nGrid(S_, B_ * H_);
    normalize_kernel<<<nGrid, 256>>>(attn_raw, mkt, stats, attn_ptr);
}

// round 7
// speedup vs baseline: 1.9843x; 1.0193x over previous
#include <cuda_runtime.h>
#include <cuda_bf16.h>
#include <math.h>
#include <stdint.h>

// Problem constants
#define B_  2
#define S_  2048
#define D_  1024
#define H_  16
#define DH_ 64
#define SCALE_ 0.125f   // DH^-0.5

typedef unsigned long long u64;

// ---------------------------------------------------------------------------
// Scratch (static device globals; no runtime allocation)
// ---------------------------------------------------------------------------
__device__ float g_q[(size_t)B_ * S_ * D_];
__device__ float g_k[(size_t)B_ * S_ * D_];
__device__ float g_v[(size_t)B_ * S_ * D_];
__device__ float g_ctx[(size_t)B_ * S_ * D_];
__device__ float g_attn_raw[(size_t)B_ * H_ * S_ * S_];
__device__ float g_mkt[(size_t)B_ * H_ * (S_ / 128) * S_];
__device__ float g_stats[(size_t)B_ * H_ * S_ * 2];

// bf16 hi/lo split operands
__device__ __nv_bfloat16 g_xhi[(size_t)B_ * S_ * D_];
__device__ __nv_bfloat16 g_xlo[(size_t)B_ * S_ * D_];
__device__ __nv_bfloat16 g_qhi[(size_t)B_ * S_ * D_], g_qlo[(size_t)B_ * S_ * D_];
__device__ __nv_bfloat16 g_khi[(size_t)B_ * S_ * D_], g_klo[(size_t)B_ * S_ * D_];
__device__ __nv_bfloat16 g_vhi[(size_t)B_ * S_ * D_], g_vlo[(size_t)B_ * S_ * D_];
__device__ __nv_bfloat16 g_chi[(size_t)B_ * S_ * D_], g_clo[(size_t)B_ * S_ * D_];
__device__ __nv_bfloat16 g_wqhi[D_ * D_], g_wqlo[D_ * D_];
__device__ __nv_bfloat16 g_wkhi[D_ * D_], g_wklo[D_ * D_];
__device__ __nv_bfloat16 g_wvhi[D_ * D_], g_wvlo[D_ * D_];
__device__ __nv_bfloat16 g_wohi[D_ * D_], g_wolo[D_ * D_];

// ---------------------------------------------------------------------------
// mma.sync / ldmatrix helpers
// ---------------------------------------------------------------------------
__device__ __forceinline__ uint32_t smem_u32(const void* p) {
    uint32_t a;
    asm("{ .reg .u64 t; cvta.to.shared.u64 t, %1; cvt.u32.u64 %0, t; }"
        : "=r"(a) : "l"(p));
    return a;
}
__device__ __forceinline__ void ldmA4(uint32_t* a, uint32_t addr) {
    asm volatile("ldmatrix.sync.aligned.m8n8.x4.shared.b16 {%0,%1,%2,%3}, [%4];"
                 : "=r"(a[0]), "=r"(a[1]), "=r"(a[2]), "=r"(a[3]) : "r"(addr));
}
__device__ __forceinline__ void ldmA4t(uint32_t* a, uint32_t addr) {
    asm volatile("ldmatrix.sync.aligned.m8n8.x4.trans.shared.b16 {%0,%1,%2,%3}, [%4];"
                 : "=r"(a[0]), "=r"(a[1]), "=r"(a[2]), "=r"(a[3]) : "r"(addr));
}
__device__ __forceinline__ void mma16816(float* c, const uint32_t* a,
                                         const uint32_t* b) {
    asm volatile(
        "mma.sync.aligned.m16n8k16.row.col.f32.bf16.bf16.f32 "
        "{%0,%1,%2,%3}, {%4,%5,%6,%7}, {%8,%9}, {%0,%1,%2,%3};"
        : "+f"(c[0]), "+f"(c[1]), "+f"(c[2]), "+f"(c[3])
        : "r"(a[0]), "r"(a[1]), "r"(a[2]), "r"(a[3]), "r"(b[0]), "r"(b[1]));
}
__device__ __forceinline__ void cpasync16(uint32_t saddr, const void* gaddr) {
    asm volatile("cp.async.cg.shared.global [%0], [%1], 16;"
                 :: "r"(saddr), "l"(gaddr));
}
#define CP_COMMIT() asm volatile("cp.async.commit_group;" ::: "memory")
#define CP_WAIT0()  asm volatile("cp.async.wait_group 0;" ::: "memory")
#define CP_WAIT1()  asm volatile("cp.async.wait_group 1;" ::: "memory")

__device__ __forceinline__ uint32_t pack_bf2(float x, float y) {
    return (uint32_t)__bfloat16_as_ushort(__float2bfloat16(x)) |
           ((uint32_t)__bfloat16_as_ushort(__float2bfloat16(y)) << 16);
}
__device__ __forceinline__ float fexp(float x) { return __expf(x); }

// ---------------------------------------------------------------------------
// Split-conversion: float -> bf16 hi + bf16 lo (residual)
// ---------------------------------------------------------------------------
__global__ __launch_bounds__(256) void conv_split(
    const float4* __restrict__ src, uint2* __restrict__ hi,
    uint2* __restrict__ lo, int n4)
{
    const int i = blockIdx.x * 256 + threadIdx.x;
    if (i >= n4) return;
    const float4 v = src[i];
    const __nv_bfloat16 h0 = __float2bfloat16(v.x);
    const __nv_bfloat16 h1 = __float2bfloat16(v.y);
    const __nv_bfloat16 h2 = __float2bfloat16(v.z);
    const __nv_bfloat16 h3 = __float2bfloat16(v.w);
    uint2 ho, lu;
    ho.x = (uint32_t)__bfloat16_as_ushort(h0) | ((uint32_t)__bfloat16_as_ushort(h1) << 16);
    ho.y = (uint32_t)__bfloat16_as_ushort(h2) | ((uint32_t)__bfloat16_as_ushort(h3) << 16);
    lu.x = pack_bf2(v.x - __bfloat162float(h0), v.y - __bfloat162float(h1));
    lu.y = pack_bf2(v.z - __bfloat162float(h2), v.w - __bfloat162float(h3));
    hi[i] = ho;
    lo[i] = lu;
}

// ---------------------------------------------------------------------------
// Tensor-core split GEMM: C = (Ahi+Alo) @ (Bhi+Blo)^T + bias.
// Fused 3-term K-loop + 2-stage cp.async double buffering.
// CTA 128x128, 8 warps 2(m)x4(n), warp 64x32, BK=64.
// ---------------------------------------------------------------------------
#define GP 72
#define GTILE (128 * GP)                       // bf16 elements per tile
#define GEMM_SMEM (2 * 4 * GTILE * 2)          // 147456 bytes

__global__ __launch_bounds__(256) void gemm_mma_split(
    const __nv_bfloat16* __restrict__ Ahi, const __nv_bfloat16* __restrict__ Alo,
    const __nv_bfloat16* __restrict__ Bhi, const __nv_bfloat16* __restrict__ Blo,
    const float* __restrict__ bias, float* __restrict__ C,
    __nv_bfloat16* __restrict__ Chi, __nv_bfloat16* __restrict__ Clo,
    int M, int N, int K)
{
    extern __shared__ __nv_bfloat16 gsm[];
    const uint32_t sb = smem_u32(gsm);
    const int tid  = threadIdx.x;
    const int lane = tid & 31, wid = tid >> 5;
    const int warp_m = wid >> 2, warp_n = wid & 3;
    const int bm = blockIdx.y * 128, bn = blockIdx.x * 128;

    const int a_r = warp_m * 64 + (lane & 15);
    const int a_c = (lane >> 4) * 8;
    // B x4 fragment address lanes (two n8 blocks per load)
    const int b4_row = ((lane >> 4) & 1) * 8 + (lane & 7);
    const int b4_col = ((lane >> 3) & 1) * 8;

    const int lrow = tid >> 3;          // 0..31
    const int lc8  = (tid & 7) * 8;

    float acc[4][4][4];
#pragma unroll
    for (int mt = 0; mt < 4; mt++)
#pragma unroll
        for (int nt = 0; nt < 4; nt++)
#pragma unroll
            for (int r = 0; r < 4; r++) acc[mt][nt][r] = 0.f;

    // stage s, operand o (0=Ah,1=Al,2=Bh,3=Bl)
#define TBASE(s, o) (sb + (uint32_t)(((s) * 4 + (o)) * GTILE) * 2)

#define LOAD_STAGE(s, k0) do {                                                \
    const uint32_t _dAh = TBASE(s, 0), _dAl = TBASE(s, 1);                    \
    const uint32_t _dBh = TBASE(s, 2), _dBl = TBASE(s, 3);                    \
    _Pragma("unroll")                                                         \
    for (int rr = 0; rr < 4; rr++) {                                          \
        const int row = lrow + rr * 32;                                       \
        const uint32_t so = (uint32_t)(row * GP + lc8) * 2;                   \
        const size_t ga = (size_t)(bm + row) * K + (k0) + lc8;                \
        const size_t gb = (size_t)(bn + row) * K + (k0) + lc8;                \
        cpasync16(_dAh + so, &Ahi[ga]);                                       \
        cpasync16(_dAl + so, &Alo[ga]);                                       \
        cpasync16(_dBh + so, &Bhi[gb]);                                       \
        cpasync16(_dBl + so, &Blo[gb]);                                       \
    }                                                                         \
    CP_COMMIT();                                                              \
} while (0)

    LOAD_STAGE(0, 0);

    const int NK = K / 64;
    for (int kc = 0; kc < NK; kc++) {
        const int cur = kc & 1;
        if (kc + 1 < NK) { LOAD_STAGE(cur ^ 1, (kc + 1) * 64); CP_WAIT1(); }
        else             { CP_WAIT0(); }
        __syncthreads();

        const uint32_t uAh = TBASE(cur, 0), uAl = TBASE(cur, 1);
        const uint32_t uBh = TBASE(cur, 2), uBl = TBASE(cur, 3);
#pragma unroll
        for (int ks = 0; ks < 4; ks++) {
            uint32_t ah[4][4], al[4][4];
#pragma unroll
            for (int mt = 0; mt < 4; mt++) {
                const uint32_t ao = (uint32_t)((a_r + mt * 16) * GP +
                                               ks * 16 + a_c) * 2;
                ldmA4(ah[mt], uAh + ao);
                ldmA4(al[mt], uAl + ao);
            }
            uint32_t bh[4][2], bl[4][2];
#pragma unroll
            for (int p = 0; p < 2; p++) {
                uint32_t r4[4];
                const uint32_t bo = (uint32_t)((warp_n * 32 + p * 16 + b4_row) * GP +
                                               ks * 16 + b4_col) * 2;
                ldmA4(r4, uBh + bo);
                bh[2*p][0] = r4[0]; bh[2*p][1] = r4[1];
                bh[2*p+1][0] = r4[2]; bh[2*p+1][1] = r4[3];
                ldmA4(r4, uBl + bo);
                bl[2*p][0] = r4[0]; bl[2*p][1] = r4[1];
                bl[2*p+1][0] = r4[2]; bl[2*p+1][1] = r4[3];
            }
#pragma unroll
            for (int mt = 0; mt < 4; mt++)
#pragma unroll
                for (int nt = 0; nt < 4; nt++) {
                    mma16816(acc[mt][nt], ah[mt], bh[nt]);
                    mma16816(acc[mt][nt], ah[mt], bl[nt]);
                    mma16816(acc[mt][nt], al[mt], bh[nt]);
                }
        }
        __syncthreads();
    }

    const int em = bm + warp_m * 64 + (lane >> 2);
    const int en = bn + warp_n * 32 + (lane & 3) * 2;
#pragma unroll
    for (int mt = 0; mt < 4; mt++) {
#pragma unroll
        for (int nt = 0; nt < 4; nt++) {
            const int n = en + nt * 8;
            const float bx = bias[n], by = bias[n + 1];
            const int m0 = em + mt * 16;
            float2 o0, o1;
            o0.x = acc[mt][nt][0] + bx; o0.y = acc[mt][nt][1] + by;
            o1.x = acc[mt][nt][2] + bx; o1.y = acc[mt][nt][3] + by;
            *(float2*)&C[(size_t)m0 * N + n]       = o0;
            *(float2*)&C[(size_t)(m0 + 8) * N + n] = o1;
            if (Chi) {
                const __nv_bfloat16 h0x = __float2bfloat16(o0.x);
                const __nv_bfloat16 h0y = __float2bfloat16(o0.y);
                const __nv_bfloat16 h1x = __float2bfloat16(o1.x);
                const __nv_bfloat16 h1y = __float2bfloat16(o1.y);
                *(uint32_t*)&Chi[(size_t)m0 * N + n] =
                    (uint32_t)__bfloat16_as_ushort(h0x) |
                    ((uint32_t)__bfloat16_as_ushort(h0y) << 16);
                *(uint32_t*)&Chi[(size_t)(m0 + 8) * N + n] =
                    (uint32_t)__bfloat16_as_ushort(h1x) |
                    ((uint32_t)__bfloat16_as_ushort(h1y) << 16);
                *(uint32_t*)&Clo[(size_t)m0 * N + n] =
                    pack_bf2(o0.x - __bfloat162float(h0x),
                             o0.y - __bfloat162float(h0y));
                *(uint32_t*)&Clo[(size_t)(m0 + 8) * N + n] =
                    pack_bf2(o1.x - __bfloat162float(h1x),
                             o1.y - __bfloat162float(h1y));
            }
        }
    }
}

// ---------------------------------------------------------------------------
// Tensor-core flash attention: per (bh, 128-row q tile), 8 warps, warp = 16
// full score rows. x4 ldmatrix for all B-side fragments.
// ---------------------------------------------------------------------------
#define FP 72
#define FLASH_SMEM (6 * 128 * FP * 2)

__global__ __launch_bounds__(256, 1) void flash_mma_kernel(
    const __nv_bfloat16* __restrict__ qhi, const __nv_bfloat16* __restrict__ qlo,
    const __nv_bfloat16* __restrict__ khi, const __nv_bfloat16* __restrict__ klo,
    const __nv_bfloat16* __restrict__ vhi, const __nv_bfloat16* __restrict__ vlo,
    const int* __restrict__ mask, float* __restrict__ Praw,
    float* __restrict__ mkt, float* __restrict__ stats, float* __restrict__ ctx)
{
    extern __shared__ __nv_bfloat16 smb[];
    __nv_bfloat16* sQh = smb;
    __nv_bfloat16* sQl = sQh + 128 * FP;
    __nv_bfloat16* sKh = sQl + 128 * FP;
    __nv_bfloat16* sKl = sKh + 128 * FP;
    __nv_bfloat16* sVh = sKl + 128 * FP;
    __nv_bfloat16* sVl = sVh + 128 * FP;

    const int t = threadIdx.x, lane = t & 31, warp = t >> 5;
    const int bh = blockIdx.y;
    const int b = bh >> 4, h = bh & 15;
    const int q0 = blockIdx.x * 128;

    const uint32_t uQh = smem_u32(sQh), uQl = smem_u32(sQl);
    const uint32_t uKh = smem_u32(sKh), uKl = smem_u32(sKl);
    const uint32_t uVh = smem_u32(sVh), uVl = smem_u32(sVl);

    for (int i = t; i < 1024; i += 256) {
        const int row = i >> 3, c8 = (i & 7) * 8;
        const size_t g = (size_t)(b * S_ + q0 + row) * D_ + h * 64 + c8;
        *(uint4*)&sQh[row * FP + c8] = *(const uint4*)&qhi[g];
        *(uint4*)&sQl[row * FP + c8] = *(const uint4*)&qlo[g];
    }
    __syncthreads();

    uint32_t qh[4][4], ql[4][4];
    const int a_r = warp * 16 + (lane & 15);
    const int a_c = (lane >> 4) * 8;
#pragma unroll
    for (int ks = 0; ks < 4; ks++) {
        ldmA4(qh[ks], uQh + (uint32_t)(a_r * FP + ks * 16 + a_c) * 2);
        ldmA4(ql[ks], uQl + (uint32_t)(a_r * FP + ks * 16 + a_c) * 2);
    }

    float O[8][4];
#pragma unroll
    for (int j = 0; j < 8; j++)
#pragma unroll
        for (int r = 0; r < 4; r++) O[j][r] = 0.f;
    float mr0 = -1e30f, mr1 = -1e30f, lr0 = 0.f, lr1 = 0.f;

    const int r0   = lane >> 2;
    const int row0 = q0 + warp * 16 + r0;
    const int row1 = row0 + 8;
    const int col0 = (lane & 3) * 2;
    const int b4_row = ((lane >> 4) & 1) * 8 + (lane & 7);   // x4 non-trans
    const int b4_col = ((lane >> 3) & 1) * 8;
    const int t4_row = ((lane >> 3) & 1) * 8 + (lane & 7);   // x4 trans (k rows)
    const int t4_sel = ((lane >> 4) & 1) * 8;                // n8 block select

    for (int kt = 0; kt < S_ / 128; kt++) {
        const int k0 = kt * 128;
        __syncthreads();
        for (int i = t; i < 1024; i += 256) {
            const int row = i >> 3, c8 = (i & 7) * 8;
            const size_t g = (size_t)(b * S_ + k0 + row) * D_ + h * 64 + c8;
            *(uint4*)&sKh[row * FP + c8] = *(const uint4*)&khi[g];
            *(uint4*)&sKl[row * FP + c8] = *(const uint4*)&klo[g];
            *(uint4*)&sVh[row * FP + c8] = *(const uint4*)&vhi[g];
            *(uint4*)&sVl[row * FP + c8] = *(const uint4*)&vlo[g];
        }
        __syncthreads();

        // --- QK^T: c[16][4] over 128 k-cols, x4 B loads (2 n8 blocks each) ---
        float c[16][4];
#pragma unroll
        for (int nt = 0; nt < 16; nt++)
#pragma unroll
            for (int r = 0; r < 4; r++) c[nt][r] = 0.f;
#pragma unroll
        for (int ks = 0; ks < 4; ks++) {
#pragma unroll
            for (int p = 0; p < 8; p++) {
                uint32_t rh[4], rl[4];
                const uint32_t off = (uint32_t)((p * 16 + b4_row) * FP +
                                                ks * 16 + b4_col) * 2;
                ldmA4(rh, uKh + off);
                ldmA4(rl, uKl + off);
                mma16816(c[2*p],   qh[ks], rh);
                mma16816(c[2*p],   qh[ks], rl);
                mma16816(c[2*p],   ql[ks], rh);
                mma16816(c[2*p+1], qh[ks], rh + 2);
                mma16816(c[2*p+1], qh[ks], rl + 2);
                mma16816(c[2*p+1], ql[ks], rh + 2);
            }
        }

        // --- scale + mask ---
#pragma unroll
        for (int nt = 0; nt < 16; nt++) {
            const int cc = k0 + nt * 8 + col0;
            const int2 m0 = *(const int2*)&mask[((size_t)b * S_ + row0) * S_ + cc];
            const int2 m1 = *(const int2*)&mask[((size_t)b * S_ + row1) * S_ + cc];
            c[nt][0] = (m0.x == 0) ? -1e9f : c[nt][0] * SCALE_;
            c[nt][1] = (m0.y == 0) ? -1e9f : c[nt][1] * SCALE_;
            c[nt][2] = (m1.x == 0) ? -1e9f : c[nt][2] * SCALE_;
            c[nt][3] = (m1.y == 0) ? -1e9f : c[nt][3] * SCALE_;
        }

        // --- online softmax ---
        float rm0 = -1e30f, rm1 = -1e30f;
#pragma unroll
        for (int nt = 0; nt < 16; nt++) {
            rm0 = fmaxf(rm0, fmaxf(c[nt][0], c[nt][1]));
            rm1 = fmaxf(rm1, fmaxf(c[nt][2], c[nt][3]));
        }
        rm0 = fmaxf(rm0, __shfl_xor_sync(0xffffffffu, rm0, 1));
        rm0 = fmaxf(rm0, __shfl_xor_sync(0xffffffffu, rm0, 2));
        rm1 = fmaxf(rm1, __shfl_xor_sync(0xffffffffu, rm1, 1));
        rm1 = fmaxf(rm1, __shfl_xor_sync(0xffffffffu, rm1, 2));
        const float mn0 = fmaxf(mr0, rm0), mn1 = fmaxf(mr1, rm1);
        const float f0 = fexp(mr0 - mn0), f1 = fexp(mr1 - mn1);
        float rs0 = 0.f, rs1 = 0.f;
#pragma unroll
        for (int nt = 0; nt < 16; nt++) {
            c[nt][0] = fexp(c[nt][0] - mn0);
            c[nt][1] = fexp(c[nt][1] - mn0);
            c[nt][2] = fexp(c[nt][2] - mn1);
            c[nt][3] = fexp(c[nt][3] - mn1);
            rs0 += c[nt][0] + c[nt][1];
            rs1 += c[nt][2] + c[nt][3];
        }
        rs0 += __shfl_xor_sync(0xffffffffu, rs0, 1);
        rs0 += __shfl_xor_sync(0xffffffffu, rs0, 2);
        rs1 += __shfl_xor_sync(0xffffffffu, rs1, 1);
        rs1 += __shfl_xor_sync(0xffffffffu, rs1, 2);
        lr0 = lr0 * f0 + rs0; mr0 = mn0;
        lr1 = lr1 * f1 + rs1; mr1 = mn1;
#pragma unroll
        for (int j = 0; j < 8; j++) {
            O[j][0] *= f0; O[j][1] *= f0;
            O[j][2] *= f1; O[j][3] *= f1;
        }

        // --- stream P + m_kt ---
        {
            const size_t gb0 = ((size_t)bh * S_ + row0) * S_ + k0 + col0;
            const size_t gb1 = ((size_t)bh * S_ + row1) * S_ + k0 + col0;
#pragma unroll
            for (int nt = 0; nt < 16; nt++) {
                float2 w0, w1;
                w0.x = c[nt][0]; w0.y = c[nt][1];
                w1.x = c[nt][2]; w1.y = c[nt][3];
                *(float2*)&Praw[gb0 + nt * 8] = w0;
                *(float2*)&Praw[gb1 + nt * 8] = w1;
            }
            if ((lane & 3) == 0) {
                mkt[((size_t)bh * 16 + kt) * S_ + row0] = mn0;
                mkt[((size_t)bh * 16 + kt) * S_ + row1] = mn1;
            }
        }

        // --- P @ V : fragments straight from c; x4 trans V loads ---
#pragma unroll
        for (int ks2 = 0; ks2 < 8; ks2++) {
            const float* c0 = c[2 * ks2];
            const float* c1 = c[2 * ks2 + 1];
            uint32_t ah[4], al[4];
            ah[0] = pack_bf2(c0[0], c0[1]);
            ah[1] = pack_bf2(c0[2], c0[3]);
            ah[2] = pack_bf2(c1[0], c1[1]);
            ah[3] = pack_bf2(c1[2], c1[3]);
            al[0] = pack_bf2(c0[0] - __bfloat162float(__ushort_as_bfloat16((unsigned short)(ah[0] & 0xffff))),
                             c0[1] - __bfloat162float(__ushort_as_bfloat16((unsigned short)(ah[0] >> 16))));
            al[1] = pack_bf2(c0[2] - __bfloat162float(__ushort_as_bfloat16((unsigned short)(ah[1] & 0xffff))),
                             c0[3] - __bfloat162float(__ushort_as_bfloat16((unsigned short)(ah[1] >> 16))));
            al[2] = pack_bf2(c1[0] - __bfloat162float(__ushort_as_bfloat16((unsigned short)(ah[2] & 0xffff))),
                             c1[1] - __bfloat162float(__ushort_as_bfloat16((unsigned short)(ah[2] >> 16))));
            al[3] = pack_bf2(c1[2] - __bfloat162float(__ushort_as_bfloat16((unsigned short)(ah[3] & 0xffff))),
                             c1[3] - __bfloat162float(__ushort_as_bfloat16((unsigned short)(ah[3] >> 16))));
#pragma unroll
            for (int p = 0; p < 4; p++) {
                uint32_t vh4[4], vl4[4];
                const uint32_t off = (uint32_t)((ks2 * 16 + t4_row) * FP +
                                                p * 16 + t4_sel) * 2;
                ldmA4t(vh4, uVh + off);
                ldmA4t(vl4, uVl + off);
                mma16816(O[2*p],   ah, vh4);
                mma16816(O[2*p],   ah, vl4);
                mma16816(O[2*p],   al, vh4);
                mma16816(O[2*p+1], ah, vh4 + 2);
                mma16816(O[2*p+1], ah, vl4 + 2);
                mma16816(O[2*p+1], al, vh4 + 2);
            }
        }
    }

    // --- epilogue ---
    const float inv0 = 1.0f / lr0, inv1 = 1.0f / lr1;
#pragma unroll
    for (int nt2 = 0; nt2 < 8; nt2++) {
        const int n = nt2 * 8 + col0;
        float2 o0, o1;
        o0.x = O[nt2][0] * inv0; o0.y = O[nt2][1] * inv0;
        o1.x = O[nt2][2] * inv1; o1.y = O[nt2][3] * inv1;
        *(float2*)&ctx[(size_t)(b * S_ + row0) * D_ + h * 64 + n] = o0;
        *(float2*)&ctx[(size_t)(b * S_ + row1) * D_ + h * 64 + n] = o1;
    }
    if ((lane & 3) == 0) {
        size_t si = ((size_t)bh * S_ + row0) * 2;
        stats[si] = mr0; stats[si + 1] = lr0;
        si = ((size_t)bh * S_ + row1) * 2;
        stats[si] = mr1; stats[si + 1] = lr1;
    }
}

// ---------------------------------------------------------------------------
// Pass 2: attn = P * exp(m_kt - m_final) / l_final  (pure memory)
// ---------------------------------------------------------------------------
__global__ __launch_bounds__(256) void normalize_kernel(
    const float* __restrict__ P, const float* __restrict__ mkt,
    const float* __restrict__ stats, float* __restrict__ attn)
{
    __shared__ float corr[16];
    const int t   = threadIdx.x;
    const int row = blockIdx.x;
    const int bh  = blockIdx.y;

    const size_t si = ((size_t)bh * S_ + row) * 2;
    const float m_f = stats[si];
    const float inv_l = 1.0f / stats[si + 1];
    if (t < 16)
        corr[t] = __expf(mkt[((size_t)bh * 16 + t) * S_ + row] - m_f) * inv_l;
    __syncthreads();

    const size_t base = ((size_t)bh * S_ + row) * S_;
    const float c = corr[t >> 4];
    float4 v0 = *(const float4*)&P[base + t * 8];
    float4 v1 = *(const float4*)&P[base + t * 8 + 4];
    v0.x *= c; v0.y *= c; v0.z *= c; v0.w *= c;
    v1.x *= c; v1.y *= c; v1.z *= c; v1.w *= c;
    *(float4*)&attn[base + t * 8]     = v0;
    *(float4*)&attn[base + t * 8 + 4] = v1;
}

// ---------------------------------------------------------------------------
extern "C" void kernel_launch(void* const* d_in, const int* in_sizes, int n_in,
                              void* d_out, int out_size)
{
    const float* x    = (const float*)d_in[0];
    const int*   mask = (const int*)  d_in[1];
    const float* wq_w = (const float*)d_in[2];
    const float* wq_b = (const float*)d_in[3];
    const float* wk_w = (const float*)d_in[4];
    const float* wk_b = (const float*)d_in[5];
    const float* wv_w = (const float*)d_in[6];
    const float* wv_b = (const float*)d_in[7];
    const float* wo_w = (const float*)d_in[8];
    const float* wo_b = (const float*)d_in[9];

    float *q, *k, *v, *ctx, *attn_raw, *mkt, *stats;
    cudaGetSymbolAddress((void**)&q,        g_q);
    cudaGetSymbolAddress((void**)&k,        g_k);
    cudaGetSymbolAddress((void**)&v,        g_v);
    cudaGetSymbolAddress((void**)&ctx,      g_ctx);
    cudaGetSymbolAddress((void**)&attn_raw, g_attn_raw);
    cudaGetSymbolAddress((void**)&mkt,      g_mkt);
    cudaGetSymbolAddress((void**)&stats,    g_stats);

    __nv_bfloat16 *xhi, *xlo, *chi, *clo;
    __nv_bfloat16 *qhi_p, *qlo_p, *khi_p, *klo_p, *vhi_p, *vlo_p;
    __nv_bfloat16 *wqhi, *wqlo, *wkhi, *wklo, *wvhi, *wvlo, *wohi, *wolo;
    cudaGetSymbolAddress((void**)&xhi, g_xhi);   cudaGetSymbolAddress((void**)&xlo, g_xlo);
    cudaGetSymbolAddress((void**)&chi, g_chi);   cudaGetSymbolAddress((void**)&clo, g_clo);
    cudaGetSymbolAddress((void**)&qhi_p, g_qhi); cudaGetSymbolAddress((void**)&qlo_p, g_qlo);
    cudaGetSymbolAddress((void**)&khi_p, g_khi); cudaGetSymbolAddress((void**)&klo_p, g_klo);
    cudaGetSymbolAddress((void**)&vhi_p, g_vhi); cudaGetSymbolAddress((void**)&vlo_p, g_vlo);
    cudaGetSymbolAddress((void**)&wqhi, g_wqhi); cudaGetSymbolAddress((void**)&wqlo, g_wqlo);
    cudaGetSymbolAddress((void**)&wkhi, g_wkhi); cudaGetSymbolAddress((void**)&wklo, g_wklo);
    cudaGetSymbolAddress((void**)&wvhi, g_wvhi); cudaGetSymbolAddress((void**)&wvlo, g_wvlo);
    cudaGetSymbolAddress((void**)&wohi, g_wohi); cudaGetSymbolAddress((void**)&wolo, g_wolo);

    const long long CTXSZ = (long long)B_ * S_ * D_;
    const long long ATTSZ = (long long)B_ * H_ * S_ * S_;

    float* out_base = (float*)d_out;
    float* out_ptr;
    float* attn_ptr;
    if ((long long)out_size >= CTXSZ + ATTSZ) {
        out_ptr  = out_base;
        attn_ptr = out_base + CTXSZ;
    } else if ((long long)out_size == ATTSZ) {
        out_ptr  = q;
        attn_ptr = out_base;
    } else {
        out_ptr  = out_base;
        attn_ptr = attn_raw;
    }

    cudaFuncSetAttribute(flash_mma_kernel,
                         cudaFuncAttributeMaxDynamicSharedMemorySize, FLASH_SMEM);
    cudaFuncSetAttribute(gemm_mma_split,
                         cudaFuncAttributeMaxDynamicSharedMemorySize, GEMM_SMEM);

    const int M = B_ * S_;   // 4096
    const int N = D_;        // 1024
    const int K = D_;        // 1024

    // Split conversions (inputs only)
    const int xn4 = (int)(CTXSZ / 4);
    const int wn4 = D_ * D_ / 4;
    conv_split<<<(xn4 + 255) / 256, 256>>>((const float4*)x, (uint2*)xhi, (uint2*)xlo, xn4);
    conv_split<<<(wn4 + 255) / 256, 256>>>((const float4*)wq_w, (uint2*)wqhi, (uint2*)wqlo, wn4);
    conv_split<<<(wn4 + 255) / 256, 256>>>((const float4*)wk_w, (uint2*)wkhi, (uint2*)wklo, wn4);
    conv_split<<<(wn4 + 255) / 256, 256>>>((const float4*)wv_w, (uint2*)wvhi, (uint2*)wvlo, wn4);
    conv_split<<<(wn4 + 255) / 256, 256>>>((const float4*)wo_w, (uint2*)wohi, (uint2*)wolo, wn4);

    // Projections (epilogues emit bf16 hi/lo for flash)
    dim3 gGrid(N / 128, M / 128);
    gemm_mma_split<<<gGrid, 256, GEMM_SMEM>>>(xhi, xlo, wqhi, wqlo, wq_b, q, qhi_p, qlo_p, M, N, K);
    gemm_mma_split<<<gGrid, 256, GEMM_SMEM>>>(xhi, xlo, wkhi, wklo, wk_b, k, khi_p, klo_p, M, N, K);
    gemm_mma_split<<<gGrid, 256, GEMM_SMEM>>>(xhi, xlo, wvhi, wvlo, wv_b, v, vhi_p, vlo_p, M, N, K);

    // Tensor-core flash attention
    dim3 fGrid(S_ / 128, B_ * H_);
    flash_mma_kernel<<<fGrid, 256, FLASH_SMEM>>>(
        qhi_p, qlo_p, khi_p, klo_p, vhi_p, vlo_p,
        mask, attn_raw, mkt, stats, ctx);

    // Output projection
    conv_split<<<(xn4 + 255) / 256, 256>>>((const float4*)ctx, (uint2*)chi, (uint2*)clo, xn4);
    gemm_mma_split<<<gGrid, 256, GEMM_SMEM>>>(chi, clo, wohi, wolo, wo_b, out_ptr,
                                              (__nv_bfloat16*)nullptr, (__nv_bfloat16*)nullptr, M, N, K);

    // attn normalize
    dim3 nGrid(S_, B_ * H_);
    normalize_kernel<<<nGrid, 256>>>(attn_raw, mkt, stats, attn_ptr);
}

// round 8
// speedup vs baseline: 2.0335x; 1.0248x over previous
#include <cuda_runtime.h>
#include <cuda_bf16.h>
#include <math.h>
#include <stdint.h>

// Problem constants
#define B_  2
#define S_  2048
#define D_  1024
#define H_  16
#define DH_ 64
#define SCALE_ 0.125f   // DH^-0.5

typedef unsigned long long u64;

// ---------------------------------------------------------------------------
// Scratch (static device globals; no runtime allocation)
// ---------------------------------------------------------------------------
__device__ float g_q[(size_t)B_ * S_ * D_];                 // dummy sink
__device__ float g_attn_raw[(size_t)B_ * H_ * S_ * S_];
__device__ float g_mkt[(size_t)B_ * H_ * (S_ / 128) * S_];
__device__ float g_stats[(size_t)B_ * H_ * S_ * 2];

// bf16 hi/lo split operands
__device__ __nv_bfloat16 g_xhi[(size_t)B_ * S_ * D_];
__device__ __nv_bfloat16 g_xlo[(size_t)B_ * S_ * D_];
__device__ __nv_bfloat16 g_qhi[(size_t)B_ * S_ * D_], g_qlo[(size_t)B_ * S_ * D_];
__device__ __nv_bfloat16 g_khi[(size_t)B_ * S_ * D_], g_klo[(size_t)B_ * S_ * D_];
__device__ __nv_bfloat16 g_vhi[(size_t)B_ * S_ * D_], g_vlo[(size_t)B_ * S_ * D_];
__device__ __nv_bfloat16 g_chi[(size_t)B_ * S_ * D_], g_clo[(size_t)B_ * S_ * D_];
__device__ __nv_bfloat16 g_wqhi[D_ * D_], g_wqlo[D_ * D_];
__device__ __nv_bfloat16 g_wkhi[D_ * D_], g_wklo[D_ * D_];
__device__ __nv_bfloat16 g_wvhi[D_ * D_], g_wvlo[D_ * D_];
__device__ __nv_bfloat16 g_wohi[D_ * D_], g_wolo[D_ * D_];

// ---------------------------------------------------------------------------
// mma.sync / ldmatrix helpers
// ---------------------------------------------------------------------------
__device__ __forceinline__ uint32_t smem_u32(const void* p) {
    uint32_t a;
    asm("{ .reg .u64 t; cvta.to.shared.u64 t, %1; cvt.u32.u64 %0, t; }"
        : "=r"(a) : "l"(p));
    return a;
}
__device__ __forceinline__ void ldmA4(uint32_t* a, uint32_t addr) {
    asm volatile("ldmatrix.sync.aligned.m8n8.x4.shared.b16 {%0,%1,%2,%3}, [%4];"
                 : "=r"(a[0]), "=r"(a[1]), "=r"(a[2]), "=r"(a[3]) : "r"(addr));
}
__device__ __forceinline__ void ldmA4t(uint32_t* a, uint32_t addr) {
    asm volatile("ldmatrix.sync.aligned.m8n8.x4.trans.shared.b16 {%0,%1,%2,%3}, [%4];"
                 : "=r"(a[0]), "=r"(a[1]), "=r"(a[2]), "=r"(a[3]) : "r"(addr));
}
__device__ __forceinline__ void mma16816(float* c, const uint32_t* a,
                                         const uint32_t* b) {
    asm volatile(
        "mma.sync.aligned.m16n8k16.row.col.f32.bf16.bf16.f32 "
        "{%0,%1,%2,%3}, {%4,%5,%6,%7}, {%8,%9}, {%0,%1,%2,%3};"
        : "+f"(c[0]), "+f"(c[1]), "+f"(c[2]), "+f"(c[3])
        : "r"(a[0]), "r"(a[1]), "r"(a[2]), "r"(a[3]), "r"(b[0]), "r"(b[1]));
}
__device__ __forceinline__ void cpasync16(uint32_t saddr, const void* gaddr) {
    asm volatile("cp.async.cg.shared.global [%0], [%1], 16;"
                 :: "r"(saddr), "l"(gaddr));
}
#define CP_COMMIT() asm volatile("cp.async.commit_group;" ::: "memory")
#define CP_WAIT0()  asm volatile("cp.async.wait_group 0;" ::: "memory")
#define CP_WAIT1()  asm volatile("cp.async.wait_group 1;" ::: "memory")

__device__ __forceinline__ uint32_t pack_bf2(float x, float y) {
    return (uint32_t)__bfloat16_as_ushort(__float2bfloat16(x)) |
           ((uint32_t)__bfloat16_as_ushort(__float2bfloat16(y)) << 16);
}
// Truncation split (cheap): hi16 bits via PRMT; residual exact via FSUB.
#define TRUNC_HI2(x, y) __byte_perm(__float_as_uint(x), __float_as_uint(y), 0x7632)
__device__ __forceinline__ float trunc_res(float x) {
    return x - __uint_as_float(__float_as_uint(x) & 0xFFFF0000u);
}
// RN split store of a float pair to hi/lo bf16 arrays (cold paths)
__device__ __forceinline__ void split_store(
    __nv_bfloat16* hi, __nv_bfloat16* lo, size_t idx, float x, float y)
{
    const __nv_bfloat16 hx = __float2bfloat16(x), hy = __float2bfloat16(y);
    *(uint32_t*)&hi[idx] = (uint32_t)__bfloat16_as_ushort(hx) |
                           ((uint32_t)__bfloat16_as_ushort(hy) << 16);
    *(uint32_t*)&lo[idx] = pack_bf2(x - __bfloat162float(hx),
                                    y - __bfloat162float(hy));
}
__device__ __forceinline__ float fexp(float x) { return __expf(x); }

// ---------------------------------------------------------------------------
// Split-conversions
// ---------------------------------------------------------------------------
__global__ __launch_bounds__(256) void conv_split(
    const float4* __restrict__ src, uint2* __restrict__ hi,
    uint2* __restrict__ lo, int n4)
{
    const int i = blockIdx.x * 256 + threadIdx.x;
    if (i >= n4) return;
    const float4 v = src[i];
    split_store((__nv_bfloat16*)hi, (__nv_bfloat16*)lo, (size_t)i * 4,     v.x, v.y);
    split_store((__nv_bfloat16*)hi, (__nv_bfloat16*)lo, (size_t)i * 4 + 2, v.z, v.w);
}

__global__ __launch_bounds__(256) void conv_split_w4(
    const float4* s0, uint2* h0, uint2* l0,
    const float4* s1, uint2* h1, uint2* l1,
    const float4* s2, uint2* h2, uint2* l2,
    const float4* s3, uint2* h3, uint2* l3, int n4)
{
    const int i = blockIdx.x * 256 + threadIdx.x;
    if (i >= n4) return;
    const int w = blockIdx.y;
    const float4* src = (w == 0) ? s0 : (w == 1) ? s1 : (w == 2) ? s2 : s3;
    uint2* hi = (w == 0) ? h0 : (w == 1) ? h1 : (w == 2) ? h2 : h3;
    uint2* lo = (w == 0) ? l0 : (w == 1) ? l1 : (w == 2) ? l2 : l3;
    const float4 v = src[i];
    split_store((__nv_bfloat16*)hi, (__nv_bfloat16*)lo, (size_t)i * 4,     v.x, v.y);
    split_store((__nv_bfloat16*)hi, (__nv_bfloat16*)lo, (size_t)i * 4 + 2, v.z, v.w);
}

// ---------------------------------------------------------------------------
// Shared GEMM body: C = (Ahi+Alo)[M,K] @ (Bhi+Blo)[N,K]^T + bias.
// Fused 3-term K-loop, 2-stage cp.async pipeline. CTA 128x128, 8 warps.
// C (fp32) and Chi/Clo (bf16 split) each optional.
// ---------------------------------------------------------------------------
#define GP 72
#define GTILE (128 * GP)
#define GEMM_SMEM (2 * 4 * GTILE * 2)          // 147456 bytes

__device__ __forceinline__ void gemm_body(
    const __nv_bfloat16* __restrict__ Ahi, const __nv_bfloat16* __restrict__ Alo,
    const __nv_bfloat16* __restrict__ Bhi, const __nv_bfloat16* __restrict__ Blo,
    const float* __restrict__ bias, float* __restrict__ C,
    __nv_bfloat16* __restrict__ Chi, __nv_bfloat16* __restrict__ Clo,
    int M, int N, int K, int bm, int bn, uint32_t sb)
{
    const int tid  = threadIdx.x;
    const int lane = tid & 31, wid = tid >> 5;
    const int warp_m = wid >> 2, warp_n = wid & 3;

    const int a_r = warp_m * 64 + (lane & 15);
    const int a_c = (lane >> 4) * 8;
    const int b4_row = ((lane >> 4) & 1) * 8 + (lane & 7);
    const int b4_col = ((lane >> 3) & 1) * 8;

    const int lrow = tid >> 3;
    const int lc8  = (tid & 7) * 8;

    float acc[4][4][4];
#pragma unroll
    for (int mt = 0; mt < 4; mt++)
#pragma unroll
        for (int nt = 0; nt < 4; nt++)
#pragma unroll
            for (int r = 0; r < 4; r++) acc[mt][nt][r] = 0.f;

#define TBASE(s, o) (sb + (uint32_t)(((s) * 4 + (o)) * GTILE) * 2)
#define LOAD_STAGE(s, k0) do {                                                \
    const uint32_t _dAh = TBASE(s, 0), _dAl = TBASE(s, 1);                    \
    const uint32_t _dBh = TBASE(s, 2), _dBl = TBASE(s, 3);                    \
    _Pragma("unroll")                                                         \
    for (int rr = 0; rr < 4; rr++) {                                          \
        const int row = lrow + rr * 32;                                       \
        const uint32_t so = (uint32_t)(row * GP + lc8) * 2;                   \
        const size_t ga = (size_t)(bm + row) * K + (k0) + lc8;                \
        const size_t gb = (size_t)(bn + row) * K + (k0) + lc8;                \
        cpasync16(_dAh + so, &Ahi[ga]);                                       \
        cpasync16(_dAl + so, &Alo[ga]);                                       \
        cpasync16(_dBh + so, &Bhi[gb]);                                       \
        cpasync16(_dBl + so, &Blo[gb]);                                       \
    }                                                                         \
    CP_COMMIT();                                                              \
} while (0)

    LOAD_STAGE(0, 0);

    const int NK = K / 64;
    for (int kc = 0; kc < NK; kc++) {
        const int cur = kc & 1;
        if (kc + 1 < NK) { LOAD_STAGE(cur ^ 1, (kc + 1) * 64); CP_WAIT1(); }
        else             { CP_WAIT0(); }
        __syncthreads();

        const uint32_t uAh = TBASE(cur, 0), uAl = TBASE(cur, 1);
        const uint32_t uBh = TBASE(cur, 2), uBl = TBASE(cur, 3);
#pragma unroll
        for (int ks = 0; ks < 4; ks++) {
            uint32_t ah[4][4], al[4][4];
#pragma unroll
            for (int mt = 0; mt < 4; mt++) {
                const uint32_t ao = (uint32_t)((a_r + mt * 16) * GP +
                                               ks * 16 + a_c) * 2;
                ldmA4(ah[mt], uAh + ao);
                ldmA4(al[mt], uAl + ao);
            }
            uint32_t bh[4][2], bl[4][2];
#pragma unroll
            for (int p = 0; p < 2; p++) {
                uint32_t r4[4];
                const uint32_t bo = (uint32_t)((warp_n * 32 + p * 16 + b4_row) * GP +
                                               ks * 16 + b4_col) * 2;
                ldmA4(r4, uBh + bo);
                bh[2*p][0] = r4[0]; bh[2*p][1] = r4[1];
                bh[2*p+1][0] = r4[2]; bh[2*p+1][1] = r4[3];
                ldmA4(r4, uBl + bo);
                bl[2*p][0] = r4[0]; bl[2*p][1] = r4[1];
                bl[2*p+1][0] = r4[2]; bl[2*p+1][1] = r4[3];
            }
#pragma unroll
            for (int mt = 0; mt < 4; mt++)
#pragma unroll
                for (int nt = 0; nt < 4; nt++) {
                    mma16816(acc[mt][nt], ah[mt], bh[nt]);
                    mma16816(acc[mt][nt], ah[mt], bl[nt]);
                    mma16816(acc[mt][nt], al[mt], bh[nt]);
                }
        }
        __syncthreads();
    }

    const int em = bm + warp_m * 64 + (lane >> 2);
    const int en = bn + warp_n * 32 + (lane & 3) * 2;
#pragma unroll
    for (int mt = 0; mt < 4; mt++) {
#pragma unroll
        for (int nt = 0; nt < 4; nt++) {
            const int n = en + nt * 8;
            const float bx = bias[n], by = bias[n + 1];
            const int m0 = em + mt * 16;
            float2 o0, o1;
            o0.x = acc[mt][nt][0] + bx; o0.y = acc[mt][nt][1] + by;
            o1.x = acc[mt][nt][2] + bx; o1.y = acc[mt][nt][3] + by;
            if (C) {
                *(float2*)&C[(size_t)m0 * N + n]       = o0;
                *(float2*)&C[(size_t)(m0 + 8) * N + n] = o1;
            }
            if (Chi) {
                split_store(Chi, Clo, (size_t)m0 * N + n,       o0.x, o0.y);
                split_store(Chi, Clo, (size_t)(m0 + 8) * N + n, o1.x, o1.y);
            }
        }
    }
#undef LOAD_STAGE
#undef TBASE
}

// Fused QKV projection: blockIdx.z selects weight / output set. bf16 out only.
__global__ __launch_bounds__(256) void gemm_qkv(
    const __nv_bfloat16* __restrict__ Ahi, const __nv_bfloat16* __restrict__ Alo,
    const __nv_bfloat16* bq_h, const __nv_bfloat16* bq_l,
    const __nv_bfloat16* bk_h, const __nv_bfloat16* bk_l,
    const __nv_bfloat16* bv_h, const __nv_bfloat16* bv_l,
    const float* biq, const float* bik, const float* biv,
    __nv_bfloat16* qh, __nv_bfloat16* ql,
    __nv_bfloat16* kh, __nv_bfloat16* kl,
    __nv_bfloat16* vh, __nv_bfloat16* vl,
    int M, int N, int K)
{
    extern __shared__ __nv_bfloat16 gsm[];
    const int z = blockIdx.z;
    const __nv_bfloat16* Bh = (z == 0) ? bq_h : (z == 1) ? bk_h : bv_h;
    const __nv_bfloat16* Bl = (z == 0) ? bq_l : (z == 1) ? bk_l : bv_l;
    const float* bias = (z == 0) ? biq : (z == 1) ? bik : biv;
    __nv_bfloat16* Ch = (z == 0) ? qh : (z == 1) ? kh : vh;
    __nv_bfloat16* Cl = (z == 0) ? ql : (z == 1) ? kl : vl;
    gemm_body(Ahi, Alo, Bh, Bl, bias, (float*)nullptr, Ch, Cl,
              M, N, K, blockIdx.y * 128, blockIdx.x * 128, smem_u32(gsm));
}

// Output projection: fp32 out only.
__global__ __launch_bounds__(256) void gemm_out(
    const __nv_bfloat16* __restrict__ Ahi, const __nv_bfloat16* __restrict__ Alo,
    const __nv_bfloat16* __restrict__ Bhi, const __nv_bfloat16* __restrict__ Blo,
    const float* __restrict__ bias, float* __restrict__ C,
    int M, int N, int K)
{
    extern __shared__ __nv_bfloat16 gsm[];
    gemm_body(Ahi, Alo, Bhi, Blo, bias, C,
              (__nv_bfloat16*)nullptr, (__nv_bfloat16*)nullptr,
              M, N, K, blockIdx.y * 128, blockIdx.x * 128, smem_u32(gsm));
}

// ---------------------------------------------------------------------------
// Tensor-core flash attention: per (bh, 128-row q tile), 8 warps.
// Truncation-split P packing; epilogue emits ctx bf16 hi/lo directly.
// ---------------------------------------------------------------------------
#define FP 72
#define FLASH_SMEM (6 * 128 * FP * 2)

__global__ __launch_bounds__(256, 1) void flash_mma_kernel(
    const __nv_bfloat16* __restrict__ qhi, const __nv_bfloat16* __restrict__ qlo,
    const __nv_bfloat16* __restrict__ khi, const __nv_bfloat16* __restrict__ klo,
    const __nv_bfloat16* __restrict__ vhi, const __nv_bfloat16* __restrict__ vlo,
    const int* __restrict__ mask, float* __restrict__ Praw,
    float* __restrict__ mkt, float* __restrict__ stats,
    __nv_bfloat16* __restrict__ chi, __nv_bfloat16* __restrict__ clo)
{
    extern __shared__ __nv_bfloat16 smb[];
    __nv_bfloat16* sQh = smb;
    __nv_bfloat16* sQl = sQh + 128 * FP;
    __nv_bfloat16* sKh = sQl + 128 * FP;
    __nv_bfloat16* sKl = sKh + 128 * FP;
    __nv_bfloat16* sVh = sKl + 128 * FP;
    __nv_bfloat16* sVl = sVh + 128 * FP;

    const int t = threadIdx.x, lane = t & 31, warp = t >> 5;
    const int bh = blockIdx.y;
    const int b = bh >> 4, h = bh & 15;
    const int q0 = blockIdx.x * 128;

    const uint32_t uQh = smem_u32(sQh), uQl = smem_u32(sQl);
    const uint32_t uKh = smem_u32(sKh), uKl = smem_u32(sKl);
    const uint32_t uVh = smem_u32(sVh), uVl = smem_u32(sVl);

    for (int i = t; i < 1024; i += 256) {
        const int row = i >> 3, c8 = (i & 7) * 8;
        const size_t g = (size_t)(b * S_ + q0 + row) * D_ + h * 64 + c8;
        *(uint4*)&sQh[row * FP + c8] = *(const uint4*)&qhi[g];
        *(uint4*)&sQl[row * FP + c8] = *(const uint4*)&qlo[g];
    }
    __syncthreads();

    uint32_t qh[4][4], ql[4][4];
    const int a_r = warp * 16 + (lane & 15);
    const int a_c = (lane >> 4) * 8;
#pragma unroll
    for (int ks = 0; ks < 4; ks++) {
        ldmA4(qh[ks], uQh + (uint32_t)(a_r * FP + ks * 16 + a_c) * 2);
        ldmA4(ql[ks], uQl + (uint32_t)(a_r * FP + ks * 16 + a_c) * 2);
    }

    float O[8][4];
#pragma unroll
    for (int j = 0; j < 8; j++)
#pragma unroll
        for (int r = 0; r < 4; r++) O[j][r] = 0.f;
    float mr0 = -1e30f, mr1 = -1e30f, lr0 = 0.f, lr1 = 0.f;

    const int row0 = q0 + warp * 16 + (lane >> 2);
    const int row1 = row0 + 8;
    const int col0 = (lane & 3) * 2;
    const int b4_row = ((lane >> 4) & 1) * 8 + (lane & 7);
    const int b4_col = ((lane >> 3) & 1) * 8;
    const int t4_row = ((lane >> 3) & 1) * 8 + (lane & 7);
    const int t4_sel = ((lane >> 4) & 1) * 8;

    for (int kt = 0; kt < S_ / 128; kt++) {
        const int k0 = kt * 128;
        __syncthreads();
        for (int i = t; i < 1024; i += 256) {
            const int row = i >> 3, c8 = (i & 7) * 8;
            const size_t g = (size_t)(b * S_ + k0 + row) * D_ + h * 64 + c8;
            *(uint4*)&sKh[row * FP + c8] = *(const uint4*)&khi[g];
            *(uint4*)&sKl[row * FP + c8] = *(const uint4*)&klo[g];
            *(uint4*)&sVh[row * FP + c8] = *(const uint4*)&vhi[g];
            *(uint4*)&sVl[row * FP + c8] = *(const uint4*)&vlo[g];
        }
        __syncthreads();

        // --- QK^T ---
        float c[16][4];
#pragma unroll
        for (int nt = 0; nt < 16; nt++)
#pragma unroll
            for (int r = 0; r < 4; r++) c[nt][r] = 0.f;
#pragma unroll
        for (int ks = 0; ks < 4; ks++) {
#pragma unroll
            for (int p = 0; p < 8; p++) {
                uint32_t rh[4], rl[4];
                const uint32_t off = (uint32_t)((p * 16 + b4_row) * FP +
                                                ks * 16 + b4_col) * 2;
                ldmA4(rh, uKh + off);
                ldmA4(rl, uKl + off);
                mma16816(c[2*p],   qh[ks], rh);
                mma16816(c[2*p],   qh[ks], rl);
                mma16816(c[2*p],   ql[ks], rh);
                mma16816(c[2*p+1], qh[ks], rh + 2);
                mma16816(c[2*p+1], qh[ks], rl + 2);
                mma16816(c[2*p+1], ql[ks], rh + 2);
            }
        }

        // --- scale + mask ---
#pragma unroll
        for (int nt = 0; nt < 16; nt++) {
            const int cc = k0 + nt * 8 + col0;
            const int2 m0 = *(const int2*)&mask[((size_t)b * S_ + row0) * S_ + cc];
            const int2 m1 = *(const int2*)&mask[((size_t)b * S_ + row1) * S_ + cc];
            c[nt][0] = (m0.x == 0) ? -1e9f : c[nt][0] * SCALE_;
            c[nt][1] = (m0.y == 0) ? -1e9f : c[nt][1] * SCALE_;
            c[nt][2] = (m1.x == 0) ? -1e9f : c[nt][2] * SCALE_;
            c[nt][3] = (m1.y == 0) ? -1e9f : c[nt][3] * SCALE_;
        }

        // --- online softmax ---
        float rm0 = -1e30f, rm1 = -1e30f;
#pragma unroll
        for (int nt = 0; nt < 16; nt++) {
            rm0 = fmaxf(rm0, fmaxf(c[nt][0], c[nt][1]));
            rm1 = fmaxf(rm1, fmaxf(c[nt][2], c[nt][3]));
        }
        rm0 = fmaxf(rm0, __shfl_xor_sync(0xffffffffu, rm0, 1));
        rm0 = fmaxf(rm0, __shfl_xor_sync(0xffffffffu, rm0, 2));
        rm1 = fmaxf(rm1, __shfl_xor_sync(0xffffffffu, rm1, 1));
        rm1 = fmaxf(rm1, __shfl_xor_sync(0xffffffffu, rm1, 2));
        const float mn0 = fmaxf(mr0, rm0), mn1 = fmaxf(mr1, rm1);
        const float f0 = fexp(mr0 - mn0), f1 = fexp(mr1 - mn1);
        float rs0 = 0.f, rs1 = 0.f;
#pragma unroll
        for (int nt = 0; nt < 16; nt++) {
            c[nt][0] = fexp(c[nt][0] - mn0);
            c[nt][1] = fexp(c[nt][1] - mn0);
            c[nt][2] = fexp(c[nt][2] - mn1);
            c[nt][3] = fexp(c[nt][3] - mn1);
            rs0 += c[nt][0] + c[nt][1];
            rs1 += c[nt][2] + c[nt][3];
        }
        rs0 += __shfl_xor_sync(0xffffffffu, rs0, 1);
        rs0 += __shfl_xor_sync(0xffffffffu, rs0, 2);
        rs1 += __shfl_xor_sync(0xffffffffu, rs1, 1);
        rs1 += __shfl_xor_sync(0xffffffffu, rs1, 2);
        lr0 = lr0 * f0 + rs0; mr0 = mn0;
        lr1 = lr1 * f1 + rs1; mr1 = mn1;
#pragma unroll
        for (int j = 0; j < 8; j++) {
            O[j][0] *= f0; O[j][1] *= f0;
            O[j][2] *= f1; O[j][3] *= f1;
        }

        // --- stream P + m_kt ---
        {
            const size_t gb0 = ((size_t)bh * S_ + row0) * S_ + k0 + col0;
            const size_t gb1 = ((size_t)bh * S_ + row1) * S_ + k0 + col0;
#pragma unroll
            for (int nt = 0; nt < 16; nt++) {
                float2 w0, w1;
                w0.x = c[nt][0]; w0.y = c[nt][1];
                w1.x = c[nt][2]; w1.y = c[nt][3];
                *(float2*)&Praw[gb0 + nt * 8] = w0;
                *(float2*)&Praw[gb1 + nt * 8] = w1;
            }
            if ((lane & 3) == 0) {
                mkt[((size_t)bh * 16 + kt) * S_ + row0] = mn0;
                mkt[((size_t)bh * 16 + kt) * S_ + row1] = mn1;
            }
        }

        // --- P @ V : truncation-split fragments straight from c ---
#pragma unroll
        for (int ks2 = 0; ks2 < 8; ks2++) {
            const float* c0 = c[2 * ks2];
            const float* c1 = c[2 * ks2 + 1];
            uint32_t ah[4], al[4];
            ah[0] = TRUNC_HI2(c0[0], c0[1]);
            ah[1] = TRUNC_HI2(c0[2], c0[3]);
            ah[2] = TRUNC_HI2(c1[0], c1[1]);
            ah[3] = TRUNC_HI2(c1[2], c1[3]);
            al[0] = TRUNC_HI2(trunc_res(c0[0]), trunc_res(c0[1]));
            al[1] = TRUNC_HI2(trunc_res(c0[2]), trunc_res(c0[3]));
            al[2] = TRUNC_HI2(trunc_res(c1[0]), trunc_res(c1[1]));
            al[3] = TRUNC_HI2(trunc_res(c1[2]), trunc_res(c1[3]));
#pragma unroll
            for (int p = 0; p < 4; p++) {
                uint32_t vh4[4], vl4[4];
                const uint32_t off = (uint32_t)((ks2 * 16 + t4_row) * FP +
                                                p * 16 + t4_sel) * 2;
                ldmA4t(vh4, uVh + off);
                ldmA4t(vl4, uVl + off);
                mma16816(O[2*p],   ah, vh4);
                mma16816(O[2*p],   ah, vl4);
                mma16816(O[2*p],   al, vh4);
                mma16816(O[2*p+1], ah, vh4 + 2);
                mma16816(O[2*p+1], ah, vl4 + 2);
                mma16816(O[2*p+1], al, vh4 + 2);
            }
        }
    }

    // --- epilogue: normalized ctx as bf16 hi/lo (consumed by out-GEMM) ---
    const float inv0 = 1.0f / lr0, inv1 = 1.0f / lr1;
#pragma unroll
    for (int nt2 = 0; nt2 < 8; nt2++) {
        const int n = nt2 * 8 + col0;
        const size_t g0 = (size_t)(b * S_ + row0) * D_ + h * 64 + n;
        const size_t g1 = (size_t)(b * S_ + row1) * D_ + h * 64 + n;
        split_store(chi, clo, g0, O[nt2][0] * inv0, O[nt2][1] * inv0);
        split_store(chi, clo, g1, O[nt2][2] * inv1, O[nt2][3] * inv1);
    }
    if ((lane & 3) == 0) {
        size_t si = ((size_t)bh * S_ + row0) * 2;
        stats[si] = mr0; stats[si + 1] = lr0;
        si = ((size_t)bh * S_ + row1) * 2;
        stats[si] = mr1; stats[si + 1] = lr1;
    }
}

// ---------------------------------------------------------------------------
// Pass 2: attn = P * exp(m_kt - m_final) / l_final  (pure memory)
// ---------------------------------------------------------------------------
__global__ __launch_bounds__(256) void normalize_kernel(
    const float* __restrict__ P, const float* __restrict__ mkt,
    const float* __restrict__ stats, float* __restrict__ attn)
{
    __shared__ float corr[16];
    const int t   = threadIdx.x;
    const int row = blockIdx.x;
    const int bh  = blockIdx.y;

    const size_t si = ((size_t)bh * S_ + row) * 2;
    const float m_f = stats[si];
    const float inv_l = 1.0f / stats[si + 1];
    if (t < 16)
        corr[t] = __expf(mkt[((size_t)bh * 16 + t) * S_ + row] - m_f) * inv_l;
    __syncthreads();

    const size_t base = ((size_t)bh * S_ + row) * S_;
    const float c = corr[t >> 4];
    float4 v0 = *(const float4*)&P[base + t * 8];
    float4 v1 = *(const float4*)&P[base + t * 8 + 4];
    v0.x *= c; v0.y *= c; v0.z *= c; v0.w *= c;
    v1.x *= c; v1.y *= c; v1.z *= c; v1.w *= c;
    *(float4*)&attn[base + t * 8]     = v0;
    *(float4*)&attn[base + t * 8 + 4] = v1;
}

// ---------------------------------------------------------------------------
extern "C" void kernel_launch(void* const* d_in, const int* in_sizes, int n_in,
                              void* d_out, int out_size)
{
    const float* x    = (const float*)d_in[0];
    const int*   mask = (const int*)  d_in[1];
    const float* wq_w = (const float*)d_in[2];
    const float* wq_b = (const float*)d_in[3];
    const float* wk_w = (const float*)d_in[4];
    const float* wk_b = (const float*)d_in[5];
    const float* wv_w = (const float*)d_in[6];
    const float* wv_b = (const float*)d_in[7];
    const float* wo_w = (const float*)d_in[8];
    const float* wo_b = (const float*)d_in[9];

    float *qdump, *attn_raw, *mkt, *stats;
    cudaGetSymbolAddress((void**)&qdump,    g_q);
    cudaGetSymbolAddress((void**)&attn_raw, g_attn_raw);
    cudaGetSymbolAddress((void**)&mkt,      g_mkt);
    cudaGetSymbolAddress((void**)&stats,    g_stats);

    __nv_bfloat16 *xhi, *xlo, *chi, *clo;
    __nv_bfloat16 *qhi_p, *qlo_p, *khi_p, *klo_p, *vhi_p, *vlo_p;
    __nv_bfloat16 *wqhi, *wqlo, *wkhi, *wklo, *wvhi, *wvlo, *wohi, *wolo;
    cudaGetSymbolAddress((void**)&xhi, g_xhi);   cudaGetSymbolAddress((void**)&xlo, g_xlo);
    cudaGetSymbolAddress((void**)&chi, g_chi);   cudaGetSymbolAddress((void**)&clo, g_clo);
    cudaGetSymbolAddress((void**)&qhi_p, g_qhi); cudaGetSymbolAddress((void**)&qlo_p, g_qlo);
    cudaGetSymbolAddress((void**)&khi_p, g_khi); cudaGetSymbolAddress((void**)&klo_p, g_klo);
    cudaGetSymbolAddress((void**)&vhi_p, g_vhi); cudaGetSymbolAddress((void**)&vlo_p, g_vlo);
    cudaGetSymbolAddress((void**)&wqhi, g_wqhi); cudaGetSymbolAddress((void**)&wqlo, g_wqlo);
    cudaGetSymbolAddress((void**)&wkhi, g_wkhi); cudaGetSymbolAddress((void**)&wklo, g_wklo);
    cudaGetSymbolAddress((void**)&wvhi, g_wvhi); cudaGetSymbolAddress((void**)&wvlo, g_wvlo);
    cudaGetSymbolAddress((void**)&wohi, g_wohi); cudaGetSymbolAddress((void**)&wolo, g_wolo);

    const long long CTXSZ = (long long)B_ * S_ * D_;
    const long long ATTSZ = (long long)B_ * H_ * S_ * S_;

    float* out_base = (float*)d_out;
    float* out_ptr;
    float* attn_ptr;
    if ((long long)out_size >= CTXSZ + ATTSZ) {
        out_ptr  = out_base;
        attn_ptr = out_base + CTXSZ;
    } else if ((long long)out_size == ATTSZ) {
        out_ptr  = qdump;
        attn_ptr = out_base;
    } else {
        out_ptr  = out_base;
        attn_ptr = attn_raw;
    }

    cudaFuncSetAttribute(flash_mma_kernel,
                         cudaFuncAttributeMaxDynamicSharedMemorySize, FLASH_SMEM);
    cudaFuncSetAttribute(gemm_qkv,
                         cudaFuncAttributeMaxDynamicSharedMemorySize, GEMM_SMEM);
    cudaFuncSetAttribute(gemm_out,
                         cudaFuncAttributeMaxDynamicSharedMemorySize, GEMM_SMEM);

    const int M = B_ * S_;   // 4096
    const int N = D_;        // 1024
    const int K = D_;        // 1024

    // Split conversions (x + 4 weights in 2 launches)
    const int xn4 = (int)(CTXSZ / 4);
    const int wn4 = D_ * D_ / 4;
    conv_split<<<(xn4 + 255) / 256, 256>>>((const float4*)x, (uint2*)xhi, (uint2*)xlo, xn4);
    dim3 wGrid((wn4 + 255) / 256, 4);
    conv_split_w4<<<wGrid, 256>>>(
        (const float4*)wq_w, (uint2*)wqhi, (uint2*)wqlo,
        (const float4*)wk_w, (uint2*)wkhi, (uint2*)wklo,
        (const float4*)wv_w, (uint2*)wvhi, (uint2*)wvlo,
        (const float4*)wo_w, (uint2*)wohi, (uint2*)wolo, wn4);

    // Fused QKV projections (bf16 hi/lo outputs only)
    dim3 qkvGrid(N / 128, M / 128, 3);
    gemm_qkv<<<qkvGrid, 256, GEMM_SMEM>>>(
        xhi, xlo,
        wqhi, wqlo, wkhi, wklo, wvhi, wvlo,
        wq_b, wk_b, wv_b,
        qhi_p, qlo_p, khi_p, klo_p, vhi_p, vlo_p, M, N, K);

    // Tensor-core flash attention (emits ctx hi/lo directly)
    dim3 fGrid(S_ / 128, B_ * H_);
    flash_mma_kernel<<<fGrid, 256, FLASH_SMEM>>>(
        qhi_p, qlo_p, khi_p, klo_p, vhi_p, vlo_p,
        mask, attn_raw, mkt, stats, chi, clo);

    // Output projection (fp32 out)
    dim3 gGrid(N / 128, M / 128);
    gemm_out<<<gGrid, 256, GEMM_SMEM>>>(chi, clo, wohi, wolo, wo_b, out_ptr, M, N, K);

    // attn normalize
    dim3 nGrid(S_, B_ * H_);
    normalize_kernel<<<nGrid, 256>>>(attn_raw, mkt, stats, attn_ptr);
}

// round 9
// speedup vs baseline: 2.3677x; 1.1643x over previous
#include <cuda_runtime.h>
#include <cuda_bf16.h>
#include <math.h>
#include <stdint.h>

// Problem constants
#define B_  2
#define S_  2048
#define D_  1024
#define H_  16
#define DH_ 64
#define SCALE_ 0.125f   // DH^-0.5

typedef unsigned long long u64;

// ---------------------------------------------------------------------------
// Scratch (static device globals; no runtime allocation)
// ---------------------------------------------------------------------------
__device__ float g_q[(size_t)B_ * S_ * D_];                 // dummy sink
__device__ float g_attn_raw[(size_t)B_ * H_ * S_ * S_];
__device__ float g_mkt[(size_t)B_ * H_ * (S_ / 64) * S_];
__device__ float g_stats[(size_t)B_ * H_ * S_ * 2];

// bf16 hi/lo split operands
__device__ __nv_bfloat16 g_xhi[(size_t)B_ * S_ * D_];
__device__ __nv_bfloat16 g_xlo[(size_t)B_ * S_ * D_];
__device__ __nv_bfloat16 g_qhi[(size_t)B_ * S_ * D_], g_qlo[(size_t)B_ * S_ * D_];
__device__ __nv_bfloat16 g_khi[(size_t)B_ * S_ * D_], g_klo[(size_t)B_ * S_ * D_];
__device__ __nv_bfloat16 g_vhi[(size_t)B_ * S_ * D_], g_vlo[(size_t)B_ * S_ * D_];
__device__ __nv_bfloat16 g_chi[(size_t)B_ * S_ * D_], g_clo[(size_t)B_ * S_ * D_];
__device__ __nv_bfloat16 g_wqhi[D_ * D_], g_wqlo[D_ * D_];
__device__ __nv_bfloat16 g_wkhi[D_ * D_], g_wklo[D_ * D_];
__device__ __nv_bfloat16 g_wvhi[D_ * D_], g_wvlo[D_ * D_];
__device__ __nv_bfloat16 g_wohi[D_ * D_], g_wolo[D_ * D_];

// ---------------------------------------------------------------------------
// mma.sync / ldmatrix helpers
// ---------------------------------------------------------------------------
__device__ __forceinline__ uint32_t smem_u32(const void* p) {
    uint32_t a;
    asm("{ .reg .u64 t; cvta.to.shared.u64 t, %1; cvt.u32.u64 %0, t; }"
        : "=r"(a) : "l"(p));
    return a;
}
__device__ __forceinline__ void ldmA4(uint32_t* a, uint32_t addr) {
    asm volatile("ldmatrix.sync.aligned.m8n8.x4.shared.b16 {%0,%1,%2,%3}, [%4];"
                 : "=r"(a[0]), "=r"(a[1]), "=r"(a[2]), "=r"(a[3]) : "r"(addr));
}
__device__ __forceinline__ void ldmA4t(uint32_t* a, uint32_t addr) {
    asm volatile("ldmatrix.sync.aligned.m8n8.x4.trans.shared.b16 {%0,%1,%2,%3}, [%4];"
                 : "=r"(a[0]), "=r"(a[1]), "=r"(a[2]), "=r"(a[3]) : "r"(addr));
}
__device__ __forceinline__ void mma16816(float* c, const uint32_t* a,
                                         const uint32_t* b) {
    asm volatile(
        "mma.sync.aligned.m16n8k16.row.col.f32.bf16.bf16.f32 "
        "{%0,%1,%2,%3}, {%4,%5,%6,%7}, {%8,%9}, {%0,%1,%2,%3};"
        : "+f"(c[0]), "+f"(c[1]), "+f"(c[2]), "+f"(c[3])
        : "r"(a[0]), "r"(a[1]), "r"(a[2]), "r"(a[3]), "r"(b[0]), "r"(b[1]));
}
__device__ __forceinline__ void cpasync16(uint32_t saddr, const void* gaddr) {
    asm volatile("cp.async.cg.shared.global [%0], [%1], 16;"
                 :: "r"(saddr), "l"(gaddr));
}
#define CP_COMMIT() asm volatile("cp.async.commit_group;" ::: "memory")
#define CP_WAIT0()  asm volatile("cp.async.wait_group 0;" ::: "memory")
#define CP_WAIT1()  asm volatile("cp.async.wait_group 1;" ::: "memory")

__device__ __forceinline__ uint32_t pack_bf2(float x, float y) {
    return (uint32_t)__bfloat16_as_ushort(__float2bfloat16(x)) |
           ((uint32_t)__bfloat16_as_ushort(__float2bfloat16(y)) << 16);
}
#define TRUNC_HI2(x, y) __byte_perm(__float_as_uint(x), __float_as_uint(y), 0x7632)
__device__ __forceinline__ float trunc_res(float x) {
    return x - __uint_as_float(__float_as_uint(x) & 0xFFFF0000u);
}
__device__ __forceinline__ void split_store(
    __nv_bfloat16* hi, __nv_bfloat16* lo, size_t idx, float x, float y)
{
    const __nv_bfloat16 hx = __float2bfloat16(x), hy = __float2bfloat16(y);
    *(uint32_t*)&hi[idx] = (uint32_t)__bfloat16_as_ushort(hx) |
                           ((uint32_t)__bfloat16_as_ushort(hy) << 16);
    *(uint32_t*)&lo[idx] = pack_bf2(x - __bfloat162float(hx),
                                    y - __bfloat162float(hy));
}
__device__ __forceinline__ float fexp(float x) { return __expf(x); }

// ---------------------------------------------------------------------------
// Split-conversions
// ---------------------------------------------------------------------------
__global__ __launch_bounds__(256) void conv_split(
    const float4* __restrict__ src, uint2* __restrict__ hi,
    uint2* __restrict__ lo, int n4)
{
    const int i = blockIdx.x * 256 + threadIdx.x;
    if (i >= n4) return;
    const float4 v = src[i];
    split_store((__nv_bfloat16*)hi, (__nv_bfloat16*)lo, (size_t)i * 4,     v.x, v.y);
    split_store((__nv_bfloat16*)hi, (__nv_bfloat16*)lo, (size_t)i * 4 + 2, v.z, v.w);
}

__global__ __launch_bounds__(256) void conv_split_w4(
    const float4* s0, uint2* h0, uint2* l0,
    const float4* s1, uint2* h1, uint2* l1,
    const float4* s2, uint2* h2, uint2* l2,
    const float4* s3, uint2* h3, uint2* l3, int n4)
{
    const int i = blockIdx.x * 256 + threadIdx.x;
    if (i >= n4) return;
    const int w = blockIdx.y;
    const float4* src = (w == 0) ? s0 : (w == 1) ? s1 : (w == 2) ? s2 : s3;
    uint2* hi = (w == 0) ? h0 : (w == 1) ? h1 : (w == 2) ? h2 : h3;
    uint2* lo = (w == 0) ? l0 : (w == 1) ? l1 : (w == 2) ? l2 : l3;
    const float4 v = src[i];
    split_store((__nv_bfloat16*)hi, (__nv_bfloat16*)lo, (size_t)i * 4,     v.x, v.y);
    split_store((__nv_bfloat16*)hi, (__nv_bfloat16*)lo, (size_t)i * 4 + 2, v.z, v.w);
}

// ---------------------------------------------------------------------------
// Shared GEMM body (unchanged from R8): 3-term fused K-loop, 2-stage pipeline.
// ---------------------------------------------------------------------------
#define GP 72
#define GTILE (128 * GP)
#define GEMM_SMEM (2 * 4 * GTILE * 2)

__device__ __forceinline__ void gemm_body(
    const __nv_bfloat16* __restrict__ Ahi, const __nv_bfloat16* __restrict__ Alo,
    const __nv_bfloat16* __restrict__ Bhi, const __nv_bfloat16* __restrict__ Blo,
    const float* __restrict__ bias, float* __restrict__ C,
    __nv_bfloat16* __restrict__ Chi, __nv_bfloat16* __restrict__ Clo,
    int M, int N, int K, int bm, int bn, uint32_t sb)
{
    const int tid  = threadIdx.x;
    const int lane = tid & 31, wid = tid >> 5;
    const int warp_m = wid >> 2, warp_n = wid & 3;

    const int a_r = warp_m * 64 + (lane & 15);
    const int a_c = (lane >> 4) * 8;
    const int b4_row = ((lane >> 4) & 1) * 8 + (lane & 7);
    const int b4_col = ((lane >> 3) & 1) * 8;

    const int lrow = tid >> 3;
    const int lc8  = (tid & 7) * 8;

    float acc[4][4][4];
#pragma unroll
    for (int mt = 0; mt < 4; mt++)
#pragma unroll
        for (int nt = 0; nt < 4; nt++)
#pragma unroll
            for (int r = 0; r < 4; r++) acc[mt][nt][r] = 0.f;

#define TBASE(s, o) (sb + (uint32_t)(((s) * 4 + (o)) * GTILE) * 2)
#define LOAD_STAGE(s, k0) do {                                                \
    const uint32_t _dAh = TBASE(s, 0), _dAl = TBASE(s, 1);                    \
    const uint32_t _dBh = TBASE(s, 2), _dBl = TBASE(s, 3);                    \
    _Pragma("unroll")                                                         \
    for (int rr = 0; rr < 4; rr++) {                                          \
        const int row = lrow + rr * 32;                                       \
        const uint32_t so = (uint32_t)(row * GP + lc8) * 2;                   \
        const size_t ga = (size_t)(bm + row) * K + (k0) + lc8;                \
        const size_t gb = (size_t)(bn + row) * K + (k0) + lc8;                \
        cpasync16(_dAh + so, &Ahi[ga]);                                       \
        cpasync16(_dAl + so, &Alo[ga]);                                       \
        cpasync16(_dBh + so, &Bhi[gb]);                                       \
        cpasync16(_dBl + so, &Blo[gb]);                                       \
    }                                                                         \
    CP_COMMIT();                                                              \
} while (0)

    LOAD_STAGE(0, 0);

    const int NK = K / 64;
    for (int kc = 0; kc < NK; kc++) {
        const int cur = kc & 1;
        if (kc + 1 < NK) { LOAD_STAGE(cur ^ 1, (kc + 1) * 64); CP_WAIT1(); }
        else             { CP_WAIT0(); }
        __syncthreads();

        const uint32_t uAh = TBASE(cur, 0), uAl = TBASE(cur, 1);
        const uint32_t uBh = TBASE(cur, 2), uBl = TBASE(cur, 3);
#pragma unroll
        for (int ks = 0; ks < 4; ks++) {
            uint32_t ah[4][4], al[4][4];
#pragma unroll
            for (int mt = 0; mt < 4; mt++) {
                const uint32_t ao = (uint32_t)((a_r + mt * 16) * GP +
                                               ks * 16 + a_c) * 2;
                ldmA4(ah[mt], uAh + ao);
                ldmA4(al[mt], uAl + ao);
            }
            uint32_t bh[4][2], bl[4][2];
#pragma unroll
            for (int p = 0; p < 2; p++) {
                uint32_t r4[4];
                const uint32_t bo = (uint32_t)((warp_n * 32 + p * 16 + b4_row) * GP +
                                               ks * 16 + b4_col) * 2;
                ldmA4(r4, uBh + bo);
                bh[2*p][0] = r4[0]; bh[2*p][1] = r4[1];
                bh[2*p+1][0] = r4[2]; bh[2*p+1][1] = r4[3];
                ldmA4(r4, uBl + bo);
                bl[2*p][0] = r4[0]; bl[2*p][1] = r4[1];
                bl[2*p+1][0] = r4[2]; bl[2*p+1][1] = r4[3];
            }
#pragma unroll
            for (int mt = 0; mt < 4; mt++)
#pragma unroll
                for (int nt = 0; nt < 4; nt++) {
                    mma16816(acc[mt][nt], ah[mt], bh[nt]);
                    mma16816(acc[mt][nt], ah[mt], bl[nt]);
                    mma16816(acc[mt][nt], al[mt], bh[nt]);
                }
        }
        __syncthreads();
    }

    const int em = bm + warp_m * 64 + (lane >> 2);
    const int en = bn + warp_n * 32 + (lane & 3) * 2;
#pragma unroll
    for (int mt = 0; mt < 4; mt++) {
#pragma unroll
        for (int nt = 0; nt < 4; nt++) {
            const int n = en + nt * 8;
            const float bx = bias[n], by = bias[n + 1];
            const int m0 = em + mt * 16;
            float2 o0, o1;
            o0.x = acc[mt][nt][0] + bx; o0.y = acc[mt][nt][1] + by;
            o1.x = acc[mt][nt][2] + bx; o1.y = acc[mt][nt][3] + by;
            if (C) {
                *(float2*)&C[(size_t)m0 * N + n]       = o0;
                *(float2*)&C[(size_t)(m0 + 8) * N + n] = o1;
            }
            if (Chi) {
                split_store(Chi, Clo, (size_t)m0 * N + n,       o0.x, o0.y);
                split_store(Chi, Clo, (size_t)(m0 + 8) * N + n, o1.x, o1.y);
            }
        }
    }
#undef LOAD_STAGE
#undef TBASE
}

__global__ __launch_bounds__(256) void gemm_qkv(
    const __nv_bfloat16* __restrict__ Ahi, const __nv_bfloat16* __restrict__ Alo,
    const __nv_bfloat16* bq_h, const __nv_bfloat16* bq_l,
    const __nv_bfloat16* bk_h, const __nv_bfloat16* bk_l,
    const __nv_bfloat16* bv_h, const __nv_bfloat16* bv_l,
    const float* biq, const float* bik, const float* biv,
    __nv_bfloat16* qh, __nv_bfloat16* ql,
    __nv_bfloat16* kh, __nv_bfloat16* kl,
    __nv_bfloat16* vh, __nv_bfloat16* vl,
    int M, int N, int K)
{
    extern __shared__ __nv_bfloat16 gsm[];
    const int z = blockIdx.z;
    const __nv_bfloat16* Bh = (z == 0) ? bq_h : (z == 1) ? bk_h : bv_h;
    const __nv_bfloat16* Bl = (z == 0) ? bq_l : (z == 1) ? bk_l : bv_l;
    const float* bias = (z == 0) ? biq : (z == 1) ? bik : biv;
    __nv_bfloat16* Ch = (z == 0) ? qh : (z == 1) ? kh : vh;
    __nv_bfloat16* Cl = (z == 0) ? ql : (z == 1) ? kl : vl;
    gemm_body(Ahi, Alo, Bh, Bl, bias, (float*)nullptr, Ch, Cl,
              M, N, K, blockIdx.y * 128, blockIdx.x * 128, smem_u32(gsm));
}

__global__ __launch_bounds__(256) void gemm_out(
    const __nv_bfloat16* __restrict__ Ahi, const __nv_bfloat16* __restrict__ Alo,
    const __nv_bfloat16* __restrict__ Bhi, const __nv_bfloat16* __restrict__ Blo,
    const float* __restrict__ bias, float* __restrict__ C,
    int M, int N, int K)
{
    extern __shared__ __nv_bfloat16 gsm[];
    gemm_body(Ahi, Alo, Bhi, Blo, bias, C,
              (__nv_bfloat16*)nullptr, (__nv_bfloat16*)nullptr,
              M, N, K, blockIdx.y * 128, blockIdx.x * 128, smem_u32(gsm));
}

// ---------------------------------------------------------------------------
// Tensor-core flash attention, low-register variant:
//   k-tile 64 (c[8][4]), Q fragments reloaded from smem per ks,
//   __launch_bounds__(256,2) -> <=128 regs, 2 CTAs/SM (smem 73.7KB).
// ---------------------------------------------------------------------------
#define FP 72
#define FLASH_SMEM ((2 * 128 + 4 * 64) * FP * 2)   // 73728 bytes

__global__ __launch_bounds__(256, 2) void flash_mma_kernel(
    const __nv_bfloat16* __restrict__ qhi, const __nv_bfloat16* __restrict__ qlo,
    const __nv_bfloat16* __restrict__ khi, const __nv_bfloat16* __restrict__ klo,
    const __nv_bfloat16* __restrict__ vhi, const __nv_bfloat16* __restrict__ vlo,
    const int* __restrict__ mask, float* __restrict__ Praw,
    float* __restrict__ mkt, float* __restrict__ stats,
    __nv_bfloat16* __restrict__ chi, __nv_bfloat16* __restrict__ clo)
{
    extern __shared__ __nv_bfloat16 smb[];
    __nv_bfloat16* sQh = smb;                    // [128][FP]
    __nv_bfloat16* sQl = sQh + 128 * FP;         // [128][FP]
    __nv_bfloat16* sKh = sQl + 128 * FP;         // [64][FP]
    __nv_bfloat16* sKl = sKh + 64 * FP;
    __nv_bfloat16* sVh = sKl + 64 * FP;
    __nv_bfloat16* sVl = sVh + 64 * FP;

    const int t = threadIdx.x, lane = t & 31, warp = t >> 5;
    const int bh = blockIdx.y;
    const int b = bh >> 4, h = bh & 15;
    const int q0 = blockIdx.x * 128;

    const uint32_t uQh = smem_u32(sQh), uQl = smem_u32(sQl);
    const uint32_t uKh = smem_u32(sKh), uKl = smem_u32(sKl);
    const uint32_t uVh = smem_u32(sVh), uVl = smem_u32(sVl);

    for (int i = t; i < 1024; i += 256) {
        const int row = i >> 3, c8 = (i & 7) * 8;
        const size_t g = (size_t)(b * S_ + q0 + row) * D_ + h * 64 + c8;
        *(uint4*)&sQh[row * FP + c8] = *(const uint4*)&qhi[g];
        *(uint4*)&sQl[row * FP + c8] = *(const uint4*)&qlo[g];
    }

    float O[8][4];
#pragma unroll
    for (int j = 0; j < 8; j++)
#pragma unroll
        for (int r = 0; r < 4; r++) O[j][r] = 0.f;
    float mr0 = -1e30f, mr1 = -1e30f, lr0 = 0.f, lr1 = 0.f;

    const int row0 = q0 + warp * 16 + (lane >> 2);
    const int row1 = row0 + 8;
    const int col0 = (lane & 3) * 2;
    const int a_r  = warp * 16 + (lane & 15);
    const int a_c  = (lane >> 4) * 8;
    const int b4_row = ((lane >> 4) & 1) * 8 + (lane & 7);
    const int b4_col = ((lane >> 3) & 1) * 8;
    const int t4_row = ((lane >> 3) & 1) * 8 + (lane & 7);
    const int t4_sel = ((lane >> 4) & 1) * 8;

    for (int kt = 0; kt < S_ / 64; kt++) {
        const int k0 = kt * 64;
        __syncthreads();
        // load K/V 64-row tiles (hi+lo): 4 arrays x 512 uint4 -> 8 per thread
        for (int i = t; i < 512; i += 256) {
            const int row = i >> 3, c8 = (i & 7) * 8;
            const size_t g = (size_t)(b * S_ + k0 + row) * D_ + h * 64 + c8;
            *(uint4*)&sKh[row * FP + c8] = *(const uint4*)&khi[g];
            *(uint4*)&sKl[row * FP + c8] = *(const uint4*)&klo[g];
            *(uint4*)&sVh[row * FP + c8] = *(const uint4*)&vhi[g];
            *(uint4*)&sVl[row * FP + c8] = *(const uint4*)&vlo[g];
        }
        __syncthreads();

        // --- QK^T: c[8][4] over 64 k-cols ---
        float c[8][4];
#pragma unroll
        for (int nt = 0; nt < 8; nt++)
#pragma unroll
            for (int r = 0; r < 4; r++) c[nt][r] = 0.f;
#pragma unroll
        for (int ks = 0; ks < 4; ks++) {
            uint32_t qh2[4], ql2[4];
            const uint32_t qo = (uint32_t)(a_r * FP + ks * 16 + a_c) * 2;
            ldmA4(qh2, uQh + qo);
            ldmA4(ql2, uQl + qo);
#pragma unroll
            for (int p = 0; p < 4; p++) {
                uint32_t rh[4], rl[4];
                const uint32_t off = (uint32_t)((p * 16 + b4_row) * FP +
                                                ks * 16 + b4_col) * 2;
                ldmA4(rh, uKh + off);
                ldmA4(rl, uKl + off);
                mma16816(c[2*p],   qh2, rh);
                mma16816(c[2*p],   qh2, rl);
                mma16816(c[2*p],   ql2, rh);
                mma16816(c[2*p+1], qh2, rh + 2);
                mma16816(c[2*p+1], qh2, rl + 2);
                mma16816(c[2*p+1], ql2, rh + 2);
            }
        }

        // --- scale + mask ---
#pragma unroll
        for (int nt = 0; nt < 8; nt++) {
            const int cc = k0 + nt * 8 + col0;
            const int2 m0 = *(const int2*)&mask[((size_t)b * S_ + row0) * S_ + cc];
            const int2 m1 = *(const int2*)&mask[((size_t)b * S_ + row1) * S_ + cc];
            c[nt][0] = (m0.x == 0) ? -1e9f : c[nt][0] * SCALE_;
            c[nt][1] = (m0.y == 0) ? -1e9f : c[nt][1] * SCALE_;
            c[nt][2] = (m1.x == 0) ? -1e9f : c[nt][2] * SCALE_;
            c[nt][3] = (m1.y == 0) ? -1e9f : c[nt][3] * SCALE_;
        }

        // --- online softmax ---
        float rm0 = -1e30f, rm1 = -1e30f;
#pragma unroll
        for (int nt = 0; nt < 8; nt++) {
            rm0 = fmaxf(rm0, fmaxf(c[nt][0], c[nt][1]));
            rm1 = fmaxf(rm1, fmaxf(c[nt][2], c[nt][3]));
        }
        rm0 = fmaxf(rm0, __shfl_xor_sync(0xffffffffu, rm0, 1));
        rm0 = fmaxf(rm0, __shfl_xor_sync(0xffffffffu, rm0, 2));
        rm1 = fmaxf(rm1, __shfl_xor_sync(0xffffffffu, rm1, 1));
        rm1 = fmaxf(rm1, __shfl_xor_sync(0xffffffffu, rm1, 2));
        const float mn0 = fmaxf(mr0, rm0), mn1 = fmaxf(mr1, rm1);
        const float f0 = fexp(mr0 - mn0), f1 = fexp(mr1 - mn1);
        float rs0 = 0.f, rs1 = 0.f;
#pragma unroll
        for (int nt = 0; nt < 8; nt++) {
            c[nt][0] = fexp(c[nt][0] - mn0);
            c[nt][1] = fexp(c[nt][1] - mn0);
            c[nt][2] = fexp(c[nt][2] - mn1);
            c[nt][3] = fexp(c[nt][3] - mn1);
            rs0 += c[nt][0] + c[nt][1];
            rs1 += c[nt][2] + c[nt][3];
        }
        rs0 += __shfl_xor_sync(0xffffffffu, rs0, 1);
        rs0 += __shfl_xor_sync(0xffffffffu, rs0, 2);
        rs1 += __shfl_xor_sync(0xffffffffu, rs1, 1);
        rs1 += __shfl_xor_sync(0xffffffffu, rs1, 2);
        lr0 = lr0 * f0 + rs0; mr0 = mn0;
        lr1 = lr1 * f1 + rs1; mr1 = mn1;
#pragma unroll
        for (int j = 0; j < 8; j++) {
            O[j][0] *= f0; O[j][1] *= f0;
            O[j][2] *= f1; O[j][3] *= f1;
        }

        // --- stream P + m_kt ---
        {
            const size_t gb0 = ((size_t)bh * S_ + row0) * S_ + k0 + col0;
            const size_t gb1 = ((size_t)bh * S_ + row1) * S_ + k0 + col0;
#pragma unroll
            for (int nt = 0; nt < 8; nt++) {
                float2 w0, w1;
                w0.x = c[nt][0]; w0.y = c[nt][1];
                w1.x = c[nt][2]; w1.y = c[nt][3];
                *(float2*)&Praw[gb0 + nt * 8] = w0;
                *(float2*)&Praw[gb1 + nt * 8] = w1;
            }
            if ((lane & 3) == 0) {
                mkt[((size_t)bh * 32 + kt) * S_ + row0] = mn0;
                mkt[((size_t)bh * 32 + kt) * S_ + row1] = mn1;
            }
        }

        // --- P @ V (truncation-split fragments) ---
#pragma unroll
        for (int ks2 = 0; ks2 < 4; ks2++) {
            const float* c0 = c[2 * ks2];
            const float* c1 = c[2 * ks2 + 1];
            uint32_t ah[4], al[4];
            ah[0] = TRUNC_HI2(c0[0], c0[1]);
            ah[1] = TRUNC_HI2(c0[2], c0[3]);
            ah[2] = TRUNC_HI2(c1[0], c1[1]);
            ah[3] = TRUNC_HI2(c1[2], c1[3]);
            al[0] = TRUNC_HI2(trunc_res(c0[0]), trunc_res(c0[1]));
            al[1] = TRUNC_HI2(trunc_res(c0[2]), trunc_res(c0[3]));
            al[2] = TRUNC_HI2(trunc_res(c1[0]), trunc_res(c1[1]));
            al[3] = TRUNC_HI2(trunc_res(c1[2]), trunc_res(c1[3]));
#pragma unroll
            for (int p = 0; p < 4; p++) {
                uint32_t vh4[4], vl4[4];
                const uint32_t off = (uint32_t)((ks2 * 16 + t4_row) * FP +
                                                p * 16 + t4_sel) * 2;
                ldmA4t(vh4, uVh + off);
                ldmA4t(vl4, uVl + off);
                mma16816(O[2*p],   ah, vh4);
                mma16816(O[2*p],   ah, vl4);
                mma16816(O[2*p],   al, vh4);
                mma16816(O[2*p+1], ah, vh4 + 2);
                mma16816(O[2*p+1], ah, vl4 + 2);
                mma16816(O[2*p+1], al, vh4 + 2);
            }
        }
    }

    // --- epilogue: normalized ctx as bf16 hi/lo ---
    const float inv0 = 1.0f / lr0, inv1 = 1.0f / lr1;
#pragma unroll
    for (int nt2 = 0; nt2 < 8; nt2++) {
        const int n = nt2 * 8 + col0;
        const size_t g0 = (size_t)(b * S_ + row0) * D_ + h * 64 + n;
        const size_t g1 = (size_t)(b * S_ + row1) * D_ + h * 64 + n;
        split_store(chi, clo, g0, O[nt2][0] * inv0, O[nt2][1] * inv0);
        split_store(chi, clo, g1, O[nt2][2] * inv1, O[nt2][3] * inv1);
    }
    if ((lane & 3) == 0) {
        size_t si = ((size_t)bh * S_ + row0) * 2;
        stats[si] = mr0; stats[si + 1] = lr0;
        si = ((size_t)bh * S_ + row1) * 2;
        stats[si] = mr1; stats[si + 1] = lr1;
    }
}

// ---------------------------------------------------------------------------
// Pass 2: attn = P * exp(m_kt - m_final) / l_final  (pure memory; 64-col kts)
// ---------------------------------------------------------------------------
__global__ __launch_bounds__(256) void normalize_kernel(
    const float* __restrict__ P, const float* __restrict__ mkt,
    const float* __restrict__ stats, float* __restrict__ attn)
{
    __shared__ float corr[32];
    const int t   = threadIdx.x;
    const int row = blockIdx.x;
    const int bh  = blockIdx.y;

    const size_t si = ((size_t)bh * S_ + row) * 2;
    const float m_f = stats[si];
    const float inv_l = 1.0f / stats[si + 1];
    if (t < 32)
        corr[t] = __expf(mkt[((size_t)bh * 32 + t) * S_ + row] - m_f) * inv_l;
    __syncthreads();

    const size_t base = ((size_t)bh * S_ + row) * S_;
    const float c = corr[t >> 3];                 // 8 floats inside one 64-col kt
    float4 v0 = *(const float4*)&P[base + t * 8];
    float4 v1 = *(const float4*)&P[base + t * 8 + 4];
    v0.x *= c; v0.y *= c; v0.z *= c; v0.w *= c;
    v1.x *= c; v1.y *= c; v1.z *= c; v1.w *= c;
    *(float4*)&attn[base + t * 8]     = v0;
    *(float4*)&attn[base + t * 8 + 4] = v1;
}

// ---------------------------------------------------------------------------
extern "C" void kernel_launch(void* const* d_in, const int* in_sizes, int n_in,
                              void* d_out, int out_size)
{
    const float* x    = (const float*)d_in[0];
    const int*   mask = (const int*)  d_in[1];
    const float* wq_w = (const float*)d_in[2];
    const float* wq_b = (const float*)d_in[3];
    const float* wk_w = (const float*)d_in[4];
    const float* wk_b = (const float*)d_in[5];
    const float* wv_w = (const float*)d_in[6];
    const float* wv_b = (const float*)d_in[7];
    const float* wo_w = (const float*)d_in[8];
    const float* wo_b = (const float*)d_in[9];

    float *qdump, *attn_raw, *mkt, *stats;
    cudaGetSymbolAddress((void**)&qdump,    g_q);
    cudaGetSymbolAddress((void**)&attn_raw, g_attn_raw);
    cudaGetSymbolAddress((void**)&mkt,      g_mkt);
    cudaGetSymbolAddress((void**)&stats,    g_stats);

    __nv_bfloat16 *xhi, *xlo, *chi, *clo;
    __nv_bfloat16 *qhi_p, *qlo_p, *khi_p, *klo_p, *vhi_p, *vlo_p;
    __nv_bfloat16 *wqhi, *wqlo, *wkhi, *wklo, *wvhi, *wvlo, *wohi, *wolo;
    cudaGetSymbolAddress((void**)&xhi, g_xhi);   cudaGetSymbolAddress((void**)&xlo, g_xlo);
    cudaGetSymbolAddress((void**)&chi, g_chi);   cudaGetSymbolAddress((void**)&clo, g_clo);
    cudaGetSymbolAddress((void**)&qhi_p, g_qhi); cudaGetSymbolAddress((void**)&qlo_p, g_qlo);
    cudaGetSymbolAddress((void**)&khi_p, g_khi); cudaGetSymbolAddress((void**)&klo_p, g_klo);
    cudaGetSymbolAddress((void**)&vhi_p, g_vhi); cudaGetSymbolAddress((void**)&vlo_p, g_vlo);
    cudaGetSymbolAddress((void**)&wqhi, g_wqhi); cudaGetSymbolAddress((void**)&wqlo, g_wqlo);
    cudaGetSymbolAddress((void**)&wkhi, g_wkhi); cudaGetSymbolAddress((void**)&wklo, g_wklo);
    cudaGetSymbolAddress((void**)&wvhi, g_wvhi); cudaGetSymbolAddress((void**)&wvlo, g_wvlo);
    cudaGetSymbolAddress((void**)&wohi, g_wohi); cudaGetSymbolAddress((void**)&wolo, g_wolo);

    const long long CTXSZ = (long long)B_ * S_ * D_;
    const long long ATTSZ = (long long)B_ * H_ * S_ * S_;

    float* out_base = (float*)d_out;
    float* out_ptr;
    float* attn_ptr;
    if ((long long)out_size >= CTXSZ + ATTSZ) {
        out_ptr  = out_base;
        attn_ptr = out_base + CTXSZ;
    } else if ((long long)out_size == ATTSZ) {
        out_ptr  = qdump;
        attn_ptr = out_base;
    } else {
        out_ptr  = out_base;
        attn_ptr = attn_raw;
    }

    cudaFuncSetAttribute(flash_mma_kernel,
                         cudaFuncAttributeMaxDynamicSharedMemorySize, FLASH_SMEM);
    cudaFuncSetAttribute(gemm_qkv,
                         cudaFuncAttributeMaxDynamicSharedMemorySize, GEMM_SMEM);
    cudaFuncSetAttribute(gemm_out,
                         cudaFuncAttributeMaxDynamicSharedMemorySize, GEMM_SMEM);

    const int M = B_ * S_;   // 4096
    const int N = D_;        // 1024
    const int K = D_;        // 1024

    const int xn4 = (int)(CTXSZ / 4);
    const int wn4 = D_ * D_ / 4;
    conv_split<<<(xn4 + 255) / 256, 256>>>((const float4*)x, (uint2*)xhi, (uint2*)xlo, xn4);
    dim3 wGrid((wn4 + 255) / 256, 4);
    conv_split_w4<<<wGrid, 256>>>(
        (const float4*)wq_w, (uint2*)wqhi, (uint2*)wqlo,
        (const float4*)wk_w, (uint2*)wkhi, (uint2*)wklo,
        (const float4*)wv_w, (uint2*)wvhi, (uint2*)wvlo,
        (const float4*)wo_w, (uint2*)wohi, (uint2*)wolo, wn4);

    dim3 qkvGrid(N / 128, M / 128, 3);
    gemm_qkv<<<qkvGrid, 256, GEMM_SMEM>>>(
        xhi, xlo,
        wqhi, wqlo, wkhi, wklo, wvhi, wvlo,
        wq_b, wk_b, wv_b,
        qhi_p, qlo_p, khi_p, klo_p, vhi_p, vlo_p, M, N, K);

    dim3 fGrid(S_ / 128, B_ * H_);
    flash_mma_kernel<<<fGrid, 256, FLASH_SMEM>>>(
        qhi_p, qlo_p, khi_p, klo_p, vhi_p, vlo_p,
        mask, attn_raw, mkt, stats, chi, clo);

    dim3 gGrid(N / 128, M / 128);
    gemm_out<<<gGrid, 256, GEMM_SMEM>>>(chi, clo, wohi, wolo, wo_b, out_ptr, M, N, K);

    dim3 nGrid(S_, B_ * H_);
    normalize_kernel<<<nGrid, 256>>>(attn_raw, mkt, stats, attn_ptr);
}

// round 10
// speedup vs baseline: 2.3871x; 1.0082x over previous
#include <cuda_runtime.h>
#include <cuda_bf16.h>
#include <math.h>
#include <stdint.h>

// Problem constants
#define B_  2
#define S_  2048
#define D_  1024
#define H_  16
#define DH_ 64
#define SCALE_ 0.125f   // DH^-0.5

typedef unsigned long long u64;

// ---------------------------------------------------------------------------
// Scratch (static device globals; no runtime allocation)
// ---------------------------------------------------------------------------
__device__ float g_q[(size_t)B_ * S_ * D_];                 // dummy sink
__device__ float g_attn_raw[(size_t)B_ * H_ * S_ * S_];
__device__ float g_mkt[(size_t)B_ * H_ * (S_ / 64) * S_];
__device__ float g_stats[(size_t)B_ * H_ * S_ * 2];

// bf16 hi/lo split operands
__device__ __nv_bfloat16 g_xhi[(size_t)B_ * S_ * D_];
__device__ __nv_bfloat16 g_xlo[(size_t)B_ * S_ * D_];
__device__ __nv_bfloat16 g_qhi[(size_t)B_ * S_ * D_], g_qlo[(size_t)B_ * S_ * D_];
__device__ __nv_bfloat16 g_khi[(size_t)B_ * S_ * D_], g_klo[(size_t)B_ * S_ * D_];
__device__ __nv_bfloat16 g_vhi[(size_t)B_ * S_ * D_], g_vlo[(size_t)B_ * S_ * D_];
__device__ __nv_bfloat16 g_chi[(size_t)B_ * S_ * D_], g_clo[(size_t)B_ * S_ * D_];
__device__ __nv_bfloat16 g_wqhi[D_ * D_], g_wqlo[D_ * D_];
__device__ __nv_bfloat16 g_wkhi[D_ * D_], g_wklo[D_ * D_];
__device__ __nv_bfloat16 g_wvhi[D_ * D_], g_wvlo[D_ * D_];
__device__ __nv_bfloat16 g_wohi[D_ * D_], g_wolo[D_ * D_];

// ---------------------------------------------------------------------------
// mma.sync / ldmatrix helpers
// ---------------------------------------------------------------------------
__device__ __forceinline__ uint32_t smem_u32(const void* p) {
    uint32_t a;
    asm("{ .reg .u64 t; cvta.to.shared.u64 t, %1; cvt.u32.u64 %0, t; }"
        : "=r"(a) : "l"(p));
    return a;
}
__device__ __forceinline__ void ldmA4(uint32_t* a, uint32_t addr) {
    asm volatile("ldmatrix.sync.aligned.m8n8.x4.shared.b16 {%0,%1,%2,%3}, [%4];"
                 : "=r"(a[0]), "=r"(a[1]), "=r"(a[2]), "=r"(a[3]) : "r"(addr));
}
__device__ __forceinline__ void ldmA4t(uint32_t* a, uint32_t addr) {
    asm volatile("ldmatrix.sync.aligned.m8n8.x4.trans.shared.b16 {%0,%1,%2,%3}, [%4];"
                 : "=r"(a[0]), "=r"(a[1]), "=r"(a[2]), "=r"(a[3]) : "r"(addr));
}
__device__ __forceinline__ void mma16816(float* c, const uint32_t* a,
                                         const uint32_t* b) {
    asm volatile(
        "mma.sync.aligned.m16n8k16.row.col.f32.bf16.bf16.f32 "
        "{%0,%1,%2,%3}, {%4,%5,%6,%7}, {%8,%9}, {%0,%1,%2,%3};"
        : "+f"(c[0]), "+f"(c[1]), "+f"(c[2]), "+f"(c[3])
        : "r"(a[0]), "r"(a[1]), "r"(a[2]), "r"(a[3]), "r"(b[0]), "r"(b[1]));
}
__device__ __forceinline__ void cpasync16(uint32_t saddr, const void* gaddr) {
    asm volatile("cp.async.cg.shared.global [%0], [%1], 16;"
                 :: "r"(saddr), "l"(gaddr));
}
#define CP_COMMIT() asm volatile("cp.async.commit_group;" ::: "memory")
#define CP_WAIT0()  asm volatile("cp.async.wait_group 0;" ::: "memory")
#define CP_WAIT1()  asm volatile("cp.async.wait_group 1;" ::: "memory")

__device__ __forceinline__ uint32_t pack_bf2(float x, float y) {
    return (uint32_t)__bfloat16_as_ushort(__float2bfloat16(x)) |
           ((uint32_t)__bfloat16_as_ushort(__float2bfloat16(y)) << 16);
}
#define TRUNC_HI2(x, y) __byte_perm(__float_as_uint(x), __float_as_uint(y), 0x7632)
__device__ __forceinline__ float trunc_res(float x) {
    return x - __uint_as_float(__float_as_uint(x) & 0xFFFF0000u);
}
__device__ __forceinline__ void split_store(
    __nv_bfloat16* hi, __nv_bfloat16* lo, size_t idx, float x, float y)
{
    const __nv_bfloat16 hx = __float2bfloat16(x), hy = __float2bfloat16(y);
    *(uint32_t*)&hi[idx] = (uint32_t)__bfloat16_as_ushort(hx) |
                           ((uint32_t)__bfloat16_as_ushort(hy) << 16);
    *(uint32_t*)&lo[idx] = pack_bf2(x - __bfloat162float(hx),
                                    y - __bfloat162float(hy));
}
__device__ __forceinline__ float fexp(float x) { return __expf(x); }

// ---------------------------------------------------------------------------
// Split-conversions
// ---------------------------------------------------------------------------
__global__ __launch_bounds__(256) void conv_split(
    const float4* __restrict__ src, uint2* __restrict__ hi,
    uint2* __restrict__ lo, int n4)
{
    const int i = blockIdx.x * 256 + threadIdx.x;
    if (i >= n4) return;
    const float4 v = src[i];
    split_store((__nv_bfloat16*)hi, (__nv_bfloat16*)lo, (size_t)i * 4,     v.x, v.y);
    split_store((__nv_bfloat16*)hi, (__nv_bfloat16*)lo, (size_t)i * 4 + 2, v.z, v.w);
}

__global__ __launch_bounds__(256) void conv_split_w4(
    const float4* s0, uint2* h0, uint2* l0,
    const float4* s1, uint2* h1, uint2* l1,
    const float4* s2, uint2* h2, uint2* l2,
    const float4* s3, uint2* h3, uint2* l3, int n4)
{
    const int i = blockIdx.x * 256 + threadIdx.x;
    if (i >= n4) return;
    const int w = blockIdx.y;
    const float4* src = (w == 0) ? s0 : (w == 1) ? s1 : (w == 2) ? s2 : s3;
    uint2* hi = (w == 0) ? h0 : (w == 1) ? h1 : (w == 2) ? h2 : h3;
    uint2* lo = (w == 0) ? l0 : (w == 1) ? l1 : (w == 2) ? l2 : l3;
    const float4 v = src[i];
    split_store((__nv_bfloat16*)hi, (__nv_bfloat16*)lo, (size_t)i * 4,     v.x, v.y);
    split_store((__nv_bfloat16*)hi, (__nv_bfloat16*)lo, (size_t)i * 4 + 2, v.z, v.w);
}

// ---------------------------------------------------------------------------
// Shared GEMM body: 3-term fused K-loop, 2-stage pipeline (unchanged).
// ---------------------------------------------------------------------------
#define GP 72
#define GTILE (128 * GP)
#define GEMM_SMEM (2 * 4 * GTILE * 2)

__device__ __forceinline__ void gemm_body(
    const __nv_bfloat16* __restrict__ Ahi, const __nv_bfloat16* __restrict__ Alo,
    const __nv_bfloat16* __restrict__ Bhi, const __nv_bfloat16* __restrict__ Blo,
    const float* __restrict__ bias, float* __restrict__ C,
    __nv_bfloat16* __restrict__ Chi, __nv_bfloat16* __restrict__ Clo,
    int M, int N, int K, int bm, int bn, uint32_t sb)
{
    const int tid  = threadIdx.x;
    const int lane = tid & 31, wid = tid >> 5;
    const int warp_m = wid >> 2, warp_n = wid & 3;

    const int a_r = warp_m * 64 + (lane & 15);
    const int a_c = (lane >> 4) * 8;
    const int b4_row = ((lane >> 4) & 1) * 8 + (lane & 7);
    const int b4_col = ((lane >> 3) & 1) * 8;

    const int lrow = tid >> 3;
    const int lc8  = (tid & 7) * 8;

    float acc[4][4][4];
#pragma unroll
    for (int mt = 0; mt < 4; mt++)
#pragma unroll
        for (int nt = 0; nt < 4; nt++)
#pragma unroll
            for (int r = 0; r < 4; r++) acc[mt][nt][r] = 0.f;

#define TBASE(s, o) (sb + (uint32_t)(((s) * 4 + (o)) * GTILE) * 2)
#define LOAD_STAGE(s, k0) do {                                                \
    const uint32_t _dAh = TBASE(s, 0), _dAl = TBASE(s, 1);                    \
    const uint32_t _dBh = TBASE(s, 2), _dBl = TBASE(s, 3);                    \
    _Pragma("unroll")                                                         \
    for (int rr = 0; rr < 4; rr++) {                                          \
        const int row = lrow + rr * 32;                                       \
        const uint32_t so = (uint32_t)(row * GP + lc8) * 2;                   \
        const size_t ga = (size_t)(bm + row) * K + (k0) + lc8;                \
        const size_t gb = (size_t)(bn + row) * K + (k0) + lc8;                \
        cpasync16(_dAh + so, &Ahi[ga]);                                       \
        cpasync16(_dAl + so, &Alo[ga]);                                       \
        cpasync16(_dBh + so, &Bhi[gb]);                                       \
        cpasync16(_dBl + so, &Blo[gb]);                                       \
    }                                                                         \
    CP_COMMIT();                                                              \
} while (0)

    LOAD_STAGE(0, 0);

    const int NK = K / 64;
    for (int kc = 0; kc < NK; kc++) {
        const int cur = kc & 1;
        if (kc + 1 < NK) { LOAD_STAGE(cur ^ 1, (kc + 1) * 64); CP_WAIT1(); }
        else             { CP_WAIT0(); }
        __syncthreads();

        const uint32_t uAh = TBASE(cur, 0), uAl = TBASE(cur, 1);
        const uint32_t uBh = TBASE(cur, 2), uBl = TBASE(cur, 3);
#pragma unroll
        for (int ks = 0; ks < 4; ks++) {
            uint32_t ah[4][4], al[4][4];
#pragma unroll
            for (int mt = 0; mt < 4; mt++) {
                const uint32_t ao = (uint32_t)((a_r + mt * 16) * GP +
                                               ks * 16 + a_c) * 2;
                ldmA4(ah[mt], uAh + ao);
                ldmA4(al[mt], uAl + ao);
            }
            uint32_t bh[4][2], bl[4][2];
#pragma unroll
            for (int p = 0; p < 2; p++) {
                uint32_t r4[4];
                const uint32_t bo = (uint32_t)((warp_n * 32 + p * 16 + b4_row) * GP +
                                               ks * 16 + b4_col) * 2;
                ldmA4(r4, uBh + bo);
                bh[2*p][0] = r4[0]; bh[2*p][1] = r4[1];
                bh[2*p+1][0] = r4[2]; bh[2*p+1][1] = r4[3];
                ldmA4(r4, uBl + bo);
                bl[2*p][0] = r4[0]; bl[2*p][1] = r4[1];
                bl[2*p+1][0] = r4[2]; bl[2*p+1][1] = r4[3];
            }
#pragma unroll
            for (int mt = 0; mt < 4; mt++)
#pragma unroll
                for (int nt = 0; nt < 4; nt++) {
                    mma16816(acc[mt][nt], ah[mt], bh[nt]);
                    mma16816(acc[mt][nt], ah[mt], bl[nt]);
                    mma16816(acc[mt][nt], al[mt], bh[nt]);
                }
        }
        __syncthreads();
    }

    const int em = bm + warp_m * 64 + (lane >> 2);
    const int en = bn + warp_n * 32 + (lane & 3) * 2;
#pragma unroll
    for (int mt = 0; mt < 4; mt++) {
#pragma unroll
        for (int nt = 0; nt < 4; nt++) {
            const int n = en + nt * 8;
            const float bx = bias[n], by = bias[n + 1];
            const int m0 = em + mt * 16;
            float2 o0, o1;
            o0.x = acc[mt][nt][0] + bx; o0.y = acc[mt][nt][1] + by;
            o1.x = acc[mt][nt][2] + bx; o1.y = acc[mt][nt][3] + by;
            if (C) {
                *(float2*)&C[(size_t)m0 * N + n]       = o0;
                *(float2*)&C[(size_t)(m0 + 8) * N + n] = o1;
            }
            if (Chi) {
                split_store(Chi, Clo, (size_t)m0 * N + n,       o0.x, o0.y);
                split_store(Chi, Clo, (size_t)(m0 + 8) * N + n, o1.x, o1.y);
            }
        }
    }
#undef LOAD_STAGE
#undef TBASE
}

__global__ __launch_bounds__(256) void gemm_qkv(
    const __nv_bfloat16* __restrict__ Ahi, const __nv_bfloat16* __restrict__ Alo,
    const __nv_bfloat16* bq_h, const __nv_bfloat16* bq_l,
    const __nv_bfloat16* bk_h, const __nv_bfloat16* bk_l,
    const __nv_bfloat16* bv_h, const __nv_bfloat16* bv_l,
    const float* biq, const float* bik, const float* biv,
    __nv_bfloat16* qh, __nv_bfloat16* ql,
    __nv_bfloat16* kh, __nv_bfloat16* kl,
    __nv_bfloat16* vh, __nv_bfloat16* vl,
    int M, int N, int K)
{
    extern __shared__ __nv_bfloat16 gsm[];
    const int z = blockIdx.z;
    const __nv_bfloat16* Bh = (z == 0) ? bq_h : (z == 1) ? bk_h : bv_h;
    const __nv_bfloat16* Bl = (z == 0) ? bq_l : (z == 1) ? bk_l : bv_l;
    const float* bias = (z == 0) ? biq : (z == 1) ? bik : biv;
    __nv_bfloat16* Ch = (z == 0) ? qh : (z == 1) ? kh : vh;
    __nv_bfloat16* Cl = (z == 0) ? ql : (z == 1) ? kl : vl;
    gemm_body(Ahi, Alo, Bh, Bl, bias, (float*)nullptr, Ch, Cl,
              M, N, K, blockIdx.y * 128, blockIdx.x * 128, smem_u32(gsm));
}

__global__ __launch_bounds__(256) void gemm_out(
    const __nv_bfloat16* __restrict__ Ahi, const __nv_bfloat16* __restrict__ Alo,
    const __nv_bfloat16* __restrict__ Bhi, const __nv_bfloat16* __restrict__ Blo,
    const float* __restrict__ bias, float* __restrict__ C,
    int M, int N, int K)
{
    extern __shared__ __nv_bfloat16 gsm[];
    gemm_body(Ahi, Alo, Bhi, Blo, bias, C,
              (__nv_bfloat16*)nullptr, (__nv_bfloat16*)nullptr,
              M, N, K, blockIdx.y * 128, blockIdx.x * 128, smem_u32(gsm));
}

// ---------------------------------------------------------------------------
// Tensor-core flash attention, low-register + cp.async K/V double buffer:
//   k-tile 64, Q resident, K/V 2-stage pipeline, 1 barrier per kt.
//   smem = Q(36.9K) + 2 stages * 4 arrays * 64*FP (73.7K) = 110.6KB; 2 CTAs/SM.
// ---------------------------------------------------------------------------
#define FP 72
#define KVT (64 * FP)                                    // elements per array
#define FLASH_SMEM ((2 * 128 * FP + 2 * 4 * KVT) * 2)    // 110592 bytes

__global__ __launch_bounds__(256, 2) void flash_mma_kernel(
    const __nv_bfloat16* __restrict__ qhi, const __nv_bfloat16* __restrict__ qlo,
    const __nv_bfloat16* __restrict__ khi, const __nv_bfloat16* __restrict__ klo,
    const __nv_bfloat16* __restrict__ vhi, const __nv_bfloat16* __restrict__ vlo,
    const int* __restrict__ mask, float* __restrict__ Praw,
    float* __restrict__ mkt, float* __restrict__ stats,
    __nv_bfloat16* __restrict__ chi, __nv_bfloat16* __restrict__ clo)
{
    extern __shared__ __nv_bfloat16 smb[];
    __nv_bfloat16* sQh = smb;                    // [128][FP]
    __nv_bfloat16* sQl = sQh + 128 * FP;         // [128][FP]
    __nv_bfloat16* sKV = sQl + 128 * FP;         // 2 stages x {Kh,Kl,Vh,Vl}

    const int t = threadIdx.x, lane = t & 31, warp = t >> 5;
    const int bh = blockIdx.y;
    const int b = bh >> 4, h = bh & 15;
    const int q0 = blockIdx.x * 128;

    const uint32_t uQh = smem_u32(sQh), uQl = smem_u32(sQl);
    const uint32_t uKV = smem_u32(sKV);
#define KVB(s, o) (uKV + (uint32_t)(((s) * 4 + (o)) * KVT) * 2)

    // Q tile -> smem (cp.async, overlapped with first K/V stage)
    for (int i = t; i < 1024; i += 256) {
        const int row = i >> 3, c8 = (i & 7) * 8;
        const size_t g = (size_t)(b * S_ + q0 + row) * D_ + h * 64 + c8;
        const uint32_t so = (uint32_t)(row * FP + c8) * 2;
        cpasync16(uQh + so, &qhi[g]);
        cpasync16(uQl + so, &qlo[g]);
    }

    const int kv_row = t >> 3;             // 0..31 (+32 on second iter)
    const int kv_c8  = (t & 7) * 8;
#define LOAD_KV(stage, k0) do {                                               \
    _Pragma("unroll")                                                         \
    for (int rr = 0; rr < 2; rr++) {                                          \
        const int row = kv_row + rr * 32;                                     \
        const size_t g = (size_t)(b * S_ + (k0) + row) * D_ + h * 64 + kv_c8; \
        const uint32_t so = (uint32_t)(row * FP + kv_c8) * 2;                 \
        cpasync16(KVB(stage, 0) + so, &khi[g]);                               \
        cpasync16(KVB(stage, 1) + so, &klo[g]);                               \
        cpasync16(KVB(stage, 2) + so, &vhi[g]);                               \
        cpasync16(KVB(stage, 3) + so, &vlo[g]);                               \
    }                                                                         \
    CP_COMMIT();                                                              \
} while (0)

    LOAD_KV(0, 0);

    float O[8][4];
#pragma unroll
    for (int j = 0; j < 8; j++)
#pragma unroll
        for (int r = 0; r < 4; r++) O[j][r] = 0.f;
    float mr0 = -1e30f, mr1 = -1e30f, lr0 = 0.f, lr1 = 0.f;

    const int row0 = q0 + warp * 16 + (lane >> 2);
    const int row1 = row0 + 8;
    const int col0 = (lane & 3) * 2;
    const int a_r  = warp * 16 + (lane & 15);
    const int a_c  = (lane >> 4) * 8;
    const int b4_row = ((lane >> 4) & 1) * 8 + (lane & 7);
    const int b4_col = ((lane >> 3) & 1) * 8;
    const int t4_row = ((lane >> 3) & 1) * 8 + (lane & 7);
    const int t4_sel = ((lane >> 4) & 1) * 8;

    const int NT = S_ / 64;
    for (int kt = 0; kt < NT; kt++) {
        const int k0 = kt * 64;
        const int cur = kt & 1;
        CP_WAIT0();          // stage `cur` (and Q on kt=0) landed
        __syncthreads();     // all warps done with stage cur^1 compute
        if (kt + 1 < NT) LOAD_KV(cur ^ 1, (kt + 1) * 64);

        const uint32_t uKh = KVB(cur, 0), uKl = KVB(cur, 1);
        const uint32_t uVh = KVB(cur, 2), uVl = KVB(cur, 3);

        // --- QK^T: c[8][4] over 64 k-cols ---
        float c[8][4];
#pragma unroll
        for (int nt = 0; nt < 8; nt++)
#pragma unroll
            for (int r = 0; r < 4; r++) c[nt][r] = 0.f;
#pragma unroll
        for (int ks = 0; ks < 4; ks++) {
            uint32_t qh2[4], ql2[4];
            const uint32_t qo = (uint32_t)(a_r * FP + ks * 16 + a_c) * 2;
            ldmA4(qh2, uQh + qo);
            ldmA4(ql2, uQl + qo);
#pragma unroll
            for (int p = 0; p < 4; p++) {
                uint32_t rh[4], rl[4];
                const uint32_t off = (uint32_t)((p * 16 + b4_row) * FP +
                                                ks * 16 + b4_col) * 2;
                ldmA4(rh, uKh + off);
                ldmA4(rl, uKl + off);
                mma16816(c[2*p],   qh2, rh);
                mma16816(c[2*p],   qh2, rl);
                mma16816(c[2*p],   ql2, rh);
                mma16816(c[2*p+1], qh2, rh + 2);
                mma16816(c[2*p+1], qh2, rl + 2);
                mma16816(c[2*p+1], ql2, rh + 2);
            }
        }

        // --- scale + mask ---
#pragma unroll
        for (int nt = 0; nt < 8; nt++) {
            const int cc = k0 + nt * 8 + col0;
            const int2 m0 = *(const int2*)&mask[((size_t)b * S_ + row0) * S_ + cc];
            const int2 m1 = *(const int2*)&mask[((size_t)b * S_ + row1) * S_ + cc];
            c[nt][0] = (m0.x == 0) ? -1e9f : c[nt][0] * SCALE_;
            c[nt][1] = (m0.y == 0) ? -1e9f : c[nt][1] * SCALE_;
            c[nt][2] = (m1.x == 0) ? -1e9f : c[nt][2] * SCALE_;
            c[nt][3] = (m1.y == 0) ? -1e9f : c[nt][3] * SCALE_;
        }

        // --- online softmax ---
        float rm0 = -1e30f, rm1 = -1e30f;
#pragma unroll
        for (int nt = 0; nt < 8; nt++) {
            rm0 = fmaxf(rm0, fmaxf(c[nt][0], c[nt][1]));
            rm1 = fmaxf(rm1, fmaxf(c[nt][2], c[nt][3]));
        }
        rm0 = fmaxf(rm0, __shfl_xor_sync(0xffffffffu, rm0, 1));
        rm0 = fmaxf(rm0, __shfl_xor_sync(0xffffffffu, rm0, 2));
        rm1 = fmaxf(rm1, __shfl_xor_sync(0xffffffffu, rm1, 1));
        rm1 = fmaxf(rm1, __shfl_xor_sync(0xffffffffu, rm1, 2));
        const float mn0 = fmaxf(mr0, rm0), mn1 = fmaxf(mr1, rm1);
        const float f0 = fexp(mr0 - mn0), f1 = fexp(mr1 - mn1);
        float rs0 = 0.f, rs1 = 0.f;
#pragma unroll
        for (int nt = 0; nt < 8; nt++) {
            c[nt][0] = fexp(c[nt][0] - mn0);
            c[nt][1] = fexp(c[nt][1] - mn0);
            c[nt][2] = fexp(c[nt][2] - mn1);
            c[nt][3] = fexp(c[nt][3] - mn1);
            rs0 += c[nt][0] + c[nt][1];
            rs1 += c[nt][2] + c[nt][3];
        }
        rs0 += __shfl_xor_sync(0xffffffffu, rs0, 1);
        rs0 += __shfl_xor_sync(0xffffffffu, rs0, 2);
        rs1 += __shfl_xor_sync(0xffffffffu, rs1, 1);
        rs1 += __shfl_xor_sync(0xffffffffu, rs1, 2);
        lr0 = lr0 * f0 + rs0; mr0 = mn0;
        lr1 = lr1 * f1 + rs1; mr1 = mn1;
#pragma unroll
        for (int j = 0; j < 8; j++) {
            O[j][0] *= f0; O[j][1] *= f0;
            O[j][2] *= f1; O[j][3] *= f1;
        }

        // --- stream P + m_kt ---
        {
            const size_t gb0 = ((size_t)bh * S_ + row0) * S_ + k0 + col0;
            const size_t gb1 = ((size_t)bh * S_ + row1) * S_ + k0 + col0;
#pragma unroll
            for (int nt = 0; nt < 8; nt++) {
                float2 w0, w1;
                w0.x = c[nt][0]; w0.y = c[nt][1];
                w1.x = c[nt][2]; w1.y = c[nt][3];
                *(float2*)&Praw[gb0 + nt * 8] = w0;
                *(float2*)&Praw[gb1 + nt * 8] = w1;
            }
            if ((lane & 3) == 0) {
                mkt[((size_t)bh * 32 + kt) * S_ + row0] = mn0;
                mkt[((size_t)bh * 32 + kt) * S_ + row1] = mn1;
            }
        }

        // --- P @ V (truncation-split fragments) ---
#pragma unroll
        for (int ks2 = 0; ks2 < 4; ks2++) {
            const float* c0 = c[2 * ks2];
            const float* c1 = c[2 * ks2 + 1];
            uint32_t ah[4], al[4];
            ah[0] = TRUNC_HI2(c0[0], c0[1]);
            ah[1] = TRUNC_HI2(c0[2], c0[3]);
            ah[2] = TRUNC_HI2(c1[0], c1[1]);
            ah[3] = TRUNC_HI2(c1[2], c1[3]);
            al[0] = TRUNC_HI2(trunc_res(c0[0]), trunc_res(c0[1]));
            al[1] = TRUNC_HI2(trunc_res(c0[2]), trunc_res(c0[3]));
            al[2] = TRUNC_HI2(trunc_res(c1[0]), trunc_res(c1[1]));
            al[3] = TRUNC_HI2(trunc_res(c1[2]), trunc_res(c1[3]));
#pragma unroll
            for (int p = 0; p < 4; p++) {
                uint32_t vh4[4], vl4[4];
                const uint32_t off = (uint32_t)((ks2 * 16 + t4_row) * FP +
                                                p * 16 + t4_sel) * 2;
                ldmA4t(vh4, uVh + off);
                ldmA4t(vl4, uVl + off);
                mma16816(O[2*p],   ah, vh4);
                mma16816(O[2*p],   ah, vl4);
                mma16816(O[2*p],   al, vh4);
                mma16816(O[2*p+1], ah, vh4 + 2);
                mma16816(O[2*p+1], ah, vl4 + 2);
                mma16816(O[2*p+1], al, vh4 + 2);
            }
        }
    }

    // --- epilogue: normalized ctx as bf16 hi/lo ---
    const float inv0 = 1.0f / lr0, inv1 = 1.0f / lr1;
#pragma unroll
    for (int nt2 = 0; nt2 < 8; nt2++) {
        const int n = nt2 * 8 + col0;
        const size_t g0 = (size_t)(b * S_ + row0) * D_ + h * 64 + n;
        const size_t g1 = (size_t)(b * S_ + row1) * D_ + h * 64 + n;
        split_store(chi, clo, g0, O[nt2][0] * inv0, O[nt2][1] * inv0);
        split_store(chi, clo, g1, O[nt2][2] * inv1, O[nt2][3] * inv1);
    }
    if ((lane & 3) == 0) {
        size_t si = ((size_t)bh * S_ + row0) * 2;
        stats[si] = mr0; stats[si + 1] = lr0;
        si = ((size_t)bh * S_ + row1) * 2;
        stats[si] = mr1; stats[si + 1] = lr1;
    }
#undef LOAD_KV
#undef KVB
}

// ---------------------------------------------------------------------------
// Pass 2: attn = P * exp(m_kt - m_final) / l_final  (pure memory; 64-col kts)
// ---------------------------------------------------------------------------
__global__ __launch_bounds__(256) void normalize_kernel(
    const float* __restrict__ P, const float* __restrict__ mkt,
    const float* __restrict__ stats, float* __restrict__ attn)
{
    __shared__ float corr[32];
    const int t   = threadIdx.x;
    const int row = blockIdx.x;
    const int bh  = blockIdx.y;

    const size_t si = ((size_t)bh * S_ + row) * 2;
    const float m_f = stats[si];
    const float inv_l = 1.0f / stats[si + 1];
    if (t < 32)
        corr[t] = __expf(mkt[((size_t)bh * 32 + t) * S_ + row] - m_f) * inv_l;
    __syncthreads();

    const size_t base = ((size_t)bh * S_ + row) * S_;
    const float c = corr[t >> 3];
    float4 v0 = *(const float4*)&P[base + t * 8];
    float4 v1 = *(const float4*)&P[base + t * 8 + 4];
    v0.x *= c; v0.y *= c; v0.z *= c; v0.w *= c;
    v1.x *= c; v1.y *= c; v1.z *= c; v1.w *= c;
    *(float4*)&attn[base + t * 8]     = v0;
    *(float4*)&attn[base + t * 8 + 4] = v1;
}

// ---------------------------------------------------------------------------
extern "C" void kernel_launch(void* const* d_in, const int* in_sizes, int n_in,
                              void* d_out, int out_size)
{
    const float* x    = (const float*)d_in[0];
    const int*   mask = (const int*)  d_in[1];
    const float* wq_w = (const float*)d_in[2];
    const float* wq_b = (const float*)d_in[3];
    const float* wk_w = (const float*)d_in[4];
    const float* wk_b = (const float*)d_in[5];
    const float* wv_w = (const float*)d_in[6];
    const float* wv_b = (const float*)d_in[7];
    const float* wo_w = (const float*)d_in[8];
    const float* wo_b = (const float*)d_in[9];

    float *qdump, *attn_raw, *mkt, *stats;
    cudaGetSymbolAddress((void**)&qdump,    g_q);
    cudaGetSymbolAddress((void**)&attn_raw, g_attn_raw);
    cudaGetSymbolAddress((void**)&mkt,      g_mkt);
    cudaGetSymbolAddress((void**)&stats,    g_stats);

    __nv_bfloat16 *xhi, *xlo, *chi, *clo;
    __nv_bfloat16 *qhi_p, *qlo_p, *khi_p, *klo_p, *vhi_p, *vlo_p;
    __nv_bfloat16 *wqhi, *wqlo, *wkhi, *wklo, *wvhi, *wvlo, *wohi, *wolo;
    cudaGetSymbolAddress((void**)&xhi, g_xhi);   cudaGetSymbolAddress((void**)&xlo, g_xlo);
    cudaGetSymbolAddress((void**)&chi, g_chi);   cudaGetSymbolAddress((void**)&clo, g_clo);
    cudaGetSymbolAddress((void**)&qhi_p, g_qhi); cudaGetSymbolAddress((void**)&qlo_p, g_qlo);
    cudaGetSymbolAddress((void**)&khi_p, g_khi); cudaGetSymbolAddress((void**)&klo_p, g_klo);
    cudaGetSymbolAddress((void**)&vhi_p, g_vhi); cudaGetSymbolAddress((void**)&vlo_p, g_vlo);
    cudaGetSymbolAddress((void**)&wqhi, g_wqhi); cudaGetSymbolAddress((void**)&wqlo, g_wqlo);
    cudaGetSymbolAddress((void**)&wkhi, g_wkhi); cudaGetSymbolAddress((void**)&wklo, g_wklo);
    cudaGetSymbolAddress((void**)&wvhi, g_wvhi); cudaGetSymbolAddress((void**)&wvlo, g_wvlo);
    cudaGetSymbolAddress((void**)&wohi, g_wohi); cudaGetSymbolAddress((void**)&wolo, g_wolo);

    const long long CTXSZ = (long long)B_ * S_ * D_;
    const long long ATTSZ = (long long)B_ * H_ * S_ * S_;

    float* out_base = (float*)d_out;
    float* out_ptr;
    float* attn_ptr;
    if ((long long)out_size >= CTXSZ + ATTSZ) {
        out_ptr  = out_base;
        attn_ptr = out_base + CTXSZ;
    } else if ((long long)out_size == ATTSZ) {
        out_ptr  = qdump;
        attn_ptr = out_base;
    } else {
        out_ptr  = out_base;
        attn_ptr = attn_raw;
    }

    cudaFuncSetAttribute(flash_mma_kernel,
                         cudaFuncAttributeMaxDynamicSharedMemorySize, FLASH_SMEM);
    cudaFuncSetAttribute(gemm_qkv,
                         cudaFuncAttributeMaxDynamicSharedMemorySize, GEMM_SMEM);
    cudaFuncSetAttribute(gemm_out,
                         cudaFuncAttributeMaxDynamicSharedMemorySize, GEMM_SMEM);

    const int M = B_ * S_;   // 4096
    const int N = D_;        // 1024
    const int K = D_;        // 1024

    const int xn4 = (int)(CTXSZ / 4);
    const int wn4 = D_ * D_ / 4;
    conv_split<<<(xn4 + 255) / 256, 256>>>((const float4*)x, (uint2*)xhi, (uint2*)xlo, xn4);
    dim3 wGrid((wn4 + 255) / 256, 4);
    conv_split_w4<<<wGrid, 256>>>(
        (const float4*)wq_w, (uint2*)wqhi, (uint2*)wqlo,
        (const float4*)wk_w, (uint2*)wkhi, (uint2*)wklo,
        (const float4*)wv_w, (uint2*)wvhi, (uint2*)wvlo,
        (const float4*)wo_w, (uint2*)wohi, (uint2*)wolo, wn4);

    dim3 qkvGrid(N / 128, M / 128, 3);
    gemm_qkv<<<qkvGrid, 256, GEMM_SMEM>>>(
        xhi, xlo,
        wqhi, wqlo, wkhi, wklo, wvhi, wvlo,
        wq_b, wk_b, wv_b,
        qhi_p, qlo_p, khi_p, klo_p, vhi_p, vlo_p, M, N, K);

    dim3 fGrid(S_ / 128, B_ * H_);
    flash_mma_kernel<<<fGrid, 256, FLASH_SMEM>>>(
        qhi_p, qlo_p, khi_p, klo_p, vhi_p, vlo_p,
        mask, attn_raw, mkt, stats, chi, clo);

    dim3 gGrid(N / 128, M / 128);
    gemm_out<<<gGrid, 256, GEMM_SMEM>>>(chi, clo, wohi, wolo, wo_b, out_ptr, M, N, K);

    dim3 nGrid(S_, B_ * H_);
    normalize_kernel<<<nGrid, 256>>>(attn_raw, mkt, stats, attn_ptr);
}

// round 11
// speedup vs baseline: 2.4469x; 1.0250x over previous
#include <cuda_runtime.h>
#include <cuda_bf16.h>
#include <math.h>
#include <stdint.h>

// Problem constants
#define B_  2
#define S_  2048
#define D_  1024
#define H_  16
#define DH_ 64
#define SCALE_ 0.125f   // DH^-0.5
#define SW_ (S_ / 32)   // mask words per row

typedef unsigned long long u64;

// ---------------------------------------------------------------------------
// Scratch (static device globals; no runtime allocation)
// ---------------------------------------------------------------------------
__device__ float g_q[(size_t)B_ * S_ * D_];                 // dummy sink
__device__ float g_attn_raw[(size_t)B_ * H_ * S_ * S_];
__device__ float g_mkt[(size_t)B_ * H_ * (S_ / 64) * S_];
__device__ float g_stats[(size_t)B_ * H_ * S_ * 2];
__device__ uint32_t g_mbits[(size_t)B_ * S_ * SW_];        // bit-packed mask

// bf16 hi/lo split operands
__device__ __nv_bfloat16 g_xhi[(size_t)B_ * S_ * D_];
__device__ __nv_bfloat16 g_xlo[(size_t)B_ * S_ * D_];
__device__ __nv_bfloat16 g_qhi[(size_t)B_ * S_ * D_], g_qlo[(size_t)B_ * S_ * D_];
__device__ __nv_bfloat16 g_khi[(size_t)B_ * S_ * D_], g_klo[(size_t)B_ * S_ * D_];
__device__ __nv_bfloat16 g_vhi[(size_t)B_ * S_ * D_], g_vlo[(size_t)B_ * S_ * D_];
__device__ __nv_bfloat16 g_chi[(size_t)B_ * S_ * D_], g_clo[(size_t)B_ * S_ * D_];
__device__ __nv_bfloat16 g_wqhi[D_ * D_], g_wqlo[D_ * D_];
__device__ __nv_bfloat16 g_wkhi[D_ * D_], g_wklo[D_ * D_];
__device__ __nv_bfloat16 g_wvhi[D_ * D_], g_wvlo[D_ * D_];
__device__ __nv_bfloat16 g_wohi[D_ * D_], g_wolo[D_ * D_];

// ---------------------------------------------------------------------------
// mma.sync / ldmatrix helpers
// ---------------------------------------------------------------------------
__device__ __forceinline__ uint32_t smem_u32(const void* p) {
    uint32_t a;
    asm("{ .reg .u64 t; cvta.to.shared.u64 t, %1; cvt.u32.u64 %0, t; }"
        : "=r"(a) : "l"(p));
    return a;
}
__device__ __forceinline__ void ldmA4(uint32_t* a, uint32_t addr) {
    asm volatile("ldmatrix.sync.aligned.m8n8.x4.shared.b16 {%0,%1,%2,%3}, [%4];"
                 : "=r"(a[0]), "=r"(a[1]), "=r"(a[2]), "=r"(a[3]) : "r"(addr));
}
__device__ __forceinline__ void ldmA4t(uint32_t* a, uint32_t addr) {
    asm volatile("ldmatrix.sync.aligned.m8n8.x4.trans.shared.b16 {%0,%1,%2,%3}, [%4];"
                 : "=r"(a[0]), "=r"(a[1]), "=r"(a[2]), "=r"(a[3]) : "r"(addr));
}
__device__ __forceinline__ void mma16816(float* c, const uint32_t* a,
                                         const uint32_t* b) {
    asm volatile(
        "mma.sync.aligned.m16n8k16.row.col.f32.bf16.bf16.f32 "
        "{%0,%1,%2,%3}, {%4,%5,%6,%7}, {%8,%9}, {%0,%1,%2,%3};"
        : "+f"(c[0]), "+f"(c[1]), "+f"(c[2]), "+f"(c[3])
        : "r"(a[0]), "r"(a[1]), "r"(a[2]), "r"(a[3]), "r"(b[0]), "r"(b[1]));
}
__device__ __forceinline__ void cpasync16(uint32_t saddr, const void* gaddr) {
    asm volatile("cp.async.cg.shared.global [%0], [%1], 16;"
                 :: "r"(saddr), "l"(gaddr));
}
#define CP_COMMIT() asm volatile("cp.async.commit_group;" ::: "memory")
#define CP_WAIT0()  asm volatile("cp.async.wait_group 0;" ::: "memory")
#define CP_WAIT1()  asm volatile("cp.async.wait_group 1;" ::: "memory")

__device__ __forceinline__ uint32_t pack_bf2(float x, float y) {
    return (uint32_t)__bfloat16_as_ushort(__float2bfloat16(x)) |
           ((uint32_t)__bfloat16_as_ushort(__float2bfloat16(y)) << 16);
}
#define TRUNC_HI2(x, y) __byte_perm(__float_as_uint(x), __float_as_uint(y), 0x7632)
__device__ __forceinline__ float trunc_res(float x) {
    return x - __uint_as_float(__float_as_uint(x) & 0xFFFF0000u);
}
__device__ __forceinline__ void split_store(
    __nv_bfloat16* hi, __nv_bfloat16* lo, size_t idx, float x, float y)
{
    const __nv_bfloat16 hx = __float2bfloat16(x), hy = __float2bfloat16(y);
    *(uint32_t*)&hi[idx] = (uint32_t)__bfloat16_as_ushort(hx) |
                           ((uint32_t)__bfloat16_as_ushort(hy) << 16);
    *(uint32_t*)&lo[idx] = pack_bf2(x - __bfloat162float(hx),
                                    y - __bfloat162float(hy));
}
__device__ __forceinline__ float fexp(float x) { return __expf(x); }

// ---------------------------------------------------------------------------
// Split-conversions
// ---------------------------------------------------------------------------
__global__ __launch_bounds__(256) void conv_split(
    const float4* __restrict__ src, uint2* __restrict__ hi,
    uint2* __restrict__ lo, int n4)
{
    const int i = blockIdx.x * 256 + threadIdx.x;
    if (i >= n4) return;
    const float4 v = src[i];
    split_store((__nv_bfloat16*)hi, (__nv_bfloat16*)lo, (size_t)i * 4,     v.x, v.y);
    split_store((__nv_bfloat16*)hi, (__nv_bfloat16*)lo, (size_t)i * 4 + 2, v.z, v.w);
}

__global__ __launch_bounds__(256) void conv_split_w4(
    const float4* s0, uint2* h0, uint2* l0,
    const float4* s1, uint2* h1, uint2* l1,
    const float4* s2, uint2* h2, uint2* l2,
    const float4* s3, uint2* h3, uint2* l3, int n4)
{
    const int i = blockIdx.x * 256 + threadIdx.x;
    if (i >= n4) return;
    const int w = blockIdx.y;
    const float4* src = (w == 0) ? s0 : (w == 1) ? s1 : (w == 2) ? s2 : s3;
    uint2* hi = (w == 0) ? h0 : (w == 1) ? h1 : (w == 2) ? h2 : h3;
    uint2* lo = (w == 0) ? l0 : (w == 1) ? l1 : (w == 2) ? l2 : l3;
    const float4 v = src[i];
    split_store((__nv_bfloat16*)hi, (__nv_bfloat16*)lo, (size_t)i * 4,     v.x, v.y);
    split_store((__nv_bfloat16*)hi, (__nv_bfloat16*)lo, (size_t)i * 4 + 2, v.z, v.w);
}

// Pack mask (int32 per element) into 1 bit per element.
__global__ __launch_bounds__(256) void conv_maskbits(
    const int4* __restrict__ mask, uint32_t* __restrict__ mbits, int nwords)
{
    const int w = blockIdx.x * 256 + threadIdx.x;
    if (w >= nwords) return;
    const int4* src = mask + (size_t)w * 8;     // 32 ints = 8 int4
    uint32_t bits = 0;
#pragma unroll
    for (int j = 0; j < 8; j++) {
        const int4 v = src[j];
        bits |= (v.x != 0 ? 1u : 0u) << (j * 4 + 0);
        bits |= (v.y != 0 ? 1u : 0u) << (j * 4 + 1);
        bits |= (v.z != 0 ? 1u : 0u) << (j * 4 + 2);
        bits |= (v.w != 0 ? 1u : 0u) << (j * 4 + 3);
    }
    mbits[w] = bits;
}

// ---------------------------------------------------------------------------
// Shared GEMM body: 3-term fused K-loop, 2-stage pipeline (unchanged).
// ---------------------------------------------------------------------------
#define GP 72
#define GTILE (128 * GP)
#define GEMM_SMEM (2 * 4 * GTILE * 2)

__device__ __forceinline__ void gemm_body(
    const __nv_bfloat16* __restrict__ Ahi, const __nv_bfloat16* __restrict__ Alo,
    const __nv_bfloat16* __restrict__ Bhi, const __nv_bfloat16* __restrict__ Blo,
    const float* __restrict__ bias, float* __restrict__ C,
    __nv_bfloat16* __restrict__ Chi, __nv_bfloat16* __restrict__ Clo,
    int M, int N, int K, int bm, int bn, uint32_t sb)
{
    const int tid  = threadIdx.x;
    const int lane = tid & 31, wid = tid >> 5;
    const int warp_m = wid >> 2, warp_n = wid & 3;

    const int a_r = warp_m * 64 + (lane & 15);
    const int a_c = (lane >> 4) * 8;
    const int b4_row = ((lane >> 4) & 1) * 8 + (lane & 7);
    const int b4_col = ((lane >> 3) & 1) * 8;

    const int lrow = tid >> 3;
    const int lc8  = (tid & 7) * 8;

    float acc[4][4][4];
#pragma unroll
    for (int mt = 0; mt < 4; mt++)
#pragma unroll
        for (int nt = 0; nt < 4; nt++)
#pragma unroll
            for (int r = 0; r < 4; r++) acc[mt][nt][r] = 0.f;

#define TBASE(s, o) (sb + (uint32_t)(((s) * 4 + (o)) * GTILE) * 2)
#define LOAD_STAGE(s, k0) do {                                                \
    const uint32_t _dAh = TBASE(s, 0), _dAl = TBASE(s, 1);                    \
    const uint32_t _dBh = TBASE(s, 2), _dBl = TBASE(s, 3);                    \
    _Pragma("unroll")                                                         \
    for (int rr = 0; rr < 4; rr++) {                                          \
        const int row = lrow + rr * 32;                                       \
        const uint32_t so = (uint32_t)(row * GP + lc8) * 2;                   \
        const size_t ga = (size_t)(bm + row) * K + (k0) + lc8;                \
        const size_t gb = (size_t)(bn + row) * K + (k0) + lc8;                \
        cpasync16(_dAh + so, &Ahi[ga]);                                       \
        cpasync16(_dAl + so, &Alo[ga]);                                       \
        cpasync16(_dBh + so, &Bhi[gb]);                                       \
        cpasync16(_dBl + so, &Blo[gb]);                                       \
    }                                                                         \
    CP_COMMIT();                                                              \
} while (0)

    LOAD_STAGE(0, 0);

    const int NK = K / 64;
    for (int kc = 0; kc < NK; kc++) {
        const int cur = kc & 1;
        if (kc + 1 < NK) { LOAD_STAGE(cur ^ 1, (kc + 1) * 64); CP_WAIT1(); }
        else             { CP_WAIT0(); }
        __syncthreads();

        const uint32_t uAh = TBASE(cur, 0), uAl = TBASE(cur, 1);
        const uint32_t uBh = TBASE(cur, 2), uBl = TBASE(cur, 3);
#pragma unroll
        for (int ks = 0; ks < 4; ks++) {
            uint32_t ah[4][4], al[4][4];
#pragma unroll
            for (int mt = 0; mt < 4; mt++) {
                const uint32_t ao = (uint32_t)((a_r + mt * 16) * GP +
                                               ks * 16 + a_c) * 2;
                ldmA4(ah[mt], uAh + ao);
                ldmA4(al[mt], uAl + ao);
            }
            uint32_t bh[4][2], bl[4][2];
#pragma unroll
            for (int p = 0; p < 2; p++) {
                uint32_t r4[4];
                const uint32_t bo = (uint32_t)((warp_n * 32 + p * 16 + b4_row) * GP +
                                               ks * 16 + b4_col) * 2;
                ldmA4(r4, uBh + bo);
                bh[2*p][0] = r4[0]; bh[2*p][1] = r4[1];
                bh[2*p+1][0] = r4[2]; bh[2*p+1][1] = r4[3];
                ldmA4(r4, uBl + bo);
                bl[2*p][0] = r4[0]; bl[2*p][1] = r4[1];
                bl[2*p+1][0] = r4[2]; bl[2*p+1][1] = r4[3];
            }
#pragma unroll
            for (int mt = 0; mt < 4; mt++)
#pragma unroll
                for (int nt = 0; nt < 4; nt++) {
                    mma16816(acc[mt][nt], ah[mt], bh[nt]);
                    mma16816(acc[mt][nt], ah[mt], bl[nt]);
                    mma16816(acc[mt][nt], al[mt], bh[nt]);
                }
        }
        __syncthreads();
    }

    const int em = bm + warp_m * 64 + (lane >> 2);
    const int en = bn + warp_n * 32 + (lane & 3) * 2;
#pragma unroll
    for (int mt = 0; mt < 4; mt++) {
#pragma unroll
        for (int nt = 0; nt < 4; nt++) {
            const int n = en + nt * 8;
            const float bx = bias[n], by = bias[n + 1];
            const int m0 = em + mt * 16;
            float2 o0, o1;
            o0.x = acc[mt][nt][0] + bx; o0.y = acc[mt][nt][1] + by;
            o1.x = acc[mt][nt][2] + bx; o1.y = acc[mt][nt][3] + by;
            if (C) {
                *(float2*)&C[(size_t)m0 * N + n]       = o0;
                *(float2*)&C[(size_t)(m0 + 8) * N + n] = o1;
            }
            if (Chi) {
                split_store(Chi, Clo, (size_t)m0 * N + n,       o0.x, o0.y);
                split_store(Chi, Clo, (size_t)(m0 + 8) * N + n, o1.x, o1.y);
            }
        }
    }
#undef LOAD_STAGE
#undef TBASE
}

__global__ __launch_bounds__(256) void gemm_qkv(
    const __nv_bfloat16* __restrict__ Ahi, const __nv_bfloat16* __restrict__ Alo,
    const __nv_bfloat16* bq_h, const __nv_bfloat16* bq_l,
    const __nv_bfloat16* bk_h, const __nv_bfloat16* bk_l,
    const __nv_bfloat16* bv_h, const __nv_bfloat16* bv_l,
    const float* biq, const float* bik, const float* biv,
    __nv_bfloat16* qh, __nv_bfloat16* ql,
    __nv_bfloat16* kh, __nv_bfloat16* kl,
    __nv_bfloat16* vh, __nv_bfloat16* vl,
    int M, int N, int K)
{
    extern __shared__ __nv_bfloat16 gsm[];
    const int z = blockIdx.z;
    const __nv_bfloat16* Bh = (z == 0) ? bq_h : (z == 1) ? bk_h : bv_h;
    const __nv_bfloat16* Bl = (z == 0) ? bq_l : (z == 1) ? bk_l : bv_l;
    const float* bias = (z == 0) ? biq : (z == 1) ? bik : biv;
    __nv_bfloat16* Ch = (z == 0) ? qh : (z == 1) ? kh : vh;
    __nv_bfloat16* Cl = (z == 0) ? ql : (z == 1) ? kl : vl;
    gemm_body(Ahi, Alo, Bh, Bl, bias, (float*)nullptr, Ch, Cl,
              M, N, K, blockIdx.y * 128, blockIdx.x * 128, smem_u32(gsm));
}

__global__ __launch_bounds__(256) void gemm_out(
    const __nv_bfloat16* __restrict__ Ahi, const __nv_bfloat16* __restrict__ Alo,
    const __nv_bfloat16* __restrict__ Bhi, const __nv_bfloat16* __restrict__ Blo,
    const float* __restrict__ bias, float* __restrict__ C,
    int M, int N, int K)
{
    extern __shared__ __nv_bfloat16 gsm[];
    gemm_body(Ahi, Alo, Bhi, Blo, bias, C,
              (__nv_bfloat16*)nullptr, (__nv_bfloat16*)nullptr,
              M, N, K, blockIdx.y * 128, blockIdx.x * 128, smem_u32(gsm));
}

// ---------------------------------------------------------------------------
// Tensor-core flash attention with bit-packed mask:
//   k-tile 64, Q resident, K/V 2-stage cp.async pipeline, <=128 regs, 2 CTAs/SM.
// ---------------------------------------------------------------------------
#define FP 72
#define KVT (64 * FP)
#define FLASH_SMEM ((2 * 128 * FP + 2 * 4 * KVT) * 2)    // 110592 bytes

__global__ __launch_bounds__(256, 2) void flash_mma_kernel(
    const __nv_bfloat16* __restrict__ qhi, const __nv_bfloat16* __restrict__ qlo,
    const __nv_bfloat16* __restrict__ khi, const __nv_bfloat16* __restrict__ klo,
    const __nv_bfloat16* __restrict__ vhi, const __nv_bfloat16* __restrict__ vlo,
    const uint32_t* __restrict__ mbits, float* __restrict__ Praw,
    float* __restrict__ mkt, float* __restrict__ stats,
    __nv_bfloat16* __restrict__ chi, __nv_bfloat16* __restrict__ clo)
{
    extern __shared__ __nv_bfloat16 smb[];
    __nv_bfloat16* sQh = smb;
    __nv_bfloat16* sQl = sQh + 128 * FP;
    __nv_bfloat16* sKV = sQl + 128 * FP;

    const int t = threadIdx.x, lane = t & 31, warp = t >> 5;
    const int bh = blockIdx.y;
    const int b = bh >> 4, h = bh & 15;
    const int q0 = blockIdx.x * 128;

    const uint32_t uQh = smem_u32(sQh), uQl = smem_u32(sQl);
    const uint32_t uKV = smem_u32(sKV);
#define KVB(s, o) (uKV + (uint32_t)(((s) * 4 + (o)) * KVT) * 2)

    for (int i = t; i < 1024; i += 256) {
        const int row = i >> 3, c8 = (i & 7) * 8;
        const size_t g = (size_t)(b * S_ + q0 + row) * D_ + h * 64 + c8;
        const uint32_t so = (uint32_t)(row * FP + c8) * 2;
        cpasync16(uQh + so, &qhi[g]);
        cpasync16(uQl + so, &qlo[g]);
    }

    const int kv_row = t >> 3;
    const int kv_c8  = (t & 7) * 8;
#define LOAD_KV(stage, k0) do {                                               \
    _Pragma("unroll")                                                         \
    for (int rr = 0; rr < 2; rr++) {                                          \
        const int row = kv_row + rr * 32;                                     \
        const size_t g = (size_t)(b * S_ + (k0) + row) * D_ + h * 64 + kv_c8; \
        const uint32_t so = (uint32_t)(row * FP + kv_c8) * 2;                 \
        cpasync16(KVB(stage, 0) + so, &khi[g]);                               \
        cpasync16(KVB(stage, 1) + so, &klo[g]);                               \
        cpasync16(KVB(stage, 2) + so, &vhi[g]);                               \
        cpasync16(KVB(stage, 3) + so, &vlo[g]);                               \
    }                                                                         \
    CP_COMMIT();                                                              \
} while (0)

    LOAD_KV(0, 0);

    float O[8][4];
#pragma unroll
    for (int j = 0; j < 8; j++)
#pragma unroll
        for (int r = 0; r < 4; r++) O[j][r] = 0.f;
    float mr0 = -1e30f, mr1 = -1e30f, lr0 = 0.f, lr1 = 0.f;

    const int row0 = q0 + warp * 16 + (lane >> 2);
    const int row1 = row0 + 8;
    const int col0 = (lane & 3) * 2;
    const int a_r  = warp * 16 + (lane & 15);
    const int a_c  = (lane >> 4) * 8;
    const int b4_row = ((lane >> 4) & 1) * 8 + (lane & 7);
    const int b4_col = ((lane >> 3) & 1) * 8;
    const int t4_row = ((lane >> 3) & 1) * 8 + (lane & 7);
    const int t4_sel = ((lane >> 4) & 1) * 8;

    const uint32_t* mrow0 = &mbits[((size_t)b * S_ + row0) * SW_];
    const uint32_t* mrow1 = &mbits[((size_t)b * S_ + row1) * SW_];

    const int NT = S_ / 64;
    for (int kt = 0; kt < NT; kt++) {
        const int k0 = kt * 64;
        const int cur = kt & 1;
        CP_WAIT0();
        __syncthreads();
        if (kt + 1 < NT) LOAD_KV(cur ^ 1, (kt + 1) * 64);

        const uint32_t uKh = KVB(cur, 0), uKl = KVB(cur, 1);
        const uint32_t uVh = KVB(cur, 2), uVl = KVB(cur, 3);

        // --- QK^T: c[8][4] over 64 k-cols ---
        float c[8][4];
#pragma unroll
        for (int nt = 0; nt < 8; nt++)
#pragma unroll
            for (int r = 0; r < 4; r++) c[nt][r] = 0.f;
#pragma unroll
        for (int ks = 0; ks < 4; ks++) {
            uint32_t qh2[4], ql2[4];
            const uint32_t qo = (uint32_t)(a_r * FP + ks * 16 + a_c) * 2;
            ldmA4(qh2, uQh + qo);
            ldmA4(ql2, uQl + qo);
#pragma unroll
            for (int p = 0; p < 4; p++) {
                uint32_t rh[4], rl[4];
                const uint32_t off = (uint32_t)((p * 16 + b4_row) * FP +
                                                ks * 16 + b4_col) * 2;
                ldmA4(rh, uKh + off);
                ldmA4(rl, uKl + off);
                mma16816(c[2*p],   qh2, rh);
                mma16816(c[2*p],   qh2, rl);
                mma16816(c[2*p],   ql2, rh);
                mma16816(c[2*p+1], qh2, rh + 2);
                mma16816(c[2*p+1], qh2, rl + 2);
                mma16816(c[2*p+1], ql2, rh + 2);
            }
        }

        // --- scale + mask (bit-packed: 2 x uint2 per thread per kt) ---
        {
            const uint2 mw0 = *(const uint2*)&mrow0[k0 >> 5];
            const uint2 mw1 = *(const uint2*)&mrow1[k0 >> 5];
#pragma unroll
            for (int nt = 0; nt < 8; nt++) {
                const int cb = ((nt & 3) * 8 + col0);      // bit pos in word
                const uint32_t w0 = (nt < 4) ? mw0.x : mw0.y;
                const uint32_t w1 = (nt < 4) ? mw1.x : mw1.y;
                c[nt][0] = ((w0 >> cb) & 1u)       ? c[nt][0] * SCALE_ : -1e9f;
                c[nt][1] = ((w0 >> (cb + 1)) & 1u) ? c[nt][1] * SCALE_ : -1e9f;
                c[nt][2] = ((w1 >> cb) & 1u)       ? c[nt][2] * SCALE_ : -1e9f;
                c[nt][3] = ((w1 >> (cb + 1)) & 1u) ? c[nt][3] * SCALE_ : -1e9f;
            }
        }

        // --- online softmax ---
        float rm0 = -1e30f, rm1 = -1e30f;
#pragma unroll
        for (int nt = 0; nt < 8; nt++) {
            rm0 = fmaxf(rm0, fmaxf(c[nt][0], c[nt][1]));
            rm1 = fmaxf(rm1, fmaxf(c[nt][2], c[nt][3]));
        }
        rm0 = fmaxf(rm0, __shfl_xor_sync(0xffffffffu, rm0, 1));
        rm0 = fmaxf(rm0, __shfl_xor_sync(0xffffffffu, rm0, 2));
        rm1 = fmaxf(rm1, __shfl_xor_sync(0xffffffffu, rm1, 1));
        rm1 = fmaxf(rm1, __shfl_xor_sync(0xffffffffu, rm1, 2));
        const float mn0 = fmaxf(mr0, rm0), mn1 = fmaxf(mr1, rm1);
        const float f0 = fexp(mr0 - mn0), f1 = fexp(mr1 - mn1);
        float rs0 = 0.f, rs1 = 0.f;
#pragma unroll
        for (int nt = 0; nt < 8; nt++) {
            c[nt][0] = fexp(c[nt][0] - mn0);
            c[nt][1] = fexp(c[nt][1] - mn0);
            c[nt][2] = fexp(c[nt][2] - mn1);
            c[nt][3] = fexp(c[nt][3] - mn1);
            rs0 += c[nt][0] + c[nt][1];
            rs1 += c[nt][2] + c[nt][3];
        }
        rs0 += __shfl_xor_sync(0xffffffffu, rs0, 1);
        rs0 += __shfl_xor_sync(0xffffffffu, rs0, 2);
        rs1 += __shfl_xor_sync(0xffffffffu, rs1, 1);
        rs1 += __shfl_xor_sync(0xffffffffu, rs1, 2);
        lr0 = lr0 * f0 + rs0; mr0 = mn0;
        lr1 = lr1 * f1 + rs1; mr1 = mn1;
#pragma unroll
        for (int j = 0; j < 8; j++) {
            O[j][0] *= f0; O[j][1] *= f0;
            O[j][2] *= f1; O[j][3] *= f1;
        }

        // --- stream P + m_kt ---
        {
            const size_t gb0 = ((size_t)bh * S_ + row0) * S_ + k0 + col0;
            const size_t gb1 = ((size_t)bh * S_ + row1) * S_ + k0 + col0;
#pragma unroll
            for (int nt = 0; nt < 8; nt++) {
                float2 w0, w1;
                w0.x = c[nt][0]; w0.y = c[nt][1];
                w1.x = c[nt][2]; w1.y = c[nt][3];
                *(float2*)&Praw[gb0 + nt * 8] = w0;
                *(float2*)&Praw[gb1 + nt * 8] = w1;
            }
            if ((lane & 3) == 0) {
                mkt[((size_t)bh * 32 + kt) * S_ + row0] = mn0;
                mkt[((size_t)bh * 32 + kt) * S_ + row1] = mn1;
            }
        }

        // --- P @ V (truncation-split fragments) ---
#pragma unroll
        for (int ks2 = 0; ks2 < 4; ks2++) {
            const float* c0 = c[2 * ks2];
            const float* c1 = c[2 * ks2 + 1];
            uint32_t ah[4], al[4];
            ah[0] = TRUNC_HI2(c0[0], c0[1]);
            ah[1] = TRUNC_HI2(c0[2], c0[3]);
            ah[2] = TRUNC_HI2(c1[0], c1[1]);
            ah[3] = TRUNC_HI2(c1[2], c1[3]);
            al[0] = TRUNC_HI2(trunc_res(c0[0]), trunc_res(c0[1]));
            al[1] = TRUNC_HI2(trunc_res(c0[2]), trunc_res(c0[3]));
            al[2] = TRUNC_HI2(trunc_res(c1[0]), trunc_res(c1[1]));
            al[3] = TRUNC_HI2(trunc_res(c1[2]), trunc_res(c1[3]));
#pragma unroll
            for (int p = 0; p < 4; p++) {
                uint32_t vh4[4], vl4[4];
                const uint32_t off = (uint32_t)((ks2 * 16 + t4_row) * FP +
                                                p * 16 + t4_sel) * 2;
                ldmA4t(vh4, uVh + off);
                ldmA4t(vl4, uVl + off);
                mma16816(O[2*p],   ah, vh4);
                mma16816(O[2*p],   ah, vl4);
                mma16816(O[2*p],   al, vh4);
                mma16816(O[2*p+1], ah, vh4 + 2);
                mma16816(O[2*p+1], ah, vl4 + 2);
                mma16816(O[2*p+1], al, vh4 + 2);
            }
        }
    }

    // --- epilogue: normalized ctx as bf16 hi/lo ---
    const float inv0 = 1.0f / lr0, inv1 = 1.0f / lr1;
#pragma unroll
    for (int nt2 = 0; nt2 < 8; nt2++) {
        const int n = nt2 * 8 + col0;
        const size_t g0 = (size_t)(b * S_ + row0) * D_ + h * 64 + n;
        const size_t g1 = (size_t)(b * S_ + row1) * D_ + h * 64 + n;
        split_store(chi, clo, g0, O[nt2][0] * inv0, O[nt2][1] * inv0);
        split_store(chi, clo, g1, O[nt2][2] * inv1, O[nt2][3] * inv1);
    }
    if ((lane & 3) == 0) {
        size_t si = ((size_t)bh * S_ + row0) * 2;
        stats[si] = mr0; stats[si + 1] = lr0;
        si = ((size_t)bh * S_ + row1) * 2;
        stats[si] = mr1; stats[si + 1] = lr1;
    }
#undef LOAD_KV
#undef KVB
}

// ---------------------------------------------------------------------------
// Pass 2: attn = P * exp(m_kt - m_final) / l_final  (pure memory; 64-col kts)
// ---------------------------------------------------------------------------
__global__ __launch_bounds__(256) void normalize_kernel(
    const float* __restrict__ P, const float* __restrict__ mkt,
    const float* __restrict__ stats, float* __restrict__ attn)
{
    __shared__ float corr[32];
    const int t   = threadIdx.x;
    const int row = blockIdx.x;
    const int bh  = blockIdx.y;

    const size_t si = ((size_t)bh * S_ + row) * 2;
    const float m_f = stats[si];
    const float inv_l = 1.0f / stats[si + 1];
    if (t < 32)
        corr[t] = __expf(mkt[((size_t)bh * 32 + t) * S_ + row] - m_f) * inv_l;
    __syncthreads();

    const size_t base = ((size_t)bh * S_ + row) * S_;
    const float c = corr[t >> 3];
    float4 v0 = *(const float4*)&P[base + t * 8];
    float4 v1 = *(const float4*)&P[base + t * 8 + 4];
    v0.x *= c; v0.y *= c; v0.z *= c; v0.w *= c;
    v1.x *= c; v1.y *= c; v1.z *= c; v1.w *= c;
    *(float4*)&attn[base + t * 8]     = v0;
    *(float4*)&attn[base + t * 8 + 4] = v1;
}

// ---------------------------------------------------------------------------
extern "C" void kernel_launch(void* const* d_in, const int* in_sizes, int n_in,
                              void* d_out, int out_size)
{
    const float* x    = (const float*)d_in[0];
    const int*   mask = (const int*)  d_in[1];
    const float* wq_w = (const float*)d_in[2];
    const float* wq_b = (const float*)d_in[3];
    const float* wk_w = (const float*)d_in[4];
    const float* wk_b = (const float*)d_in[5];
    const float* wv_w = (const float*)d_in[6];
    const float* wv_b = (const float*)d_in[7];
    const float* wo_w = (const float*)d_in[8];
    const float* wo_b = (const float*)d_in[9];

    float *qdump, *attn_raw, *mkt, *stats;
    uint32_t* mbits;
    cudaGetSymbolAddress((void**)&qdump,    g_q);
    cudaGetSymbolAddress((void**)&attn_raw, g_attn_raw);
    cudaGetSymbolAddress((void**)&mkt,      g_mkt);
    cudaGetSymbolAddress((void**)&stats,    g_stats);
    cudaGetSymbolAddress((void**)&mbits,    g_mbits);

    __nv_bfloat16 *xhi, *xlo, *chi, *clo;
    __nv_bfloat16 *qhi_p, *qlo_p, *khi_p, *klo_p, *vhi_p, *vlo_p;
    __nv_bfloat16 *wqhi, *wqlo, *wkhi, *wklo, *wvhi, *wvlo, *wohi, *wolo;
    cudaGetSymbolAddress((void**)&xhi, g_xhi);   cudaGetSymbolAddress((void**)&xlo, g_xlo);
    cudaGetSymbolAddress((void**)&chi, g_chi);   cudaGetSymbolAddress((void**)&clo, g_clo);
    cudaGetSymbolAddress((void**)&qhi_p, g_qhi); cudaGetSymbolAddress((void**)&qlo_p, g_qlo);
    cudaGetSymbolAddress((void**)&khi_p, g_khi); cudaGetSymbolAddress((void**)&klo_p, g_klo);
    cudaGetSymbolAddress((void**)&vhi_p, g_vhi); cudaGetSymbolAddress((void**)&vlo_p, g_vlo);
    cudaGetSymbolAddress((void**)&wqhi, g_wqhi); cudaGetSymbolAddress((void**)&wqlo, g_wqlo);
    cudaGetSymbolAddress((void**)&wkhi, g_wkhi); cudaGetSymbolAddress((void**)&wklo, g_wklo);
    cudaGetSymbolAddress((void**)&wvhi, g_wvhi); cudaGetSymbolAddress((void**)&wvlo, g_wvlo);
    cudaGetSymbolAddress((void**)&wohi, g_wohi); cudaGetSymbolAddress((void**)&wolo, g_wolo);

    const long long CTXSZ = (long long)B_ * S_ * D_;
    const long long ATTSZ = (long long)B_ * H_ * S_ * S_;

    float* out_base = (float*)d_out;
    float* out_ptr;
    float* attn_ptr;
    if ((long long)out_size >= CTXSZ + ATTSZ) {
        out_ptr  = out_base;
        attn_ptr = out_base + CTXSZ;
    } else if ((long long)out_size == ATTSZ) {
        out_ptr  = qdump;
        attn_ptr = out_base;
    } else {
        out_ptr  = out_base;
        attn_ptr = attn_raw;
    }

    cudaFuncSetAttribute(flash_mma_kernel,
                         cudaFuncAttributeMaxDynamicSharedMemorySize, FLASH_SMEM);
    cudaFuncSetAttribute(gemm_qkv,
                         cudaFuncAttributeMaxDynamicSharedMemorySize, GEMM_SMEM);
    cudaFuncSetAttribute(gemm_out,
                         cudaFuncAttributeMaxDynamicSharedMemorySize, GEMM_SMEM);

    const int M = B_ * S_;   // 4096
    const int N = D_;        // 1024
    const int K = D_;        // 1024

    const int xn4 = (int)(CTXSZ / 4);
    const int wn4 = D_ * D_ / 4;
    conv_split<<<(xn4 + 255) / 256, 256>>>((const float4*)x, (uint2*)xhi, (uint2*)xlo, xn4);
    dim3 wGrid((wn4 + 255) / 256, 4);
    conv_split_w4<<<wGrid, 256>>>(
        (const float4*)wq_w, (uint2*)wqhi, (uint2*)wqlo,
        (const float4*)wk_w, (uint2*)wkhi, (uint2*)wklo,
        (const float4*)wv_w, (uint2*)wvhi, (uint2*)wvlo,
        (const float4*)wo_w, (uint2*)wohi, (uint2*)wolo, wn4);

    const int nwords = B_ * S_ * SW_;
    conv_maskbits<<<(nwords + 255) / 256, 256>>>((const int4*)mask, mbits, nwords);

    dim3 qkvGrid(N / 128, M / 128, 3);
    gemm_qkv<<<qkvGrid, 256, GEMM_SMEM>>>(
        xhi, xlo,
        wqhi, wqlo, wkhi, wklo, wvhi, wvlo,
        wq_b, wk_b, wv_b,
        qhi_p, qlo_p, khi_p, klo_p, vhi_p, vlo_p, M, N, K);

    dim3 fGrid(S_ / 128, B_ * H_);
    flash_mma_kernel<<<fGrid, 256, FLASH_SMEM>>>(
        qhi_p, qlo_p, khi_p, klo_p, vhi_p, vlo_p,
        mbits, attn_raw, mkt, stats, chi, clo);

    dim3 gGrid(N / 128, M / 128);
    gemm_out<<<gGrid, 256, GEMM_SMEM>>>(chi, clo, wohi, wolo, wo_b, out_ptr, M, N, K);

    dim3 nGrid(S_, B_ * H_);
    normalize_kernel<<<nGrid, 256>>>(attn_raw, mkt, stats, attn_ptr);
}

// round 12
// speedup vs baseline: 2.5107x; 1.0261x over previous
#include <cuda_runtime.h>
#include <cuda_bf16.h>
#include <math.h>
#include <stdint.h>

// Problem constants
#define B_  2
#define S_  2048
#define D_  1024
#define H_  16
#define DH_ 64
#define SCALE_ 0.125f   // DH^-0.5
#define SW_ (S_ / 32)   // mask words per row

typedef unsigned long long u64;

// ---------------------------------------------------------------------------
// Scratch (static device globals; no runtime allocation)
// ---------------------------------------------------------------------------
__device__ float g_q[(size_t)B_ * S_ * D_];                 // dummy sink
__device__ float g_attn_raw[(size_t)B_ * H_ * S_ * S_];
__device__ float g_mkt[(size_t)B_ * H_ * (S_ / 64) * S_];
__device__ float g_stats[(size_t)B_ * H_ * S_ * 2];
__device__ uint32_t g_mbits[(size_t)B_ * S_ * SW_];        // bit-packed mask

// bf16 hi/lo split operands
__device__ __nv_bfloat16 g_xhi[(size_t)B_ * S_ * D_];
__device__ __nv_bfloat16 g_xlo[(size_t)B_ * S_ * D_];
__device__ __nv_bfloat16 g_qhi[(size_t)B_ * S_ * D_], g_qlo[(size_t)B_ * S_ * D_];
__device__ __nv_bfloat16 g_khi[(size_t)B_ * S_ * D_], g_klo[(size_t)B_ * S_ * D_];
__device__ __nv_bfloat16 g_vhi[(size_t)B_ * S_ * D_], g_vlo[(size_t)B_ * S_ * D_];
__device__ __nv_bfloat16 g_chi[(size_t)B_ * S_ * D_], g_clo[(size_t)B_ * S_ * D_];
__device__ __nv_bfloat16 g_wqhi[D_ * D_], g_wqlo[D_ * D_];
__device__ __nv_bfloat16 g_wkhi[D_ * D_], g_wklo[D_ * D_];
__device__ __nv_bfloat16 g_wvhi[D_ * D_], g_wvlo[D_ * D_];
__device__ __nv_bfloat16 g_wohi[D_ * D_], g_wolo[D_ * D_];

// ---------------------------------------------------------------------------
// mma.sync / ldmatrix helpers
// ---------------------------------------------------------------------------
__device__ __forceinline__ uint32_t smem_u32(const void* p) {
    uint32_t a;
    asm("{ .reg .u64 t; cvta.to.shared.u64 t, %1; cvt.u32.u64 %0, t; }"
        : "=r"(a) : "l"(p));
    return a;
}
__device__ __forceinline__ void ldmA4(uint32_t* a, uint32_t addr) {
    asm volatile("ldmatrix.sync.aligned.m8n8.x4.shared.b16 {%0,%1,%2,%3}, [%4];"
                 : "=r"(a[0]), "=r"(a[1]), "=r"(a[2]), "=r"(a[3]) : "r"(addr));
}
__device__ __forceinline__ void ldmA4t(uint32_t* a, uint32_t addr) {
    asm volatile("ldmatrix.sync.aligned.m8n8.x4.trans.shared.b16 {%0,%1,%2,%3}, [%4];"
                 : "=r"(a[0]), "=r"(a[1]), "=r"(a[2]), "=r"(a[3]) : "r"(addr));
}
__device__ __forceinline__ void mma16816(float* c, const uint32_t* a,
                                         const uint32_t* b) {
    asm volatile(
        "mma.sync.aligned.m16n8k16.row.col.f32.bf16.bf16.f32 "
        "{%0,%1,%2,%3}, {%4,%5,%6,%7}, {%8,%9}, {%0,%1,%2,%3};"
        : "+f"(c[0]), "+f"(c[1]), "+f"(c[2]), "+f"(c[3])
        : "r"(a[0]), "r"(a[1]), "r"(a[2]), "r"(a[3]), "r"(b[0]), "r"(b[1]));
}
__device__ __forceinline__ void cpasync16(uint32_t saddr, const void* gaddr) {
    asm volatile("cp.async.cg.shared.global [%0], [%1], 16;"
                 :: "r"(saddr), "l"(gaddr));
}
#define CP_COMMIT() asm volatile("cp.async.commit_group;" ::: "memory")
#define CP_WAIT0()  asm volatile("cp.async.wait_group 0;" ::: "memory")
#define CP_WAIT1()  asm volatile("cp.async.wait_group 1;" ::: "memory")

__device__ __forceinline__ uint32_t pack_bf2(float x, float y) {
    return (uint32_t)__bfloat16_as_ushort(__float2bfloat16(x)) |
           ((uint32_t)__bfloat16_as_ushort(__float2bfloat16(y)) << 16);
}
#define TRUNC_HI2(x, y) __byte_perm(__float_as_uint(x), __float_as_uint(y), 0x7632)
__device__ __forceinline__ float trunc_res(float x) {
    return x - __uint_as_float(__float_as_uint(x) & 0xFFFF0000u);
}
__device__ __forceinline__ void split_store(
    __nv_bfloat16* hi, __nv_bfloat16* lo, size_t idx, float x, float y)
{
    const __nv_bfloat16 hx = __float2bfloat16(x), hy = __float2bfloat16(y);
    *(uint32_t*)&hi[idx] = (uint32_t)__bfloat16_as_ushort(hx) |
                           ((uint32_t)__bfloat16_as_ushort(hy) << 16);
    *(uint32_t*)&lo[idx] = pack_bf2(x - __bfloat162float(hx),
                                    y - __bfloat162float(hy));
}
__device__ __forceinline__ float fexp(float x) { return __expf(x); }

// ---------------------------------------------------------------------------
// Split-conversions
// ---------------------------------------------------------------------------
__global__ __launch_bounds__(256) void conv_split(
    const float4* __restrict__ src, uint2* __restrict__ hi,
    uint2* __restrict__ lo, int n4)
{
    const int i = blockIdx.x * 256 + threadIdx.x;
    if (i >= n4) return;
    const float4 v = src[i];
    split_store((__nv_bfloat16*)hi, (__nv_bfloat16*)lo, (size_t)i * 4,     v.x, v.y);
    split_store((__nv_bfloat16*)hi, (__nv_bfloat16*)lo, (size_t)i * 4 + 2, v.z, v.w);
}

__global__ __launch_bounds__(256) void conv_split_w4(
    const float4* s0, uint2* h0, uint2* l0,
    const float4* s1, uint2* h1, uint2* l1,
    const float4* s2, uint2* h2, uint2* l2,
    const float4* s3, uint2* h3, uint2* l3, int n4)
{
    const int i = blockIdx.x * 256 + threadIdx.x;
    if (i >= n4) return;
    const int w = blockIdx.y;
    const float4* src = (w == 0) ? s0 : (w == 1) ? s1 : (w == 2) ? s2 : s3;
    uint2* hi = (w == 0) ? h0 : (w == 1) ? h1 : (w == 2) ? h2 : h3;
    uint2* lo = (w == 0) ? l0 : (w == 1) ? l1 : (w == 2) ? l2 : l3;
    const float4 v = src[i];
    split_store((__nv_bfloat16*)hi, (__nv_bfloat16*)lo, (size_t)i * 4,     v.x, v.y);
    split_store((__nv_bfloat16*)hi, (__nv_bfloat16*)lo, (size_t)i * 4 + 2, v.z, v.w);
}

// Pack mask (int32 per element) into 1 bit per element.
__global__ __launch_bounds__(256) void conv_maskbits(
    const int4* __restrict__ mask, uint32_t* __restrict__ mbits, int nwords)
{
    const int w = blockIdx.x * 256 + threadIdx.x;
    if (w >= nwords) return;
    const int4* src = mask + (size_t)w * 8;
    uint32_t bits = 0;
#pragma unroll
    for (int j = 0; j < 8; j++) {
        const int4 v = src[j];
        bits |= (v.x != 0 ? 1u : 0u) << (j * 4 + 0);
        bits |= (v.y != 0 ? 1u : 0u) << (j * 4 + 1);
        bits |= (v.z != 0 ? 1u : 0u) << (j * 4 + 2);
        bits |= (v.w != 0 ? 1u : 0u) << (j * 4 + 3);
    }
    mbits[w] = bits;
}

// ---------------------------------------------------------------------------
// Shared GEMM body: 3-term fused K-loop, BK=32, 2-stage pipeline, 2 CTAs/SM.
// smem per CTA: 2 stages * 4 operands * 128 rows * 40 bf16 = 80 KB.
// ---------------------------------------------------------------------------
#define GP 40
#define GTILE (128 * GP)
#define GEMM_SMEM (2 * 4 * GTILE * 2)          // 81920 bytes

__device__ __forceinline__ void gemm_body(
    const __nv_bfloat16* __restrict__ Ahi, const __nv_bfloat16* __restrict__ Alo,
    const __nv_bfloat16* __restrict__ Bhi, const __nv_bfloat16* __restrict__ Blo,
    const float* __restrict__ bias, float* __restrict__ C,
    __nv_bfloat16* __restrict__ Chi, __nv_bfloat16* __restrict__ Clo,
    int M, int N, int K, int bm, int bn, uint32_t sb)
{
    const int tid  = threadIdx.x;
    const int lane = tid & 31, wid = tid >> 5;
    const int warp_m = wid >> 2, warp_n = wid & 3;

    const int a_r = warp_m * 64 + (lane & 15);
    const int a_c = (lane >> 4) * 8;
    const int b4_row = ((lane >> 4) & 1) * 8 + (lane & 7);
    const int b4_col = ((lane >> 3) & 1) * 8;

    const int lrow = tid >> 2;          // 0..63
    const int lc8  = (tid & 3) * 8;     // bf16 col within 32-wide chunk

    float acc[4][4][4];
#pragma unroll
    for (int mt = 0; mt < 4; mt++)
#pragma unroll
        for (int nt = 0; nt < 4; nt++)
#pragma unroll
            for (int r = 0; r < 4; r++) acc[mt][nt][r] = 0.f;

#define TBASE(s, o) (sb + (uint32_t)(((s) * 4 + (o)) * GTILE) * 2)
#define LOAD_STAGE(s, k0) do {                                                \
    const uint32_t _dAh = TBASE(s, 0), _dAl = TBASE(s, 1);                    \
    const uint32_t _dBh = TBASE(s, 2), _dBl = TBASE(s, 3);                    \
    _Pragma("unroll")                                                         \
    for (int rr = 0; rr < 2; rr++) {                                          \
        const int row = lrow + rr * 64;                                       \
        const uint32_t so = (uint32_t)(row * GP + lc8) * 2;                   \
        const size_t ga = (size_t)(bm + row) * K + (k0) + lc8;                \
        const size_t gb = (size_t)(bn + row) * K + (k0) + lc8;                \
        cpasync16(_dAh + so, &Ahi[ga]);                                       \
        cpasync16(_dAl + so, &Alo[ga]);                                       \
        cpasync16(_dBh + so, &Bhi[gb]);                                       \
        cpasync16(_dBl + so, &Blo[gb]);                                       \
    }                                                                         \
    CP_COMMIT();                                                              \
} while (0)

    LOAD_STAGE(0, 0);

    const int NK = K / 32;
    for (int kc = 0; kc < NK; kc++) {
        const int cur = kc & 1;
        if (kc + 1 < NK) { LOAD_STAGE(cur ^ 1, (kc + 1) * 32); CP_WAIT1(); }
        else             { CP_WAIT0(); }
        __syncthreads();

        const uint32_t uAh = TBASE(cur, 0), uAl = TBASE(cur, 1);
        const uint32_t uBh = TBASE(cur, 2), uBl = TBASE(cur, 3);
#pragma unroll
        for (int ks = 0; ks < 2; ks++) {
            uint32_t ah[4][4], al[4][4];
#pragma unroll
            for (int mt = 0; mt < 4; mt++) {
                const uint32_t ao = (uint32_t)((a_r + mt * 16) * GP +
                                               ks * 16 + a_c) * 2;
                ldmA4(ah[mt], uAh + ao);
                ldmA4(al[mt], uAl + ao);
            }
            uint32_t bh[4][2], bl[4][2];
#pragma unroll
            for (int p = 0; p < 2; p++) {
                uint32_t r4[4];
                const uint32_t bo = (uint32_t)((warp_n * 32 + p * 16 + b4_row) * GP +
                                               ks * 16 + b4_col) * 2;
                ldmA4(r4, uBh + bo);
                bh[2*p][0] = r4[0]; bh[2*p][1] = r4[1];
                bh[2*p+1][0] = r4[2]; bh[2*p+1][1] = r4[3];
                ldmA4(r4, uBl + bo);
                bl[2*p][0] = r4[0]; bl[2*p][1] = r4[1];
                bl[2*p+1][0] = r4[2]; bl[2*p+1][1] = r4[3];
            }
#pragma unroll
            for (int mt = 0; mt < 4; mt++)
#pragma unroll
                for (int nt = 0; nt < 4; nt++) {
                    mma16816(acc[mt][nt], ah[mt], bh[nt]);
                    mma16816(acc[mt][nt], ah[mt], bl[nt]);
                    mma16816(acc[mt][nt], al[mt], bh[nt]);
                }
        }
        __syncthreads();
    }

    const int em = bm + warp_m * 64 + (lane >> 2);
    const int en = bn + warp_n * 32 + (lane & 3) * 2;
#pragma unroll
    for (int mt = 0; mt < 4; mt++) {
#pragma unroll
        for (int nt = 0; nt < 4; nt++) {
            const int n = en + nt * 8;
            const float bx = bias[n], by = bias[n + 1];
            const int m0 = em + mt * 16;
            float2 o0, o1;
            o0.x = acc[mt][nt][0] + bx; o0.y = acc[mt][nt][1] + by;
            o1.x = acc[mt][nt][2] + bx; o1.y = acc[mt][nt][3] + by;
            if (C) {
                *(float2*)&C[(size_t)m0 * N + n]       = o0;
                *(float2*)&C[(size_t)(m0 + 8) * N + n] = o1;
            }
            if (Chi) {
                split_store(Chi, Clo, (size_t)m0 * N + n,       o0.x, o0.y);
                split_store(Chi, Clo, (size_t)(m0 + 8) * N + n, o1.x, o1.y);
            }
        }
    }
#undef LOAD_STAGE
#undef TBASE
}

__global__ __launch_bounds__(256, 2) void gemm_qkv(
    const __nv_bfloat16* __restrict__ Ahi, const __nv_bfloat16* __restrict__ Alo,
    const __nv_bfloat16* bq_h, const __nv_bfloat16* bq_l,
    const __nv_bfloat16* bk_h, const __nv_bfloat16* bk_l,
    const __nv_bfloat16* bv_h, const __nv_bfloat16* bv_l,
    const float* biq, const float* bik, const float* biv,
    __nv_bfloat16* qh, __nv_bfloat16* ql,
    __nv_bfloat16* kh, __nv_bfloat16* kl,
    __nv_bfloat16* vh, __nv_bfloat16* vl,
    int M, int N, int K)
{
    extern __shared__ __nv_bfloat16 gsm[];
    const int z = blockIdx.z;
    const __nv_bfloat16* Bh = (z == 0) ? bq_h : (z == 1) ? bk_h : bv_h;
    const __nv_bfloat16* Bl = (z == 0) ? bq_l : (z == 1) ? bk_l : bv_l;
    const float* bias = (z == 0) ? biq : (z == 1) ? bik : biv;
    __nv_bfloat16* Ch = (z == 0) ? qh : (z == 1) ? kh : vh;
    __nv_bfloat16* Cl = (z == 0) ? ql : (z == 1) ? kl : vl;
    gemm_body(Ahi, Alo, Bh, Bl, bias, (float*)nullptr, Ch, Cl,
              M, N, K, blockIdx.y * 128, blockIdx.x * 128, smem_u32(gsm));
}

__global__ __launch_bounds__(256, 2) void gemm_out(
    const __nv_bfloat16* __restrict__ Ahi, const __nv_bfloat16* __restrict__ Alo,
    const __nv_bfloat16* __restrict__ Bhi, const __nv_bfloat16* __restrict__ Blo,
    const float* __restrict__ bias, float* __restrict__ C,
    int M, int N, int K)
{
    extern __shared__ __nv_bfloat16 gsm[];
    gemm_body(Ahi, Alo, Bhi, Blo, bias, C,
              (__nv_bfloat16*)nullptr, (__nv_bfloat16*)nullptr,
              M, N, K, blockIdx.y * 128, blockIdx.x * 128, smem_u32(gsm));
}

// ---------------------------------------------------------------------------
// Tensor-core flash attention with bit-packed mask (unchanged from R11):
//   k-tile 64, Q resident, K/V 2-stage cp.async pipeline, <=128 regs, 2 CTAs/SM.
// ---------------------------------------------------------------------------
#define FP 72
#define KVT (64 * FP)
#define FLASH_SMEM ((2 * 128 * FP + 2 * 4 * KVT) * 2)    // 110592 bytes

__global__ __launch_bounds__(256, 2) void flash_mma_kernel(
    const __nv_bfloat16* __restrict__ qhi, const __nv_bfloat16* __restrict__ qlo,
    const __nv_bfloat16* __restrict__ khi, const __nv_bfloat16* __restrict__ klo,
    const __nv_bfloat16* __restrict__ vhi, const __nv_bfloat16* __restrict__ vlo,
    const uint32_t* __restrict__ mbits, float* __restrict__ Praw,
    float* __restrict__ mkt, float* __restrict__ stats,
    __nv_bfloat16* __restrict__ chi, __nv_bfloat16* __restrict__ clo)
{
    extern __shared__ __nv_bfloat16 smb[];
    __nv_bfloat16* sQh = smb;
    __nv_bfloat16* sQl = sQh + 128 * FP;
    __nv_bfloat16* sKV = sQl + 128 * FP;

    const int t = threadIdx.x, lane = t & 31, warp = t >> 5;
    const int bh = blockIdx.y;
    const int b = bh >> 4, h = bh & 15;
    const int q0 = blockIdx.x * 128;

    const uint32_t uQh = smem_u32(sQh), uQl = smem_u32(sQl);
    const uint32_t uKV = smem_u32(sKV);
#define KVB(s, o) (uKV + (uint32_t)(((s) * 4 + (o)) * KVT) * 2)

    for (int i = t; i < 1024; i += 256) {
        const int row = i >> 3, c8 = (i & 7) * 8;
        const size_t g = (size_t)(b * S_ + q0 + row) * D_ + h * 64 + c8;
        const uint32_t so = (uint32_t)(row * FP + c8) * 2;
        cpasync16(uQh + so, &qhi[g]);
        cpasync16(uQl + so, &qlo[g]);
    }

    const int kv_row = t >> 3;
    const int kv_c8  = (t & 7) * 8;
#define LOAD_KV(stage, k0) do {                                               \
    _Pragma("unroll")                                                         \
    for (int rr = 0; rr < 2; rr++) {                                          \
        const int row = kv_row + rr * 32;                                     \
        const size_t g = (size_t)(b * S_ + (k0) + row) * D_ + h * 64 + kv_c8; \
        const uint32_t so = (uint32_t)(row * FP + kv_c8) * 2;                 \
        cpasync16(KVB(stage, 0) + so, &khi[g]);                               \
        cpasync16(KVB(stage, 1) + so, &klo[g]);                               \
        cpasync16(KVB(stage, 2) + so, &vhi[g]);                               \
        cpasync16(KVB(stage, 3) + so, &vlo[g]);                               \
    }                                                                         \
    CP_COMMIT();                                                              \
} while (0)

    LOAD_KV(0, 0);

    float O[8][4];
#pragma unroll
    for (int j = 0; j < 8; j++)
#pragma unroll
        for (int r = 0; r < 4; r++) O[j][r] = 0.f;
    float mr0 = -1e30f, mr1 = -1e30f, lr0 = 0.f, lr1 = 0.f;

    const int row0 = q0 + warp * 16 + (lane >> 2);
    const int row1 = row0 + 8;
    const int col0 = (lane & 3) * 2;
    const int a_r  = warp * 16 + (lane & 15);
    const int a_c  = (lane >> 4) * 8;
    const int b4_row = ((lane >> 4) & 1) * 8 + (lane & 7);
    const int b4_col = ((lane >> 3) & 1) * 8;
    const int t4_row = ((lane >> 3) & 1) * 8 + (lane & 7);
    const int t4_sel = ((lane >> 4) & 1) * 8;

    const uint32_t* mrow0 = &mbits[((size_t)b * S_ + row0) * SW_];
    const uint32_t* mrow1 = &mbits[((size_t)b * S_ + row1) * SW_];

    const int NT = S_ / 64;
    for (int kt = 0; kt < NT; kt++) {
        const int k0 = kt * 64;
        const int cur = kt & 1;
        CP_WAIT0();
        __syncthreads();
        if (kt + 1 < NT) LOAD_KV(cur ^ 1, (kt + 1) * 64);

        const uint32_t uKh = KVB(cur, 0), uKl = KVB(cur, 1);
        const uint32_t uVh = KVB(cur, 2), uVl = KVB(cur, 3);

        // --- QK^T: c[8][4] over 64 k-cols ---
        float c[8][4];
#pragma unroll
        for (int nt = 0; nt < 8; nt++)
#pragma unroll
            for (int r = 0; r < 4; r++) c[nt][r] = 0.f;
#pragma unroll
        for (int ks = 0; ks < 4; ks++) {
            uint32_t qh2[4], ql2[4];
            const uint32_t qo = (uint32_t)(a_r * FP + ks * 16 + a_c) * 2;
            ldmA4(qh2, uQh + qo);
            ldmA4(ql2, uQl + qo);
#pragma unroll
            for (int p = 0; p < 4; p++) {
                uint32_t rh[4], rl[4];
                const uint32_t off = (uint32_t)((p * 16 + b4_row) * FP +
                                                ks * 16 + b4_col) * 2;
                ldmA4(rh, uKh + off);
                ldmA4(rl, uKl + off);
                mma16816(c[2*p],   qh2, rh);
                mma16816(c[2*p],   qh2, rl);
                mma16816(c[2*p],   ql2, rh);
                mma16816(c[2*p+1], qh2, rh + 2);
                mma16816(c[2*p+1], qh2, rl + 2);
                mma16816(c[2*p+1], ql2, rh + 2);
            }
        }

        // --- scale + mask (bit-packed) ---
        {
            const uint2 mw0 = *(const uint2*)&mrow0[k0 >> 5];
            const uint2 mw1 = *(const uint2*)&mrow1[k0 >> 5];
#pragma unroll
            for (int nt = 0; nt < 8; nt++) {
                const int cb = ((nt & 3) * 8 + col0);
                const uint32_t w0 = (nt < 4) ? mw0.x : mw0.y;
                const uint32_t w1 = (nt < 4) ? mw1.x : mw1.y;
                c[nt][0] = ((w0 >> cb) & 1u)       ? c[nt][0] * SCALE_ : -1e9f;
                c[nt][1] = ((w0 >> (cb + 1)) & 1u) ? c[nt][1] * SCALE_ : -1e9f;
                c[nt][2] = ((w1 >> cb) & 1u)       ? c[nt][2] * SCALE_ : -1e9f;
                c[nt][3] = ((w1 >> (cb + 1)) & 1u) ? c[nt][3] * SCALE_ : -1e9f;
            }
        }

        // --- online softmax ---
        float rm0 = -1e30f, rm1 = -1e30f;
#pragma unroll
        for (int nt = 0; nt < 8; nt++) {
            rm0 = fmaxf(rm0, fmaxf(c[nt][0], c[nt][1]));
            rm1 = fmaxf(rm1, fmaxf(c[nt][2], c[nt][3]));
        }
        rm0 = fmaxf(rm0, __shfl_xor_sync(0xffffffffu, rm0, 1));
        rm0 = fmaxf(rm0, __shfl_xor_sync(0xffffffffu, rm0, 2));
        rm1 = fmaxf(rm1, __shfl_xor_sync(0xffffffffu, rm1, 1));
        rm1 = fmaxf(rm1, __shfl_xor_sync(0xffffffffu, rm1, 2));
        const float mn0 = fmaxf(mr0, rm0), mn1 = fmaxf(mr1, rm1);
        const float f0 = fexp(mr0 - mn0), f1 = fexp(mr1 - mn1);
        float rs0 = 0.f, rs1 = 0.f;
#pragma unroll
        for (int nt = 0; nt < 8; nt++) {
            c[nt][0] = fexp(c[nt][0] - mn0);
            c[nt][1] = fexp(c[nt][1] - mn0);
            c[nt][2] = fexp(c[nt][2] - mn1);
            c[nt][3] = fexp(c[nt][3] - mn1);
            rs0 += c[nt][0] + c[nt][1];
            rs1 += c[nt][2] + c[nt][3];
        }
        rs0 += __shfl_xor_sync(0xffffffffu, rs0, 1);
        rs0 += __shfl_xor_sync(0xffffffffu, rs0, 2);
        rs1 += __shfl_xor_sync(0xffffffffu, rs1, 1);
        rs1 += __shfl_xor_sync(0xffffffffu, rs1, 2);
        lr0 = lr0 * f0 + rs0; mr0 = mn0;
        lr1 = lr1 * f1 + rs1; mr1 = mn1;
#pragma unroll
        for (int j = 0; j < 8; j++) {
            O[j][0] *= f0; O[j][1] *= f0;
            O[j][2] *= f1; O[j][3] *= f1;
        }

        // --- stream P + m_kt ---
        {
            const size_t gb0 = ((size_t)bh * S_ + row0) * S_ + k0 + col0;
            const size_t gb1 = ((size_t)bh * S_ + row1) * S_ + k0 + col0;
#pragma unroll
            for (int nt = 0; nt < 8; nt++) {
                float2 w0, w1;
                w0.x = c[nt][0]; w0.y = c[nt][1];
                w1.x = c[nt][2]; w1.y = c[nt][3];
                *(float2*)&Praw[gb0 + nt * 8] = w0;
                *(float2*)&Praw[gb1 + nt * 8] = w1;
            }
            if ((lane & 3) == 0) {
                mkt[((size_t)bh * 32 + kt) * S_ + row0] = mn0;
                mkt[((size_t)bh * 32 + kt) * S_ + row1] = mn1;
            }
        }

        // --- P @ V (truncation-split fragments) ---
#pragma unroll
        for (int ks2 = 0; ks2 < 4; ks2++) {
            const float* c0 = c[2 * ks2];
            const float* c1 = c[2 * ks2 + 1];
            uint32_t ah[4], al[4];
            ah[0] = TRUNC_HI2(c0[0], c0[1]);
            ah[1] = TRUNC_HI2(c0[2], c0[3]);
            ah[2] = TRUNC_HI2(c1[0], c1[1]);
            ah[3] = TRUNC_HI2(c1[2], c1[3]);
            al[0] = TRUNC_HI2(trunc_res(c0[0]), trunc_res(c0[1]));
            al[1] = TRUNC_HI2(trunc_res(c0[2]), trunc_res(c0[3]));
            al[2] = TRUNC_HI2(trunc_res(c1[0]), trunc_res(c1[1]));
            al[3] = TRUNC_HI2(trunc_res(c1[2]), trunc_res(c1[3]));
#pragma unroll
            for (int p = 0; p < 4; p++) {
                uint32_t vh4[4], vl4[4];
                const uint32_t off = (uint32_t)((ks2 * 16 + t4_row) * FP +
                                                p * 16 + t4_sel) * 2;
                ldmA4t(vh4, uVh + off);
                ldmA4t(vl4, uVl + off);
                mma16816(O[2*p],   ah, vh4);
                mma16816(O[2*p],   ah, vl4);
                mma16816(O[2*p],   al, vh4);
                mma16816(O[2*p+1], ah, vh4 + 2);
                mma16816(O[2*p+1], ah, vl4 + 2);
                mma16816(O[2*p+1], al, vh4 + 2);
            }
        }
    }

    // --- epilogue: normalized ctx as bf16 hi/lo ---
    const float inv0 = 1.0f / lr0, inv1 = 1.0f / lr1;
#pragma unroll
    for (int nt2 = 0; nt2 < 8; nt2++) {
        const int n = nt2 * 8 + col0;
        const size_t g0 = (size_t)(b * S_ + row0) * D_ + h * 64 + n;
        const size_t g1 = (size_t)(b * S_ + row1) * D_ + h * 64 + n;
        split_store(chi, clo, g0, O[nt2][0] * inv0, O[nt2][1] * inv0);
        split_store(chi, clo, g1, O[nt2][2] * inv1, O[nt2][3] * inv1);
    }
    if ((lane & 3) == 0) {
        size_t si = ((size_t)bh * S_ + row0) * 2;
        stats[si] = mr0; stats[si + 1] = lr0;
        si = ((size_t)bh * S_ + row1) * 2;
        stats[si] = mr1; stats[si + 1] = lr1;
    }
#undef LOAD_KV
#undef KVB
}

// ---------------------------------------------------------------------------
// Pass 2: attn = P * exp(m_kt - m_final) / l_final  (pure memory; 64-col kts)
// ---------------------------------------------------------------------------
__global__ __launch_bounds__(256) void normalize_kernel(
    const float* __restrict__ P, const float* __restrict__ mkt,
    const float* __restrict__ stats, float* __restrict__ attn)
{
    __shared__ float corr[32];
    const int t   = threadIdx.x;
    const int row = blockIdx.x;
    const int bh  = blockIdx.y;

    const size_t si = ((size_t)bh * S_ + row) * 2;
    const float m_f = stats[si];
    const float inv_l = 1.0f / stats[si + 1];
    if (t < 32)
        corr[t] = __expf(mkt[((size_t)bh * 32 + t) * S_ + row] - m_f) * inv_l;
    __syncthreads();

    const size_t base = ((size_t)bh * S_ + row) * S_;
    const float c = corr[t >> 3];
    float4 v0 = *(const float4*)&P[base + t * 8];
    float4 v1 = *(const float4*)&P[base + t * 8 + 4];
    v0.x *= c; v0.y *= c; v0.z *= c; v0.w *= c;
    v1.x *= c; v1.y *= c; v1.z *= c; v1.w *= c;
    *(float4*)&attn[base + t * 8]     = v0;
    *(float4*)&attn[base + t * 8 + 4] = v1;
}

// ---------------------------------------------------------------------------
extern "C" void kernel_launch(void* const* d_in, const int* in_sizes, int n_in,
                              void* d_out, int out_size)
{
    const float* x    = (const float*)d_in[0];
    const int*   mask = (const int*)  d_in[1];
    const float* wq_w = (const float*)d_in[2];
    const float* wq_b = (const float*)d_in[3];
    const float* wk_w = (const float*)d_in[4];
    const float* wk_b = (const float*)d_in[5];
    const float* wv_w = (const float*)d_in[6];
    const float* wv_b = (const float*)d_in[7];
    const float* wo_w = (const float*)d_in[8];
    const float* wo_b = (const float*)d_in[9];

    float *qdump, *attn_raw, *mkt, *stats;
    uint32_t* mbits;
    cudaGetSymbolAddress((void**)&qdump,    g_q);
    cudaGetSymbolAddress((void**)&attn_raw, g_attn_raw);
    cudaGetSymbolAddress((void**)&mkt,      g_mkt);
    cudaGetSymbolAddress((void**)&stats,    g_stats);
    cudaGetSymbolAddress((void**)&mbits,    g_mbits);

    __nv_bfloat16 *xhi, *xlo, *chi, *clo;
    __nv_bfloat16 *qhi_p, *qlo_p, *khi_p, *klo_p, *vhi_p, *vlo_p;
    __nv_bfloat16 *wqhi, *wqlo, *wkhi, *wklo, *wvhi, *wvlo, *wohi, *wolo;
    cudaGetSymbolAddress((void**)&xhi, g_xhi);   cudaGetSymbolAddress((void**)&xlo, g_xlo);
    cudaGetSymbolAddress((void**)&chi, g_chi);   cudaGetSymbolAddress((void**)&clo, g_clo);
    cudaGetSymbolAddress((void**)&qhi_p, g_qhi); cudaGetSymbolAddress((void**)&qlo_p, g_qlo);
    cudaGetSymbolAddress((void**)&khi_p, g_khi); cudaGetSymbolAddress((void**)&klo_p, g_klo);
    cudaGetSymbolAddress((void**)&vhi_p, g_vhi); cudaGetSymbolAddress((void**)&vlo_p, g_vlo);
    cudaGetSymbolAddress((void**)&wqhi, g_wqhi); cudaGetSymbolAddress((void**)&wqlo, g_wqlo);
    cudaGetSymbolAddress((void**)&wkhi, g_wkhi); cudaGetSymbolAddress((void**)&wklo, g_wklo);
    cudaGetSymbolAddress((void**)&wvhi, g_wvhi); cudaGetSymbolAddress((void**)&wvlo, g_wvlo);
    cudaGetSymbolAddress((void**)&wohi, g_wohi); cudaGetSymbolAddress((void**)&wolo, g_wolo);

    const long long CTXSZ = (long long)B_ * S_ * D_;
    const long long ATTSZ = (long long)B_ * H_ * S_ * S_;

    float* out_base = (float*)d_out;
    float* out_ptr;
    float* attn_ptr;
    if ((long long)out_size >= CTXSZ + ATTSZ) {
        out_ptr  = out_base;
        attn_ptr = out_base + CTXSZ;
    } else if ((long long)out_size == ATTSZ) {
        out_ptr  = qdump;
        attn_ptr = out_base;
    } else {
        out_ptr  = out_base;
        attn_ptr = attn_raw;
    }

    cudaFuncSetAttribute(flash_mma_kernel,
                         cudaFuncAttributeMaxDynamicSharedMemorySize, FLASH_SMEM);
    cudaFuncSetAttribute(gemm_qkv,
                         cudaFuncAttributeMaxDynamicSharedMemorySize, GEMM_SMEM);
    cudaFuncSetAttribute(gemm_out,
                         cudaFuncAttributeMaxDynamicSharedMemorySize, GEMM_SMEM);

    const int M = B_ * S_;   // 4096
    const int N = D_;        // 1024
    const int K = D_;        // 1024

    const int xn4 = (int)(CTXSZ / 4);
    const int wn4 = D_ * D_ / 4;
    conv_split<<<(xn4 + 255) / 256, 256>>>((const float4*)x, (uint2*)xhi, (uint2*)xlo, xn4);
    dim3 wGrid((wn4 + 255) / 256, 4);
    conv_split_w4<<<wGrid, 256>>>(
        (const float4*)wq_w, (uint2*)wqhi, (uint2*)wqlo,
        (const float4*)wk_w, (uint2*)wkhi, (uint2*)wklo,
        (const float4*)wv_w, (uint2*)wvhi, (uint2*)wvlo,
        (const float4*)wo_w, (uint2*)wohi, (uint2*)wolo, wn4);

    const int nwords = B_ * S_ * SW_;
    conv_maskbits<<<(nwords + 255) / 256, 256>>>((const int4*)mask, mbits, nwords);

    dim3 qkvGrid(N / 128, M / 128, 3);
    gemm_qkv<<<qkvGrid, 256, GEMM_SMEM>>>(
        xhi, xlo,
        wqhi, wqlo, wkhi, wklo, wvhi, wvlo,
        wq_b, wk_b, wv_b,
        qhi_p, qlo_p, khi_p, klo_p, vhi_p, vlo_p, M, N, K);

    dim3 fGrid(S_ / 128, B_ * H_);
    flash_mma_kernel<<<fGrid, 256, FLASH_SMEM>>>(
        qhi_p, qlo_p, khi_p, klo_p, vhi_p, vlo_p,
        mbits, attn_raw, mkt, stats, chi, clo);

    dim3 gGrid(N / 128, M / 128);
    gemm_out<<<gGrid, 256, GEMM_SMEM>>>(chi, clo, wohi, wolo, wo_b, out_ptr, M, N, K);

    dim3 nGrid(S_, B_ * H_);
    normalize_kernel<<<nGrid, 256>>>(attn_raw, mkt, stats, attn_ptr);
}

// round 13
// speedup vs baseline: 2.5239x; 1.0052x over previous
#include <cuda_runtime.h>
#include <cuda_bf16.h>
#include <math.h>
#include <stdint.h>

// Problem constants
#define B_  2
#define S_  2048
#define D_  1024
#define H_  16
#define DH_ 64
#define SCALE_ 0.125f   // DH^-0.5
#define SW_ (S_ / 32)   // mask words per row

typedef unsigned long long u64;

// ---------------------------------------------------------------------------
// Scratch (static device globals; no runtime allocation)
// ---------------------------------------------------------------------------
__device__ float g_q[(size_t)B_ * S_ * D_];                 // dummy sink
__device__ float g_attn_raw[(size_t)B_ * H_ * S_ * S_];     // P, permuted chunks
__device__ float g_mkt[(size_t)B_ * H_ * (S_ / 64) * S_];
__device__ float g_stats[(size_t)B_ * H_ * S_ * 2];
__device__ uint32_t g_mbits[(size_t)B_ * S_ * SW_];        // bit-packed mask

// bf16 hi/lo split operands
__device__ __nv_bfloat16 g_xhi[(size_t)B_ * S_ * D_];
__device__ __nv_bfloat16 g_xlo[(size_t)B_ * S_ * D_];
__device__ __nv_bfloat16 g_qhi[(size_t)B_ * S_ * D_], g_qlo[(size_t)B_ * S_ * D_];
__device__ __nv_bfloat16 g_khi[(size_t)B_ * S_ * D_], g_klo[(size_t)B_ * S_ * D_];
__device__ __nv_bfloat16 g_vhi[(size_t)B_ * S_ * D_], g_vlo[(size_t)B_ * S_ * D_];
__device__ __nv_bfloat16 g_chi[(size_t)B_ * S_ * D_], g_clo[(size_t)B_ * S_ * D_];
__device__ __nv_bfloat16 g_wqhi[D_ * D_], g_wqlo[D_ * D_];
__device__ __nv_bfloat16 g_wkhi[D_ * D_], g_wklo[D_ * D_];
__device__ __nv_bfloat16 g_wvhi[D_ * D_], g_wvlo[D_ * D_];
__device__ __nv_bfloat16 g_wohi[D_ * D_], g_wolo[D_ * D_];

// ---------------------------------------------------------------------------
// mma.sync / ldmatrix helpers
// ---------------------------------------------------------------------------
__device__ __forceinline__ uint32_t smem_u32(const void* p) {
    uint32_t a;
    asm("{ .reg .u64 t; cvta.to.shared.u64 t, %1; cvt.u32.u64 %0, t; }"
        : "=r"(a) : "l"(p));
    return a;
}
__device__ __forceinline__ void ldmA4(uint32_t* a, uint32_t addr) {
    asm volatile("ldmatrix.sync.aligned.m8n8.x4.shared.b16 {%0,%1,%2,%3}, [%4];"
                 : "=r"(a[0]), "=r"(a[1]), "=r"(a[2]), "=r"(a[3]) : "r"(addr));
}
__device__ __forceinline__ void ldmA4t(uint32_t* a, uint32_t addr) {
    asm volatile("ldmatrix.sync.aligned.m8n8.x4.trans.shared.b16 {%0,%1,%2,%3}, [%4];"
                 : "=r"(a[0]), "=r"(a[1]), "=r"(a[2]), "=r"(a[3]) : "r"(addr));
}
__device__ __forceinline__ void mma16816(float* c, const uint32_t* a,
                                         const uint32_t* b) {
    asm volatile(
        "mma.sync.aligned.m16n8k16.row.col.f32.bf16.bf16.f32 "
        "{%0,%1,%2,%3}, {%4,%5,%6,%7}, {%8,%9}, {%0,%1,%2,%3};"
        : "+f"(c[0]), "+f"(c[1]), "+f"(c[2]), "+f"(c[3])
        : "r"(a[0]), "r"(a[1]), "r"(a[2]), "r"(a[3]), "r"(b[0]), "r"(b[1]));
}
__device__ __forceinline__ void cpasync16(uint32_t saddr, const void* gaddr) {
    asm volatile("cp.async.cg.shared.global [%0], [%1], 16;"
                 :: "r"(saddr), "l"(gaddr));
}
#define CP_COMMIT() asm volatile("cp.async.commit_group;" ::: "memory")
#define CP_WAIT0()  asm volatile("cp.async.wait_group 0;" ::: "memory")
#define CP_WAIT1()  asm volatile("cp.async.wait_group 1;" ::: "memory")

__device__ __forceinline__ uint32_t pack_bf2(float x, float y) {
    return (uint32_t)__bfloat16_as_ushort(__float2bfloat16(x)) |
           ((uint32_t)__bfloat16_as_ushort(__float2bfloat16(y)) << 16);
}
#define TRUNC_HI2(x, y) __byte_perm(__float_as_uint(x), __float_as_uint(y), 0x7632)
__device__ __forceinline__ float trunc_res(float x) {
    return x - __uint_as_float(__float_as_uint(x) & 0xFFFF0000u);
}
__device__ __forceinline__ void split_store(
    __nv_bfloat16* hi, __nv_bfloat16* lo, size_t idx, float x, float y)
{
    const __nv_bfloat16 hx = __float2bfloat16(x), hy = __float2bfloat16(y);
    *(uint32_t*)&hi[idx] = (uint32_t)__bfloat16_as_ushort(hx) |
                           ((uint32_t)__bfloat16_as_ushort(hy) << 16);
    *(uint32_t*)&lo[idx] = pack_bf2(x - __bfloat162float(hx),
                                    y - __bfloat162float(hy));
}
__device__ __forceinline__ float fexp(float x) { return __expf(x); }

// ---------------------------------------------------------------------------
// Split-conversions
// ---------------------------------------------------------------------------
__global__ __launch_bounds__(256) void conv_split(
    const float4* __restrict__ src, uint2* __restrict__ hi,
    uint2* __restrict__ lo, int n4)
{
    const int i = blockIdx.x * 256 + threadIdx.x;
    if (i >= n4) return;
    const float4 v = src[i];
    split_store((__nv_bfloat16*)hi, (__nv_bfloat16*)lo, (size_t)i * 4,     v.x, v.y);
    split_store((__nv_bfloat16*)hi, (__nv_bfloat16*)lo, (size_t)i * 4 + 2, v.z, v.w);
}

__global__ __launch_bounds__(256) void conv_split_w4(
    const float4* s0, uint2* h0, uint2* l0,
    const float4* s1, uint2* h1, uint2* l1,
    const float4* s2, uint2* h2, uint2* l2,
    const float4* s3, uint2* h3, uint2* l3, int n4)
{
    const int i = blockIdx.x * 256 + threadIdx.x;
    if (i >= n4) return;
    const int w = blockIdx.y;
    const float4* src = (w == 0) ? s0 : (w == 1) ? s1 : (w == 2) ? s2 : s3;
    uint2* hi = (w == 0) ? h0 : (w == 1) ? h1 : (w == 2) ? h2 : h3;
    uint2* lo = (w == 0) ? l0 : (w == 1) ? l1 : (w == 2) ? l2 : l3;
    const float4 v = src[i];
    split_store((__nv_bfloat16*)hi, (__nv_bfloat16*)lo, (size_t)i * 4,     v.x, v.y);
    split_store((__nv_bfloat16*)hi, (__nv_bfloat16*)lo, (size_t)i * 4 + 2, v.z, v.w);
}

// Pack mask (int32 per element) into 1 bit per element.
__global__ __launch_bounds__(256) void conv_maskbits(
    const int4* __restrict__ mask, uint32_t* __restrict__ mbits, int nwords)
{
    const int w = blockIdx.x * 256 + threadIdx.x;
    if (w >= nwords) return;
    const int4* src = mask + (size_t)w * 8;
    uint32_t bits = 0;
#pragma unroll
    for (int j = 0; j < 8; j++) {
        const int4 v = src[j];
        bits |= (v.x != 0 ? 1u : 0u) << (j * 4 + 0);
        bits |= (v.y != 0 ? 1u : 0u) << (j * 4 + 1);
        bits |= (v.z != 0 ? 1u : 0u) << (j * 4 + 2);
        bits |= (v.w != 0 ? 1u : 0u) << (j * 4 + 3);
    }
    mbits[w] = bits;
}

// ---------------------------------------------------------------------------
// Shared GEMM body: 3-term fused K-loop, BK=32, 2-stage pipeline, 2 CTAs/SM.
// ---------------------------------------------------------------------------
#define GP 40
#define GTILE (128 * GP)
#define GEMM_SMEM (2 * 4 * GTILE * 2)          // 81920 bytes

__device__ __forceinline__ void gemm_body(
    const __nv_bfloat16* __restrict__ Ahi, const __nv_bfloat16* __restrict__ Alo,
    const __nv_bfloat16* __restrict__ Bhi, const __nv_bfloat16* __restrict__ Blo,
    const float* __restrict__ bias, float* __restrict__ C,
    __nv_bfloat16* __restrict__ Chi, __nv_bfloat16* __restrict__ Clo,
    int M, int N, int K, int bm, int bn, uint32_t sb)
{
    const int tid  = threadIdx.x;
    const int lane = tid & 31, wid = tid >> 5;
    const int warp_m = wid >> 2, warp_n = wid & 3;

    const int a_r = warp_m * 64 + (lane & 15);
    const int a_c = (lane >> 4) * 8;
    const int b4_row = ((lane >> 4) & 1) * 8 + (lane & 7);
    const int b4_col = ((lane >> 3) & 1) * 8;

    const int lrow = tid >> 2;          // 0..63
    const int lc8  = (tid & 3) * 8;

    float acc[4][4][4];
#pragma unroll
    for (int mt = 0; mt < 4; mt++)
#pragma unroll
        for (int nt = 0; nt < 4; nt++)
#pragma unroll
            for (int r = 0; r < 4; r++) acc[mt][nt][r] = 0.f;

#define TBASE(s, o) (sb + (uint32_t)(((s) * 4 + (o)) * GTILE) * 2)
#define LOAD_STAGE(s, k0) do {                                                \
    const uint32_t _dAh = TBASE(s, 0), _dAl = TBASE(s, 1);                    \
    const uint32_t _dBh = TBASE(s, 2), _dBl = TBASE(s, 3);                    \
    _Pragma("unroll")                                                         \
    for (int rr = 0; rr < 2; rr++) {                                          \
        const int row = lrow + rr * 64;                                       \
        const uint32_t so = (uint32_t)(row * GP + lc8) * 2;                   \
        const size_t ga = (size_t)(bm + row) * K + (k0) + lc8;                \
        const size_t gb = (size_t)(bn + row) * K + (k0) + lc8;                \
        cpasync16(_dAh + so, &Ahi[ga]);                                       \
        cpasync16(_dAl + so, &Alo[ga]);                                       \
        cpasync16(_dBh + so, &Bhi[gb]);                                       \
        cpasync16(_dBl + so, &Blo[gb]);                                       \
    }                                                                         \
    CP_COMMIT();                                                              \
} while (0)

    LOAD_STAGE(0, 0);

    const int NK = K / 32;
    for (int kc = 0; kc < NK; kc++) {
        const int cur = kc & 1;
        if (kc + 1 < NK) { LOAD_STAGE(cur ^ 1, (kc + 1) * 32); CP_WAIT1(); }
        else             { CP_WAIT0(); }
        __syncthreads();

        const uint32_t uAh = TBASE(cur, 0), uAl = TBASE(cur, 1);
        const uint32_t uBh = TBASE(cur, 2), uBl = TBASE(cur, 3);
#pragma unroll
        for (int ks = 0; ks < 2; ks++) {
            uint32_t ah[4][4], al[4][4];
#pragma unroll
            for (int mt = 0; mt < 4; mt++) {
                const uint32_t ao = (uint32_t)((a_r + mt * 16) * GP +
                                               ks * 16 + a_c) * 2;
                ldmA4(ah[mt], uAh + ao);
                ldmA4(al[mt], uAl + ao);
            }
            uint32_t bh[4][2], bl[4][2];
#pragma unroll
            for (int p = 0; p < 2; p++) {
                uint32_t r4[4];
                const uint32_t bo = (uint32_t)((warp_n * 32 + p * 16 + b4_row) * GP +
                                               ks * 16 + b4_col) * 2;
                ldmA4(r4, uBh + bo);
                bh[2*p][0] = r4[0]; bh[2*p][1] = r4[1];
                bh[2*p+1][0] = r4[2]; bh[2*p+1][1] = r4[3];
                ldmA4(r4, uBl + bo);
                bl[2*p][0] = r4[0]; bl[2*p][1] = r4[1];
                bl[2*p+1][0] = r4[2]; bl[2*p+1][1] = r4[3];
            }
#pragma unroll
            for (int mt = 0; mt < 4; mt++)
#pragma unroll
                for (int nt = 0; nt < 4; nt++) {
                    mma16816(acc[mt][nt], ah[mt], bh[nt]);
                    mma16816(acc[mt][nt], ah[mt], bl[nt]);
                    mma16816(acc[mt][nt], al[mt], bh[nt]);
                }
        }
        __syncthreads();
    }

    const int em = bm + warp_m * 64 + (lane >> 2);
    const int en = bn + warp_n * 32 + (lane & 3) * 2;
#pragma unroll
    for (int mt = 0; mt < 4; mt++) {
#pragma unroll
        for (int nt = 0; nt < 4; nt++) {
            const int n = en + nt * 8;
            const float bx = bias[n], by = bias[n + 1];
            const int m0 = em + mt * 16;
            float2 o0, o1;
            o0.x = acc[mt][nt][0] + bx; o0.y = acc[mt][nt][1] + by;
            o1.x = acc[mt][nt][2] + bx; o1.y = acc[mt][nt][3] + by;
            if (C) {
                *(float2*)&C[(size_t)m0 * N + n]       = o0;
                *(float2*)&C[(size_t)(m0 + 8) * N + n] = o1;
            }
            if (Chi) {
                split_store(Chi, Clo, (size_t)m0 * N + n,       o0.x, o0.y);
                split_store(Chi, Clo, (size_t)(m0 + 8) * N + n, o1.x, o1.y);
            }
        }
    }
#undef LOAD_STAGE
#undef TBASE
}

__global__ __launch_bounds__(256, 2) void gemm_qkv(
    const __nv_bfloat16* __restrict__ Ahi, const __nv_bfloat16* __restrict__ Alo,
    const __nv_bfloat16* bq_h, const __nv_bfloat16* bq_l,
    const __nv_bfloat16* bk_h, const __nv_bfloat16* bk_l,
    const __nv_bfloat16* bv_h, const __nv_bfloat16* bv_l,
    const float* biq, const float* bik, const float* biv,
    __nv_bfloat16* qh, __nv_bfloat16* ql,
    __nv_bfloat16* kh, __nv_bfloat16* kl,
    __nv_bfloat16* vh, __nv_bfloat16* vl,
    int M, int N, int K)
{
    extern __shared__ __nv_bfloat16 gsm[];
    const int z = blockIdx.z;
    const __nv_bfloat16* Bh = (z == 0) ? bq_h : (z == 1) ? bk_h : bv_h;
    const __nv_bfloat16* Bl = (z == 0) ? bq_l : (z == 1) ? bk_l : bv_l;
    const float* bias = (z == 0) ? biq : (z == 1) ? bik : biv;
    __nv_bfloat16* Ch = (z == 0) ? qh : (z == 1) ? kh : vh;
    __nv_bfloat16* Cl = (z == 0) ? ql : (z == 1) ? kl : vl;
    gemm_body(Ahi, Alo, Bh, Bl, bias, (float*)nullptr, Ch, Cl,
              M, N, K, blockIdx.y * 128, blockIdx.x * 128, smem_u32(gsm));
}

__global__ __launch_bounds__(256, 2) void gemm_out(
    const __nv_bfloat16* __restrict__ Ahi, const __nv_bfloat16* __restrict__ Alo,
    const __nv_bfloat16* __restrict__ Bhi, const __nv_bfloat16* __restrict__ Blo,
    const float* __restrict__ bias, float* __restrict__ C,
    int M, int N, int K)
{
    extern __shared__ __nv_bfloat16 gsm[];
    gemm_body(Ahi, Alo, Bhi, Blo, bias, C,
              (__nv_bfloat16*)nullptr, (__nv_bfloat16*)nullptr,
              M, N, K, blockIdx.y * 128, blockIdx.x * 128, smem_u32(gsm));
}

// ---------------------------------------------------------------------------
// Tensor-core flash attention with bit-packed mask + permuted P stores:
//   P chunk layout per (bh, qt, kt): [warp][s(16)][lane][2]  (8192 floats)
//   -> each warp P-store writes 256 contiguous bytes (2 wavefronts vs 8).
// ---------------------------------------------------------------------------
#define FP 72
#define KVT (64 * FP)
#define FLASH_SMEM ((2 * 128 * FP + 2 * 4 * KVT) * 2)    // 110592 bytes

__global__ __launch_bounds__(256, 2) void flash_mma_kernel(
    const __nv_bfloat16* __restrict__ qhi, const __nv_bfloat16* __restrict__ qlo,
    const __nv_bfloat16* __restrict__ khi, const __nv_bfloat16* __restrict__ klo,
    const __nv_bfloat16* __restrict__ vhi, const __nv_bfloat16* __restrict__ vlo,
    const uint32_t* __restrict__ mbits, float* __restrict__ Praw,
    float* __restrict__ mkt, float* __restrict__ stats,
    __nv_bfloat16* __restrict__ chi, __nv_bfloat16* __restrict__ clo)
{
    extern __shared__ __nv_bfloat16 smb[];
    __nv_bfloat16* sQh = smb;
    __nv_bfloat16* sQl = sQh + 128 * FP;
    __nv_bfloat16* sKV = sQl + 128 * FP;

    const int t = threadIdx.x, lane = t & 31, warp = t >> 5;
    const int bh = blockIdx.y;
    const int b = bh >> 4, h = bh & 15;
    const int q0 = blockIdx.x * 128;

    const uint32_t uQh = smem_u32(sQh), uQl = smem_u32(sQl);
    const uint32_t uKV = smem_u32(sKV);
#define KVB(s, o) (uKV + (uint32_t)(((s) * 4 + (o)) * KVT) * 2)

    for (int i = t; i < 1024; i += 256) {
        const int row = i >> 3, c8 = (i & 7) * 8;
        const size_t g = (size_t)(b * S_ + q0 + row) * D_ + h * 64 + c8;
        const uint32_t so = (uint32_t)(row * FP + c8) * 2;
        cpasync16(uQh + so, &qhi[g]);
        cpasync16(uQl + so, &qlo[g]);
    }

    const int kv_row = t >> 3;
    const int kv_c8  = (t & 7) * 8;
#define LOAD_KV(stage, k0) do {                                               \
    _Pragma("unroll")                                                         \
    for (int rr = 0; rr < 2; rr++) {                                          \
        const int row = kv_row + rr * 32;                                     \
        const size_t g = (size_t)(b * S_ + (k0) + row) * D_ + h * 64 + kv_c8; \
        const uint32_t so = (uint32_t)(row * FP + kv_c8) * 2;                 \
        cpasync16(KVB(stage, 0) + so, &khi[g]);                               \
        cpasync16(KVB(stage, 1) + so, &klo[g]);                               \
        cpasync16(KVB(stage, 2) + so, &vhi[g]);                               \
        cpasync16(KVB(stage, 3) + so, &vlo[g]);                               \
    }                                                                         \
    CP_COMMIT();                                                              \
} while (0)

    LOAD_KV(0, 0);

    float O[8][4];
#pragma unroll
    for (int j = 0; j < 8; j++)
#pragma unroll
        for (int r = 0; r < 4; r++) O[j][r] = 0.f;
    float mr0 = -1e30f, mr1 = -1e30f, lr0 = 0.f, lr1 = 0.f;

    const int row0 = q0 + warp * 16 + (lane >> 2);
    const int row1 = row0 + 8;
    const int col0 = (lane & 3) * 2;
    const int a_r  = warp * 16 + (lane & 15);
    const int a_c  = (lane >> 4) * 8;
    const int b4_row = ((lane >> 4) & 1) * 8 + (lane & 7);
    const int b4_col = ((lane >> 3) & 1) * 8;
    const int t4_row = ((lane >> 3) & 1) * 8 + (lane & 7);
    const int t4_sel = ((lane >> 4) & 1) * 8;

    const uint32_t* mrow0 = &mbits[((size_t)b * S_ + row0) * SW_];
    const uint32_t* mrow1 = &mbits[((size_t)b * S_ + row1) * SW_];

    const int NT = S_ / 64;
    for (int kt = 0; kt < NT; kt++) {
        const int k0 = kt * 64;
        const int cur = kt & 1;
        CP_WAIT0();
        __syncthreads();
        if (kt + 1 < NT) LOAD_KV(cur ^ 1, (kt + 1) * 64);

        const uint32_t uKh = KVB(cur, 0), uKl = KVB(cur, 1);
        const uint32_t uVh = KVB(cur, 2), uVl = KVB(cur, 3);

        // --- QK^T: c[8][4] over 64 k-cols ---
        float c[8][4];
#pragma unroll
        for (int nt = 0; nt < 8; nt++)
#pragma unroll
            for (int r = 0; r < 4; r++) c[nt][r] = 0.f;
#pragma unroll
        for (int ks = 0; ks < 4; ks++) {
            uint32_t qh2[4], ql2[4];
            const uint32_t qo = (uint32_t)(a_r * FP + ks * 16 + a_c) * 2;
            ldmA4(qh2, uQh + qo);
            ldmA4(ql2, uQl + qo);
#pragma unroll
            for (int p = 0; p < 4; p++) {
                uint32_t rh[4], rl[4];
                const uint32_t off = (uint32_t)((p * 16 + b4_row) * FP +
                                                ks * 16 + b4_col) * 2;
                ldmA4(rh, uKh + off);
                ldmA4(rl, uKl + off);
                mma16816(c[2*p],   qh2, rh);
                mma16816(c[2*p],   qh2, rl);
                mma16816(c[2*p],   ql2, rh);
                mma16816(c[2*p+1], qh2, rh + 2);
                mma16816(c[2*p+1], qh2, rl + 2);
                mma16816(c[2*p+1], ql2, rh + 2);
            }
        }

        // --- scale + mask (bit-packed) ---
        {
            const uint2 mw0 = *(const uint2*)&mrow0[k0 >> 5];
            const uint2 mw1 = *(const uint2*)&mrow1[k0 >> 5];
#pragma unroll
            for (int nt = 0; nt < 8; nt++) {
                const int cb = ((nt & 3) * 8 + col0);
                const uint32_t w0 = (nt < 4) ? mw0.x : mw0.y;
                const uint32_t w1 = (nt < 4) ? mw1.x : mw1.y;
                c[nt][0] = ((w0 >> cb) & 1u)       ? c[nt][0] * SCALE_ : -1e9f;
                c[nt][1] = ((w0 >> (cb + 1)) & 1u) ? c[nt][1] * SCALE_ : -1e9f;
                c[nt][2] = ((w1 >> cb) & 1u)       ? c[nt][2] * SCALE_ : -1e9f;
                c[nt][3] = ((w1 >> (cb + 1)) & 1u) ? c[nt][3] * SCALE_ : -1e9f;
            }
        }

        // --- online softmax ---
        float rm0 = -1e30f, rm1 = -1e30f;
#pragma unroll
        for (int nt = 0; nt < 8; nt++) {
            rm0 = fmaxf(rm0, fmaxf(c[nt][0], c[nt][1]));
            rm1 = fmaxf(rm1, fmaxf(c[nt][2], c[nt][3]));
        }
        rm0 = fmaxf(rm0, __shfl_xor_sync(0xffffffffu, rm0, 1));
        rm0 = fmaxf(rm0, __shfl_xor_sync(0xffffffffu, rm0, 2));
        rm1 = fmaxf(rm1, __shfl_xor_sync(0xffffffffu, rm1, 1));
        rm1 = fmaxf(rm1, __shfl_xor_sync(0xffffffffu, rm1, 2));
        const float mn0 = fmaxf(mr0, rm0), mn1 = fmaxf(mr1, rm1);
        const float f0 = fexp(mr0 - mn0), f1 = fexp(mr1 - mn1);
        float rs0 = 0.f, rs1 = 0.f;
#pragma unroll
        for (int nt = 0; nt < 8; nt++) {
            c[nt][0] = fexp(c[nt][0] - mn0);
            c[nt][1] = fexp(c[nt][1] - mn0);
            c[nt][2] = fexp(c[nt][2] - mn1);
            c[nt][3] = fexp(c[nt][3] - mn1);
            rs0 += c[nt][0] + c[nt][1];
            rs1 += c[nt][2] + c[nt][3];
        }
        rs0 += __shfl_xor_sync(0xffffffffu, rs0, 1);
        rs0 += __shfl_xor_sync(0xffffffffu, rs0, 2);
        rs1 += __shfl_xor_sync(0xffffffffu, rs1, 1);
        rs1 += __shfl_xor_sync(0xffffffffu, rs1, 2);
        lr0 = lr0 * f0 + rs0; mr0 = mn0;
        lr1 = lr1 * f1 + rs1; mr1 = mn1;
#pragma unroll
        for (int j = 0; j < 8; j++) {
            O[j][0] *= f0; O[j][1] *= f0;
            O[j][2] *= f1; O[j][3] *= f1;
        }

        // --- stream P (permuted, warp-contiguous) + m_kt ---
        {
            // chunk = (bh, qt, kt); within: [warp][s=nt+8*rh][lane][2]
            float* pb = Praw +
                ((((size_t)bh * 16 + (q0 >> 7)) * 32 + kt) * 8192) +
                warp * 1024 + lane * 2;
#pragma unroll
            for (int nt = 0; nt < 8; nt++) {
                float2 w0, w1;
                w0.x = c[nt][0]; w0.y = c[nt][1];
                w1.x = c[nt][2]; w1.y = c[nt][3];
                *(float2*)&pb[nt * 64]       = w0;   // rh=0 rows
                *(float2*)&pb[(nt + 8) * 64] = w1;   // rh=1 rows
            }
            if ((lane & 3) == 0) {
                mkt[((size_t)bh * 32 + kt) * S_ + row0] = mn0;
                mkt[((size_t)bh * 32 + kt) * S_ + row1] = mn1;
            }
        }

        // --- P @ V (truncation-split fragments) ---
#pragma unroll
        for (int ks2 = 0; ks2 < 4; ks2++) {
            const float* c0 = c[2 * ks2];
            const float* c1 = c[2 * ks2 + 1];
            uint32_t ah[4], al[4];
            ah[0] = TRUNC_HI2(c0[0], c0[1]);
            ah[1] = TRUNC_HI2(c0[2], c0[3]);
            ah[2] = TRUNC_HI2(c1[0], c1[1]);
            ah[3] = TRUNC_HI2(c1[2], c1[3]);
            al[0] = TRUNC_HI2(trunc_res(c0[0]), trunc_res(c0[1]));
            al[1] = TRUNC_HI2(trunc_res(c0[2]), trunc_res(c0[3]));
            al[2] = TRUNC_HI2(trunc_res(c1[0]), trunc_res(c1[1]));
            al[3] = TRUNC_HI2(trunc_res(c1[2]), trunc_res(c1[3]));
#pragma unroll
            for (int p = 0; p < 4; p++) {
                uint32_t vh4[4], vl4[4];
                const uint32_t off = (uint32_t)((ks2 * 16 + t4_row) * FP +
                                                p * 16 + t4_sel) * 2;
                ldmA4t(vh4, uVh + off);
                ldmA4t(vl4, uVl + off);
                mma16816(O[2*p],   ah, vh4);
                mma16816(O[2*p],   ah, vl4);
                mma16816(O[2*p],   al, vh4);
                mma16816(O[2*p+1], ah, vh4 + 2);
                mma16816(O[2*p+1], ah, vl4 + 2);
                mma16816(O[2*p+1], al, vh4 + 2);
            }
        }
    }

    // --- epilogue: normalized ctx as bf16 hi/lo ---
    const float inv0 = 1.0f / lr0, inv1 = 1.0f / lr1;
#pragma unroll
    for (int nt2 = 0; nt2 < 8; nt2++) {
        const int n = nt2 * 8 + col0;
        const size_t g0 = (size_t)(b * S_ + row0) * D_ + h * 64 + n;
        const size_t g1 = (size_t)(b * S_ + row1) * D_ + h * 64 + n;
        split_store(chi, clo, g0, O[nt2][0] * inv0, O[nt2][1] * inv0);
        split_store(chi, clo, g1, O[nt2][2] * inv1, O[nt2][3] * inv1);
    }
    if ((lane & 3) == 0) {
        size_t si = ((size_t)bh * S_ + row0) * 2;
        stats[si] = mr0; stats[si + 1] = lr0;
        si = ((size_t)bh * S_ + row1) * 2;
        stats[si] = mr1; stats[si + 1] = lr1;
    }
#undef LOAD_KV
#undef KVB
}

// ---------------------------------------------------------------------------
// Pass 2: un-permute + normalize. Block = one (bh, qt, kt) chunk:
//   read 8192 floats coalesced -> smem, write canonical coalesced.
// ---------------------------------------------------------------------------
__global__ __launch_bounds__(256) void normalize_kernel(
    const float* __restrict__ P, const float* __restrict__ mkt,
    const float* __restrict__ stats, float* __restrict__ attn)
{
    __shared__ float sp[8192];
    __shared__ float corr[128];
    const int t  = threadIdx.x;
    const int qt = blockIdx.x >> 5, kt = blockIdx.x & 31;
    const int bh = blockIdx.y;
    const int q0 = qt * 128, k0 = kt * 64;

    if (t < 128) {
        const int row = q0 + t;
        const size_t si = ((size_t)bh * S_ + row) * 2;
        corr[t] = __expf(mkt[((size_t)bh * 32 + kt) * S_ + row] - stats[si]) /
                  stats[si + 1];
    }
    const float4* src = (const float4*)(P +
        ((((size_t)bh * 16 + qt) * 32 + kt) * 8192));
#pragma unroll
    for (int j = 0; j < 8; j++)
        ((float4*)sp)[t + j * 256] = src[t + j * 256];
    __syncthreads();

#pragma unroll
    for (int j = 0; j < 8; j++) {
        const int o   = t + j * 256;        // float4 index in canonical order
        const int row = o >> 4;             // 16 float4 per 64-col row
        const int c   = (o & 15) * 4;
        const float cr = corr[row];
        float v[4];
#pragma unroll
        for (int e = 0; e < 4; e++) {
            const int ci = c + e;
            const int idx = (row >> 4) * 1024 +
                            ((ci >> 3) + 8 * ((row >> 3) & 1)) * 64 +
                            ((row & 7) * 4 + ((ci & 7) >> 1)) * 2 + (ci & 1);
            v[e] = sp[idx] * cr;
        }
        float4 o4;
        o4.x = v[0]; o4.y = v[1]; o4.z = v[2]; o4.w = v[3];
        *(float4*)&attn[((size_t)bh * S_ + q0 + row) * S_ + k0 + c] = o4;
    }
}

// ---------------------------------------------------------------------------
extern "C" void kernel_launch(void* const* d_in, const int* in_sizes, int n_in,
                              void* d_out, int out_size)
{
    const float* x    = (const float*)d_in[0];
    const int*   mask = (const int*)  d_in[1];
    const float* wq_w = (const float*)d_in[2];
    const float* wq_b = (const float*)d_in[3];
    const float* wk_w = (const float*)d_in[4];
    const float* wk_b = (const float*)d_in[5];
    const float* wv_w = (const float*)d_in[6];
    const float* wv_b = (const float*)d_in[7];
    const float* wo_w = (const float*)d_in[8];
    const float* wo_b = (const float*)d_in[9];

    float *qdump, *attn_raw, *mkt, *stats;
    uint32_t* mbits;
    cudaGetSymbolAddress((void**)&qdump,    g_q);
    cudaGetSymbolAddress((void**)&attn_raw, g_attn_raw);
    cudaGetSymbolAddress((void**)&mkt,      g_mkt);
    cudaGetSymbolAddress((void**)&stats,    g_stats);
    cudaGetSymbolAddress((void**)&mbits,    g_mbits);

    __nv_bfloat16 *xhi, *xlo, *chi, *clo;
    __nv_bfloat16 *qhi_p, *qlo_p, *khi_p, *klo_p, *vhi_p, *vlo_p;
    __nv_bfloat16 *wqhi, *wqlo, *wkhi, *wklo, *wvhi, *wvlo, *wohi, *wolo;
    cudaGetSymbolAddress((void**)&xhi, g_xhi);   cudaGetSymbolAddress((void**)&xlo, g_xlo);
    cudaGetSymbolAddress((void**)&chi, g_chi);   cudaGetSymbolAddress((void**)&clo, g_clo);
    cudaGetSymbolAddress((void**)&qhi_p, g_qhi); cudaGetSymbolAddress((void**)&qlo_p, g_qlo);
    cudaGetSymbolAddress((void**)&khi_p, g_khi); cudaGetSymbolAddress((void**)&klo_p, g_klo);
    cudaGetSymbolAddress((void**)&vhi_p, g_vhi); cudaGetSymbolAddress((void**)&vlo_p, g_vlo);
    cudaGetSymbolAddress((void**)&wqhi, g_wqhi); cudaGetSymbolAddress((void**)&wqlo, g_wqlo);
    cudaGetSymbolAddress((void**)&wkhi, g_wkhi); cudaGetSymbolAddress((void**)&wklo, g_wklo);
    cudaGetSymbolAddress((void**)&wvhi, g_wvhi); cudaGetSymbolAddress((void**)&wvlo, g_wvlo);
    cudaGetSymbolAddress((void**)&wohi, g_wohi); cudaGetSymbolAddress((void**)&wolo, g_wolo);

    const long long CTXSZ = (long long)B_ * S_ * D_;
    const long long ATTSZ = (long long)B_ * H_ * S_ * S_;

    float* out_base = (float*)d_out;
    float* out_ptr;
    float* attn_ptr;
    if ((long long)out_size >= CTXSZ + ATTSZ) {
        out_ptr  = out_base;
        attn_ptr = out_base + CTXSZ;
    } else if ((long long)out_size == ATTSZ) {
        out_ptr  = qdump;
        attn_ptr = out_base;
    } else {
        out_ptr  = out_base;
        attn_ptr = attn_raw;
    }

    cudaFuncSetAttribute(flash_mma_kernel,
                         cudaFuncAttributeMaxDynamicSharedMemorySize, FLASH_SMEM);
    cudaFuncSetAttribute(gemm_qkv,
                         cudaFuncAttributeMaxDynamicSharedMemorySize, GEMM_SMEM);
    cudaFuncSetAttribute(gemm_out,
                         cudaFuncAttributeMaxDynamicSharedMemorySize, GEMM_SMEM);

    const int M = B_ * S_;   // 4096
    const int N = D_;        // 1024
    const int K = D_;        // 1024

    const int xn4 = (int)(CTXSZ / 4);
    const int wn4 = D_ * D_ / 4;
    conv_split<<<(xn4 + 255) / 256, 256>>>((const float4*)x, (uint2*)xhi, (uint2*)xlo, xn4);
    dim3 wGrid((wn4 + 255) / 256, 4);
    conv_split_w4<<<wGrid, 256>>>(
        (const float4*)wq_w, (uint2*)wqhi, (uint2*)wqlo,
        (const float4*)wk_w, (uint2*)wkhi, (uint2*)wklo,
        (const float4*)wv_w, (uint2*)wvhi, (uint2*)wvlo,
        (const float4*)wo_w, (uint2*)wohi, (uint2*)wolo, wn4);

    const int nwords = B_ * S_ * SW_;
    conv_maskbits<<<(nwords + 255) / 256, 256>>>((const int4*)mask, mbits, nwords);

    dim3 qkvGrid(N / 128, M / 128, 3);
    gemm_qkv<<<qkvGrid, 256, GEMM_SMEM>>>(
        xhi, xlo,
        wqhi, wqlo, wkhi, wklo, wvhi, wvlo,
        wq_b, wk_b, wv_b,
        qhi_p, qlo_p, khi_p, klo_p, vhi_p, vlo_p, M, N, K);

    dim3 fGrid(S_ / 128, B_ * H_);
    flash_mma_kernel<<<fGrid, 256, FLASH_SMEM>>>(
        qhi_p, qlo_p, khi_p, klo_p, vhi_p, vlo_p,
        mbits, attn_raw, mkt, stats, chi, clo);

    dim3 gGrid(N / 128, M / 128);
    gemm_out<<<gGrid, 256, GEMM_SMEM>>>(chi, clo, wohi, wolo, wo_b, out_ptr, M, N, K);

    dim3 nGrid(16 * 32, B_ * H_);
    normalize_kernel<<<nGrid, 256>>>(attn_raw, mkt, stats, attn_ptr);
}

// round 14
// speedup vs baseline: 2.5697x; 1.0182x over previous
#include <cuda_runtime.h>
#include <cuda_bf16.h>
#include <math.h>
#include <stdint.h>

// Problem constants
#define B_  2
#define S_  2048
#define D_  1024
#define H_  16
#define DH_ 64
#define SCALE_ 0.125f   // DH^-0.5
#define SW_ (S_ / 32)   // mask words per row

typedef unsigned long long u64;

// ---------------------------------------------------------------------------
// Scratch (static device globals; no runtime allocation)
// ---------------------------------------------------------------------------
__device__ float g_q[(size_t)B_ * S_ * D_];                 // dummy sink
__device__ float g_attn_raw[(size_t)B_ * H_ * S_ * S_];     // P, permuted chunks
__device__ float g_mkt[(size_t)B_ * H_ * (S_ / 64) * S_];
__device__ float g_stats[(size_t)B_ * H_ * S_ * 2];
__device__ uint32_t g_mbits[(size_t)B_ * S_ * SW_];        // bit-packed mask

// bf16 hi/lo split operands
__device__ __nv_bfloat16 g_xhi[(size_t)B_ * S_ * D_];
__device__ __nv_bfloat16 g_xlo[(size_t)B_ * S_ * D_];
__device__ __nv_bfloat16 g_qhi[(size_t)B_ * S_ * D_], g_qlo[(size_t)B_ * S_ * D_];
__device__ __nv_bfloat16 g_khi[(size_t)B_ * S_ * D_], g_klo[(size_t)B_ * S_ * D_];
__device__ __nv_bfloat16 g_vhi[(size_t)B_ * S_ * D_], g_vlo[(size_t)B_ * S_ * D_];
__device__ __nv_bfloat16 g_chi[(size_t)B_ * S_ * D_], g_clo[(size_t)B_ * S_ * D_];
__device__ __nv_bfloat16 g_wqhi[D_ * D_], g_wqlo[D_ * D_];
__device__ __nv_bfloat16 g_wkhi[D_ * D_], g_wklo[D_ * D_];
__device__ __nv_bfloat16 g_wvhi[D_ * D_], g_wvlo[D_ * D_];
__device__ __nv_bfloat16 g_wohi[D_ * D_], g_wolo[D_ * D_];

// ---------------------------------------------------------------------------
// mma.sync / ldmatrix helpers
// ---------------------------------------------------------------------------
__device__ __forceinline__ uint32_t smem_u32(const void* p) {
    uint32_t a;
    asm("{ .reg .u64 t; cvta.to.shared.u64 t, %1; cvt.u32.u64 %0, t; }"
        : "=r"(a) : "l"(p));
    return a;
}
__device__ __forceinline__ void ldmA4(uint32_t* a, uint32_t addr) {
    asm volatile("ldmatrix.sync.aligned.m8n8.x4.shared.b16 {%0,%1,%2,%3}, [%4];"
                 : "=r"(a[0]), "=r"(a[1]), "=r"(a[2]), "=r"(a[3]) : "r"(addr));
}
__device__ __forceinline__ void ldmA4t(uint32_t* a, uint32_t addr) {
    asm volatile("ldmatrix.sync.aligned.m8n8.x4.trans.shared.b16 {%0,%1,%2,%3}, [%4];"
                 : "=r"(a[0]), "=r"(a[1]), "=r"(a[2]), "=r"(a[3]) : "r"(addr));
}
__device__ __forceinline__ void mma16816(float* c, const uint32_t* a,
                                         const uint32_t* b) {
    asm volatile(
        "mma.sync.aligned.m16n8k16.row.col.f32.bf16.bf16.f32 "
        "{%0,%1,%2,%3}, {%4,%5,%6,%7}, {%8,%9}, {%0,%1,%2,%3};"
        : "+f"(c[0]), "+f"(c[1]), "+f"(c[2]), "+f"(c[3])
        : "r"(a[0]), "r"(a[1]), "r"(a[2]), "r"(a[3]), "r"(b[0]), "r"(b[1]));
}
__device__ __forceinline__ void cpasync16(uint32_t saddr, const void* gaddr) {
    asm volatile("cp.async.cg.shared.global [%0], [%1], 16;"
                 :: "r"(saddr), "l"(gaddr));
}
#define CP_COMMIT() asm volatile("cp.async.commit_group;" ::: "memory")
#define CP_WAIT0()  asm volatile("cp.async.wait_group 0;" ::: "memory")
#define CP_WAIT1()  asm volatile("cp.async.wait_group 1;" ::: "memory")

__device__ __forceinline__ uint32_t pack_bf2(float x, float y) {
    return (uint32_t)__bfloat16_as_ushort(__float2bfloat16(x)) |
           ((uint32_t)__bfloat16_as_ushort(__float2bfloat16(y)) << 16);
}
#define TRUNC_HI2(x, y) __byte_perm(__float_as_uint(x), __float_as_uint(y), 0x7632)
__device__ __forceinline__ float trunc_res(float x) {
    return x - __uint_as_float(__float_as_uint(x) & 0xFFFF0000u);
}
__device__ __forceinline__ void split_store(
    __nv_bfloat16* hi, __nv_bfloat16* lo, size_t idx, float x, float y)
{
    const __nv_bfloat16 hx = __float2bfloat16(x), hy = __float2bfloat16(y);
    *(uint32_t*)&hi[idx] = (uint32_t)__bfloat16_as_ushort(hx) |
                           ((uint32_t)__bfloat16_as_ushort(hy) << 16);
    *(uint32_t*)&lo[idx] = pack_bf2(x - __bfloat162float(hx),
                                    y - __bfloat162float(hy));
}
__device__ __forceinline__ float fexp(float x) { return __expf(x); }

// ---------------------------------------------------------------------------
// Split-conversions
// ---------------------------------------------------------------------------
__global__ __launch_bounds__(256) void conv_split(
    const float4* __restrict__ src, uint2* __restrict__ hi,
    uint2* __restrict__ lo, int n4)
{
    const int i = blockIdx.x * 256 + threadIdx.x;
    if (i >= n4) return;
    const float4 v = src[i];
    split_store((__nv_bfloat16*)hi, (__nv_bfloat16*)lo, (size_t)i * 4,     v.x, v.y);
    split_store((__nv_bfloat16*)hi, (__nv_bfloat16*)lo, (size_t)i * 4 + 2, v.z, v.w);
}

__global__ __launch_bounds__(256) void conv_split_w4(
    const float4* s0, uint2* h0, uint2* l0,
    const float4* s1, uint2* h1, uint2* l1,
    const float4* s2, uint2* h2, uint2* l2,
    const float4* s3, uint2* h3, uint2* l3, int n4)
{
    const int i = blockIdx.x * 256 + threadIdx.x;
    if (i >= n4) return;
    const int w = blockIdx.y;
    const float4* src = (w == 0) ? s0 : (w == 1) ? s1 : (w == 2) ? s2 : s3;
    uint2* hi = (w == 0) ? h0 : (w == 1) ? h1 : (w == 2) ? h2 : h3;
    uint2* lo = (w == 0) ? l0 : (w == 1) ? l1 : (w == 2) ? l2 : l3;
    const float4 v = src[i];
    split_store((__nv_bfloat16*)hi, (__nv_bfloat16*)lo, (size_t)i * 4,     v.x, v.y);
    split_store((__nv_bfloat16*)hi, (__nv_bfloat16*)lo, (size_t)i * 4 + 2, v.z, v.w);
}

// Pack mask (int32 per element) into 1 bit per element.
__global__ __launch_bounds__(256) void conv_maskbits(
    const int4* __restrict__ mask, uint32_t* __restrict__ mbits, int nwords)
{
    const int w = blockIdx.x * 256 + threadIdx.x;
    if (w >= nwords) return;
    const int4* src = mask + (size_t)w * 8;
    uint32_t bits = 0;
#pragma unroll
    for (int j = 0; j < 8; j++) {
        const int4 v = src[j];
        bits |= (v.x != 0 ? 1u : 0u) << (j * 4 + 0);
        bits |= (v.y != 0 ? 1u : 0u) << (j * 4 + 1);
        bits |= (v.z != 0 ? 1u : 0u) << (j * 4 + 2);
        bits |= (v.w != 0 ? 1u : 0u) << (j * 4 + 3);
    }
    mbits[w] = bits;
}

// ---------------------------------------------------------------------------
// Shared GEMM body: 3-term fused K-loop, BK=32, 2-stage pipeline, 2 CTAs/SM.
// ---------------------------------------------------------------------------
#define GP 40
#define GTILE (128 * GP)
#define GEMM_SMEM (2 * 4 * GTILE * 2)          // 81920 bytes

__device__ __forceinline__ void gemm_body(
    const __nv_bfloat16* __restrict__ Ahi, const __nv_bfloat16* __restrict__ Alo,
    const __nv_bfloat16* __restrict__ Bhi, const __nv_bfloat16* __restrict__ Blo,
    const float* __restrict__ bias, float* __restrict__ C,
    __nv_bfloat16* __restrict__ Chi, __nv_bfloat16* __restrict__ Clo,
    int M, int N, int K, int bm, int bn, uint32_t sb)
{
    const int tid  = threadIdx.x;
    const int lane = tid & 31, wid = tid >> 5;
    const int warp_m = wid >> 2, warp_n = wid & 3;

    const int a_r = warp_m * 64 + (lane & 15);
    const int a_c = (lane >> 4) * 8;
    const int b4_row = ((lane >> 4) & 1) * 8 + (lane & 7);
    const int b4_col = ((lane >> 3) & 1) * 8;

    const int lrow = tid >> 2;          // 0..63
    const int lc8  = (tid & 3) * 8;

    float acc[4][4][4];
#pragma unroll
    for (int mt = 0; mt < 4; mt++)
#pragma unroll
        for (int nt = 0; nt < 4; nt++)
#pragma unroll
            for (int r = 0; r < 4; r++) acc[mt][nt][r] = 0.f;

#define TBASE(s, o) (sb + (uint32_t)(((s) * 4 + (o)) * GTILE) * 2)
#define LOAD_STAGE(s, k0) do {                                                \
    const uint32_t _dAh = TBASE(s, 0), _dAl = TBASE(s, 1);                    \
    const uint32_t _dBh = TBASE(s, 2), _dBl = TBASE(s, 3);                    \
    _Pragma("unroll")                                                         \
    for (int rr = 0; rr < 2; rr++) {                                          \
        const int row = lrow + rr * 64;                                       \
        const uint32_t so = (uint32_t)(row * GP + lc8) * 2;                   \
        const size_t ga = (size_t)(bm + row) * K + (k0) + lc8;                \
        const size_t gb = (size_t)(bn + row) * K + (k0) + lc8;                \
        cpasync16(_dAh + so, &Ahi[ga]);                                       \
        cpasync16(_dAl + so, &Alo[ga]);                                       \
        cpasync16(_dBh + so, &Bhi[gb]);                                       \
        cpasync16(_dBl + so, &Blo[gb]);                                       \
    }                                                                         \
    CP_COMMIT();                                                              \
} while (0)

    LOAD_STAGE(0, 0);

    const int NK = K / 32;
    for (int kc = 0; kc < NK; kc++) {
        const int cur = kc & 1;
        if (kc + 1 < NK) { LOAD_STAGE(cur ^ 1, (kc + 1) * 32); CP_WAIT1(); }
        else             { CP_WAIT0(); }
        __syncthreads();

        const uint32_t uAh = TBASE(cur, 0), uAl = TBASE(cur, 1);
        const uint32_t uBh = TBASE(cur, 2), uBl = TBASE(cur, 3);
#pragma unroll
        for (int ks = 0; ks < 2; ks++) {
            uint32_t ah[4][4], al[4][4];
#pragma unroll
            for (int mt = 0; mt < 4; mt++) {
                const uint32_t ao = (uint32_t)((a_r + mt * 16) * GP +
                                               ks * 16 + a_c) * 2;
                ldmA4(ah[mt], uAh + ao);
                ldmA4(al[mt], uAl + ao);
            }
            uint32_t bh[4][2], bl[4][2];
#pragma unroll
            for (int p = 0; p < 2; p++) {
                uint32_t r4[4];
                const uint32_t bo = (uint32_t)((warp_n * 32 + p * 16 + b4_row) * GP +
                                               ks * 16 + b4_col) * 2;
                ldmA4(r4, uBh + bo);
                bh[2*p][0] = r4[0]; bh[2*p][1] = r4[1];
                bh[2*p+1][0] = r4[2]; bh[2*p+1][1] = r4[3];
                ldmA4(r4, uBl + bo);
                bl[2*p][0] = r4[0]; bl[2*p][1] = r4[1];
                bl[2*p+1][0] = r4[2]; bl[2*p+1][1] = r4[3];
            }
#pragma unroll
            for (int mt = 0; mt < 4; mt++)
#pragma unroll
                for (int nt = 0; nt < 4; nt++) {
                    mma16816(acc[mt][nt], ah[mt], bh[nt]);
                    mma16816(acc[mt][nt], ah[mt], bl[nt]);
                    mma16816(acc[mt][nt], al[mt], bh[nt]);
                }
        }
        __syncthreads();
    }

    const int em = bm + warp_m * 64 + (lane >> 2);
    const int en = bn + warp_n * 32 + (lane & 3) * 2;
#pragma unroll
    for (int mt = 0; mt < 4; mt++) {
#pragma unroll
        for (int nt = 0; nt < 4; nt++) {
            const int n = en + nt * 8;
            const float bx = bias[n], by = bias[n + 1];
            const int m0 = em + mt * 16;
            float2 o0, o1;
            o0.x = acc[mt][nt][0] + bx; o0.y = acc[mt][nt][1] + by;
            o1.x = acc[mt][nt][2] + bx; o1.y = acc[mt][nt][3] + by;
            if (C) {
                *(float2*)&C[(size_t)m0 * N + n]       = o0;
                *(float2*)&C[(size_t)(m0 + 8) * N + n] = o1;
            }
            if (Chi) {
                split_store(Chi, Clo, (size_t)m0 * N + n,       o0.x, o0.y);
                split_store(Chi, Clo, (size_t)(m0 + 8) * N + n, o1.x, o1.y);
            }
        }
    }
#undef LOAD_STAGE
#undef TBASE
}

__global__ __launch_bounds__(256, 2) void gemm_qkv(
    const __nv_bfloat16* __restrict__ Ahi, const __nv_bfloat16* __restrict__ Alo,
    const __nv_bfloat16* bq_h, const __nv_bfloat16* bq_l,
    const __nv_bfloat16* bk_h, const __nv_bfloat16* bk_l,
    const __nv_bfloat16* bv_h, const __nv_bfloat16* bv_l,
    const float* biq, const float* bik, const float* biv,
    __nv_bfloat16* qh, __nv_bfloat16* ql,
    __nv_bfloat16* kh, __nv_bfloat16* kl,
    __nv_bfloat16* vh, __nv_bfloat16* vl,
    int M, int N, int K)
{
    extern __shared__ __nv_bfloat16 gsm[];
    const int z = blockIdx.z;
    const __nv_bfloat16* Bh = (z == 0) ? bq_h : (z == 1) ? bk_h : bv_h;
    const __nv_bfloat16* Bl = (z == 0) ? bq_l : (z == 1) ? bk_l : bv_l;
    const float* bias = (z == 0) ? biq : (z == 1) ? bik : biv;
    __nv_bfloat16* Ch = (z == 0) ? qh : (z == 1) ? kh : vh;
    __nv_bfloat16* Cl = (z == 0) ? ql : (z == 1) ? kl : vl;
    gemm_body(Ahi, Alo, Bh, Bl, bias, (float*)nullptr, Ch, Cl,
              M, N, K, blockIdx.y * 128, blockIdx.x * 128, smem_u32(gsm));
}

__global__ __launch_bounds__(256, 2) void gemm_out(
    const __nv_bfloat16* __restrict__ Ahi, const __nv_bfloat16* __restrict__ Alo,
    const __nv_bfloat16* __restrict__ Bhi, const __nv_bfloat16* __restrict__ Blo,
    const float* __restrict__ bias, float* __restrict__ C,
    int M, int N, int K)
{
    extern __shared__ __nv_bfloat16 gsm[];
    gemm_body(Ahi, Alo, Bhi, Blo, bias, C,
              (__nv_bfloat16*)nullptr, (__nv_bfloat16*)nullptr,
              M, N, K, blockIdx.y * 128, blockIdx.x * 128, smem_u32(gsm));
}

// ---------------------------------------------------------------------------
// Tensor-core flash attention with bit-packed mask + permuted P stores.
// ---------------------------------------------------------------------------
#define FP 72
#define KVT (64 * FP)
#define FLASH_SMEM ((2 * 128 * FP + 2 * 4 * KVT) * 2)    // 110592 bytes

__global__ __launch_bounds__(256, 2) void flash_mma_kernel(
    const __nv_bfloat16* __restrict__ qhi, const __nv_bfloat16* __restrict__ qlo,
    const __nv_bfloat16* __restrict__ khi, const __nv_bfloat16* __restrict__ klo,
    const __nv_bfloat16* __restrict__ vhi, const __nv_bfloat16* __restrict__ vlo,
    const uint32_t* __restrict__ mbits, float* __restrict__ Praw,
    float* __restrict__ mkt, float* __restrict__ stats,
    __nv_bfloat16* __restrict__ chi, __nv_bfloat16* __restrict__ clo)
{
    extern __shared__ __nv_bfloat16 smb[];
    __nv_bfloat16* sQh = smb;
    __nv_bfloat16* sQl = sQh + 128 * FP;
    __nv_bfloat16* sKV = sQl + 128 * FP;

    const int t = threadIdx.x, lane = t & 31, warp = t >> 5;
    const int bh = blockIdx.y;
    const int b = bh >> 4, h = bh & 15;
    const int q0 = blockIdx.x * 128;

    const uint32_t uQh = smem_u32(sQh), uQl = smem_u32(sQl);
    const uint32_t uKV = smem_u32(sKV);
#define KVB(s, o) (uKV + (uint32_t)(((s) * 4 + (o)) * KVT) * 2)

    for (int i = t; i < 1024; i += 256) {
        const int row = i >> 3, c8 = (i & 7) * 8;
        const size_t g = (size_t)(b * S_ + q0 + row) * D_ + h * 64 + c8;
        const uint32_t so = (uint32_t)(row * FP + c8) * 2;
        cpasync16(uQh + so, &qhi[g]);
        cpasync16(uQl + so, &qlo[g]);
    }

    const int kv_row = t >> 3;
    const int kv_c8  = (t & 7) * 8;
#define LOAD_KV(stage, k0) do {                                               \
    _Pragma("unroll")                                                         \
    for (int rr = 0; rr < 2; rr++) {                                          \
        const int row = kv_row + rr * 32;                                     \
        const size_t g = (size_t)(b * S_ + (k0) + row) * D_ + h * 64 + kv_c8; \
        const uint32_t so = (uint32_t)(row * FP + kv_c8) * 2;                 \
        cpasync16(KVB(stage, 0) + so, &khi[g]);                               \
        cpasync16(KVB(stage, 1) + so, &klo[g]);                               \
        cpasync16(KVB(stage, 2) + so, &vhi[g]);                               \
        cpasync16(KVB(stage, 3) + so, &vlo[g]);                               \
    }                                                                         \
    CP_COMMIT();                                                              \
} while (0)

    LOAD_KV(0, 0);

    float O[8][4];
#pragma unroll
    for (int j = 0; j < 8; j++)
#pragma unroll
        for (int r = 0; r < 4; r++) O[j][r] = 0.f;
    float mr0 = -1e30f, mr1 = -1e30f, lr0 = 0.f, lr1 = 0.f;

    const int row0 = q0 + warp * 16 + (lane >> 2);
    const int row1 = row0 + 8;
    const int col0 = (lane & 3) * 2;
    const int a_r  = warp * 16 + (lane & 15);
    const int a_c  = (lane >> 4) * 8;
    const int b4_row = ((lane >> 4) & 1) * 8 + (lane & 7);
    const int b4_col = ((lane >> 3) & 1) * 8;
    const int t4_row = ((lane >> 3) & 1) * 8 + (lane & 7);
    const int t4_sel = ((lane >> 4) & 1) * 8;

    const uint32_t* mrow0 = &mbits[((size_t)b * S_ + row0) * SW_];
    const uint32_t* mrow1 = &mbits[((size_t)b * S_ + row1) * SW_];

    const int NT = S_ / 64;
    for (int kt = 0; kt < NT; kt++) {
        const int k0 = kt * 64;
        const int cur = kt & 1;
        CP_WAIT0();
        __syncthreads();
        if (kt + 1 < NT) LOAD_KV(cur ^ 1, (kt + 1) * 64);

        const uint32_t uKh = KVB(cur, 0), uKl = KVB(cur, 1);
        const uint32_t uVh = KVB(cur, 2), uVl = KVB(cur, 3);

        // --- QK^T: c[8][4] over 64 k-cols ---
        float c[8][4];
#pragma unroll
        for (int nt = 0; nt < 8; nt++)
#pragma unroll
            for (int r = 0; r < 4; r++) c[nt][r] = 0.f;
#pragma unroll
        for (int ks = 0; ks < 4; ks++) {
            uint32_t qh2[4], ql2[4];
            const uint32_t qo = (uint32_t)(a_r * FP + ks * 16 + a_c) * 2;
            ldmA4(qh2, uQh + qo);
            ldmA4(ql2, uQl + qo);
#pragma unroll
            for (int p = 0; p < 4; p++) {
                uint32_t rh[4], rl[4];
                const uint32_t off = (uint32_t)((p * 16 + b4_row) * FP +
                                                ks * 16 + b4_col) * 2;
                ldmA4(rh, uKh + off);
                ldmA4(rl, uKl + off);
                mma16816(c[2*p],   qh2, rh);
                mma16816(c[2*p],   qh2, rl);
                mma16816(c[2*p],   ql2, rh);
                mma16816(c[2*p+1], qh2, rh + 2);
                mma16816(c[2*p+1], qh2, rl + 2);
                mma16816(c[2*p+1], ql2, rh + 2);
            }
        }

        // --- scale + mask (bit-packed) ---
        {
            const uint2 mw0 = *(const uint2*)&mrow0[k0 >> 5];
            const uint2 mw1 = *(const uint2*)&mrow1[k0 >> 5];
#pragma unroll
            for (int nt = 0; nt < 8; nt++) {
                const int cb = ((nt & 3) * 8 + col0);
                const uint32_t w0 = (nt < 4) ? mw0.x : mw0.y;
                const uint32_t w1 = (nt < 4) ? mw1.x : mw1.y;
                c[nt][0] = ((w0 >> cb) & 1u)       ? c[nt][0] * SCALE_ : -1e9f;
                c[nt][1] = ((w0 >> (cb + 1)) & 1u) ? c[nt][1] * SCALE_ : -1e9f;
                c[nt][2] = ((w1 >> cb) & 1u)       ? c[nt][2] * SCALE_ : -1e9f;
                c[nt][3] = ((w1 >> (cb + 1)) & 1u) ? c[nt][3] * SCALE_ : -1e9f;
            }
        }

        // --- online softmax ---
        float rm0 = -1e30f, rm1 = -1e30f;
#pragma unroll
        for (int nt = 0; nt < 8; nt++) {
            rm0 = fmaxf(rm0, fmaxf(c[nt][0], c[nt][1]));
            rm1 = fmaxf(rm1, fmaxf(c[nt][2], c[nt][3]));
        }
        rm0 = fmaxf(rm0, __shfl_xor_sync(0xffffffffu, rm0, 1));
        rm0 = fmaxf(rm0, __shfl_xor_sync(0xffffffffu, rm0, 2));
        rm1 = fmaxf(rm1, __shfl_xor_sync(0xffffffffu, rm1, 1));
        rm1 = fmaxf(rm1, __shfl_xor_sync(0xffffffffu, rm1, 2));
        const float mn0 = fmaxf(mr0, rm0), mn1 = fmaxf(mr1, rm1);
        const float f0 = fexp(mr0 - mn0), f1 = fexp(mr1 - mn1);
        float rs0 = 0.f, rs1 = 0.f;
#pragma unroll
        for (int nt = 0; nt < 8; nt++) {
            c[nt][0] = fexp(c[nt][0] - mn0);
            c[nt][1] = fexp(c[nt][1] - mn0);
            c[nt][2] = fexp(c[nt][2] - mn1);
            c[nt][3] = fexp(c[nt][3] - mn1);
            rs0 += c[nt][0] + c[nt][1];
            rs1 += c[nt][2] + c[nt][3];
        }
        rs0 += __shfl_xor_sync(0xffffffffu, rs0, 1);
        rs0 += __shfl_xor_sync(0xffffffffu, rs0, 2);
        rs1 += __shfl_xor_sync(0xffffffffu, rs1, 1);
        rs1 += __shfl_xor_sync(0xffffffffu, rs1, 2);
        lr0 = lr0 * f0 + rs0; mr0 = mn0;
        lr1 = lr1 * f1 + rs1; mr1 = mn1;
#pragma unroll
        for (int j = 0; j < 8; j++) {
            O[j][0] *= f0; O[j][1] *= f0;
            O[j][2] *= f1; O[j][3] *= f1;
        }

        // --- stream P (permuted, warp-contiguous) + m_kt ---
        {
            float* pb = Praw +
                ((((size_t)bh * 16 + (q0 >> 7)) * 32 + kt) * 8192) +
                warp * 1024 + lane * 2;
#pragma unroll
            for (int nt = 0; nt < 8; nt++) {
                float2 w0, w1;
                w0.x = c[nt][0]; w0.y = c[nt][1];
                w1.x = c[nt][2]; w1.y = c[nt][3];
                *(float2*)&pb[nt * 64]       = w0;
                *(float2*)&pb[(nt + 8) * 64] = w1;
            }
            if ((lane & 3) == 0) {
                mkt[((size_t)bh * 32 + kt) * S_ + row0] = mn0;
                mkt[((size_t)bh * 32 + kt) * S_ + row1] = mn1;
            }
        }

        // --- P @ V (truncation-split fragments) ---
#pragma unroll
        for (int ks2 = 0; ks2 < 4; ks2++) {
            const float* c0 = c[2 * ks2];
            const float* c1 = c[2 * ks2 + 1];
            uint32_t ah[4], al[4];
            ah[0] = TRUNC_HI2(c0[0], c0[1]);
            ah[1] = TRUNC_HI2(c0[2], c0[3]);
            ah[2] = TRUNC_HI2(c1[0], c1[1]);
            ah[3] = TRUNC_HI2(c1[2], c1[3]);
            al[0] = TRUNC_HI2(trunc_res(c0[0]), trunc_res(c0[1]));
            al[1] = TRUNC_HI2(trunc_res(c0[2]), trunc_res(c0[3]));
            al[2] = TRUNC_HI2(trunc_res(c1[0]), trunc_res(c1[1]));
            al[3] = TRUNC_HI2(trunc_res(c1[2]), trunc_res(c1[3]));
#pragma unroll
            for (int p = 0; p < 4; p++) {
                uint32_t vh4[4], vl4[4];
                const uint32_t off = (uint32_t)((ks2 * 16 + t4_row) * FP +
                                                p * 16 + t4_sel) * 2;
                ldmA4t(vh4, uVh + off);
                ldmA4t(vl4, uVl + off);
                mma16816(O[2*p],   ah, vh4);
                mma16816(O[2*p],   ah, vl4);
                mma16816(O[2*p],   al, vh4);
                mma16816(O[2*p+1], ah, vh4 + 2);
                mma16816(O[2*p+1], ah, vl4 + 2);
                mma16816(O[2*p+1], al, vh4 + 2);
            }
        }
    }

    // --- epilogue: normalized ctx as bf16 hi/lo ---
    const float inv0 = 1.0f / lr0, inv1 = 1.0f / lr1;
#pragma unroll
    for (int nt2 = 0; nt2 < 8; nt2++) {
        const int n = nt2 * 8 + col0;
        const size_t g0 = (size_t)(b * S_ + row0) * D_ + h * 64 + n;
        const size_t g1 = (size_t)(b * S_ + row1) * D_ + h * 64 + n;
        split_store(chi, clo, g0, O[nt2][0] * inv0, O[nt2][1] * inv0);
        split_store(chi, clo, g1, O[nt2][2] * inv1, O[nt2][3] * inv1);
    }
    if ((lane & 3) == 0) {
        size_t si = ((size_t)bh * S_ + row0) * 2;
        stats[si] = mr0; stats[si + 1] = lr0;
        si = ((size_t)bh * S_ + row1) * 2;
        stats[si] = mr1; stats[si + 1] = lr1;
    }
#undef LOAD_KV
#undef KVB
}

// ---------------------------------------------------------------------------
// Pass 2: un-permute + normalize (one (bh,qt,kt) chunk per block).
// ---------------------------------------------------------------------------
__global__ __launch_bounds__(256) void normalize_kernel(
    const float* __restrict__ P, const float* __restrict__ mkt,
    const float* __restrict__ stats, float* __restrict__ attn)
{
    __shared__ float sp[8192];
    __shared__ float corr[128];
    const int t  = threadIdx.x;
    const int qt = blockIdx.x >> 5, kt = blockIdx.x & 31;
    const int bh = blockIdx.y;
    const int q0 = qt * 128, k0 = kt * 64;

    if (t < 128) {
        const int row = q0 + t;
        const size_t si = ((size_t)bh * S_ + row) * 2;
        corr[t] = __expf(mkt[((size_t)bh * 32 + kt) * S_ + row] - stats[si]) /
                  stats[si + 1];
    }
    const float4* src = (const float4*)(P +
        ((((size_t)bh * 16 + qt) * 32 + kt) * 8192));
#pragma unroll
    for (int j = 0; j < 8; j++)
        ((float4*)sp)[t + j * 256] = src[t + j * 256];
    __syncthreads();

#pragma unroll
    for (int j = 0; j < 8; j++) {
        const int o   = t + j * 256;
        const int row = o >> 4;
        const int c   = (o & 15) * 4;
        const float cr = corr[row];
        float v[4];
#pragma unroll
        for (int e = 0; e < 4; e++) {
            const int ci = c + e;
            const int idx = (row >> 4) * 1024 +
                            ((ci >> 3) + 8 * ((row >> 3) & 1)) * 64 +
                            ((row & 7) * 4 + ((ci & 7) >> 1)) * 2 + (ci & 1);
            v[e] = sp[idx] * cr;
        }
        float4 o4;
        o4.x = v[0]; o4.y = v[1]; o4.z = v[2]; o4.w = v[3];
        *(float4*)&attn[((size_t)bh * S_ + q0 + row) * S_ + k0 + c] = o4;
    }
}

// ---------------------------------------------------------------------------
extern "C" void kernel_launch(void* const* d_in, const int* in_sizes, int n_in,
                              void* d_out, int out_size)
{
    const float* x    = (const float*)d_in[0];
    const int*   mask = (const int*)  d_in[1];
    const float* wq_w = (const float*)d_in[2];
    const float* wq_b = (const float*)d_in[3];
    const float* wk_w = (const float*)d_in[4];
    const float* wk_b = (const float*)d_in[5];
    const float* wv_w = (const float*)d_in[6];
    const float* wv_b = (const float*)d_in[7];
    const float* wo_w = (const float*)d_in[8];
    const float* wo_b = (const float*)d_in[9];

    float *qdump, *attn_raw, *mkt, *stats;
    uint32_t* mbits;
    cudaGetSymbolAddress((void**)&qdump,    g_q);
    cudaGetSymbolAddress((void**)&attn_raw, g_attn_raw);
    cudaGetSymbolAddress((void**)&mkt,      g_mkt);
    cudaGetSymbolAddress((void**)&stats,    g_stats);
    cudaGetSymbolAddress((void**)&mbits,    g_mbits);

    __nv_bfloat16 *xhi, *xlo, *chi, *clo;
    __nv_bfloat16 *qhi_p, *qlo_p, *khi_p, *klo_p, *vhi_p, *vlo_p;
    __nv_bfloat16 *wqhi, *wqlo, *wkhi, *wklo, *wvhi, *wvlo, *wohi, *wolo;
    cudaGetSymbolAddress((void**)&xhi, g_xhi);   cudaGetSymbolAddress((void**)&xlo, g_xlo);
    cudaGetSymbolAddress((void**)&chi, g_chi);   cudaGetSymbolAddress((void**)&clo, g_clo);
    cudaGetSymbolAddress((void**)&qhi_p, g_qhi); cudaGetSymbolAddress((void**)&qlo_p, g_qlo);
    cudaGetSymbolAddress((void**)&khi_p, g_khi); cudaGetSymbolAddress((void**)&klo_p, g_klo);
    cudaGetSymbolAddress((void**)&vhi_p, g_vhi); cudaGetSymbolAddress((void**)&vlo_p, g_vlo);
    cudaGetSymbolAddress((void**)&wqhi, g_wqhi); cudaGetSymbolAddress((void**)&wqlo, g_wqlo);
    cudaGetSymbolAddress((void**)&wkhi, g_wkhi); cudaGetSymbolAddress((void**)&wklo, g_wklo);
    cudaGetSymbolAddress((void**)&wvhi, g_wvhi); cudaGetSymbolAddress((void**)&wvlo, g_wvlo);
    cudaGetSymbolAddress((void**)&wohi, g_wohi); cudaGetSymbolAddress((void**)&wolo, g_wolo);

    const long long CTXSZ = (long long)B_ * S_ * D_;
    const long long ATTSZ = (long long)B_ * H_ * S_ * S_;

    float* out_base = (float*)d_out;
    float* out_ptr;
    float* attn_ptr;
    if ((long long)out_size >= CTXSZ + ATTSZ) {
        out_ptr  = out_base;
        attn_ptr = out_base + CTXSZ;
    } else if ((long long)out_size == ATTSZ) {
        out_ptr  = qdump;
        attn_ptr = out_base;
    } else {
        out_ptr  = out_base;
        attn_ptr = attn_raw;
    }

    cudaFuncSetAttribute(flash_mma_kernel,
                         cudaFuncAttributeMaxDynamicSharedMemorySize, FLASH_SMEM);
    cudaFuncSetAttribute(gemm_qkv,
                         cudaFuncAttributeMaxDynamicSharedMemorySize, GEMM_SMEM);
    cudaFuncSetAttribute(gemm_out,
                         cudaFuncAttributeMaxDynamicSharedMemorySize, GEMM_SMEM);

    // Side stream + events for fork-join inside graph capture (created once;
    // host objects, not device memory).
    static cudaStream_t s1 = nullptr;
    static cudaEvent_t evFork = nullptr, evMask = nullptr, evJoin = nullptr;
    if (!s1) {
        cudaStreamCreateWithFlags(&s1, cudaStreamNonBlocking);
        cudaEventCreateWithFlags(&evFork, cudaEventDisableTiming);
        cudaEventCreateWithFlags(&evMask, cudaEventDisableTiming);
        cudaEventCreateWithFlags(&evJoin, cudaEventDisableTiming);
    }

    const int M = B_ * S_;   // 4096
    const int N = D_;        // 1024
    const int K = D_;        // 1024

    const int xn4 = (int)(CTXSZ / 4);
    const int wn4 = D_ * D_ / 4;

    // Main stream: x conv + weight convs (needed by gemm_qkv).
    conv_split<<<(xn4 + 255) / 256, 256>>>((const float4*)x, (uint2*)xhi, (uint2*)xlo, xn4);
    dim3 wGrid((wn4 + 255) / 256, 4);
    conv_split_w4<<<wGrid, 256>>>(
        (const float4*)wq_w, (uint2*)wqhi, (uint2*)wqlo,
        (const float4*)wk_w, (uint2*)wkhi, (uint2*)wklo,
        (const float4*)wv_w, (uint2*)wvhi, (uint2*)wvlo,
        (const float4*)wo_w, (uint2*)wohi, (uint2*)wolo, wn4);

    // Fork: mask bit-pack runs on s1, concurrent with gemm_qkv on main.
    cudaEventRecord(evFork, 0);
    cudaStreamWaitEvent(s1, evFork, 0);
    const int nwords = B_ * S_ * SW_;
    conv_maskbits<<<(nwords + 255) / 256, 256, 0, s1>>>(
        (const int4*)mask, mbits, nwords);
    cudaEventRecord(evMask, s1);

    dim3 qkvGrid(N / 128, M / 128, 3);
    gemm_qkv<<<qkvGrid, 256, GEMM_SMEM>>>(
        xhi, xlo,
        wqhi, wqlo, wkhi, wklo, wvhi, wvlo,
        wq_b, wk_b, wv_b,
        qhi_p, qlo_p, khi_p, klo_p, vhi_p, vlo_p, M, N, K);

    // Join mask before flash.
    cudaStreamWaitEvent(0, evMask, 0);
    dim3 fGrid(S_ / 128, B_ * H_);
    flash_mma_kernel<<<fGrid, 256, FLASH_SMEM>>>(
        qhi_p, qlo_p, khi_p, klo_p, vhi_p, vlo_p,
        mbits, attn_raw, mkt, stats, chi, clo);

    // Fork: gemm_out (tensor-bound) on s1, normalize (DRAM-bound) on main.
    cudaEventRecord(evFork, 0);
    cudaStreamWaitEvent(s1, evFork, 0);
    dim3 gGrid(N / 128, M / 128);
    gemm_out<<<gGrid, 256, GEMM_SMEM, s1>>>(chi, clo, wohi, wolo, wo_b,
                                            out_ptr, M, N, K);
    cudaEventRecord(evJoin, s1);

    dim3 nGrid(16 * 32, B_ * H_);
    normalize_kernel<<<nGrid, 256>>>(attn_raw, mkt, stats, attn_ptr);

    // Join side stream before returning.
    cudaStreamWaitEvent(0, evJoin, 0);
}

// round 15
// speedup vs baseline: 2.7363x; 1.0648x over previous
#include <cuda_runtime.h>
#include <cuda_bf16.h>
#include <cuda_fp16.h>
#include <math.h>
#include <stdint.h>

// Problem constants
#define B_  2
#define S_  2048
#define D_  1024
#define H_  16
#define DH_ 64
#define SCALE_ 0.125f   // DH^-0.5
#define SW_ (S_ / 32)   // mask words per row

typedef unsigned long long u64;

// ---------------------------------------------------------------------------
// Scratch (static device globals; no runtime allocation)
// ---------------------------------------------------------------------------
__device__ float g_q[(size_t)B_ * S_ * D_];                 // dummy sink
__device__ float g_attn_raw[(size_t)B_ * H_ * S_ * S_];     // fallback attn (fp32)
__device__ __half g_p16[(size_t)B_ * H_ * S_ * S_];         // P, fp16 permuted
__device__ float g_mkt[(size_t)B_ * H_ * (S_ / 64) * S_];
__device__ float g_stats[(size_t)B_ * H_ * S_ * 2];
__device__ uint32_t g_mbits[(size_t)B_ * S_ * SW_];        // bit-packed mask

// bf16 hi/lo split operands
__device__ __nv_bfloat16 g_xhi[(size_t)B_ * S_ * D_];
__device__ __nv_bfloat16 g_xlo[(size_t)B_ * S_ * D_];
__device__ __nv_bfloat16 g_qhi[(size_t)B_ * S_ * D_], g_qlo[(size_t)B_ * S_ * D_];
__device__ __nv_bfloat16 g_khi[(size_t)B_ * S_ * D_], g_klo[(size_t)B_ * S_ * D_];
__device__ __nv_bfloat16 g_vhi[(size_t)B_ * S_ * D_], g_vlo[(size_t)B_ * S_ * D_];
__device__ __nv_bfloat16 g_chi[(size_t)B_ * S_ * D_], g_clo[(size_t)B_ * S_ * D_];
__device__ __nv_bfloat16 g_wqhi[D_ * D_], g_wqlo[D_ * D_];
__device__ __nv_bfloat16 g_wkhi[D_ * D_], g_wklo[D_ * D_];
__device__ __nv_bfloat16 g_wvhi[D_ * D_], g_wvlo[D_ * D_];
__device__ __nv_bfloat16 g_wohi[D_ * D_], g_wolo[D_ * D_];

// ---------------------------------------------------------------------------
// mma.sync / ldmatrix helpers
// ---------------------------------------------------------------------------
__device__ __forceinline__ uint32_t smem_u32(const void* p) {
    uint32_t a;
    asm("{ .reg .u64 t; cvta.to.shared.u64 t, %1; cvt.u32.u64 %0, t; }"
        : "=r"(a) : "l"(p));
    return a;
}
__device__ __forceinline__ void ldmA4(uint32_t* a, uint32_t addr) {
    asm volatile("ldmatrix.sync.aligned.m8n8.x4.shared.b16 {%0,%1,%2,%3}, [%4];"
                 : "=r"(a[0]), "=r"(a[1]), "=r"(a[2]), "=r"(a[3]) : "r"(addr));
}
__device__ __forceinline__ void ldmA4t(uint32_t* a, uint32_t addr) {
    asm volatile("ldmatrix.sync.aligned.m8n8.x4.trans.shared.b16 {%0,%1,%2,%3}, [%4];"
                 : "=r"(a[0]), "=r"(a[1]), "=r"(a[2]), "=r"(a[3]) : "r"(addr));
}
__device__ __forceinline__ void mma16816(float* c, const uint32_t* a,
                                         const uint32_t* b) {
    asm volatile(
        "mma.sync.aligned.m16n8k16.row.col.f32.bf16.bf16.f32 "
        "{%0,%1,%2,%3}, {%4,%5,%6,%7}, {%8,%9}, {%0,%1,%2,%3};"
        : "+f"(c[0]), "+f"(c[1]), "+f"(c[2]), "+f"(c[3])
        : "r"(a[0]), "r"(a[1]), "r"(a[2]), "r"(a[3]), "r"(b[0]), "r"(b[1]));
}
__device__ __forceinline__ void cpasync16(uint32_t saddr, const void* gaddr) {
    asm volatile("cp.async.cg.shared.global [%0], [%1], 16;"
                 :: "r"(saddr), "l"(gaddr));
}
#define CP_COMMIT() asm volatile("cp.async.commit_group;" ::: "memory")
#define CP_WAIT0()  asm volatile("cp.async.wait_group 0;" ::: "memory")
#define CP_WAIT1()  asm volatile("cp.async.wait_group 1;" ::: "memory")

__device__ __forceinline__ uint32_t pack_bf2(float x, float y) {
    return (uint32_t)__bfloat16_as_ushort(__float2bfloat16(x)) |
           ((uint32_t)__bfloat16_as_ushort(__float2bfloat16(y)) << 16);
}
#define TRUNC_HI2(x, y) __byte_perm(__float_as_uint(x), __float_as_uint(y), 0x7632)
__device__ __forceinline__ float trunc_res(float x) {
    return x - __uint_as_float(__float_as_uint(x) & 0xFFFF0000u);
}
__device__ __forceinline__ void split_store(
    __nv_bfloat16* hi, __nv_bfloat16* lo, size_t idx, float x, float y)
{
    const __nv_bfloat16 hx = __float2bfloat16(x), hy = __float2bfloat16(y);
    *(uint32_t*)&hi[idx] = (uint32_t)__bfloat16_as_ushort(hx) |
                           ((uint32_t)__bfloat16_as_ushort(hy) << 16);
    *(uint32_t*)&lo[idx] = pack_bf2(x - __bfloat162float(hx),
                                    y - __bfloat162float(hy));
}
__device__ __forceinline__ float fexp(float x) { return __expf(x); }

// ---------------------------------------------------------------------------
// Split-conversions
// ---------------------------------------------------------------------------
__global__ __launch_bounds__(256) void conv_split(
    const float4* __restrict__ src, uint2* __restrict__ hi,
    uint2* __restrict__ lo, int n4)
{
    const int i = blockIdx.x * 256 + threadIdx.x;
    if (i >= n4) return;
    const float4 v = src[i];
    split_store((__nv_bfloat16*)hi, (__nv_bfloat16*)lo, (size_t)i * 4,     v.x, v.y);
    split_store((__nv_bfloat16*)hi, (__nv_bfloat16*)lo, (size_t)i * 4 + 2, v.z, v.w);
}

__global__ __launch_bounds__(256) void conv_split_w4(
    const float4* s0, uint2* h0, uint2* l0,
    const float4* s1, uint2* h1, uint2* l1,
    const float4* s2, uint2* h2, uint2* l2,
    const float4* s3, uint2* h3, uint2* l3, int n4)
{
    const int i = blockIdx.x * 256 + threadIdx.x;
    if (i >= n4) return;
    const int w = blockIdx.y;
    const float4* src = (w == 0) ? s0 : (w == 1) ? s1 : (w == 2) ? s2 : s3;
    uint2* hi = (w == 0) ? h0 : (w == 1) ? h1 : (w == 2) ? h2 : h3;
    uint2* lo = (w == 0) ? l0 : (w == 1) ? l1 : (w == 2) ? l2 : l3;
    const float4 v = src[i];
    split_store((__nv_bfloat16*)hi, (__nv_bfloat16*)lo, (size_t)i * 4,     v.x, v.y);
    split_store((__nv_bfloat16*)hi, (__nv_bfloat16*)lo, (size_t)i * 4 + 2, v.z, v.w);
}

// Pack mask (int32 per element) into 1 bit per element.
__global__ __launch_bounds__(256) void conv_maskbits(
    const int4* __restrict__ mask, uint32_t* __restrict__ mbits, int nwords)
{
    const int w = blockIdx.x * 256 + threadIdx.x;
    if (w >= nwords) return;
    const int4* src = mask + (size_t)w * 8;
    uint32_t bits = 0;
#pragma unroll
    for (int j = 0; j < 8; j++) {
        const int4 v = src[j];
        bits |= (v.x != 0 ? 1u : 0u) << (j * 4 + 0);
        bits |= (v.y != 0 ? 1u : 0u) << (j * 4 + 1);
        bits |= (v.z != 0 ? 1u : 0u) << (j * 4 + 2);
        bits |= (v.w != 0 ? 1u : 0u) << (j * 4 + 3);
    }
    mbits[w] = bits;
}

// ---------------------------------------------------------------------------
// Shared GEMM body: 3-term fused K-loop, BK=32, 2-stage pipeline, 2 CTAs/SM.
// ---------------------------------------------------------------------------
#define GP 40
#define GTILE (128 * GP)
#define GEMM_SMEM (2 * 4 * GTILE * 2)          // 81920 bytes

__device__ __forceinline__ void gemm_body(
    const __nv_bfloat16* __restrict__ Ahi, const __nv_bfloat16* __restrict__ Alo,
    const __nv_bfloat16* __restrict__ Bhi, const __nv_bfloat16* __restrict__ Blo,
    const float* __restrict__ bias, float* __restrict__ C,
    __nv_bfloat16* __restrict__ Chi, __nv_bfloat16* __restrict__ Clo,
    int M, int N, int K, int bm, int bn, uint32_t sb)
{
    const int tid  = threadIdx.x;
    const int lane = tid & 31, wid = tid >> 5;
    const int warp_m = wid >> 2, warp_n = wid & 3;

    const int a_r = warp_m * 64 + (lane & 15);
    const int a_c = (lane >> 4) * 8;
    const int b4_row = ((lane >> 4) & 1) * 8 + (lane & 7);
    const int b4_col = ((lane >> 3) & 1) * 8;

    const int lrow = tid >> 2;          // 0..63
    const int lc8  = (tid & 3) * 8;

    float acc[4][4][4];
#pragma unroll
    for (int mt = 0; mt < 4; mt++)
#pragma unroll
        for (int nt = 0; nt < 4; nt++)
#pragma unroll
            for (int r = 0; r < 4; r++) acc[mt][nt][r] = 0.f;

#define TBASE(s, o) (sb + (uint32_t)(((s) * 4 + (o)) * GTILE) * 2)
#define LOAD_STAGE(s, k0) do {                                                \
    const uint32_t _dAh = TBASE(s, 0), _dAl = TBASE(s, 1);                    \
    const uint32_t _dBh = TBASE(s, 2), _dBl = TBASE(s, 3);                    \
    _Pragma("unroll")                                                         \
    for (int rr = 0; rr < 2; rr++) {                                          \
        const int row = lrow + rr * 64;                                       \
        const uint32_t so = (uint32_t)(row * GP + lc8) * 2;                   \
        const size_t ga = (size_t)(bm + row) * K + (k0) + lc8;                \
        const size_t gb = (size_t)(bn + row) * K + (k0) + lc8;                \
        cpasync16(_dAh + so, &Ahi[ga]);                                       \
        cpasync16(_dAl + so, &Alo[ga]);                                       \
        cpasync16(_dBh + so, &Bhi[gb]);                                       \
        cpasync16(_dBl + so, &Blo[gb]);                                       \
    }                                                                         \
    CP_COMMIT();                                                              \
} while (0)

    LOAD_STAGE(0, 0);

    const int NK = K / 32;
    for (int kc = 0; kc < NK; kc++) {
        const int cur = kc & 1;
        if (kc + 1 < NK) { LOAD_STAGE(cur ^ 1, (kc + 1) * 32); CP_WAIT1(); }
        else             { CP_WAIT0(); }
        __syncthreads();

        const uint32_t uAh = TBASE(cur, 0), uAl = TBASE(cur, 1);
        const uint32_t uBh = TBASE(cur, 2), uBl = TBASE(cur, 3);
#pragma unroll
        for (int ks = 0; ks < 2; ks++) {
            uint32_t ah[4][4], al[4][4];
#pragma unroll
            for (int mt = 0; mt < 4; mt++) {
                const uint32_t ao = (uint32_t)((a_r + mt * 16) * GP +
                                               ks * 16 + a_c) * 2;
                ldmA4(ah[mt], uAh + ao);
                ldmA4(al[mt], uAl + ao);
            }
            uint32_t bh[4][2], bl[4][2];
#pragma unroll
            for (int p = 0; p < 2; p++) {
                uint32_t r4[4];
                const uint32_t bo = (uint32_t)((warp_n * 32 + p * 16 + b4_row) * GP +
                                               ks * 16 + b4_col) * 2;
                ldmA4(r4, uBh + bo);
                bh[2*p][0] = r4[0]; bh[2*p][1] = r4[1];
                bh[2*p+1][0] = r4[2]; bh[2*p+1][1] = r4[3];
                ldmA4(r4, uBl + bo);
                bl[2*p][0] = r4[0]; bl[2*p][1] = r4[1];
                bl[2*p+1][0] = r4[2]; bl[2*p+1][1] = r4[3];
            }
#pragma unroll
            for (int mt = 0; mt < 4; mt++)
#pragma unroll
                for (int nt = 0; nt < 4; nt++) {
                    mma16816(acc[mt][nt], ah[mt], bh[nt]);
                    mma16816(acc[mt][nt], ah[mt], bl[nt]);
                    mma16816(acc[mt][nt], al[mt], bh[nt]);
                }
        }
        __syncthreads();
    }

    const int em = bm + warp_m * 64 + (lane >> 2);
    const int en = bn + warp_n * 32 + (lane & 3) * 2;
#pragma unroll
    for (int mt = 0; mt < 4; mt++) {
#pragma unroll
        for (int nt = 0; nt < 4; nt++) {
            const int n = en + nt * 8;
            const float bx = bias[n], by = bias[n + 1];
            const int m0 = em + mt * 16;
            float2 o0, o1;
            o0.x = acc[mt][nt][0] + bx; o0.y = acc[mt][nt][1] + by;
            o1.x = acc[mt][nt][2] + bx; o1.y = acc[mt][nt][3] + by;
            if (C) {
                *(float2*)&C[(size_t)m0 * N + n]       = o0;
                *(float2*)&C[(size_t)(m0 + 8) * N + n] = o1;
            }
            if (Chi) {
                split_store(Chi, Clo, (size_t)m0 * N + n,       o0.x, o0.y);
                split_store(Chi, Clo, (size_t)(m0 + 8) * N + n, o1.x, o1.y);
            }
        }
    }
#undef LOAD_STAGE
#undef TBASE
}

__global__ __launch_bounds__(256, 2) void gemm_qkv(
    const __nv_bfloat16* __restrict__ Ahi, const __nv_bfloat16* __restrict__ Alo,
    const __nv_bfloat16* bq_h, const __nv_bfloat16* bq_l,
    const __nv_bfloat16* bk_h, const __nv_bfloat16* bk_l,
    const __nv_bfloat16* bv_h, const __nv_bfloat16* bv_l,
    const float* biq, const float* bik, const float* biv,
    __nv_bfloat16* qh, __nv_bfloat16* ql,
    __nv_bfloat16* kh, __nv_bfloat16* kl,
    __nv_bfloat16* vh, __nv_bfloat16* vl,
    int M, int N, int K)
{
    extern __shared__ __nv_bfloat16 gsm[];
    const int z = blockIdx.z;
    const __nv_bfloat16* Bh = (z == 0) ? bq_h : (z == 1) ? bk_h : bv_h;
    const __nv_bfloat16* Bl = (z == 0) ? bq_l : (z == 1) ? bk_l : bv_l;
    const float* bias = (z == 0) ? biq : (z == 1) ? bik : biv;
    __nv_bfloat16* Ch = (z == 0) ? qh : (z == 1) ? kh : vh;
    __nv_bfloat16* Cl = (z == 0) ? ql : (z == 1) ? kl : vl;
    gemm_body(Ahi, Alo, Bh, Bl, bias, (float*)nullptr, Ch, Cl,
              M, N, K, blockIdx.y * 128, blockIdx.x * 128, smem_u32(gsm));
}

__global__ __launch_bounds__(256, 2) void gemm_out(
    const __nv_bfloat16* __restrict__ Ahi, const __nv_bfloat16* __restrict__ Alo,
    const __nv_bfloat16* __restrict__ Bhi, const __nv_bfloat16* __restrict__ Blo,
    const float* __restrict__ bias, float* __restrict__ C,
    int M, int N, int K)
{
    extern __shared__ __nv_bfloat16 gsm[];
    gemm_body(Ahi, Alo, Bhi, Blo, bias, C,
              (__nv_bfloat16*)nullptr, (__nv_bfloat16*)nullptr,
              M, N, K, blockIdx.y * 128, blockIdx.x * 128, smem_u32(gsm));
}

// ---------------------------------------------------------------------------
// Tensor-core flash attention with bit-packed mask + permuted fp16 P stores.
// ---------------------------------------------------------------------------
#define FP 72
#define KVT (64 * FP)
#define FLASH_SMEM ((2 * 128 * FP + 2 * 4 * KVT) * 2)    // 110592 bytes

__global__ __launch_bounds__(256, 2) void flash_mma_kernel(
    const __nv_bfloat16* __restrict__ qhi, const __nv_bfloat16* __restrict__ qlo,
    const __nv_bfloat16* __restrict__ khi, const __nv_bfloat16* __restrict__ klo,
    const __nv_bfloat16* __restrict__ vhi, const __nv_bfloat16* __restrict__ vlo,
    const uint32_t* __restrict__ mbits, __half* __restrict__ P16,
    float* __restrict__ mkt, float* __restrict__ stats,
    __nv_bfloat16* __restrict__ chi, __nv_bfloat16* __restrict__ clo)
{
    extern __shared__ __nv_bfloat16 smb[];
    __nv_bfloat16* sQh = smb;
    __nv_bfloat16* sQl = sQh + 128 * FP;
    __nv_bfloat16* sKV = sQl + 128 * FP;

    const int t = threadIdx.x, lane = t & 31, warp = t >> 5;
    const int bh = blockIdx.y;
    const int b = bh >> 4, h = bh & 15;
    const int q0 = blockIdx.x * 128;

    const uint32_t uQh = smem_u32(sQh), uQl = smem_u32(sQl);
    const uint32_t uKV = smem_u32(sKV);
#define KVB(s, o) (uKV + (uint32_t)(((s) * 4 + (o)) * KVT) * 2)

    for (int i = t; i < 1024; i += 256) {
        const int row = i >> 3, c8 = (i & 7) * 8;
        const size_t g = (size_t)(b * S_ + q0 + row) * D_ + h * 64 + c8;
        const uint32_t so = (uint32_t)(row * FP + c8) * 2;
        cpasync16(uQh + so, &qhi[g]);
        cpasync16(uQl + so, &qlo[g]);
    }

    const int kv_row = t >> 3;
    const int kv_c8  = (t & 7) * 8;
#define LOAD_KV(stage, k0) do {                                               \
    _Pragma("unroll")                                                         \
    for (int rr = 0; rr < 2; rr++) {                                          \
        const int row = kv_row + rr * 32;                                     \
        const size_t g = (size_t)(b * S_ + (k0) + row) * D_ + h * 64 + kv_c8; \
        const uint32_t so = (uint32_t)(row * FP + kv_c8) * 2;                 \
        cpasync16(KVB(stage, 0) + so, &khi[g]);                               \
        cpasync16(KVB(stage, 1) + so, &klo[g]);                               \
        cpasync16(KVB(stage, 2) + so, &vhi[g]);                               \
        cpasync16(KVB(stage, 3) + so, &vlo[g]);                               \
    }                                                                         \
    CP_COMMIT();                                                              \
} while (0)

    LOAD_KV(0, 0);

    float O[8][4];
#pragma unroll
    for (int j = 0; j < 8; j++)
#pragma unroll
        for (int r = 0; r < 4; r++) O[j][r] = 0.f;
    float mr0 = -1e30f, mr1 = -1e30f, lr0 = 0.f, lr1 = 0.f;

    const int row0 = q0 + warp * 16 + (lane >> 2);
    const int row1 = row0 + 8;
    const int col0 = (lane & 3) * 2;
    const int a_r  = warp * 16 + (lane & 15);
    const int a_c  = (lane >> 4) * 8;
    const int b4_row = ((lane >> 4) & 1) * 8 + (lane & 7);
    const int b4_col = ((lane >> 3) & 1) * 8;
    const int t4_row = ((lane >> 3) & 1) * 8 + (lane & 7);
    const int t4_sel = ((lane >> 4) & 1) * 8;

    const uint32_t* mrow0 = &mbits[((size_t)b * S_ + row0) * SW_];
    const uint32_t* mrow1 = &mbits[((size_t)b * S_ + row1) * SW_];

    const int NT = S_ / 64;
    for (int kt = 0; kt < NT; kt++) {
        const int k0 = kt * 64;
        const int cur = kt & 1;
        CP_WAIT0();
        __syncthreads();
        if (kt + 1 < NT) LOAD_KV(cur ^ 1, (kt + 1) * 64);

        const uint32_t uKh = KVB(cur, 0), uKl = KVB(cur, 1);
        const uint32_t uVh = KVB(cur, 2), uVl = KVB(cur, 3);

        // --- QK^T: c[8][4] over 64 k-cols ---
        float c[8][4];
#pragma unroll
        for (int nt = 0; nt < 8; nt++)
#pragma unroll
            for (int r = 0; r < 4; r++) c[nt][r] = 0.f;
#pragma unroll
        for (int ks = 0; ks < 4; ks++) {
            uint32_t qh2[4], ql2[4];
            const uint32_t qo = (uint32_t)(a_r * FP + ks * 16 + a_c) * 2;
            ldmA4(qh2, uQh + qo);
            ldmA4(ql2, uQl + qo);
#pragma unroll
            for (int p = 0; p < 4; p++) {
                uint32_t rh[4], rl[4];
                const uint32_t off = (uint32_t)((p * 16 + b4_row) * FP +
                                                ks * 16 + b4_col) * 2;
                ldmA4(rh, uKh + off);
                ldmA4(rl, uKl + off);
                mma16816(c[2*p],   qh2, rh);
                mma16816(c[2*p],   qh2, rl);
                mma16816(c[2*p],   ql2, rh);
                mma16816(c[2*p+1], qh2, rh + 2);
                mma16816(c[2*p+1], qh2, rl + 2);
                mma16816(c[2*p+1], ql2, rh + 2);
            }
        }

        // --- scale + mask (bit-packed) ---
        {
            const uint2 mw0 = *(const uint2*)&mrow0[k0 >> 5];
            const uint2 mw1 = *(const uint2*)&mrow1[k0 >> 5];
#pragma unroll
            for (int nt = 0; nt < 8; nt++) {
                const int cb = ((nt & 3) * 8 + col0);
                const uint32_t w0 = (nt < 4) ? mw0.x : mw0.y;
                const uint32_t w1 = (nt < 4) ? mw1.x : mw1.y;
                c[nt][0] = ((w0 >> cb) & 1u)       ? c[nt][0] * SCALE_ : -1e9f;
                c[nt][1] = ((w0 >> (cb + 1)) & 1u) ? c[nt][1] * SCALE_ : -1e9f;
                c[nt][2] = ((w1 >> cb) & 1u)       ? c[nt][2] * SCALE_ : -1e9f;
                c[nt][3] = ((w1 >> (cb + 1)) & 1u) ? c[nt][3] * SCALE_ : -1e9f;
            }
        }

        // --- online softmax ---
        float rm0 = -1e30f, rm1 = -1e30f;
#pragma unroll
        for (int nt = 0; nt < 8; nt++) {
            rm0 = fmaxf(rm0, fmaxf(c[nt][0], c[nt][1]));
            rm1 = fmaxf(rm1, fmaxf(c[nt][2], c[nt][3]));
        }
        rm0 = fmaxf(rm0, __shfl_xor_sync(0xffffffffu, rm0, 1));
        rm0 = fmaxf(rm0, __shfl_xor_sync(0xffffffffu, rm0, 2));
        rm1 = fmaxf(rm1, __shfl_xor_sync(0xffffffffu, rm1, 1));
        rm1 = fmaxf(rm1, __shfl_xor_sync(0xffffffffu, rm1, 2));
        const float mn0 = fmaxf(mr0, rm0), mn1 = fmaxf(mr1, rm1);
        const float f0 = fexp(mr0 - mn0), f1 = fexp(mr1 - mn1);
        float rs0 = 0.f, rs1 = 0.f;
#pragma unroll
        for (int nt = 0; nt < 8; nt++) {
            c[nt][0] = fexp(c[nt][0] - mn0);
            c[nt][1] = fexp(c[nt][1] - mn0);
            c[nt][2] = fexp(c[nt][2] - mn1);
            c[nt][3] = fexp(c[nt][3] - mn1);
            rs0 += c[nt][0] + c[nt][1];
            rs1 += c[nt][2] + c[nt][3];
        }
        rs0 += __shfl_xor_sync(0xffffffffu, rs0, 1);
        rs0 += __shfl_xor_sync(0xffffffffu, rs0, 2);
        rs1 += __shfl_xor_sync(0xffffffffu, rs1, 1);
        rs1 += __shfl_xor_sync(0xffffffffu, rs1, 2);
        lr0 = lr0 * f0 + rs0; mr0 = mn0;
        lr1 = lr1 * f1 + rs1; mr1 = mn1;
#pragma unroll
        for (int j = 0; j < 8; j++) {
            O[j][0] *= f0; O[j][1] *= f0;
            O[j][2] *= f1; O[j][3] *= f1;
        }

        // --- stream P (fp16, permuted, warp-contiguous) + m_kt ---
        {
            __half* pb = P16 +
                ((((size_t)bh * 16 + (q0 >> 7)) * 32 + kt) * 8192) +
                warp * 1024 + lane * 2;
#pragma unroll
            for (int nt = 0; nt < 8; nt++) {
                *(__half2*)&pb[nt * 64] =
                    __floats2half2_rn(c[nt][0], c[nt][1]);
                *(__half2*)&pb[(nt + 8) * 64] =
                    __floats2half2_rn(c[nt][2], c[nt][3]);
            }
            if ((lane & 3) == 0) {
                mkt[((size_t)bh * 32 + kt) * S_ + row0] = mn0;
                mkt[((size_t)bh * 32 + kt) * S_ + row1] = mn1;
            }
        }

        // --- P @ V (truncation-split fragments) ---
#pragma unroll
        for (int ks2 = 0; ks2 < 4; ks2++) {
            const float* c0 = c[2 * ks2];
            const float* c1 = c[2 * ks2 + 1];
            uint32_t ah[4], al[4];
            ah[0] = TRUNC_HI2(c0[0], c0[1]);
            ah[1] = TRUNC_HI2(c0[2], c0[3]);
            ah[2] = TRUNC_HI2(c1[0], c1[1]);
            ah[3] = TRUNC_HI2(c1[2], c1[3]);
            al[0] = TRUNC_HI2(trunc_res(c0[0]), trunc_res(c0[1]));
            al[1] = TRUNC_HI2(trunc_res(c0[2]), trunc_res(c0[3]));
            al[2] = TRUNC_HI2(trunc_res(c1[0]), trunc_res(c1[1]));
            al[3] = TRUNC_HI2(trunc_res(c1[2]), trunc_res(c1[3]));
#pragma unroll
            for (int p = 0; p < 4; p++) {
                uint32_t vh4[4], vl4[4];
                const uint32_t off = (uint32_t)((ks2 * 16 + t4_row) * FP +
                                                p * 16 + t4_sel) * 2;
                ldmA4t(vh4, uVh + off);
                ldmA4t(vl4, uVl + off);
                mma16816(O[2*p],   ah, vh4);
                mma16816(O[2*p],   ah, vl4);
                mma16816(O[2*p],   al, vh4);
                mma16816(O[2*p+1], ah, vh4 + 2);
                mma16816(O[2*p+1], ah, vl4 + 2);
                mma16816(O[2*p+1], al, vh4 + 2);
            }
        }
    }

    // --- epilogue: normalized ctx as bf16 hi/lo ---
    const float inv0 = 1.0f / lr0, inv1 = 1.0f / lr1;
#pragma unroll
    for (int nt2 = 0; nt2 < 8; nt2++) {
        const int n = nt2 * 8 + col0;
        const size_t g0 = (size_t)(b * S_ + row0) * D_ + h * 64 + n;
        const size_t g1 = (size_t)(b * S_ + row1) * D_ + h * 64 + n;
        split_store(chi, clo, g0, O[nt2][0] * inv0, O[nt2][1] * inv0);
        split_store(chi, clo, g1, O[nt2][2] * inv1, O[nt2][3] * inv1);
    }
    if ((lane & 3) == 0) {
        size_t si = ((size_t)bh * S_ + row0) * 2;
        stats[si] = mr0; stats[si + 1] = lr0;
        si = ((size_t)bh * S_ + row1) * 2;
        stats[si] = mr1; stats[si + 1] = lr1;
    }
#undef LOAD_KV
#undef KVB
}

// ---------------------------------------------------------------------------
// Pass 2: un-permute fp16 P + normalize (one (bh,qt,kt) chunk per block).
// ---------------------------------------------------------------------------
__global__ __launch_bounds__(256) void normalize_kernel(
    const __half* __restrict__ P16, const float* __restrict__ mkt,
    const float* __restrict__ stats, float* __restrict__ attn)
{
    __shared__ __half sp[8192];
    __shared__ float corr[128];
    const int t  = threadIdx.x;
    const int qt = blockIdx.x >> 5, kt = blockIdx.x & 31;
    const int bh = blockIdx.y;
    const int q0 = qt * 128, k0 = kt * 64;

    if (t < 128) {
        const int row = q0 + t;
        const size_t si = ((size_t)bh * S_ + row) * 2;
        corr[t] = __expf(mkt[((size_t)bh * 32 + kt) * S_ + row] - stats[si]) /
                  stats[si + 1];
    }
    const uint4* src = (const uint4*)(P16 +
        ((((size_t)bh * 16 + qt) * 32 + kt) * 8192));
#pragma unroll
    for (int j = 0; j < 4; j++)
        ((uint4*)sp)[t + j * 256] = src[t + j * 256];
    __syncthreads();

#pragma unroll
    for (int j = 0; j < 8; j++) {
        const int o   = t + j * 256;
        const int row = o >> 4;
        const int c   = (o & 15) * 4;
        const float cr = corr[row];
        float v[4];
#pragma unroll
        for (int e = 0; e < 4; e++) {
            const int ci = c + e;
            const int idx = (row >> 4) * 1024 +
                            ((ci >> 3) + 8 * ((row >> 3) & 1)) * 64 +
                            ((row & 7) * 4 + ((ci & 7) >> 1)) * 2 + (ci & 1);
            v[e] = __half2float(sp[idx]) * cr;
        }
        float4 o4;
        o4.x = v[0]; o4.y = v[1]; o4.z = v[2]; o4.w = v[3];
        *(float4*)&attn[((size_t)bh * S_ + q0 + row) * S_ + k0 + c] = o4;
    }
}

// ---------------------------------------------------------------------------
extern "C" void kernel_launch(void* const* d_in, const int* in_sizes, int n_in,
                              void* d_out, int out_size)
{
    const float* x    = (const float*)d_in[0];
    const int*   mask = (const int*)  d_in[1];
    const float* wq_w = (const float*)d_in[2];
    const float* wq_b = (const float*)d_in[3];
    const float* wk_w = (const float*)d_in[4];
    const float* wk_b = (const float*)d_in[5];
    const float* wv_w = (const float*)d_in[6];
    const float* wv_b = (const float*)d_in[7];
    const float* wo_w = (const float*)d_in[8];
    const float* wo_b = (const float*)d_in[9];

    float *qdump, *attn_raw, *mkt, *stats;
    __half* p16;
    uint32_t* mbits;
    cudaGetSymbolAddress((void**)&qdump,    g_q);
    cudaGetSymbolAddress((void**)&attn_raw, g_attn_raw);
    cudaGetSymbolAddress((void**)&p16,      g_p16);
    cudaGetSymbolAddress((void**)&mkt,      g_mkt);
    cudaGetSymbolAddress((void**)&stats,    g_stats);
    cudaGetSymbolAddress((void**)&mbits,    g_mbits);

    __nv_bfloat16 *xhi, *xlo, *chi, *clo;
    __nv_bfloat16 *qhi_p, *qlo_p, *khi_p, *klo_p, *vhi_p, *vlo_p;
    __nv_bfloat16 *wqhi, *wqlo, *wkhi, *wklo, *wvhi, *wvlo, *wohi, *wolo;
    cudaGetSymbolAddress((void**)&xhi, g_xhi);   cudaGetSymbolAddress((void**)&xlo, g_xlo);
    cudaGetSymbolAddress((void**)&chi, g_chi);   cudaGetSymbolAddress((void**)&clo, g_clo);
    cudaGetSymbolAddress((void**)&qhi_p, g_qhi); cudaGetSymbolAddress((void**)&qlo_p, g_qlo);
    cudaGetSymbolAddress((void**)&khi_p, g_khi); cudaGetSymbolAddress((void**)&klo_p, g_klo);
    cudaGetSymbolAddress((void**)&vhi_p, g_vhi); cudaGetSymbolAddress((void**)&vlo_p, g_vlo);
    cudaGetSymbolAddress((void**)&wqhi, g_wqhi); cudaGetSymbolAddress((void**)&wqlo, g_wqlo);
    cudaGetSymbolAddress((void**)&wkhi, g_wkhi); cudaGetSymbolAddress((void**)&wklo, g_wklo);
    cudaGetSymbolAddress((void**)&wvhi, g_wvhi); cudaGetSymbolAddress((void**)&wvlo, g_wvlo);
    cudaGetSymbolAddress((void**)&wohi, g_wohi); cudaGetSymbolAddress((void**)&wolo, g_wolo);

    const long long CTXSZ = (long long)B_ * S_ * D_;
    const long long ATTSZ = (long long)B_ * H_ * S_ * S_;

    float* out_base = (float*)d_out;
    float* out_ptr;
    float* attn_ptr;
    if ((long long)out_size >= CTXSZ + ATTSZ) {
        out_ptr  = out_base;
        attn_ptr = out_base + CTXSZ;
    } else if ((long long)out_size == ATTSZ) {
        out_ptr  = qdump;
        attn_ptr = out_base;
    } else {
        out_ptr  = out_base;
        attn_ptr = attn_raw;     // fp32 fallback buffer (distinct from p16)
    }

    cudaFuncSetAttribute(flash_mma_kernel,
                         cudaFuncAttributeMaxDynamicSharedMemorySize, FLASH_SMEM);
    cudaFuncSetAttribute(gemm_qkv,
                         cudaFuncAttributeMaxDynamicSharedMemorySize, GEMM_SMEM);
    cudaFuncSetAttribute(gemm_out,
                         cudaFuncAttributeMaxDynamicSharedMemorySize, GEMM_SMEM);

    static cudaStream_t s1 = nullptr;
    static cudaEvent_t evFork = nullptr, evW = nullptr, evMask = nullptr,
                       evJoin = nullptr;
    if (!s1) {
        cudaStreamCreateWithFlags(&s1, cudaStreamNonBlocking);
        cudaEventCreateWithFlags(&evFork, cudaEventDisableTiming);
        cudaEventCreateWithFlags(&evW,    cudaEventDisableTiming);
        cudaEventCreateWithFlags(&evMask, cudaEventDisableTiming);
        cudaEventCreateWithFlags(&evJoin, cudaEventDisableTiming);
    }

    const int M = B_ * S_;   // 4096
    const int N = D_;        // 1024
    const int K = D_;        // 1024

    const int xn4 = (int)(CTXSZ / 4);
    const int wn4 = D_ * D_ / 4;

    // Fork: weight convs + mask pack on s1; x conv on main (all feed later).
    cudaEventRecord(evFork, 0);
    cudaStreamWaitEvent(s1, evFork, 0);
    dim3 wGrid((wn4 + 255) / 256, 4);
    conv_split_w4<<<wGrid, 256, 0, s1>>>(
        (const float4*)wq_w, (uint2*)wqhi, (uint2*)wqlo,
        (const float4*)wk_w, (uint2*)wkhi, (uint2*)wklo,
        (const float4*)wv_w, (uint2*)wvhi, (uint2*)wvlo,
        (const float4*)wo_w, (uint2*)wohi, (uint2*)wolo, wn4);
    cudaEventRecord(evW, s1);
    const int nwords = B_ * S_ * SW_;
    conv_maskbits<<<(nwords + 255) / 256, 256, 0, s1>>>(
        (const int4*)mask, mbits, nwords);
    cudaEventRecord(evMask, s1);

    conv_split<<<(xn4 + 255) / 256, 256>>>((const float4*)x,
                                           (uint2*)xhi, (uint2*)xlo, xn4);
    cudaStreamWaitEvent(0, evW, 0);      // weights ready before qkv

    dim3 qkvGrid(N / 128, M / 128, 3);
    gemm_qkv<<<qkvGrid, 256, GEMM_SMEM>>>(
        xhi, xlo,
        wqhi, wqlo, wkhi, wklo, wvhi, wvlo,
        wq_b, wk_b, wv_b,
        qhi_p, qlo_p, khi_p, klo_p, vhi_p, vlo_p, M, N, K);

    cudaStreamWaitEvent(0, evMask, 0);   // mask ready before flash
    dim3 fGrid(S_ / 128, B_ * H_);
    flash_mma_kernel<<<fGrid, 256, FLASH_SMEM>>>(
        qhi_p, qlo_p, khi_p, klo_p, vhi_p, vlo_p,
        mbits, p16, mkt, stats, chi, clo);

    // Fork: gemm_out on s1, normalize on main.
    cudaEventRecord(evFork, 0);
    cudaStreamWaitEvent(s1, evFork, 0);
    dim3 gGrid(N / 128, M / 128);
    gemm_out<<<gGrid, 256, GEMM_SMEM, s1>>>(chi, clo, wohi, wolo, wo_b,
                                            out_ptr, M, N, K);
    cudaEventRecord(evJoin, s1);

    dim3 nGrid(16 * 32, B_ * H_);
    normalize_kernel<<<nGrid, 256>>>(p16, mkt, stats, attn_ptr);

    cudaStreamWaitEvent(0, evJoin, 0);
}

// round 16
// speedup vs baseline: 2.9458x; 1.0765x over previous
#include <cuda_runtime.h>
#include <cuda_bf16.h>
#include <cuda_fp16.h>
#include <math.h>
#include <stdint.h>

// Problem constants
#define B_  2
#define S_  2048
#define D_  1024
#define H_  16
#define DH_ 64
#define SCALE_ 0.125f   // DH^-0.5
#define SW_ (S_ / 32)   // mask words per row

typedef unsigned long long u64;

// ---------------------------------------------------------------------------
// Scratch (static device globals; no runtime allocation)
// ---------------------------------------------------------------------------
__device__ float g_q[(size_t)B_ * S_ * D_];                 // dummy sink
__device__ float g_attn_raw[(size_t)B_ * H_ * S_ * S_];     // fallback attn (fp32)
__device__ __half g_p16[(size_t)B_ * H_ * S_ * S_];         // P, fp16 permuted
__device__ float g_mkt[(size_t)B_ * H_ * (S_ / 64) * S_];
__device__ float g_stats[(size_t)B_ * H_ * S_ * 2];
__device__ uint32_t g_mbits[(size_t)B_ * S_ * SW_];        // bit-packed mask

// bf16 hi/lo split operands
__device__ __nv_bfloat16 g_xhi[(size_t)B_ * S_ * D_];
__device__ __nv_bfloat16 g_xlo[(size_t)B_ * S_ * D_];
__device__ __nv_bfloat16 g_qhi[(size_t)B_ * S_ * D_], g_qlo[(size_t)B_ * S_ * D_];
__device__ __nv_bfloat16 g_khi[(size_t)B_ * S_ * D_], g_klo[(size_t)B_ * S_ * D_];
__device__ __nv_bfloat16 g_vhi[(size_t)B_ * S_ * D_], g_vlo[(size_t)B_ * S_ * D_];
__device__ __nv_bfloat16 g_chi[(size_t)B_ * S_ * D_], g_clo[(size_t)B_ * S_ * D_];
__device__ __nv_bfloat16 g_wqhi[D_ * D_], g_wqlo[D_ * D_];
__device__ __nv_bfloat16 g_wkhi[D_ * D_], g_wklo[D_ * D_];
__device__ __nv_bfloat16 g_wvhi[D_ * D_], g_wvlo[D_ * D_];
__device__ __nv_bfloat16 g_wohi[D_ * D_], g_wolo[D_ * D_];

// ---------------------------------------------------------------------------
// mma.sync / ldmatrix helpers
// ---------------------------------------------------------------------------
__device__ __forceinline__ uint32_t smem_u32(const void* p) {
    uint32_t a;
    asm("{ .reg .u64 t; cvta.to.shared.u64 t, %1; cvt.u32.u64 %0, t; }"
        : "=r"(a) : "l"(p));
    return a;
}
__device__ __forceinline__ void ldmA4(uint32_t* a, uint32_t addr) {
    asm volatile("ldmatrix.sync.aligned.m8n8.x4.shared.b16 {%0,%1,%2,%3}, [%4];"
                 : "=r"(a[0]), "=r"(a[1]), "=r"(a[2]), "=r"(a[3]) : "r"(addr));
}
__device__ __forceinline__ void ldmA4t(uint32_t* a, uint32_t addr) {
    asm volatile("ldmatrix.sync.aligned.m8n8.x4.trans.shared.b16 {%0,%1,%2,%3}, [%4];"
                 : "=r"(a[0]), "=r"(a[1]), "=r"(a[2]), "=r"(a[3]) : "r"(addr));
}
__device__ __forceinline__ void mma16816(float* c, const uint32_t* a,
                                         const uint32_t* b) {
    asm volatile(
        "mma.sync.aligned.m16n8k16.row.col.f32.bf16.bf16.f32 "
        "{%0,%1,%2,%3}, {%4,%5,%6,%7}, {%8,%9}, {%0,%1,%2,%3};"
        : "+f"(c[0]), "+f"(c[1]), "+f"(c[2]), "+f"(c[3])
        : "r"(a[0]), "r"(a[1]), "r"(a[2]), "r"(a[3]), "r"(b[0]), "r"(b[1]));
}
__device__ __forceinline__ void cpasync16(uint32_t saddr, const void* gaddr) {
    asm volatile("cp.async.cg.shared.global [%0], [%1], 16;"
                 :: "r"(saddr), "l"(gaddr));
}
#define CP_COMMIT() asm volatile("cp.async.commit_group;" ::: "memory")
#define CP_WAIT0()  asm volatile("cp.async.wait_group 0;" ::: "memory")
#define CP_WAIT1()  asm volatile("cp.async.wait_group 1;" ::: "memory")

__device__ __forceinline__ uint32_t pack_bf2(float x, float y) {
    return (uint32_t)__bfloat16_as_ushort(__float2bfloat16(x)) |
           ((uint32_t)__bfloat16_as_ushort(__float2bfloat16(y)) << 16);
}
#define TRUNC_HI2(x, y) __byte_perm(__float_as_uint(x), __float_as_uint(y), 0x7632)
__device__ __forceinline__ float trunc_res(float x) {
    return x - __uint_as_float(__float_as_uint(x) & 0xFFFF0000u);
}
__device__ __forceinline__ void split_store(
    __nv_bfloat16* hi, __nv_bfloat16* lo, size_t idx, float x, float y)
{
    const __nv_bfloat16 hx = __float2bfloat16(x), hy = __float2bfloat16(y);
    *(uint32_t*)&hi[idx] = (uint32_t)__bfloat16_as_ushort(hx) |
                           ((uint32_t)__bfloat16_as_ushort(hy) << 16);
    *(uint32_t*)&lo[idx] = pack_bf2(x - __bfloat162float(hx),
                                    y - __bfloat162float(hy));
}
__device__ __forceinline__ float fexp(float x) { return __expf(x); }

// ---------------------------------------------------------------------------
// Split-conversions
// ---------------------------------------------------------------------------
__global__ __launch_bounds__(256) void conv_split(
    const float4* __restrict__ src, uint2* __restrict__ hi,
    uint2* __restrict__ lo, int n4)
{
    const int i = blockIdx.x * 256 + threadIdx.x;
    if (i >= n4) return;
    const float4 v = src[i];
    split_store((__nv_bfloat16*)hi, (__nv_bfloat16*)lo, (size_t)i * 4,     v.x, v.y);
    split_store((__nv_bfloat16*)hi, (__nv_bfloat16*)lo, (size_t)i * 4 + 2, v.z, v.w);
}

__global__ __launch_bounds__(256) void conv_split_w4(
    const float4* s0, uint2* h0, uint2* l0,
    const float4* s1, uint2* h1, uint2* l1,
    const float4* s2, uint2* h2, uint2* l2,
    const float4* s3, uint2* h3, uint2* l3, int n4)
{
    const int i = blockIdx.x * 256 + threadIdx.x;
    if (i >= n4) return;
    const int w = blockIdx.y;
    const float4* src = (w == 0) ? s0 : (w == 1) ? s1 : (w == 2) ? s2 : s3;
    uint2* hi = (w == 0) ? h0 : (w == 1) ? h1 : (w == 2) ? h2 : h3;
    uint2* lo = (w == 0) ? l0 : (w == 1) ? l1 : (w == 2) ? l2 : l3;
    const float4 v = src[i];
    split_store((__nv_bfloat16*)hi, (__nv_bfloat16*)lo, (size_t)i * 4,     v.x, v.y);
    split_store((__nv_bfloat16*)hi, (__nv_bfloat16*)lo, (size_t)i * 4 + 2, v.z, v.w);
}

// Pack mask (int32 per element) into 1 bit per element.
__global__ __launch_bounds__(256) void conv_maskbits(
    const int4* __restrict__ mask, uint32_t* __restrict__ mbits, int nwords)
{
    const int w = blockIdx.x * 256 + threadIdx.x;
    if (w >= nwords) return;
    const int4* src = mask + (size_t)w * 8;
    uint32_t bits = 0;
#pragma unroll
    for (int j = 0; j < 8; j++) {
        const int4 v = src[j];
        bits |= (v.x != 0 ? 1u : 0u) << (j * 4 + 0);
        bits |= (v.y != 0 ? 1u : 0u) << (j * 4 + 1);
        bits |= (v.z != 0 ? 1u : 0u) << (j * 4 + 2);
        bits |= (v.w != 0 ? 1u : 0u) << (j * 4 + 3);
    }
    mbits[w] = bits;
}

// ---------------------------------------------------------------------------
// Shared GEMM body: 3-term fused K-loop, BK=32, 2-stage pipeline, 2 CTAs/SM.
// ---------------------------------------------------------------------------
#define GP 40
#define GTILE (128 * GP)
#define GEMM_SMEM (2 * 4 * GTILE * 2)          // 81920 bytes

__device__ __forceinline__ void gemm_body(
    const __nv_bfloat16* __restrict__ Ahi, const __nv_bfloat16* __restrict__ Alo,
    const __nv_bfloat16* __restrict__ Bhi, const __nv_bfloat16* __restrict__ Blo,
    const float* __restrict__ bias, float* __restrict__ C,
    __nv_bfloat16* __restrict__ Chi, __nv_bfloat16* __restrict__ Clo,
    int M, int N, int K, int bm, int bn, uint32_t sb)
{
    const int tid  = threadIdx.x;
    const int lane = tid & 31, wid = tid >> 5;
    const int warp_m = wid >> 2, warp_n = wid & 3;

    const int a_r = warp_m * 64 + (lane & 15);
    const int a_c = (lane >> 4) * 8;
    const int b4_row = ((lane >> 4) & 1) * 8 + (lane & 7);
    const int b4_col = ((lane >> 3) & 1) * 8;

    const int lrow = tid >> 2;          // 0..63
    const int lc8  = (tid & 3) * 8;

    float acc[4][4][4];
#pragma unroll
    for (int mt = 0; mt < 4; mt++)
#pragma unroll
        for (int nt = 0; nt < 4; nt++)
#pragma unroll
            for (int r = 0; r < 4; r++) acc[mt][nt][r] = 0.f;

#define TBASE(s, o) (sb + (uint32_t)(((s) * 4 + (o)) * GTILE) * 2)
#define LOAD_STAGE(s, k0) do {                                                \
    const uint32_t _dAh = TBASE(s, 0), _dAl = TBASE(s, 1);                    \
    const uint32_t _dBh = TBASE(s, 2), _dBl = TBASE(s, 3);                    \
    _Pragma("unroll")                                                         \
    for (int rr = 0; rr < 2; rr++) {                                          \
        const int row = lrow + rr * 64;                                       \
        const uint32_t so = (uint32_t)(row * GP + lc8) * 2;                   \
        const size_t ga = (size_t)(bm + row) * K + (k0) + lc8;                \
        const size_t gb = (size_t)(bn + row) * K + (k0) + lc8;                \
        cpasync16(_dAh + so, &Ahi[ga]);                                       \
        cpasync16(_dAl + so, &Alo[ga]);                                       \
        cpasync16(_dBh + so, &Bhi[gb]);                                       \
        cpasync16(_dBl + so, &Blo[gb]);                                       \
    }                                                                         \
    CP_COMMIT();                                                              \
} while (0)

    LOAD_STAGE(0, 0);

    const int NK = K / 32;
    for (int kc = 0; kc < NK; kc++) {
        const int cur = kc & 1;
        if (kc + 1 < NK) { LOAD_STAGE(cur ^ 1, (kc + 1) * 32); CP_WAIT1(); }
        else             { CP_WAIT0(); }
        __syncthreads();

        const uint32_t uAh = TBASE(cur, 0), uAl = TBASE(cur, 1);
        const uint32_t uBh = TBASE(cur, 2), uBl = TBASE(cur, 3);
#pragma unroll
        for (int ks = 0; ks < 2; ks++) {
            uint32_t ah[4][4], al[4][4];
#pragma unroll
            for (int mt = 0; mt < 4; mt++) {
                const uint32_t ao = (uint32_t)((a_r + mt * 16) * GP +
                                               ks * 16 + a_c) * 2;
                ldmA4(ah[mt], uAh + ao);
                ldmA4(al[mt], uAl + ao);
            }
            uint32_t bh[4][2], bl[4][2];
#pragma unroll
            for (int p = 0; p < 2; p++) {
                uint32_t r4[4];
                const uint32_t bo = (uint32_t)((warp_n * 32 + p * 16 + b4_row) * GP +
                                               ks * 16 + b4_col) * 2;
                ldmA4(r4, uBh + bo);
                bh[2*p][0] = r4[0]; bh[2*p][1] = r4[1];
                bh[2*p+1][0] = r4[2]; bh[2*p+1][1] = r4[3];
                ldmA4(r4, uBl + bo);
                bl[2*p][0] = r4[0]; bl[2*p][1] = r4[1];
                bl[2*p+1][0] = r4[2]; bl[2*p+1][1] = r4[3];
            }
#pragma unroll
            for (int mt = 0; mt < 4; mt++)
#pragma unroll
                for (int nt = 0; nt < 4; nt++) {
                    mma16816(acc[mt][nt], ah[mt], bh[nt]);
                    mma16816(acc[mt][nt], ah[mt], bl[nt]);
                    mma16816(acc[mt][nt], al[mt], bh[nt]);
                }
        }
        __syncthreads();
    }

    const int em = bm + warp_m * 64 + (lane >> 2);
    const int en = bn + warp_n * 32 + (lane & 3) * 2;
#pragma unroll
    for (int mt = 0; mt < 4; mt++) {
#pragma unroll
        for (int nt = 0; nt < 4; nt++) {
            const int n = en + nt * 8;
            const float bx = bias[n], by = bias[n + 1];
            const int m0 = em + mt * 16;
            float2 o0, o1;
            o0.x = acc[mt][nt][0] + bx; o0.y = acc[mt][nt][1] + by;
            o1.x = acc[mt][nt][2] + bx; o1.y = acc[mt][nt][3] + by;
            if (C) {
                *(float2*)&C[(size_t)m0 * N + n]       = o0;
                *(float2*)&C[(size_t)(m0 + 8) * N + n] = o1;
            }
            if (Chi) {
                split_store(Chi, Clo, (size_t)m0 * N + n,       o0.x, o0.y);
                split_store(Chi, Clo, (size_t)(m0 + 8) * N + n, o1.x, o1.y);
            }
        }
    }
#undef LOAD_STAGE
#undef TBASE
}

__global__ __launch_bounds__(256, 2) void gemm_qkv(
    const __nv_bfloat16* __restrict__ Ahi, const __nv_bfloat16* __restrict__ Alo,
    const __nv_bfloat16* bq_h, const __nv_bfloat16* bq_l,
    const __nv_bfloat16* bk_h, const __nv_bfloat16* bk_l,
    const __nv_bfloat16* bv_h, const __nv_bfloat16* bv_l,
    const float* biq, const float* bik, const float* biv,
    __nv_bfloat16* qh, __nv_bfloat16* ql,
    __nv_bfloat16* kh, __nv_bfloat16* kl,
    __nv_bfloat16* vh, __nv_bfloat16* vl,
    int M, int N, int K)
{
    extern __shared__ __nv_bfloat16 gsm[];
    const int z = blockIdx.z;
    const __nv_bfloat16* Bh = (z == 0) ? bq_h : (z == 1) ? bk_h : bv_h;
    const __nv_bfloat16* Bl = (z == 0) ? bq_l : (z == 1) ? bk_l : bv_l;
    const float* bias = (z == 0) ? biq : (z == 1) ? bik : biv;
    __nv_bfloat16* Ch = (z == 0) ? qh : (z == 1) ? kh : vh;
    __nv_bfloat16* Cl = (z == 0) ? ql : (z == 1) ? kl : vl;
    gemm_body(Ahi, Alo, Bh, Bl, bias, (float*)nullptr, Ch, Cl,
              M, N, K, blockIdx.y * 128, blockIdx.x * 128, smem_u32(gsm));
}

__global__ __launch_bounds__(256, 2) void gemm_out(
    const __nv_bfloat16* __restrict__ Ahi, const __nv_bfloat16* __restrict__ Alo,
    const __nv_bfloat16* __restrict__ Bhi, const __nv_bfloat16* __restrict__ Blo,
    const float* __restrict__ bias, float* __restrict__ C,
    int M, int N, int K)
{
    extern __shared__ __nv_bfloat16 gsm[];
    gemm_body(Ahi, Alo, Bhi, Blo, bias, C,
              (__nv_bfloat16*)nullptr, (__nv_bfloat16*)nullptr,
              M, N, K, blockIdx.y * 128, blockIdx.x * 128, smem_u32(gsm));
}

// ---------------------------------------------------------------------------
// Tensor-core flash attention (bit-packed mask, permuted fp16 P, bh-chunked).
// ---------------------------------------------------------------------------
#define FP 72
#define KVT (64 * FP)
#define FLASH_SMEM ((2 * 128 * FP + 2 * 4 * KVT) * 2)    // 110592 bytes

__global__ __launch_bounds__(256, 2) void flash_mma_kernel(
    const __nv_bfloat16* __restrict__ qhi, const __nv_bfloat16* __restrict__ qlo,
    const __nv_bfloat16* __restrict__ khi, const __nv_bfloat16* __restrict__ klo,
    const __nv_bfloat16* __restrict__ vhi, const __nv_bfloat16* __restrict__ vlo,
    const uint32_t* __restrict__ mbits, __half* __restrict__ P16,
    float* __restrict__ mkt, float* __restrict__ stats,
    __nv_bfloat16* __restrict__ chi, __nv_bfloat16* __restrict__ clo,
    int bhOff)
{
    extern __shared__ __nv_bfloat16 smb[];
    __nv_bfloat16* sQh = smb;
    __nv_bfloat16* sQl = sQh + 128 * FP;
    __nv_bfloat16* sKV = sQl + 128 * FP;

    const int t = threadIdx.x, lane = t & 31, warp = t >> 5;
    const int bh = blockIdx.y + bhOff;
    const int b = bh >> 4, h = bh & 15;
    const int q0 = blockIdx.x * 128;

    const uint32_t uQh = smem_u32(sQh), uQl = smem_u32(sQl);
    const uint32_t uKV = smem_u32(sKV);
#define KVB(s, o) (uKV + (uint32_t)(((s) * 4 + (o)) * KVT) * 2)

    for (int i = t; i < 1024; i += 256) {
        const int row = i >> 3, c8 = (i & 7) * 8;
        const size_t g = (size_t)(b * S_ + q0 + row) * D_ + h * 64 + c8;
        const uint32_t so = (uint32_t)(row * FP + c8) * 2;
        cpasync16(uQh + so, &qhi[g]);
        cpasync16(uQl + so, &qlo[g]);
    }

    const int kv_row = t >> 3;
    const int kv_c8  = (t & 7) * 8;
#define LOAD_KV(stage, k0) do {                                               \
    _Pragma("unroll")                                                         \
    for (int rr = 0; rr < 2; rr++) {                                          \
        const int row = kv_row + rr * 32;                                     \
        const size_t g = (size_t)(b * S_ + (k0) + row) * D_ + h * 64 + kv_c8; \
        const uint32_t so = (uint32_t)(row * FP + kv_c8) * 2;                 \
        cpasync16(KVB(stage, 0) + so, &khi[g]);                               \
        cpasync16(KVB(stage, 1) + so, &klo[g]);                               \
        cpasync16(KVB(stage, 2) + so, &vhi[g]);                               \
        cpasync16(KVB(stage, 3) + so, &vlo[g]);                               \
    }                                                                         \
    CP_COMMIT();                                                              \
} while (0)

    LOAD_KV(0, 0);

    float O[8][4];
#pragma unroll
    for (int j = 0; j < 8; j++)
#pragma unroll
        for (int r = 0; r < 4; r++) O[j][r] = 0.f;
    float mr0 = -1e30f, mr1 = -1e30f, lr0 = 0.f, lr1 = 0.f;

    const int row0 = q0 + warp * 16 + (lane >> 2);
    const int row1 = row0 + 8;
    const int col0 = (lane & 3) * 2;
    const int a_r  = warp * 16 + (lane & 15);
    const int a_c  = (lane >> 4) * 8;
    const int b4_row = ((lane >> 4) & 1) * 8 + (lane & 7);
    const int b4_col = ((lane >> 3) & 1) * 8;
    const int t4_row = ((lane >> 3) & 1) * 8 + (lane & 7);
    const int t4_sel = ((lane >> 4) & 1) * 8;

    const uint32_t* mrow0 = &mbits[((size_t)b * S_ + row0) * SW_];
    const uint32_t* mrow1 = &mbits[((size_t)b * S_ + row1) * SW_];

    const int NT = S_ / 64;
    for (int kt = 0; kt < NT; kt++) {
        const int k0 = kt * 64;
        const int cur = kt & 1;
        CP_WAIT0();
        __syncthreads();
        if (kt + 1 < NT) LOAD_KV(cur ^ 1, (kt + 1) * 64);

        const uint32_t uKh = KVB(cur, 0), uKl = KVB(cur, 1);
        const uint32_t uVh = KVB(cur, 2), uVl = KVB(cur, 3);

        // --- QK^T ---
        float c[8][4];
#pragma unroll
        for (int nt = 0; nt < 8; nt++)
#pragma unroll
            for (int r = 0; r < 4; r++) c[nt][r] = 0.f;
#pragma unroll
        for (int ks = 0; ks < 4; ks++) {
            uint32_t qh2[4], ql2[4];
            const uint32_t qo = (uint32_t)(a_r * FP + ks * 16 + a_c) * 2;
            ldmA4(qh2, uQh + qo);
            ldmA4(ql2, uQl + qo);
#pragma unroll
            for (int p = 0; p < 4; p++) {
                uint32_t rh[4], rl[4];
                const uint32_t off = (uint32_t)((p * 16 + b4_row) * FP +
                                                ks * 16 + b4_col) * 2;
                ldmA4(rh, uKh + off);
                ldmA4(rl, uKl + off);
                mma16816(c[2*p],   qh2, rh);
                mma16816(c[2*p],   qh2, rl);
                mma16816(c[2*p],   ql2, rh);
                mma16816(c[2*p+1], qh2, rh + 2);
                mma16816(c[2*p+1], qh2, rl + 2);
                mma16816(c[2*p+1], ql2, rh + 2);
            }
        }

        // --- scale + mask (bit-packed) ---
        {
            const uint2 mw0 = *(const uint2*)&mrow0[k0 >> 5];
            const uint2 mw1 = *(const uint2*)&mrow1[k0 >> 5];
#pragma unroll
            for (int nt = 0; nt < 8; nt++) {
                const int cb = ((nt & 3) * 8 + col0);
                const uint32_t w0 = (nt < 4) ? mw0.x : mw0.y;
                const uint32_t w1 = (nt < 4) ? mw1.x : mw1.y;
                c[nt][0] = ((w0 >> cb) & 1u)       ? c[nt][0] * SCALE_ : -1e9f;
                c[nt][1] = ((w0 >> (cb + 1)) & 1u) ? c[nt][1] * SCALE_ : -1e9f;
                c[nt][2] = ((w1 >> cb) & 1u)       ? c[nt][2] * SCALE_ : -1e9f;
                c[nt][3] = ((w1 >> (cb + 1)) & 1u) ? c[nt][3] * SCALE_ : -1e9f;
            }
        }

        // --- online softmax ---
        float rm0 = -1e30f, rm1 = -1e30f;
#pragma unroll
        for (int nt = 0; nt < 8; nt++) {
            rm0 = fmaxf(rm0, fmaxf(c[nt][0], c[nt][1]));
            rm1 = fmaxf(rm1, fmaxf(c[nt][2], c[nt][3]));
        }
        rm0 = fmaxf(rm0, __shfl_xor_sync(0xffffffffu, rm0, 1));
        rm0 = fmaxf(rm0, __shfl_xor_sync(0xffffffffu, rm0, 2));
        rm1 = fmaxf(rm1, __shfl_xor_sync(0xffffffffu, rm1, 1));
        rm1 = fmaxf(rm1, __shfl_xor_sync(0xffffffffu, rm1, 2));
        const float mn0 = fmaxf(mr0, rm0), mn1 = fmaxf(mr1, rm1);
        const float f0 = fexp(mr0 - mn0), f1 = fexp(mr1 - mn1);
        float rs0 = 0.f, rs1 = 0.f;
#pragma unroll
        for (int nt = 0; nt < 8; nt++) {
            c[nt][0] = fexp(c[nt][0] - mn0);
            c[nt][1] = fexp(c[nt][1] - mn0);
            c[nt][2] = fexp(c[nt][2] - mn1);
            c[nt][3] = fexp(c[nt][3] - mn1);
            rs0 += c[nt][0] + c[nt][1];
            rs1 += c[nt][2] + c[nt][3];
        }
        rs0 += __shfl_xor_sync(0xffffffffu, rs0, 1);
        rs0 += __shfl_xor_sync(0xffffffffu, rs0, 2);
        rs1 += __shfl_xor_sync(0xffffffffu, rs1, 1);
        rs1 += __shfl_xor_sync(0xffffffffu, rs1, 2);
        lr0 = lr0 * f0 + rs0; mr0 = mn0;
        lr1 = lr1 * f1 + rs1; mr1 = mn1;
#pragma unroll
        for (int j = 0; j < 8; j++) {
            O[j][0] *= f0; O[j][1] *= f0;
            O[j][2] *= f1; O[j][3] *= f1;
        }

        // --- stream P (fp16, permuted, warp-contiguous) + m_kt ---
        {
            __half* pb = P16 +
                ((((size_t)bh * 16 + (q0 >> 7)) * 32 + kt) * 8192) +
                warp * 1024 + lane * 2;
#pragma unroll
            for (int nt = 0; nt < 8; nt++) {
                *(__half2*)&pb[nt * 64] =
                    __floats2half2_rn(c[nt][0], c[nt][1]);
                *(__half2*)&pb[(nt + 8) * 64] =
                    __floats2half2_rn(c[nt][2], c[nt][3]);
            }
            if ((lane & 3) == 0) {
                mkt[((size_t)bh * 32 + kt) * S_ + row0] = mn0;
                mkt[((size_t)bh * 32 + kt) * S_ + row1] = mn1;
            }
        }

        // --- P @ V (truncation-split fragments) ---
#pragma unroll
        for (int ks2 = 0; ks2 < 4; ks2++) {
            const float* c0 = c[2 * ks2];
            const float* c1 = c[2 * ks2 + 1];
            uint32_t ah[4], al[4];
            ah[0] = TRUNC_HI2(c0[0], c0[1]);
            ah[1] = TRUNC_HI2(c0[2], c0[3]);
            ah[2] = TRUNC_HI2(c1[0], c1[1]);
            ah[3] = TRUNC_HI2(c1[2], c1[3]);
            al[0] = TRUNC_HI2(trunc_res(c0[0]), trunc_res(c0[1]));
            al[1] = TRUNC_HI2(trunc_res(c0[2]), trunc_res(c0[3]));
            al[2] = TRUNC_HI2(trunc_res(c1[0]), trunc_res(c1[1]));
            al[3] = TRUNC_HI2(trunc_res(c1[2]), trunc_res(c1[3]));
#pragma unroll
            for (int p = 0; p < 4; p++) {
                uint32_t vh4[4], vl4[4];
                const uint32_t off = (uint32_t)((ks2 * 16 + t4_row) * FP +
                                                p * 16 + t4_sel) * 2;
                ldmA4t(vh4, uVh + off);
                ldmA4t(vl4, uVl + off);
                mma16816(O[2*p],   ah, vh4);
                mma16816(O[2*p],   ah, vl4);
                mma16816(O[2*p],   al, vh4);
                mma16816(O[2*p+1], ah, vh4 + 2);
                mma16816(O[2*p+1], ah, vl4 + 2);
                mma16816(O[2*p+1], al, vh4 + 2);
            }
        }
    }

    // --- epilogue: normalized ctx as bf16 hi/lo ---
    const float inv0 = 1.0f / lr0, inv1 = 1.0f / lr1;
#pragma unroll
    for (int nt2 = 0; nt2 < 8; nt2++) {
        const int n = nt2 * 8 + col0;
        const size_t g0 = (size_t)(b * S_ + row0) * D_ + h * 64 + n;
        const size_t g1 = (size_t)(b * S_ + row1) * D_ + h * 64 + n;
        split_store(chi, clo, g0, O[nt2][0] * inv0, O[nt2][1] * inv0);
        split_store(chi, clo, g1, O[nt2][2] * inv1, O[nt2][3] * inv1);
    }
    if ((lane & 3) == 0) {
        size_t si = ((size_t)bh * S_ + row0) * 2;
        stats[si] = mr0; stats[si + 1] = lr0;
        si = ((size_t)bh * S_ + row1) * 2;
        stats[si] = mr1; stats[si + 1] = lr1;
    }
#undef LOAD_KV
#undef KVB
}

// ---------------------------------------------------------------------------
// Pass 2: un-permute fp16 P + normalize (bh-chunked).
// ---------------------------------------------------------------------------
__global__ __launch_bounds__(256) void normalize_kernel(
    const __half* __restrict__ P16, const float* __restrict__ mkt,
    const float* __restrict__ stats, float* __restrict__ attn, int bhOff)
{
    __shared__ __half sp[8192];
    __shared__ float corr[128];
    const int t  = threadIdx.x;
    const int qt = blockIdx.x >> 5, kt = blockIdx.x & 31;
    const int bh = blockIdx.y + bhOff;
    const int q0 = qt * 128, k0 = kt * 64;

    if (t < 128) {
        const int row = q0 + t;
        const size_t si = ((size_t)bh * S_ + row) * 2;
        corr[t] = __expf(mkt[((size_t)bh * 32 + kt) * S_ + row] - stats[si]) /
                  stats[si + 1];
    }
    const uint4* src = (const uint4*)(P16 +
        ((((size_t)bh * 16 + qt) * 32 + kt) * 8192));
#pragma unroll
    for (int j = 0; j < 4; j++)
        ((uint4*)sp)[t + j * 256] = src[t + j * 256];
    __syncthreads();

#pragma unroll
    for (int j = 0; j < 8; j++) {
        const int o   = t + j * 256;
        const int row = o >> 4;
        const int c   = (o & 15) * 4;
        const float cr = corr[row];
        float v[4];
#pragma unroll
        for (int e = 0; e < 4; e++) {
            const int ci = c + e;
            const int idx = (row >> 4) * 1024 +
                            ((ci >> 3) + 8 * ((row >> 3) & 1)) * 64 +
                            ((row & 7) * 4 + ((ci & 7) >> 1)) * 2 + (ci & 1);
            v[e] = __half2float(sp[idx]) * cr;
        }
        float4 o4;
        o4.x = v[0]; o4.y = v[1]; o4.z = v[2]; o4.w = v[3];
        *(float4*)&attn[((size_t)bh * S_ + q0 + row) * S_ + k0 + c] = o4;
    }
}

// ---------------------------------------------------------------------------
extern "C" void kernel_launch(void* const* d_in, const int* in_sizes, int n_in,
                              void* d_out, int out_size)
{
    const float* x    = (const float*)d_in[0];
    const int*   mask = (const int*)  d_in[1];
    const float* wq_w = (const float*)d_in[2];
    const float* wq_b = (const float*)d_in[3];
    const float* wk_w = (const float*)d_in[4];
    const float* wk_b = (const float*)d_in[5];
    const float* wv_w = (const float*)d_in[6];
    const float* wv_b = (const float*)d_in[7];
    const float* wo_w = (const float*)d_in[8];
    const float* wo_b = (const float*)d_in[9];

    float *qdump, *attn_raw, *mkt, *stats;
    __half* p16;
    uint32_t* mbits;
    cudaGetSymbolAddress((void**)&qdump,    g_q);
    cudaGetSymbolAddress((void**)&attn_raw, g_attn_raw);
    cudaGetSymbolAddress((void**)&p16,      g_p16);
    cudaGetSymbolAddress((void**)&mkt,      g_mkt);
    cudaGetSymbolAddress((void**)&stats,    g_stats);
    cudaGetSymbolAddress((void**)&mbits,    g_mbits);

    __nv_bfloat16 *xhi, *xlo, *chi, *clo;
    __nv_bfloat16 *qhi_p, *qlo_p, *khi_p, *klo_p, *vhi_p, *vlo_p;
    __nv_bfloat16 *wqhi, *wqlo, *wkhi, *wklo, *wvhi, *wvlo, *wohi, *wolo;
    cudaGetSymbolAddress((void**)&xhi, g_xhi);   cudaGetSymbolAddress((void**)&xlo, g_xlo);
    cudaGetSymbolAddress((void**)&chi, g_chi);   cudaGetSymbolAddress((void**)&clo, g_clo);
    cudaGetSymbolAddress((void**)&qhi_p, g_qhi); cudaGetSymbolAddress((void**)&qlo_p, g_qlo);
    cudaGetSymbolAddress((void**)&khi_p, g_khi); cudaGetSymbolAddress((void**)&klo_p, g_klo);
    cudaGetSymbolAddress((void**)&vhi_p, g_vhi); cudaGetSymbolAddress((void**)&vlo_p, g_vlo);
    cudaGetSymbolAddress((void**)&wqhi, g_wqhi); cudaGetSymbolAddress((void**)&wqlo, g_wqlo);
    cudaGetSymbolAddress((void**)&wkhi, g_wkhi); cudaGetSymbolAddress((void**)&wklo, g_wklo);
    cudaGetSymbolAddress((void**)&wvhi, g_wvhi); cudaGetSymbolAddress((void**)&wvlo, g_wvlo);
    cudaGetSymbolAddress((void**)&wohi, g_wohi); cudaGetSymbolAddress((void**)&wolo, g_wolo);

    const long long CTXSZ = (long long)B_ * S_ * D_;
    const long long ATTSZ = (long long)B_ * H_ * S_ * S_;

    float* out_base = (float*)d_out;
    float* out_ptr;
    float* attn_ptr;
    if ((long long)out_size >= CTXSZ + ATTSZ) {
        out_ptr  = out_base;
        attn_ptr = out_base + CTXSZ;
    } else if ((long long)out_size == ATTSZ) {
        out_ptr  = qdump;
        attn_ptr = out_base;
    } else {
        out_ptr  = out_base;
        attn_ptr = attn_raw;
    }

    cudaFuncSetAttribute(flash_mma_kernel,
                         cudaFuncAttributeMaxDynamicSharedMemorySize, FLASH_SMEM);
    cudaFuncSetAttribute(gemm_qkv,
                         cudaFuncAttributeMaxDynamicSharedMemorySize, GEMM_SMEM);
    cudaFuncSetAttribute(gemm_out,
                         cudaFuncAttributeMaxDynamicSharedMemorySize, GEMM_SMEM);

    static cudaStream_t s1 = nullptr;
    static cudaEvent_t evFork = nullptr, evW = nullptr, evMask = nullptr,
                       evF1 = nullptr, evF2 = nullptr, evJoin = nullptr;
    if (!s1) {
        cudaStreamCreateWithFlags(&s1, cudaStreamNonBlocking);
        cudaEventCreateWithFlags(&evFork, cudaEventDisableTiming);
        cudaEventCreateWithFlags(&evW,    cudaEventDisableTiming);
        cudaEventCreateWithFlags(&evMask, cudaEventDisableTiming);
        cudaEventCreateWithFlags(&evF1,   cudaEventDisableTiming);
        cudaEventCreateWithFlags(&evF2,   cudaEventDisableTiming);
        cudaEventCreateWithFlags(&evJoin, cudaEventDisableTiming);
    }

    const int M = B_ * S_;   // 4096
    const int N = D_;        // 1024
    const int K = D_;        // 1024

    const int xn4 = (int)(CTXSZ / 4);
    const int wn4 = D_ * D_ / 4;

    // Fork: weight convs + mask pack on s1; x conv on main.
    cudaEventRecord(evFork, 0);
    cudaStreamWaitEvent(s1, evFork, 0);
    dim3 wGrid((wn4 + 255) / 256, 4);
    conv_split_w4<<<wGrid, 256, 0, s1>>>(
        (const float4*)wq_w, (uint2*)wqhi, (uint2*)wqlo,
        (const float4*)wk_w, (uint2*)wkhi, (uint2*)wklo,
        (const float4*)wv_w, (uint2*)wvhi, (uint2*)wvlo,
        (const float4*)wo_w, (uint2*)wohi, (uint2*)wolo, wn4);
    cudaEventRecord(evW, s1);
    const int nwords = B_ * S_ * SW_;
    conv_maskbits<<<(nwords + 255) / 256, 256, 0, s1>>>(
        (const int4*)mask, mbits, nwords);
    cudaEventRecord(evMask, s1);

    conv_split<<<(xn4 + 255) / 256, 256>>>((const float4*)x,
                                           (uint2*)xhi, (uint2*)xlo, xn4);
    cudaStreamWaitEvent(0, evW, 0);

    dim3 qkvGrid(N / 128, M / 128, 3);
    gemm_qkv<<<qkvGrid, 256, GEMM_SMEM>>>(
        xhi, xlo,
        wqhi, wqlo, wkhi, wklo, wvhi, wvlo,
        wq_b, wk_b, wv_b,
        qhi_p, qlo_p, khi_p, klo_p, vhi_p, vlo_p, M, N, K);

    cudaStreamWaitEvent(0, evMask, 0);

    // Flash chunk 1 (bh 0..15)
    dim3 fGrid(S_ / 128, 16);
    flash_mma_kernel<<<fGrid, 256, FLASH_SMEM>>>(
        qhi_p, qlo_p, khi_p, klo_p, vhi_p, vlo_p,
        mbits, p16, mkt, stats, chi, clo, 0);
    cudaEventRecord(evF1, 0);

    // s1: normalize chunk 1 overlaps flash chunk 2.
    cudaStreamWaitEvent(s1, evF1, 0);
    dim3 nGrid(16 * 32, 16);
    normalize_kernel<<<nGrid, 256, 0, s1>>>(p16, mkt, stats, attn_ptr, 0);

    // Flash chunk 2 (bh 16..31)
    flash_mma_kernel<<<fGrid, 256, FLASH_SMEM>>>(
        qhi_p, qlo_p, khi_p, klo_p, vhi_p, vlo_p,
        mbits, p16, mkt, stats, chi, clo, 16);
    cudaEventRecord(evF2, 0);

    // s1: gemm_out after all ctx (flash chunk 2) done.
    cudaStreamWaitEvent(s1, evF2, 0);
    dim3 gGrid(N / 128, M / 128);
    gemm_out<<<gGrid, 256, GEMM_SMEM, s1>>>(chi, clo, wohi, wolo, wo_b,
                                            out_ptr, M, N, K);
    cudaEventRecord(evJoin, s1);

    // Main: normalize chunk 2 overlaps gemm_out.
    normalize_kernel<<<nGrid, 256>>>(p16, mkt, stats, attn_ptr, 16);

    cudaStreamWaitEvent(0, evJoin, 0);
}

// round 17
// speedup vs baseline: 2.9665x; 1.0070x over previous
#include <cuda_runtime.h>
#include <cuda_bf16.h>
#include <cuda_fp16.h>
#include <math.h>
#include <stdint.h>

// Problem constants
#define B_  2
#define S_  2048
#define D_  1024
#define H_  16
#define DH_ 64
#define SCALE_ 0.125f   // DH^-0.5
#define SW_ (S_ / 32)   // mask words per row

typedef unsigned long long u64;

// ---------------------------------------------------------------------------
// Scratch (static device globals; no runtime allocation)
// ---------------------------------------------------------------------------
__device__ float g_q[(size_t)B_ * S_ * D_];                 // dummy sink
__device__ float g_attn_raw[(size_t)B_ * H_ * S_ * S_];     // fallback attn (fp32)
__device__ __half g_p16[(size_t)B_ * H_ * S_ * S_];         // P, fp16 permuted
__device__ float g_mkt[(size_t)B_ * H_ * (S_ / 64) * S_];
__device__ float g_stats[(size_t)B_ * H_ * S_ * 2];
__device__ uint32_t g_mbits[(size_t)B_ * S_ * SW_];        // bit-packed mask

// bf16 hi/lo split operands
__device__ __nv_bfloat16 g_xhi[(size_t)B_ * S_ * D_];
__device__ __nv_bfloat16 g_xlo[(size_t)B_ * S_ * D_];
__device__ __nv_bfloat16 g_qhi[(size_t)B_ * S_ * D_], g_qlo[(size_t)B_ * S_ * D_];
__device__ __nv_bfloat16 g_khi[(size_t)B_ * S_ * D_], g_klo[(size_t)B_ * S_ * D_];
__device__ __nv_bfloat16 g_vhi[(size_t)B_ * S_ * D_], g_vlo[(size_t)B_ * S_ * D_];
__device__ __nv_bfloat16 g_chi[(size_t)B_ * S_ * D_], g_clo[(size_t)B_ * S_ * D_];
__device__ __nv_bfloat16 g_wqhi[D_ * D_], g_wqlo[D_ * D_];
__device__ __nv_bfloat16 g_wkhi[D_ * D_], g_wklo[D_ * D_];
__device__ __nv_bfloat16 g_wvhi[D_ * D_], g_wvlo[D_ * D_];
__device__ __nv_bfloat16 g_wohi[D_ * D_], g_wolo[D_ * D_];

// ---------------------------------------------------------------------------
// mma.sync / ldmatrix helpers
// ---------------------------------------------------------------------------
__device__ __forceinline__ uint32_t smem_u32(const void* p) {
    uint32_t a;
    asm("{ .reg .u64 t; cvta.to.shared.u64 t, %1; cvt.u32.u64 %0, t; }"
        : "=r"(a) : "l"(p));
    return a;
}
__device__ __forceinline__ void ldmA4(uint32_t* a, uint32_t addr) {
    asm volatile("ldmatrix.sync.aligned.m8n8.x4.shared.b16 {%0,%1,%2,%3}, [%4];"
                 : "=r"(a[0]), "=r"(a[1]), "=r"(a[2]), "=r"(a[3]) : "r"(addr));
}
__device__ __forceinline__ void ldmA4t(uint32_t* a, uint32_t addr) {
    asm volatile("ldmatrix.sync.aligned.m8n8.x4.trans.shared.b16 {%0,%1,%2,%3}, [%4];"
                 : "=r"(a[0]), "=r"(a[1]), "=r"(a[2]), "=r"(a[3]) : "r"(addr));
}
__device__ __forceinline__ void mma16816(float* c, const uint32_t* a,
                                         const uint32_t* b) {
    asm volatile(
        "mma.sync.aligned.m16n8k16.row.col.f32.bf16.bf16.f32 "
        "{%0,%1,%2,%3}, {%4,%5,%6,%7}, {%8,%9}, {%0,%1,%2,%3};"
        : "+f"(c[0]), "+f"(c[1]), "+f"(c[2]), "+f"(c[3])
        : "r"(a[0]), "r"(a[1]), "r"(a[2]), "r"(a[3]), "r"(b[0]), "r"(b[1]));
}
__device__ __forceinline__ void cpasync16(uint32_t saddr, const void* gaddr) {
    asm volatile("cp.async.cg.shared.global [%0], [%1], 16;"
                 :: "r"(saddr), "l"(gaddr));
}
#define CP_COMMIT() asm volatile("cp.async.commit_group;" ::: "memory")
#define CP_WAIT0()  asm volatile("cp.async.wait_group 0;" ::: "memory")
#define CP_WAIT1()  asm volatile("cp.async.wait_group 1;" ::: "memory")

__device__ __forceinline__ uint32_t pack_bf2(float x, float y) {
    return (uint32_t)__bfloat16_as_ushort(__float2bfloat16(x)) |
           ((uint32_t)__bfloat16_as_ushort(__float2bfloat16(y)) << 16);
}
#define TRUNC_HI2(x, y) __byte_perm(__float_as_uint(x), __float_as_uint(y), 0x7632)
__device__ __forceinline__ float trunc_res(float x) {
    return x - __uint_as_float(__float_as_uint(x) & 0xFFFF0000u);
}
__device__ __forceinline__ void split_store(
    __nv_bfloat16* hi, __nv_bfloat16* lo, size_t idx, float x, float y)
{
    const __nv_bfloat16 hx = __float2bfloat16(x), hy = __float2bfloat16(y);
    *(uint32_t*)&hi[idx] = (uint32_t)__bfloat16_as_ushort(hx) |
                           ((uint32_t)__bfloat16_as_ushort(hy) << 16);
    *(uint32_t*)&lo[idx] = pack_bf2(x - __bfloat162float(hx),
                                    y - __bfloat162float(hy));
}
__device__ __forceinline__ float fexp(float x) { return __expf(x); }

// ---------------------------------------------------------------------------
// Split-conversions
// ---------------------------------------------------------------------------
__global__ __launch_bounds__(256) void conv_split(
    const float4* __restrict__ src, uint2* __restrict__ hi,
    uint2* __restrict__ lo, int n4)
{
    const int i = blockIdx.x * 256 + threadIdx.x;
    if (i >= n4) return;
    const float4 v = src[i];
    split_store((__nv_bfloat16*)hi, (__nv_bfloat16*)lo, (size_t)i * 4,     v.x, v.y);
    split_store((__nv_bfloat16*)hi, (__nv_bfloat16*)lo, (size_t)i * 4 + 2, v.z, v.w);
}

__global__ __launch_bounds__(256) void conv_split_w4(
    const float4* s0, uint2* h0, uint2* l0,
    const float4* s1, uint2* h1, uint2* l1,
    const float4* s2, uint2* h2, uint2* l2,
    const float4* s3, uint2* h3, uint2* l3, int n4)
{
    const int i = blockIdx.x * 256 + threadIdx.x;
    if (i >= n4) return;
    const int w = blockIdx.y;
    const float4* src = (w == 0) ? s0 : (w == 1) ? s1 : (w == 2) ? s2 : s3;
    uint2* hi = (w == 0) ? h0 : (w == 1) ? h1 : (w == 2) ? h2 : h3;
    uint2* lo = (w == 0) ? l0 : (w == 1) ? l1 : (w == 2) ? l2 : l3;
    const float4 v = src[i];
    split_store((__nv_bfloat16*)hi, (__nv_bfloat16*)lo, (size_t)i * 4,     v.x, v.y);
    split_store((__nv_bfloat16*)hi, (__nv_bfloat16*)lo, (size_t)i * 4 + 2, v.z, v.w);
}

// Pack mask (int32 per element) into 1 bit per element.
__global__ __launch_bounds__(256) void conv_maskbits(
    const int4* __restrict__ mask, uint32_t* __restrict__ mbits, int nwords)
{
    const int w = blockIdx.x * 256 + threadIdx.x;
    if (w >= nwords) return;
    const int4* src = mask + (size_t)w * 8;
    uint32_t bits = 0;
#pragma unroll
    for (int j = 0; j < 8; j++) {
        const int4 v = src[j];
        bits |= (v.x != 0 ? 1u : 0u) << (j * 4 + 0);
        bits |= (v.y != 0 ? 1u : 0u) << (j * 4 + 1);
        bits |= (v.z != 0 ? 1u : 0u) << (j * 4 + 2);
        bits |= (v.w != 0 ? 1u : 0u) << (j * 4 + 3);
    }
    mbits[w] = bits;
}

// ---------------------------------------------------------------------------
// Shared GEMM body: 3-term fused K-loop, BK=32, 2-stage pipeline, 2 CTAs/SM.
// ---------------------------------------------------------------------------
#define GP 40
#define GTILE (128 * GP)
#define GEMM_SMEM (2 * 4 * GTILE * 2)          // 81920 bytes

__device__ __forceinline__ void gemm_body(
    const __nv_bfloat16* __restrict__ Ahi, const __nv_bfloat16* __restrict__ Alo,
    const __nv_bfloat16* __restrict__ Bhi, const __nv_bfloat16* __restrict__ Blo,
    const float* __restrict__ bias, float* __restrict__ C,
    __nv_bfloat16* __restrict__ Chi, __nv_bfloat16* __restrict__ Clo,
    int M, int N, int K, int bm, int bn, uint32_t sb)
{
    const int tid  = threadIdx.x;
    const int lane = tid & 31, wid = tid >> 5;
    const int warp_m = wid >> 2, warp_n = wid & 3;

    const int a_r = warp_m * 64 + (lane & 15);
    const int a_c = (lane >> 4) * 8;
    const int b4_row = ((lane >> 4) & 1) * 8 + (lane & 7);
    const int b4_col = ((lane >> 3) & 1) * 8;

    const int lrow = tid >> 2;          // 0..63
    const int lc8  = (tid & 3) * 8;

    float acc[4][4][4];
#pragma unroll
    for (int mt = 0; mt < 4; mt++)
#pragma unroll
        for (int nt = 0; nt < 4; nt++)
#pragma unroll
            for (int r = 0; r < 4; r++) acc[mt][nt][r] = 0.f;

#define TBASE(s, o) (sb + (uint32_t)(((s) * 4 + (o)) * GTILE) * 2)
#define LOAD_STAGE(s, k0) do {                                                \
    const uint32_t _dAh = TBASE(s, 0), _dAl = TBASE(s, 1);                    \
    const uint32_t _dBh = TBASE(s, 2), _dBl = TBASE(s, 3);                    \
    _Pragma("unroll")                                                         \
    for (int rr = 0; rr < 2; rr++) {                                          \
        const int row = lrow + rr * 64;                                       \
        const uint32_t so = (uint32_t)(row * GP + lc8) * 2;                   \
        const size_t ga = (size_t)(bm + row) * K + (k0) + lc8;                \
        const size_t gb = (size_t)(bn + row) * K + (k0) + lc8;                \
        cpasync16(_dAh + so, &Ahi[ga]);                                       \
        cpasync16(_dAl + so, &Alo[ga]);                                       \
        cpasync16(_dBh + so, &Bhi[gb]);                                       \
        cpasync16(_dBl + so, &Blo[gb]);                                       \
    }                                                                         \
    CP_COMMIT();                                                              \
} while (0)

    LOAD_STAGE(0, 0);

    const int NK = K / 32;
    for (int kc = 0; kc < NK; kc++) {
        const int cur = kc & 1;
        if (kc + 1 < NK) { LOAD_STAGE(cur ^ 1, (kc + 1) * 32); CP_WAIT1(); }
        else             { CP_WAIT0(); }
        __syncthreads();

        const uint32_t uAh = TBASE(cur, 0), uAl = TBASE(cur, 1);
        const uint32_t uBh = TBASE(cur, 2), uBl = TBASE(cur, 3);
#pragma unroll
        for (int ks = 0; ks < 2; ks++) {
            uint32_t ah[4][4], al[4][4];
#pragma unroll
            for (int mt = 0; mt < 4; mt++) {
                const uint32_t ao = (uint32_t)((a_r + mt * 16) * GP +
                                               ks * 16 + a_c) * 2;
                ldmA4(ah[mt], uAh + ao);
                ldmA4(al[mt], uAl + ao);
            }
            uint32_t bh[4][2], bl[4][2];
#pragma unroll
            for (int p = 0; p < 2; p++) {
                uint32_t r4[4];
                const uint32_t bo = (uint32_t)((warp_n * 32 + p * 16 + b4_row) * GP +
                                               ks * 16 + b4_col) * 2;
                ldmA4(r4, uBh + bo);
                bh[2*p][0] = r4[0]; bh[2*p][1] = r4[1];
                bh[2*p+1][0] = r4[2]; bh[2*p+1][1] = r4[3];
                ldmA4(r4, uBl + bo);
                bl[2*p][0] = r4[0]; bl[2*p][1] = r4[1];
                bl[2*p+1][0] = r4[2]; bl[2*p+1][1] = r4[3];
            }
#pragma unroll
            for (int mt = 0; mt < 4; mt++)
#pragma unroll
                for (int nt = 0; nt < 4; nt++) {
                    mma16816(acc[mt][nt], ah[mt], bh[nt]);
                    mma16816(acc[mt][nt], ah[mt], bl[nt]);
                    mma16816(acc[mt][nt], al[mt], bh[nt]);
                }
        }
        __syncthreads();
    }

    const int em = bm + warp_m * 64 + (lane >> 2);
    const int en = bn + warp_n * 32 + (lane & 3) * 2;
#pragma unroll
    for (int mt = 0; mt < 4; mt++) {
#pragma unroll
        for (int nt = 0; nt < 4; nt++) {
            const int n = en + nt * 8;
            const float bx = bias[n], by = bias[n + 1];
            const int m0 = em + mt * 16;
            float2 o0, o1;
            o0.x = acc[mt][nt][0] + bx; o0.y = acc[mt][nt][1] + by;
            o1.x = acc[mt][nt][2] + bx; o1.y = acc[mt][nt][3] + by;
            if (C) {
                *(float2*)&C[(size_t)m0 * N + n]       = o0;
                *(float2*)&C[(size_t)(m0 + 8) * N + n] = o1;
            }
            if (Chi) {
                split_store(Chi, Clo, (size_t)m0 * N + n,       o0.x, o0.y);
                split_store(Chi, Clo, (size_t)(m0 + 8) * N + n, o1.x, o1.y);
            }
        }
    }
#undef LOAD_STAGE
#undef TBASE
}

__global__ __launch_bounds__(256, 2) void gemm_qkv(
    const __nv_bfloat16* __restrict__ Ahi, const __nv_bfloat16* __restrict__ Alo,
    const __nv_bfloat16* bq_h, const __nv_bfloat16* bq_l,
    const __nv_bfloat16* bk_h, const __nv_bfloat16* bk_l,
    const __nv_bfloat16* bv_h, const __nv_bfloat16* bv_l,
    const float* biq, const float* bik, const float* biv,
    __nv_bfloat16* qh, __nv_bfloat16* ql,
    __nv_bfloat16* kh, __nv_bfloat16* kl,
    __nv_bfloat16* vh, __nv_bfloat16* vl,
    int M, int N, int K, int mOff)
{
    extern __shared__ __nv_bfloat16 gsm[];
    const int z = blockIdx.z;
    const __nv_bfloat16* Bh = (z == 0) ? bq_h : (z == 1) ? bk_h : bv_h;
    const __nv_bfloat16* Bl = (z == 0) ? bq_l : (z == 1) ? bk_l : bv_l;
    const float* bias = (z == 0) ? biq : (z == 1) ? bik : biv;
    __nv_bfloat16* Ch = (z == 0) ? qh : (z == 1) ? kh : vh;
    __nv_bfloat16* Cl = (z == 0) ? ql : (z == 1) ? kl : vl;
    gemm_body(Ahi, Alo, Bh, Bl, bias, (float*)nullptr, Ch, Cl,
              M, N, K, blockIdx.y * 128 + mOff, blockIdx.x * 128, smem_u32(gsm));
}

__global__ __launch_bounds__(256, 2) void gemm_out(
    const __nv_bfloat16* __restrict__ Ahi, const __nv_bfloat16* __restrict__ Alo,
    const __nv_bfloat16* __restrict__ Bhi, const __nv_bfloat16* __restrict__ Blo,
    const float* __restrict__ bias, float* __restrict__ C,
    int M, int N, int K, int mOff)
{
    extern __shared__ __nv_bfloat16 gsm[];
    gemm_body(Ahi, Alo, Bhi, Blo, bias, C,
              (__nv_bfloat16*)nullptr, (__nv_bfloat16*)nullptr,
              M, N, K, blockIdx.y * 128 + mOff, blockIdx.x * 128, smem_u32(gsm));
}

// ---------------------------------------------------------------------------
// Tensor-core flash attention (bit-packed mask, permuted fp16 P, bh-chunked).
// ---------------------------------------------------------------------------
#define FP 72
#define KVT (64 * FP)
#define FLASH_SMEM ((2 * 128 * FP + 2 * 4 * KVT) * 2)    // 110592 bytes

__global__ __launch_bounds__(256, 2) void flash_mma_kernel(
    const __nv_bfloat16* __restrict__ qhi, const __nv_bfloat16* __restrict__ qlo,
    const __nv_bfloat16* __restrict__ khi, const __nv_bfloat16* __restrict__ klo,
    const __nv_bfloat16* __restrict__ vhi, const __nv_bfloat16* __restrict__ vlo,
    const uint32_t* __restrict__ mbits, __half* __restrict__ P16,
    float* __restrict__ mkt, float* __restrict__ stats,
    __nv_bfloat16* __restrict__ chi, __nv_bfloat16* __restrict__ clo,
    int bhOff)
{
    extern __shared__ __nv_bfloat16 smb[];
    __nv_bfloat16* sQh = smb;
    __nv_bfloat16* sQl = sQh + 128 * FP;
    __nv_bfloat16* sKV = sQl + 128 * FP;

    const int t = threadIdx.x, lane = t & 31, warp = t >> 5;
    const int bh = blockIdx.y + bhOff;
    const int b = bh >> 4, h = bh & 15;
    const int q0 = blockIdx.x * 128;

    const uint32_t uQh = smem_u32(sQh), uQl = smem_u32(sQl);
    const uint32_t uKV = smem_u32(sKV);
#define KVB(s, o) (uKV + (uint32_t)(((s) * 4 + (o)) * KVT) * 2)

    for (int i = t; i < 1024; i += 256) {
        const int row = i >> 3, c8 = (i & 7) * 8;
        const size_t g = (size_t)(b * S_ + q0 + row) * D_ + h * 64 + c8;
        const uint32_t so = (uint32_t)(row * FP + c8) * 2;
        cpasync16(uQh + so, &qhi[g]);
        cpasync16(uQl + so, &qlo[g]);
    }

    const int kv_row = t >> 3;
    const int kv_c8  = (t & 7) * 8;
#define LOAD_KV(stage, k0) do {                                               \
    _Pragma("unroll")                                                         \
    for (int rr = 0; rr < 2; rr++) {                                          \
        const int row = kv_row + rr * 32;                                     \
        const size_t g = (size_t)(b * S_ + (k0) + row) * D_ + h * 64 + kv_c8; \
        const uint32_t so = (uint32_t)(row * FP + kv_c8) * 2;                 \
        cpasync16(KVB(stage, 0) + so, &khi[g]);                               \
        cpasync16(KVB(stage, 1) + so, &klo[g]);                               \
        cpasync16(KVB(stage, 2) + so, &vhi[g]);                               \
        cpasync16(KVB(stage, 3) + so, &vlo[g]);                               \
    }                                                                         \
    CP_COMMIT();                                                              \
} while (0)

    LOAD_KV(0, 0);

    float O[8][4];
#pragma unroll
    for (int j = 0; j < 8; j++)
#pragma unroll
        for (int r = 0; r < 4; r++) O[j][r] = 0.f;
    float mr0 = -1e30f, mr1 = -1e30f, lr0 = 0.f, lr1 = 0.f;

    const int row0 = q0 + warp * 16 + (lane >> 2);
    const int row1 = row0 + 8;
    const int col0 = (lane & 3) * 2;
    const int a_r  = warp * 16 + (lane & 15);
    const int a_c  = (lane >> 4) * 8;
    const int b4_row = ((lane >> 4) & 1) * 8 + (lane & 7);
    const int b4_col = ((lane >> 3) & 1) * 8;
    const int t4_row = ((lane >> 3) & 1) * 8 + (lane & 7);
    const int t4_sel = ((lane >> 4) & 1) * 8;

    const uint32_t* mrow0 = &mbits[((size_t)b * S_ + row0) * SW_];
    const uint32_t* mrow1 = &mbits[((size_t)b * S_ + row1) * SW_];

    const int NT = S_ / 64;
    for (int kt = 0; kt < NT; kt++) {
        const int k0 = kt * 64;
        const int cur = kt & 1;
        CP_WAIT0();
        __syncthreads();
        if (kt + 1 < NT) LOAD_KV(cur ^ 1, (kt + 1) * 64);

        const uint32_t uKh = KVB(cur, 0), uKl = KVB(cur, 1);
        const uint32_t uVh = KVB(cur, 2), uVl = KVB(cur, 3);

        // --- QK^T ---
        float c[8][4];
#pragma unroll
        for (int nt = 0; nt < 8; nt++)
#pragma unroll
            for (int r = 0; r < 4; r++) c[nt][r] = 0.f;
#pragma unroll
        for (int ks = 0; ks < 4; ks++) {
            uint32_t qh2[4], ql2[4];
            const uint32_t qo = (uint32_t)(a_r * FP + ks * 16 + a_c) * 2;
            ldmA4(qh2, uQh + qo);
            ldmA4(ql2, uQl + qo);
#pragma unroll
            for (int p = 0; p < 4; p++) {
                uint32_t rh[4], rl[4];
                const uint32_t off = (uint32_t)((p * 16 + b4_row) * FP +
                                                ks * 16 + b4_col) * 2;
                ldmA4(rh, uKh + off);
                ldmA4(rl, uKl + off);
                mma16816(c[2*p],   qh2, rh);
                mma16816(c[2*p],   qh2, rl);
                mma16816(c[2*p],   ql2, rh);
                mma16816(c[2*p+1], qh2, rh + 2);
                mma16816(c[2*p+1], qh2, rl + 2);
                mma16816(c[2*p+1], ql2, rh + 2);
            }
        }

        // --- scale + mask (bit-packed) ---
        {
            const uint2 mw0 = *(const uint2*)&mrow0[k0 >> 5];
            const uint2 mw1 = *(const uint2*)&mrow1[k0 >> 5];
#pragma unroll
            for (int nt = 0; nt < 8; nt++) {
                const int cb = ((nt & 3) * 8 + col0);
                const uint32_t w0 = (nt < 4) ? mw0.x : mw0.y;
                const uint32_t w1 = (nt < 4) ? mw1.x : mw1.y;
                c[nt][0] = ((w0 >> cb) & 1u)       ? c[nt][0] * SCALE_ : -1e9f;
                c[nt][1] = ((w0 >> (cb + 1)) & 1u) ? c[nt][1] * SCALE_ : -1e9f;
                c[nt][2] = ((w1 >> cb) & 1u)       ? c[nt][2] * SCALE_ : -1e9f;
                c[nt][3] = ((w1 >> (cb + 1)) & 1u) ? c[nt][3] * SCALE_ : -1e9f;
            }
        }

        // --- online softmax ---
        float rm0 = -1e30f, rm1 = -1e30f;
#pragma unroll
        for (int nt = 0; nt < 8; nt++) {
            rm0 = fmaxf(rm0, fmaxf(c[nt][0], c[nt][1]));
            rm1 = fmaxf(rm1, fmaxf(c[nt][2], c[nt][3]));
        }
        rm0 = fmaxf(rm0, __shfl_xor_sync(0xffffffffu, rm0, 1));
        rm0 = fmaxf(rm0, __shfl_xor_sync(0xffffffffu, rm0, 2));
        rm1 = fmaxf(rm1, __shfl_xor_sync(0xffffffffu, rm1, 1));
        rm1 = fmaxf(rm1, __shfl_xor_sync(0xffffffffu, rm1, 2));
        const float mn0 = fmaxf(mr0, rm0), mn1 = fmaxf(mr1, rm1);
        const float f0 = fexp(mr0 - mn0), f1 = fexp(mr1 - mn1);
        float rs0 = 0.f, rs1 = 0.f;
#pragma unroll
        for (int nt = 0; nt < 8; nt++) {
            c[nt][0] = fexp(c[nt][0] - mn0);
            c[nt][1] = fexp(c[nt][1] - mn0);
            c[nt][2] = fexp(c[nt][2] - mn1);
            c[nt][3] = fexp(c[nt][3] - mn1);
            rs0 += c[nt][0] + c[nt][1];
            rs1 += c[nt][2] + c[nt][3];
        }
        rs0 += __shfl_xor_sync(0xffffffffu, rs0, 1);
        rs0 += __shfl_xor_sync(0xffffffffu, rs0, 2);
        rs1 += __shfl_xor_sync(0xffffffffu, rs1, 1);
        rs1 += __shfl_xor_sync(0xffffffffu, rs1, 2);
        lr0 = lr0 * f0 + rs0; mr0 = mn0;
        lr1 = lr1 * f1 + rs1; mr1 = mn1;
#pragma unroll
        for (int j = 0; j < 8; j++) {
            O[j][0] *= f0; O[j][1] *= f0;
            O[j][2] *= f1; O[j][3] *= f1;
        }

        // --- stream P (fp16, permuted, warp-contiguous) + m_kt ---
        {
            __half* pb = P16 +
                ((((size_t)bh * 16 + (q0 >> 7)) * 32 + kt) * 8192) +
                warp * 1024 + lane * 2;
#pragma unroll
            for (int nt = 0; nt < 8; nt++) {
                *(__half2*)&pb[nt * 64] =
                    __floats2half2_rn(c[nt][0], c[nt][1]);
                *(__half2*)&pb[(nt + 8) * 64] =
                    __floats2half2_rn(c[nt][2], c[nt][3]);
            }
            if ((lane & 3) == 0) {
                mkt[((size_t)bh * 32 + kt) * S_ + row0] = mn0;
                mkt[((size_t)bh * 32 + kt) * S_ + row1] = mn1;
            }
        }

        // --- P @ V (truncation-split fragments) ---
#pragma unroll
        for (int ks2 = 0; ks2 < 4; ks2++) {
            const float* c0 = c[2 * ks2];
            const float* c1 = c[2 * ks2 + 1];
            uint32_t ah[4], al[4];
            ah[0] = TRUNC_HI2(c0[0], c0[1]);
            ah[1] = TRUNC_HI2(c0[2], c0[3]);
            ah[2] = TRUNC_HI2(c1[0], c1[1]);
            ah[3] = TRUNC_HI2(c1[2], c1[3]);
            al[0] = TRUNC_HI2(trunc_res(c0[0]), trunc_res(c0[1]));
            al[1] = TRUNC_HI2(trunc_res(c0[2]), trunc_res(c0[3]));
            al[2] = TRUNC_HI2(trunc_res(c1[0]), trunc_res(c1[1]));
            al[3] = TRUNC_HI2(trunc_res(c1[2]), trunc_res(c1[3]));
#pragma unroll
            for (int p = 0; p < 4; p++) {
                uint32_t vh4[4], vl4[4];
                const uint32_t off = (uint32_t)((ks2 * 16 + t4_row) * FP +
                                                p * 16 + t4_sel) * 2;
                ldmA4t(vh4, uVh + off);
                ldmA4t(vl4, uVl + off);
                mma16816(O[2*p],   ah, vh4);
                mma16816(O[2*p],   ah, vl4);
                mma16816(O[2*p],   al, vh4);
                mma16816(O[2*p+1], ah, vh4 + 2);
                mma16816(O[2*p+1], ah, vl4 + 2);
                mma16816(O[2*p+1], al, vh4 + 2);
            }
        }
    }

    // --- epilogue: normalized ctx as bf16 hi/lo ---
    const float inv0 = 1.0f / lr0, inv1 = 1.0f / lr1;
#pragma unroll
    for (int nt2 = 0; nt2 < 8; nt2++) {
        const int n = nt2 * 8 + col0;
        const size_t g0 = (size_t)(b * S_ + row0) * D_ + h * 64 + n;
        const size_t g1 = (size_t)(b * S_ + row1) * D_ + h * 64 + n;
        split_store(chi, clo, g0, O[nt2][0] * inv0, O[nt2][1] * inv0);
        split_store(chi, clo, g1, O[nt2][2] * inv1, O[nt2][3] * inv1);
    }
    if ((lane & 3) == 0) {
        size_t si = ((size_t)bh * S_ + row0) * 2;
        stats[si] = mr0; stats[si + 1] = lr0;
        si = ((size_t)bh * S_ + row1) * 2;
        stats[si] = mr1; stats[si + 1] = lr1;
    }
#undef LOAD_KV
#undef KVB
}

// ---------------------------------------------------------------------------
// Pass 2: un-permute fp16 P + normalize (bh-chunked).
// ---------------------------------------------------------------------------
__global__ __launch_bounds__(256) void normalize_kernel(
    const __half* __restrict__ P16, const float* __restrict__ mkt,
    const float* __restrict__ stats, float* __restrict__ attn, int bhOff)
{
    __shared__ __half sp[8192];
    __shared__ float corr[128];
    const int t  = threadIdx.x;
    const int qt = blockIdx.x >> 5, kt = blockIdx.x & 31;
    const int bh = blockIdx.y + bhOff;
    const int q0 = qt * 128, k0 = kt * 64;

    if (t < 128) {
        const int row = q0 + t;
        const size_t si = ((size_t)bh * S_ + row) * 2;
        corr[t] = __expf(mkt[((size_t)bh * 32 + kt) * S_ + row] - stats[si]) /
                  stats[si + 1];
    }
    const uint4* src = (const uint4*)(P16 +
        ((((size_t)bh * 16 + qt) * 32 + kt) * 8192));
#pragma unroll
    for (int j = 0; j < 4; j++)
        ((uint4*)sp)[t + j * 256] = src[t + j * 256];
    __syncthreads();

#pragma unroll
    for (int j = 0; j < 8; j++) {
        const int o   = t + j * 256;
        const int row = o >> 4;
        const int c   = (o & 15) * 4;
        const float cr = corr[row];
        float v[4];
#pragma unroll
        for (int e = 0; e < 4; e++) {
            const int ci = c + e;
            const int idx = (row >> 4) * 1024 +
                            ((ci >> 3) + 8 * ((row >> 3) & 1)) * 64 +
                            ((row & 7) * 4 + ((ci & 7) >> 1)) * 2 + (ci & 1);
            v[e] = __half2float(sp[idx]) * cr;
        }
        float4 o4;
        o4.x = v[0]; o4.y = v[1]; o4.z = v[2]; o4.w = v[3];
        *(float4*)&attn[((size_t)bh * S_ + q0 + row) * S_ + k0 + c] = o4;
    }
}

// ---------------------------------------------------------------------------
extern "C" void kernel_launch(void* const* d_in, const int* in_sizes, int n_in,
                              void* d_out, int out_size)
{
    const float* x    = (const float*)d_in[0];
    const int*   mask = (const int*)  d_in[1];
    const float* wq_w = (const float*)d_in[2];
    const float* wq_b = (const float*)d_in[3];
    const float* wk_w = (const float*)d_in[4];
    const float* wk_b = (const float*)d_in[5];
    const float* wv_w = (const float*)d_in[6];
    const float* wv_b = (const float*)d_in[7];
    const float* wo_w = (const float*)d_in[8];
    const float* wo_b = (const float*)d_in[9];

    float *qdump, *attn_raw, *mkt, *stats;
    __half* p16;
    uint32_t* mbits;
    cudaGetSymbolAddress((void**)&qdump,    g_q);
    cudaGetSymbolAddress((void**)&attn_raw, g_attn_raw);
    cudaGetSymbolAddress((void**)&p16,      g_p16);
    cudaGetSymbolAddress((void**)&mkt,      g_mkt);
    cudaGetSymbolAddress((void**)&stats,    g_stats);
    cudaGetSymbolAddress((void**)&mbits,    g_mbits);

    __nv_bfloat16 *xhi, *xlo, *chi, *clo;
    __nv_bfloat16 *qhi_p, *qlo_p, *khi_p, *klo_p, *vhi_p, *vlo_p;
    __nv_bfloat16 *wqhi, *wqlo, *wkhi, *wklo, *wvhi, *wvlo, *wohi, *wolo;
    cudaGetSymbolAddress((void**)&xhi, g_xhi);   cudaGetSymbolAddress((void**)&xlo, g_xlo);
    cudaGetSymbolAddress((void**)&chi, g_chi);   cudaGetSymbolAddress((void**)&clo, g_clo);
    cudaGetSymbolAddress((void**)&qhi_p, g_qhi); cudaGetSymbolAddress((void**)&qlo_p, g_qlo);
    cudaGetSymbolAddress((void**)&khi_p, g_khi); cudaGetSymbolAddress((void**)&klo_p, g_klo);
    cudaGetSymbolAddress((void**)&vhi_p, g_vhi); cudaGetSymbolAddress((void**)&vlo_p, g_vlo);
    cudaGetSymbolAddress((void**)&wqhi, g_wqhi); cudaGetSymbolAddress((void**)&wqlo, g_wqlo);
    cudaGetSymbolAddress((void**)&wkhi, g_wkhi); cudaGetSymbolAddress((void**)&wklo, g_wklo);
    cudaGetSymbolAddress((void**)&wvhi, g_wvhi); cudaGetSymbolAddress((void**)&wvlo, g_wvlo);
    cudaGetSymbolAddress((void**)&wohi, g_wohi); cudaGetSymbolAddress((void**)&wolo, g_wolo);

    const long long CTXSZ = (long long)B_ * S_ * D_;
    const long long ATTSZ = (long long)B_ * H_ * S_ * S_;

    float* out_base = (float*)d_out;
    float* out_ptr;
    float* attn_ptr;
    if ((long long)out_size >= CTXSZ + ATTSZ) {
        out_ptr  = out_base;
        attn_ptr = out_base + CTXSZ;
    } else if ((long long)out_size == ATTSZ) {
        out_ptr  = qdump;
        attn_ptr = out_base;
    } else {
        out_ptr  = out_base;
        attn_ptr = attn_raw;
    }

    cudaFuncSetAttribute(flash_mma_kernel,
                         cudaFuncAttributeMaxDynamicSharedMemorySize, FLASH_SMEM);
    cudaFuncSetAttribute(gemm_qkv,
                         cudaFuncAttributeMaxDynamicSharedMemorySize, GEMM_SMEM);
    cudaFuncSetAttribute(gemm_out,
                         cudaFuncAttributeMaxDynamicSharedMemorySize, GEMM_SMEM);

    static cudaStream_t s1 = nullptr;
    static cudaEvent_t evX = nullptr, evW = nullptr, evMask = nullptr,
                       evQ1 = nullptr, evF1 = nullptr, evF2 = nullptr,
                       evFork = nullptr, evJoin = nullptr;
    if (!s1) {
        cudaStreamCreateWithFlags(&s1, cudaStreamNonBlocking);
        cudaEventCreateWithFlags(&evX,    cudaEventDisableTiming);
        cudaEventCreateWithFlags(&evW,    cudaEventDisableTiming);
        cudaEventCreateWithFlags(&evMask, cudaEventDisableTiming);
        cudaEventCreateWithFlags(&evQ1,   cudaEventDisableTiming);
        cudaEventCreateWithFlags(&evF1,   cudaEventDisableTiming);
        cudaEventCreateWithFlags(&evF2,   cudaEventDisableTiming);
        cudaEventCreateWithFlags(&evFork, cudaEventDisableTiming);
        cudaEventCreateWithFlags(&evJoin, cudaEventDisableTiming);
    }

    const int M = B_ * S_;   // 4096
    const int N = D_;        // 1024
    const int K = D_;        // 1024
    const int MH = M / 2;    // per-batch rows (2048)

    const int xn4 = (int)(CTXSZ / 4);
    const int wn4 = D_ * D_ / 4;

    // Fork: weight convs + mask pack on s1; x conv on main.
    cudaEventRecord(evFork, 0);
    cudaStreamWaitEvent(s1, evFork, 0);
    dim3 wGrid((wn4 + 255) / 256, 4);
    conv_split_w4<<<wGrid, 256, 0, s1>>>(
        (const float4*)wq_w, (uint2*)wqhi, (uint2*)wqlo,
        (const float4*)wk_w, (uint2*)wkhi, (uint2*)wklo,
        (const float4*)wv_w, (uint2*)wvhi, (uint2*)wvlo,
        (const float4*)wo_w, (uint2*)wohi, (uint2*)wolo, wn4);
    cudaEventRecord(evW, s1);
    const int nwords = B_ * S_ * SW_;
    conv_maskbits<<<(nwords + 255) / 256, 256, 0, s1>>>(
        (const int4*)mask, mbits, nwords);
    cudaEventRecord(evMask, s1);

    conv_split<<<(xn4 + 255) / 256, 256>>>((const float4*)x,
                                           (uint2*)xhi, (uint2*)xlo, xn4);
    cudaEventRecord(evX, 0);

    // qkv batch 1 on s1 (after x conv + weights) — overlaps qkv_b0 / flash_b0.
    cudaStreamWaitEvent(s1, evX, 0);
    dim3 qkvHGrid(N / 128, MH / 128, 3);
    gemm_qkv<<<qkvHGrid, 256, GEMM_SMEM, s1>>>(
        xhi, xlo, wqhi, wqlo, wkhi, wklo, wvhi, wvlo,
        wq_b, wk_b, wv_b,
        qhi_p, qlo_p, khi_p, klo_p, vhi_p, vlo_p, M, N, K, MH);
    cudaEventRecord(evQ1, s1);

    // qkv batch 0 on main.
    cudaStreamWaitEvent(0, evW, 0);
    gemm_qkv<<<qkvHGrid, 256, GEMM_SMEM>>>(
        xhi, xlo, wqhi, wqlo, wkhi, wklo, wvhi, wvlo,
        wq_b, wk_b, wv_b,
        qhi_p, qlo_p, khi_p, klo_p, vhi_p, vlo_p, M, N, K, 0);

    // Flash chunk 1 (bh 0..15, batch 0) — needs qkv_b0 + mask.
    cudaStreamWaitEvent(0, evMask, 0);
    dim3 fGrid(S_ / 128, 16);
    flash_mma_kernel<<<fGrid, 256, FLASH_SMEM>>>(
        qhi_p, qlo_p, khi_p, klo_p, vhi_p, vlo_p,
        mbits, p16, mkt, stats, chi, clo, 0);
    cudaEventRecord(evF1, 0);

    // s1: after flash_b0 -> normalize_b0 then gemm_out_b0 (overlap flash_b1).
    cudaStreamWaitEvent(s1, evF1, 0);
    dim3 nGrid(16 * 32, 16);
    normalize_kernel<<<nGrid, 256, 0, s1>>>(p16, mkt, stats, attn_ptr, 0);
    dim3 gHGrid(N / 128, MH / 128);
    gemm_out<<<gHGrid, 256, GEMM_SMEM, s1>>>(chi, clo, wohi, wolo, wo_b,
                                             out_ptr, M, N, K, 0);

    // Flash chunk 2 (bh 16..31, batch 1) — needs qkv_b1.
    cudaStreamWaitEvent(0, evQ1, 0);
    flash_mma_kernel<<<fGrid, 256, FLASH_SMEM>>>(
        qhi_p, qlo_p, khi_p, klo_p, vhi_p, vlo_p,
        mbits, p16, mkt, stats, chi, clo, 16);
    cudaEventRecord(evF2, 0);

    // s1: gemm_out batch 1 after flash_b1.
    cudaStreamWaitEvent(s1, evF2, 0);
    gemm_out<<<gHGrid, 256, GEMM_SMEM, s1>>>(chi, clo, wohi, wolo, wo_b,
                                             out_ptr, M, N, K, MH);
    cudaEventRecord(evJoin, s1);

    // Main: normalize chunk 2 overlaps gemm_out_b1.
    normalize_kernel<<<nGrid, 256>>>(p16, mkt, stats, attn_ptr, 16);

    cudaStreamWaitEvent(0, evJoin, 0);
}